// round 5
// baseline (speedup 1.0000x reference)
#include <cuda_runtime.h>
#include <cuda_bf16.h>

// Problem constants
#define B_  2
#define S_  4096
#define HID_ 1024
#define NH_ 16
#define HD_ 64
#define NL_ 128
#define BH_ (B_*NH_)          // 32
#define SEG_ (S_/NL_)         // 32
#define D_ (NH_*HD_)          // 1024
#define SCALE_ 0.35355339059327373f  // HD^-0.25

// ---------------- device scratch (allocation-free rule: __device__ globals) ----
__device__ float g_Q[B_*NH_*S_*HD_];     // (b,h,s,d) scaled+masked
__device__ float g_K[B_*NH_*S_*HD_];
__device__ float g_V[B_*NH_*S_*HD_];
__device__ float g_ctx[B_*S_*D_];        // attention output, (b,s, h*64+d)
__device__ float g_Ql[BH_*NL_*HD_];
__device__ float g_Kl[BH_*NL_*HD_];
__device__ float g_k2[BH_*NL_*NL_];
__device__ float g_bhmax[BH_];
__device__ float g_k3V[BH_*NL_*HD_];
__device__ float g_W2[BH_*NL_*HD_];

// ---------------- f32x2 helpers -----------------------------------------------
typedef unsigned long long u64;
__device__ __forceinline__ u64 pack2(float x, float y){
    u64 r; asm("mov.b64 %0, {%1, %2};" : "=l"(r) : "f"(x), "f"(y)); return r;
}
__device__ __forceinline__ void unpack2(u64 v, float& x, float& y){
    asm("mov.b64 {%0, %1}, %2;" : "=f"(x), "=f"(y) : "l"(v));
}
__device__ __forceinline__ void fma2(u64& d, u64 a, u64 b){
    asm("fma.rn.f32x2 %0, %1, %2, %0;" : "+l"(d) : "l"(a), "l"(b));
}

// ---------------- GEMM: C = (A @ Bm + bias) * (rowscale?alpha) -----------------
// A: M x 1024 row-major (M = 8192). Bm: 1024 x 1024 row-major.
// mode 0: out[row*1024+col]; mode 1: out[((b*16+h)*4096+s)*64+d] (bhsd).
__global__ __launch_bounds__(256, 2)
void gemm_kernel(const float* __restrict__ A, const float* __restrict__ Bm,
                 const float* __restrict__ bias, const float* __restrict__ rowscale,
                 float alpha, float* __restrict__ out, int mode)
{
    const int Kdim = 1024, N = 1024;
    __shared__ float As[16][128];
    __shared__ float Bs[16][128];
    int tid = threadIdx.x;
    int tx = tid & 15, ty = tid >> 4;

    u64 acc2[8][4];
    #pragma unroll
    for (int i=0;i<8;i++)
        #pragma unroll
        for (int j=0;j<4;j++) acc2[i][j] = 0ULL;

    const float* Ab = A + (size_t)blockIdx.y * 128 * Kdim;
    const float* Bb = Bm + blockIdx.x * 128;

    for (int k0=0; k0<Kdim; k0+=16){
        #pragma unroll
        for (int r=0;r<2;r++){
            int idx = tid + r*256;
            int m  = idx >> 2, k4 = idx & 3;
            float4 v = *(const float4*)(Ab + (size_t)m*Kdim + k0 + k4*4);
            As[k4*4+0][m]=v.x; As[k4*4+1][m]=v.y; As[k4*4+2][m]=v.z; As[k4*4+3][m]=v.w;
        }
        #pragma unroll
        for (int r=0;r<2;r++){
            int idx = tid + r*256;
            int kk = idx >> 5, n4 = idx & 31;
            *(float4*)&Bs[kk][n4*4] = *(const float4*)(Bb + (size_t)(k0+kk)*N + n4*4);
        }
        __syncthreads();
        #pragma unroll
        for (int kk=0; kk<16; kk++){
            float4 af0 = *(const float4*)&As[kk][ty*8];
            float4 af1 = *(const float4*)&As[kk][ty*8+4];
            u64 b2[4];
            b2[0] = *(const u64*)&Bs[kk][tx*8+0];
            b2[1] = *(const u64*)&Bs[kk][tx*8+2];
            b2[2] = *(const u64*)&Bs[kk][tx*8+4];
            b2[3] = *(const u64*)&Bs[kk][tx*8+6];
            float av[8] = {af0.x,af0.y,af0.z,af0.w, af1.x,af1.y,af1.z,af1.w};
            #pragma unroll
            for (int ii=0; ii<8; ii++){
                u64 a2 = pack2(av[ii], av[ii]);
                fma2(acc2[ii][0], a2, b2[0]);
                fma2(acc2[ii][1], a2, b2[1]);
                fma2(acc2[ii][2], a2, b2[2]);
                fma2(acc2[ii][3], a2, b2[3]);
            }
        }
        __syncthreads();
    }

    int rowbase = blockIdx.y*128 + ty*8;
    int colbase = blockIdx.x*128 + tx*8;
    #pragma unroll
    for (int ii=0; ii<8; ii++){
        int row = rowbase + ii;
        float rs = alpha;
        if (rowscale) rs *= rowscale[row];
        #pragma unroll
        for (int jj=0; jj<4; jj++){
            float lo, hi;
            unpack2(acc2[ii][jj], lo, hi);
            int col = colbase + jj*2;
            float c0 = (lo + bias[col])   * rs;
            float c1 = (hi + bias[col+1]) * rs;
            if (mode == 0){
                out[(size_t)row*N + col]     = c0;
                out[(size_t)row*N + col + 1] = c1;
            } else {
                int b = row >> 12, s = row & 4095;
                int h = col >> 6,  d = col & 63;
                float* o = out + ((size_t)(b*NH_ + h)*S_ + s)*HD_ + d;
                o[0] = c0; o[1] = c1;
            }
        }
    }
}

// ---------------- landmarks: Ql/Kl = segment means ------------------------------
__global__ void landmark_kernel(){
    int idx = blockIdx.x*blockDim.x + threadIdx.x;   // < 32*128*64
    int d  = idx & 63;
    int l  = (idx >> 6) & 127;
    int bh = idx >> 13;
    const float* q = g_Q + ((size_t)bh*S_ + l*SEG_)*HD_ + d;
    const float* k = g_K + ((size_t)bh*S_ + l*SEG_)*HD_ + d;
    float sq = 0.f, sk = 0.f;
    #pragma unroll
    for (int j=0; j<SEG_; j++){ sq += q[j*HD_]; sk += k[j*HD_]; }
    g_Ql[idx] = sq * (1.f/SEG_);
    g_Kl[idx] = sk * (1.f/SEG_);
}

// ---------------- k2 = softmax(Ql @ Kl^T) --------------------------------------
__global__ void k2_kernel(){
    int l = blockIdx.x, bh = blockIdx.y, m = threadIdx.x;
    const float4* ql = (const float4*)(g_Ql + ((size_t)bh*NL_ + l)*HD_);
    const float4* kl = (const float4*)(g_Kl + ((size_t)bh*NL_ + m)*HD_);
    float acc = 0.f;
    #pragma unroll
    for (int d4=0; d4<16; d4++){
        float4 a = ql[d4], b = kl[d4];
        acc += a.x*b.x + a.y*b.y + a.z*b.z + a.w*b.w;
    }
    __shared__ float red[128];
    red[m] = acc; __syncthreads();
    for (int off=64; off>0; off>>=1){
        if (m < off) red[m] = fmaxf(red[m], red[m+off]);
        __syncthreads();
    }
    float mx = red[0]; __syncthreads();
    float p = __expf(acc - mx);
    red[m] = p; __syncthreads();
    for (int off=64; off>0; off>>=1){
        if (m < off) red[m] += red[m+off];
        __syncthreads();
    }
    g_k2[((size_t)bh*NL_ + l)*NL_ + m] = p / red[0];
}

// ---------------- column sums of k2 -> per-bh max (Newton init scalar) ---------
__global__ void colmax_kernel(){
    int bh = blockIdx.x, m = threadIdx.x;
    float s = 0.f;
    for (int l=0; l<NL_; l++) s += g_k2[((size_t)bh*NL_ + l)*NL_ + m];
    __shared__ float red[128];
    red[m] = s; __syncthreads();
    for (int off=64; off>0; off>>=1){
        if (m < off) red[m] = fmaxf(red[m], red[m+off]);
        __syncthreads();
    }
    if (m == 0) g_bhmax[bh] = red[0];
}

// ---------------- k3V = softmax(Ql@K^T - 1e9(1-mask)) @ V  (online softmax) ----
__global__ void k3_kernel(const float* __restrict__ mask){
    __shared__ float Qls[16*64];
    __shared__ float Kt[64*65];
    __shared__ float Vc[64*64];
    __shared__ float psm[8*2*64];
    int lg = blockIdx.x;          // landmark group (16 each)
    int bh = blockIdx.y;
    int tid = threadIdx.x;        // 256
    int w = tid >> 5, lane = tid & 31;
    int b = bh >> 4;
    int l0 = lg * 16;

    for (int i = tid; i < 16*64; i += 256)
        Qls[i] = g_Ql[((size_t)bh*NL_ + l0)*HD_ + i];
    __syncthreads();

    const float* Kbh = g_K + (size_t)bh*S_*HD_;
    const float* Vbh = g_V + (size_t)bh*S_*HD_;
    const float* mrow = mask + (size_t)b*S_;

    float m0=-1e30f, m1=-1e30f, z0=0.f, z1=0.f;
    float o00=0.f,o01=0.f,o10=0.f,o11=0.f;
    const float* q0 = Qls + (w*2+0)*64;
    const float* q1 = Qls + (w*2+1)*64;

    for (int c=0; c<S_/64; c++){
        int s0 = c*64;
        #pragma unroll
        for (int r=0; r<4; r++){
            int idx = tid + r*256;           // (s, d4)
            int s = idx >> 4, d4 = idx & 15;
            float4 kv = *(const float4*)(Kbh + (size_t)(s0+s)*HD_ + d4*4);
            Kt[(d4*4+0)*65 + s] = kv.x;
            Kt[(d4*4+1)*65 + s] = kv.y;
            Kt[(d4*4+2)*65 + s] = kv.z;
            Kt[(d4*4+3)*65 + s] = kv.w;
            float4 vv = *(const float4*)(Vbh + (size_t)(s0+s)*HD_ + d4*4);
            *(float4*)&Vc[s*64 + d4*4] = vv;
        }
        __syncthreads();

        float sc00=0.f,sc01=0.f,sc10=0.f,sc11=0.f;
        #pragma unroll 8
        for (int d=0; d<64; d++){
            float k0v = Kt[d*65 + lane];
            float k1v = Kt[d*65 + lane + 32];
            float a = q0[d], bb = q1[d];
            sc00 += a*k0v;  sc01 += a*k1v;
            sc10 += bb*k0v; sc11 += bb*k1v;
        }
        float mk0 = mrow[s0 + lane], mk1 = mrow[s0 + lane + 32];
        float pen0 = -1e9f*(1.f-mk0), pen1 = -1e9f*(1.f-mk1);
        sc00 += pen0; sc01 += pen1; sc10 += pen0; sc11 += pen1;

        // online softmax, row l0+w*2
        {
            float cm = fmaxf(sc00, sc01);
            #pragma unroll
            for (int off=16; off; off>>=1) cm = fmaxf(cm, __shfl_xor_sync(0xffffffffu, cm, off));
            float mn = fmaxf(m0, cm);
            float corr = __expf(m0 - mn);
            m0 = mn; z0 *= corr; o00 *= corr; o01 *= corr;
            float p0 = __expf(sc00 - mn), p1 = __expf(sc01 - mn);
            float pz = p0 + p1;
            #pragma unroll
            for (int off=16; off; off>>=1) pz += __shfl_xor_sync(0xffffffffu, pz, off);
            z0 += pz;
            psm[(w*2+0)*64 + lane]      = p0;
            psm[(w*2+0)*64 + lane + 32] = p1;
        }
        // row l0+w*2+1
        {
            float cm = fmaxf(sc10, sc11);
            #pragma unroll
            for (int off=16; off; off>>=1) cm = fmaxf(cm, __shfl_xor_sync(0xffffffffu, cm, off));
            float mn = fmaxf(m1, cm);
            float corr = __expf(m1 - mn);
            m1 = mn; z1 *= corr; o10 *= corr; o11 *= corr;
            float p0 = __expf(sc10 - mn), p1 = __expf(sc11 - mn);
            float pz = p0 + p1;
            #pragma unroll
            for (int off=16; off; off>>=1) pz += __shfl_xor_sync(0xffffffffu, pz, off);
            z1 += pz;
            psm[(w*2+1)*64 + lane]      = p0;
            psm[(w*2+1)*64 + lane + 32] = p1;
        }
        __syncwarp();
        #pragma unroll 8
        for (int s=0; s<64; s++){
            float pa = psm[(w*2+0)*64 + s];
            float pb = psm[(w*2+1)*64 + s];
            float v0 = Vc[s*64 + lane], v1 = Vc[s*64 + lane + 32];
            o00 += pa*v0; o01 += pa*v1;
            o10 += pb*v0; o11 += pb*v1;
        }
        __syncwarp();
        __syncthreads();
    }
    int l = l0 + w*2;
    g_k3V[((size_t)bh*NL_ + l)*HD_ + lane]        = o00 / z0;
    g_k3V[((size_t)bh*NL_ + l)*HD_ + lane + 32]   = o01 / z0;
    g_k3V[((size_t)bh*NL_ + l+1)*HD_ + lane]      = o10 / z1;
    g_k3V[((size_t)bh*NL_ + l+1)*HD_ + lane + 32] = o11 / z1;
}

// ---------------- Newton iterative inverse + W2 = inv @ k3V --------------------
__device__ __forceinline__ void mm128(float acc[32], const float* __restrict__ L,
                                      const float* __restrict__ R, int i, int jb){
    #pragma unroll
    for (int j=0;j<32;j++) acc[j]=0.f;
    #pragma unroll 4
    for (int k=0;k<128;k++){
        float lv = L[i*128 + k];
        const float4* rr = (const float4*)(R + k*128 + jb);
        #pragma unroll
        for (int j4=0;j4<8;j4++){
            float4 rv = rr[j4];
            acc[j4*4+0] += lv*rv.x;
            acc[j4*4+1] += lv*rv.y;
            acc[j4*4+2] += lv*rv.z;
            acc[j4*4+3] += lv*rv.w;
        }
    }
}

__global__ __launch_bounds__(512, 1)
void inv_kernel(){
    extern __shared__ float sm[];
    float* Vs = sm;               // 128*128
    float* As = sm + 16384;       // 128*128
    float* Cs = sm + 32768;       // 128*128
    float* Ks = sm + 49152;       // 128*17
    int bh = blockIdx.x;
    int t = threadIdx.x;          // 512
    int i  = t >> 2;
    int jb = (t & 3) * 32;

    float cmax = g_bhmax[0];
    #pragma unroll
    for (int q=1; q<BH_; q++) cmax = fmaxf(cmax, g_bhmax[q]);
    float rinv = 1.f / cmax;

    const float* Kg = g_k2 + (size_t)bh*NL_*NL_;
    // V0 = K^T / c
    #pragma unroll 4
    for (int j=0; j<32; j++)
        Vs[i*128 + jb + j] = Kg[(jb+j)*128 + i] * rinv;
    __syncthreads();

    float acc[32];
    for (int iter=0; iter<6; iter++){
        // A = K @ V  (K streamed from L2 through smem tiles)
        #pragma unroll
        for (int j=0;j<32;j++) acc[j]=0.f;
        for (int k0=0; k0<128; k0+=16){
            #pragma unroll
            for (int r=0; r<4; r++){
                int idx = t + r*512;
                int ii = idx >> 4, kk = idx & 15;
                Ks[ii*17 + kk] = Kg[ii*128 + k0 + kk];
            }
            __syncthreads();
            #pragma unroll
            for (int kk=0; kk<16; kk++){
                float kv = Ks[i*17 + kk];
                const float4* vr = (const float4*)(Vs + (k0+kk)*128 + jb);
                #pragma unroll
                for (int j4=0;j4<8;j4++){
                    float4 rv = vr[j4];
                    acc[j4*4+0] += kv*rv.x;
                    acc[j4*4+1] += kv*rv.y;
                    acc[j4*4+2] += kv*rv.z;
                    acc[j4*4+3] += kv*rv.w;
                }
            }
            __syncthreads();
        }
        #pragma unroll
        for (int j=0;j<32;j++) As[i*128 + jb + j] = acc[j];
        __syncthreads();

        // C = 7A - A@A
        mm128(acc, As, As, i, jb);
        #pragma unroll
        for (int j=0;j<32;j++) Cs[i*128 + jb + j] = 7.f*As[i*128 + jb + j] - acc[j];
        __syncthreads();

        // E = 15A - A@C  (overwrite Cs)
        mm128(acc, As, Cs, i, jb);
        __syncthreads();
        #pragma unroll
        for (int j=0;j<32;j++) Cs[i*128 + jb + j] = 15.f*As[i*128 + jb + j] - acc[j];
        __syncthreads();

        // V = 0.25*(13V - V@E)
        mm128(acc, Vs, Cs, i, jb);
        __syncthreads();
        #pragma unroll
        for (int j=0;j<32;j++)
            Vs[i*128 + jb + j] = 0.25f*(13.f*Vs[i*128 + jb + j] - acc[j]);
        __syncthreads();
    }

    // W2 = inv @ k3V  (128x128 @ 128x64)
    float* Ns = As;
    for (int idx = t; idx < 128*64; idx += 512) Ns[idx] = g_k3V[(size_t)bh*8192 + idx];
    __syncthreads();
    int jb2 = (t & 3) * 16;
    float accw[16];
    #pragma unroll
    for (int j=0;j<16;j++) accw[j]=0.f;
    #pragma unroll 4
    for (int k=0; k<128; k++){
        float v = Vs[i*128 + k];
        const float* nr = Ns + k*64 + jb2;
        #pragma unroll
        for (int j=0;j<16;j++) accw[j] += v * nr[j];
    }
    #pragma unroll
    for (int j=0;j<16;j++) g_W2[(size_t)bh*8192 + i*64 + jb2 + j] = accw[j];
}

// ---------------- k1 fused: ctx = softmax(Q @ Kl^T) @ W2 -----------------------
__global__ __launch_bounds__(256, 4)
void k1_kernel(){
    extern __shared__ float sm[];
    float* Klt = sm;            // [64][128] transposed
    float* W2s = sm + 8192;     // [128][64]
    float* ps  = sm + 16384;    // [8][128]
    int chunk = blockIdx.x;     // 0..7 (512 rows each)
    int bh = blockIdx.y;
    int tid = threadIdx.x;
    int w = tid >> 5, lane = tid & 31;

    for (int idx = tid; idx < 8192; idx += 256){
        int l = idx >> 6, d = idx & 63;
        Klt[d*128 + l] = g_Kl[(size_t)bh*8192 + idx];
    }
    for (int idx = tid; idx < 8192; idx += 256)
        W2s[idx] = g_W2[(size_t)bh*8192 + idx];
    __syncthreads();

    int b = bh >> 4, h = bh & 15;
    for (int it=0; it<64; it++){
        int s = chunk*512 + it*8 + w;
        const float4* Q4 = (const float4*)(g_Q + ((size_t)bh*S_ + s)*HD_);
        float a0=0.f,a1=0.f,a2=0.f,a3=0.f;   // scores for l = lane*4+0..3
        #pragma unroll
        for (int d4=0; d4<16; d4++){
            float4 q = Q4[d4];
            const float* kb = Klt + (d4*4)*128 + lane*4;
            float4 k0 = *(const float4*)(kb);
            float4 k1 = *(const float4*)(kb + 128);
            float4 k2 = *(const float4*)(kb + 256);
            float4 k3 = *(const float4*)(kb + 384);
            a0 += q.x*k0.x + q.y*k1.x + q.z*k2.x + q.w*k3.x;
            a1 += q.x*k0.y + q.y*k1.y + q.z*k2.y + q.w*k3.y;
            a2 += q.x*k0.z + q.y*k1.z + q.z*k2.z + q.w*k3.z;
            a3 += q.x*k0.w + q.y*k1.w + q.z*k2.w + q.w*k3.w;
        }
        float mx = fmaxf(fmaxf(a0,a1), fmaxf(a2,a3));
        #pragma unroll
        for (int off=16; off; off>>=1) mx = fmaxf(mx, __shfl_xor_sync(0xffffffffu, mx, off));
        float p0=__expf(a0-mx), p1=__expf(a1-mx), p2=__expf(a2-mx), p3=__expf(a3-mx);
        float zs = p0+p1+p2+p3;
        #pragma unroll
        for (int off=16; off; off>>=1) zs += __shfl_xor_sync(0xffffffffu, zs, off);
        float zi = 1.f/zs;
        *(float4*)&ps[w*128 + lane*4] = make_float4(p0*zi, p1*zi, p2*zi, p3*zi);
        __syncwarp();

        float o0=0.f, o1=0.f;   // d = lane, lane+32
        const float4* P4 = (const float4*)(ps + w*128);
        #pragma unroll 8
        for (int l4=0; l4<32; l4++){
            float4 p = P4[l4];
            const float* wrow = W2s + l4*4*64;
            o0 += p.x*wrow[lane]      + p.y*wrow[64+lane]
                + p.z*wrow[128+lane]  + p.w*wrow[192+lane];
            o1 += p.x*wrow[32+lane]   + p.y*wrow[96+lane]
                + p.z*wrow[160+lane]  + p.w*wrow[224+lane];
        }
        float* orow = g_ctx + ((size_t)(b*S_ + s))*D_ + h*64;
        orow[lane]      = o0;
        orow[lane + 32] = o1;
        __syncwarp();
    }
}

// ---------------- launch -------------------------------------------------------
extern "C" void kernel_launch(void* const* d_in, const int* in_sizes, int n_in,
                              void* d_out, int out_size)
{
    const float* X    = (const float*)d_in[0];
    const float* mask = (const float*)d_in[1];
    const float* Wq   = (const float*)d_in[2];
    const float* bq   = (const float*)d_in[3];
    const float* Wk   = (const float*)d_in[4];
    const float* bk   = (const float*)d_in[5];
    const float* Wv   = (const float*)d_in[6];
    const float* bv   = (const float*)d_in[7];
    const float* Wo   = (const float*)d_in[8];
    const float* bo   = (const float*)d_in[9];
    float* out = (float*)d_out;

    void *pQ, *pK, *pV, *pctx;
    cudaGetSymbolAddress(&pQ, g_Q);
    cudaGetSymbolAddress(&pK, g_K);
    cudaGetSymbolAddress(&pV, g_V);
    cudaGetSymbolAddress(&pctx, g_ctx);

    static const int INV_SMEM = (16384*3 + 128*17) * 4;   // 205,312 B
    static const int K1_SMEM  = (8192 + 8192 + 1024) * 4; // 69,632 B
    cudaFuncSetAttribute(inv_kernel, cudaFuncAttributeMaxDynamicSharedMemorySize, INV_SMEM);
    cudaFuncSetAttribute(k1_kernel,  cudaFuncAttributeMaxDynamicSharedMemorySize, K1_SMEM);

    dim3 gg(8, 64);   // 1024/128 x 8192/128
    gemm_kernel<<<gg, 256>>>(X, Wq, bq, mask, SCALE_, (float*)pQ, 1);
    gemm_kernel<<<gg, 256>>>(X, Wk, bk, mask, SCALE_, (float*)pK, 1);
    gemm_kernel<<<gg, 256>>>(X, Wv, bv, nullptr, 1.0f, (float*)pV, 1);

    landmark_kernel<<<(BH_*NL_*HD_)/256, 256>>>();
    k2_kernel<<<dim3(NL_, BH_), 128>>>();
    colmax_kernel<<<BH_, 128>>>();
    k3_kernel<<<dim3(8, BH_), 256>>>(mask);
    inv_kernel<<<BH_, 512, INV_SMEM>>>();
    k1_kernel<<<dim3(8, BH_), 256, K1_SMEM>>>();

    gemm_kernel<<<gg, 256>>>((const float*)pctx, Wo, bo, nullptr, 1.0f, out, 0);
}

// round 7
// speedup vs baseline: 1.2413x; 1.2413x over previous
#include <cuda_runtime.h>
#include <cuda_bf16.h>

// Problem constants
#define B_  2
#define S_  4096
#define HID_ 1024
#define NH_ 16
#define HD_ 64
#define NL_ 128
#define BH_ (B_*NH_)          // 32
#define SEG_ (S_/NL_)         // 32
#define D_ (NH_*HD_)          // 1024
#define SCALE_ 0.35355339059327373f  // HD^-0.25

// ---------------- device scratch (allocation-free rule: __device__ globals) ----
__device__ float g_Q[B_*NH_*S_*HD_];     // (b,h,s,d) scaled+masked
__device__ float g_K[B_*NH_*S_*HD_];
__device__ float g_V[B_*NH_*S_*HD_];
__device__ float g_ctx[B_*S_*D_];        // attention output, (b,s, h*64+d)
__device__ float g_Ql[BH_*NL_*HD_];
__device__ float g_Kl[BH_*NL_*HD_];
__device__ float g_k2[BH_*NL_*NL_];
__device__ float g_bhmax[BH_];
__device__ float g_k3V[BH_*NL_*HD_];
__device__ float g_W2[BH_*NL_*HD_];

__device__ __forceinline__ unsigned smem_u32(const void* p){
    unsigned a;
    asm("{ .reg .u64 t; cvta.to.shared.u64 t, %1; cvt.u32.u64 %0, t; }" : "=r"(a) : "l"(p));
    return a;
}

// ---- mma.sync helpers (base-target PTX: works on plain sm_103) ----------------
__device__ __forceinline__ void ldsm4(unsigned& r0, unsigned& r1, unsigned& r2, unsigned& r3,
                                      unsigned addr){
    asm volatile("ldmatrix.sync.aligned.m8n8.x4.shared.b16 {%0,%1,%2,%3}, [%4];"
        : "=r"(r0), "=r"(r1), "=r"(r2), "=r"(r3) : "r"(addr));
}
__device__ __forceinline__ void mma16816(float* c, const unsigned* a, const unsigned* b){
    asm volatile(
        "mma.sync.aligned.m16n8k16.row.col.f32.bf16.bf16.f32 "
        "{%0,%1,%2,%3}, {%4,%5,%6,%7}, {%8,%9}, {%0,%1,%2,%3};"
        : "+f"(c[0]), "+f"(c[1]), "+f"(c[2]), "+f"(c[3])
        : "r"(a[0]), "r"(a[1]), "r"(a[2]), "r"(a[3]), "r"(b[0]), "r"(b[1]));
}
__device__ __forceinline__ unsigned pack_hi(float x, float y, float& lx, float& ly){
    __nv_bfloat162 h = __floats2bfloat162_rn(x, y);
    lx = x - __bfloat162float(h.x);
    ly = y - __bfloat162float(h.y);
    return *(unsigned*)&h;
}
__device__ __forceinline__ unsigned pack_bf2(float x, float y){
    __nv_bfloat162 h = __floats2bfloat162_rn(x, y);
    return *(unsigned*)&h;
}

// ================= HMMA GEMM: C = (A @ Bm + bias) * (rowscale?alpha) ==========
// A: 8192 x 1024 fp32 row-major. Bm: 1024 x 1024 fp32 row-major.
// CTA 128x128, K chunk 16, double-buffered smem, 2-split bf16, 3 products.
// Stage: Ahi[128][24] Alo[128][24] Bhi[128][24] Blo[128][24] bf16 (24 = 16+8 pad)
#define ROWB 48          // bytes per padded row
#define TSZ  (128*ROWB)  // 6144B per tile
#define STAGE_B (4*TSZ)  // 24576B
__global__ __launch_bounds__(256, 2)
void gemm_mma(const float* __restrict__ A, const float* __restrict__ Bm,
              const float* __restrict__ bias, const float* __restrict__ rowscale,
              float alpha, float* __restrict__ out, int mode)
{
    extern __shared__ __align__(16) char smem[];
    const unsigned smb = smem_u32(smem);
    const int tid = threadIdx.x;
    const int w = tid >> 5, lane = tid & 31;
    const int wr = w & 3, wc = w >> 2;          // warp tile: rows wr*32, cols wc*64

    const float* Ab = A + (size_t)blockIdx.y * 128 * 1024;
    const float* Bb = Bm + blockIdx.x * 128;

    // ldmatrix offsets (within a tile) for this lane
    unsigned aoff[2], boff[4];
    {
        int i = lane & 7;
        int t8 = lane >> 3;                      // tile index 0..3
        #pragma unroll
        for (int t = 0; t < 2; t++)
            aoff[t] = (unsigned)((wr*32 + t*16 + (t8 & 1)*8 + i) * ROWB + (t8 >> 1) * 16);
        #pragma unroll
        for (int q = 0; q < 4; q++)
            boff[q] = (unsigned)((wc*64 + q*16 + (t8 >> 1)*8 + i) * ROWB + (t8 & 1) * 16);
    }

    float acc[2][8][4];
    #pragma unroll
    for (int t=0;t<2;t++)
        #pragma unroll
        for (int j=0;j<8;j++)
            #pragma unroll
            for (int e=0;e<4;e++) acc[t][j][e] = 0.f;

    // per-thread load mapping
    // A: idx = tid + r*256 (r=0,1): m = idx>>2, k4 = idx&3  -> float4
    // B: idx = tid + r*256: n = idx&127, kq = idx>>7        -> 4 strided floats
    float4 apre[2];
    float  bpre[2][4];

    // ---- helper macro: convert prefetch regs -> smem stage st, k-chunk base
    #define STORE_STAGE(st) do {                                                   \
        char* sb = smem + (st)*STAGE_B;                                            \
        _Pragma("unroll")                                                          \
        for (int r = 0; r < 2; r++){                                               \
            int idx = tid + r*256;                                                 \
            int m = idx >> 2, k4 = idx & 3;                                        \
            float lx, ly, lz, lw;                                                  \
            unsigned h01 = pack_hi(apre[r].x, apre[r].y, lx, ly);                  \
            unsigned h23 = pack_hi(apre[r].z, apre[r].w, lz, lw);                  \
            unsigned l01 = pack_bf2(lx, ly), l23 = pack_bf2(lz, lw);               \
            *(uint2*)(sb + 0*TSZ + m*ROWB + k4*8) = make_uint2(h01, h23);          \
            *(uint2*)(sb + 1*TSZ + m*ROWB + k4*8) = make_uint2(l01, l23);          \
        }                                                                          \
        _Pragma("unroll")                                                          \
        for (int r = 0; r < 2; r++){                                               \
            int idx = tid + r*256;                                                 \
            int n = idx & 127, kq = idx >> 7;                                      \
            float lx, ly, lz, lw;                                                  \
            unsigned h01 = pack_hi(bpre[r][0], bpre[r][1], lx, ly);                \
            unsigned h23 = pack_hi(bpre[r][2], bpre[r][3], lz, lw);                \
            unsigned l01 = pack_bf2(lx, ly), l23 = pack_bf2(lz, lw);               \
            *(uint2*)(sb + 2*TSZ + n*ROWB + kq*8) = make_uint2(h01, h23);          \
            *(uint2*)(sb + 3*TSZ + n*ROWB + kq*8) = make_uint2(l01, l23);          \
        }                                                                          \
    } while(0)

    #define LOAD_PRE(k0) do {                                                      \
        _Pragma("unroll")                                                          \
        for (int r = 0; r < 2; r++){                                               \
            int idx = tid + r*256;                                                 \
            int m = idx >> 2, k4 = idx & 3;                                        \
            apre[r] = *(const float4*)(Ab + (size_t)m*1024 + (k0) + k4*4);         \
        }                                                                          \
        _Pragma("unroll")                                                          \
        for (int r = 0; r < 2; r++){                                               \
            int idx = tid + r*256;                                                 \
            int n = idx & 127, kq = idx >> 7;                                      \
            const float* src = Bb + (size_t)((k0) + kq*4)*1024 + n;                \
            bpre[r][0] = src[0];    bpre[r][1] = src[1024];                        \
            bpre[r][2] = src[2048]; bpre[r][3] = src[3072];                        \
        }                                                                          \
    } while(0)

    LOAD_PRE(0);
    STORE_STAGE(0);
    __syncthreads();

    for (int s = 0; s < 64; s++){
        int cur = s & 1;
        if (s < 63) LOAD_PRE((s+1)*16);

        unsigned Ah = smb + cur*STAGE_B;
        unsigned Al = Ah + TSZ;
        unsigned Bh = Ah + 2*TSZ;
        unsigned Bl = Ah + 3*TSZ;

        unsigned aR[2][4], bR[4][4];
        #pragma unroll
        for (int p = 0; p < 3; p++){
            unsigned ab = (p == 2) ? Al : Ah;
            unsigned bb = (p == 1) ? Bl : Bh;
            #pragma unroll
            for (int t = 0; t < 2; t++)
                ldsm4(aR[t][0], aR[t][1], aR[t][2], aR[t][3], ab + aoff[t]);
            #pragma unroll
            for (int q = 0; q < 4; q++)
                ldsm4(bR[q][0], bR[q][1], bR[q][2], bR[q][3], bb + boff[q]);
            #pragma unroll
            for (int t = 0; t < 2; t++)
                #pragma unroll
                for (int q = 0; q < 4; q++){
                    mma16816(acc[t][2*q],   aR[t], &bR[q][0]);
                    mma16816(acc[t][2*q+1], aR[t], &bR[q][2]);
                }
        }

        if (s < 63) STORE_STAGE(cur ^ 1);
        __syncthreads();
    }

    // ---- epilogue
    int g = lane >> 2, tg = lane & 3;
    #pragma unroll
    for (int t = 0; t < 2; t++){
        #pragma unroll
        for (int half = 0; half < 2; half++){
            int row = blockIdx.y*128 + wr*32 + t*16 + g + half*8;
            float rs = alpha;
            if (rowscale) rs *= rowscale[row];
            #pragma unroll
            for (int j = 0; j < 8; j++){
                int col = blockIdx.x*128 + wc*64 + j*8 + tg*2;
                float c0 = (acc[t][j][half*2]   + bias[col])   * rs;
                float c1 = (acc[t][j][half*2+1] + bias[col+1]) * rs;
                if (mode == 0){
                    *(float2*)(out + (size_t)row*1024 + col) = make_float2(c0, c1);
                } else {
                    int bb = row >> 12, sI = row & 4095;
                    int h = col >> 6, d = col & 63;
                    *(float2*)(out + ((size_t)(bb*NH_ + h)*S_ + sI)*HD_ + d) = make_float2(c0, c1);
                }
            }
        }
    }
}

// ---------------- landmarks: Ql/Kl = segment means ------------------------------
__global__ void landmark_kernel(){
    int idx = blockIdx.x*blockDim.x + threadIdx.x;   // < 32*128*64
    int d  = idx & 63;
    int l  = (idx >> 6) & 127;
    int bh = idx >> 13;
    const float* q = g_Q + ((size_t)bh*S_ + l*SEG_)*HD_ + d;
    const float* k = g_K + ((size_t)bh*S_ + l*SEG_)*HD_ + d;
    float sq = 0.f, sk = 0.f;
    #pragma unroll
    for (int j=0; j<SEG_; j++){ sq += q[j*HD_]; sk += k[j*HD_]; }
    g_Ql[idx] = sq * (1.f/SEG_);
    g_Kl[idx] = sk * (1.f/SEG_);
}

// ---------------- k2 = softmax(Ql @ Kl^T) --------------------------------------
__global__ void k2_kernel(){
    int l = blockIdx.x, bh = blockIdx.y, m = threadIdx.x;
    const float4* ql = (const float4*)(g_Ql + ((size_t)bh*NL_ + l)*HD_);
    const float4* kl = (const float4*)(g_Kl + ((size_t)bh*NL_ + m)*HD_);
    float acc = 0.f;
    #pragma unroll
    for (int d4=0; d4<16; d4++){
        float4 a = ql[d4], b = kl[d4];
        acc += a.x*b.x + a.y*b.y + a.z*b.z + a.w*b.w;
    }
    __shared__ float red[128];
    red[m] = acc; __syncthreads();
    for (int off=64; off>0; off>>=1){
        if (m < off) red[m] = fmaxf(red[m], red[m+off]);
        __syncthreads();
    }
    float mx = red[0]; __syncthreads();
    float p = __expf(acc - mx);
    red[m] = p; __syncthreads();
    for (int off=64; off>0; off>>=1){
        if (m < off) red[m] += red[m+off];
        __syncthreads();
    }
    g_k2[((size_t)bh*NL_ + l)*NL_ + m] = p / red[0];
}

// ---------------- column sums of k2 -> per-bh max (Newton init scalar) ---------
__global__ void colmax_kernel(){
    int bh = blockIdx.x, m = threadIdx.x;
    float s = 0.f;
    for (int l=0; l<NL_; l++) s += g_k2[((size_t)bh*NL_ + l)*NL_ + m];
    __shared__ float red[128];
    red[m] = s; __syncthreads();
    for (int off=64; off>0; off>>=1){
        if (m < off) red[m] = fmaxf(red[m], red[m+off]);
        __syncthreads();
    }
    if (m == 0) g_bhmax[bh] = red[0];
}

// ---------------- k3V = softmax(Ql@K^T - 1e9(1-mask)) @ V  (online softmax) ----
__global__ void k3_kernel(const float* __restrict__ mask){
    __shared__ float Qls[16*64];
    __shared__ float Kt[64*65];
    __shared__ float Vc[64*64];
    __shared__ float psm[8*2*64];
    int lg = blockIdx.x;          // landmark group (16 each)
    int bh = blockIdx.y;
    int tid = threadIdx.x;        // 256
    int w = tid >> 5, lane = tid & 31;
    int b = bh >> 4;
    int l0 = lg * 16;

    for (int i = tid; i < 16*64; i += 256)
        Qls[i] = g_Ql[((size_t)bh*NL_ + l0)*HD_ + i];
    __syncthreads();

    const float* Kbh = g_K + (size_t)bh*S_*HD_;
    const float* Vbh = g_V + (size_t)bh*S_*HD_;
    const float* mrow = mask + (size_t)b*S_;

    float m0=-1e30f, m1=-1e30f, z0=0.f, z1=0.f;
    float o00=0.f,o01=0.f,o10=0.f,o11=0.f;
    const float* q0 = Qls + (w*2+0)*64;
    const float* q1 = Qls + (w*2+1)*64;

    for (int c=0; c<S_/64; c++){
        int s0 = c*64;
        #pragma unroll
        for (int r=0; r<4; r++){
            int idx = tid + r*256;           // (s, d4)
            int s = idx >> 4, d4 = idx & 15;
            float4 kv = *(const float4*)(Kbh + (size_t)(s0+s)*HD_ + d4*4);
            Kt[(d4*4+0)*65 + s] = kv.x;
            Kt[(d4*4+1)*65 + s] = kv.y;
            Kt[(d4*4+2)*65 + s] = kv.z;
            Kt[(d4*4+3)*65 + s] = kv.w;
            float4 vv = *(const float4*)(Vbh + (size_t)(s0+s)*HD_ + d4*4);
            *(float4*)&Vc[s*64 + d4*4] = vv;
        }
        __syncthreads();

        float sc00=0.f,sc01=0.f,sc10=0.f,sc11=0.f;
        #pragma unroll 8
        for (int d=0; d<64; d++){
            float k0v = Kt[d*65 + lane];
            float k1v = Kt[d*65 + lane + 32];
            float a = q0[d], bb = q1[d];
            sc00 += a*k0v;  sc01 += a*k1v;
            sc10 += bb*k0v; sc11 += bb*k1v;
        }
        float mk0 = mrow[s0 + lane], mk1 = mrow[s0 + lane + 32];
        float pen0 = -1e9f*(1.f-mk0), pen1 = -1e9f*(1.f-mk1);
        sc00 += pen0; sc01 += pen1; sc10 += pen0; sc11 += pen1;

        {
            float cm = fmaxf(sc00, sc01);
            #pragma unroll
            for (int off=16; off; off>>=1) cm = fmaxf(cm, __shfl_xor_sync(0xffffffffu, cm, off));
            float mn = fmaxf(m0, cm);
            float corr = __expf(m0 - mn);
            m0 = mn; z0 *= corr; o00 *= corr; o01 *= corr;
            float p0 = __expf(sc00 - mn), p1 = __expf(sc01 - mn);
            float pz = p0 + p1;
            #pragma unroll
            for (int off=16; off; off>>=1) pz += __shfl_xor_sync(0xffffffffu, pz, off);
            z0 += pz;
            psm[(w*2+0)*64 + lane]      = p0;
            psm[(w*2+0)*64 + lane + 32] = p1;
        }
        {
            float cm = fmaxf(sc10, sc11);
            #pragma unroll
            for (int off=16; off; off>>=1) cm = fmaxf(cm, __shfl_xor_sync(0xffffffffu, cm, off));
            float mn = fmaxf(m1, cm);
            float corr = __expf(m1 - mn);
            m1 = mn; z1 *= corr; o10 *= corr; o11 *= corr;
            float p0 = __expf(sc10 - mn), p1 = __expf(sc11 - mn);
            float pz = p0 + p1;
            #pragma unroll
            for (int off=16; off; off>>=1) pz += __shfl_xor_sync(0xffffffffu, pz, off);
            z1 += pz;
            psm[(w*2+1)*64 + lane]      = p0;
            psm[(w*2+1)*64 + lane + 32] = p1;
        }
        __syncwarp();
        #pragma unroll 8
        for (int s=0; s<64; s++){
            float pa = psm[(w*2+0)*64 + s];
            float pb = psm[(w*2+1)*64 + s];
            float v0 = Vc[s*64 + lane], v1 = Vc[s*64 + lane + 32];
            o00 += pa*v0; o01 += pa*v1;
            o10 += pb*v0; o11 += pb*v1;
        }
        __syncwarp();
        __syncthreads();
    }
    int l = l0 + w*2;
    g_k3V[((size_t)bh*NL_ + l)*HD_ + lane]        = o00 / z0;
    g_k3V[((size_t)bh*NL_ + l)*HD_ + lane + 32]   = o01 / z0;
    g_k3V[((size_t)bh*NL_ + l+1)*HD_ + lane]      = o10 / z1;
    g_k3V[((size_t)bh*NL_ + l+1)*HD_ + lane + 32] = o11 / z1;
}

// ---------------- Newton iterative inverse + W2 = inv @ k3V --------------------
__device__ __forceinline__ void mm128(float acc[32], const float* __restrict__ L,
                                      const float* __restrict__ R, int i, int jb){
    #pragma unroll
    for (int j=0;j<32;j++) acc[j]=0.f;
    #pragma unroll 4
    for (int k=0;k<128;k++){
        float lv = L[i*128 + k];
        const float4* rr = (const float4*)(R + k*128 + jb);
        #pragma unroll
        for (int j4=0;j4<8;j4++){
            float4 rv = rr[j4];
            acc[j4*4+0] += lv*rv.x;
            acc[j4*4+1] += lv*rv.y;
            acc[j4*4+2] += lv*rv.z;
            acc[j4*4+3] += lv*rv.w;
        }
    }
}

__global__ __launch_bounds__(512, 1)
void inv_kernel(){
    extern __shared__ float sm[];
    float* Vs = sm;               // 128*128
    float* As = sm + 16384;       // 128*128
    float* Cs = sm + 32768;       // 128*128
    float* Ks = sm + 49152;       // 128*17
    int bh = blockIdx.x;
    int t = threadIdx.x;          // 512
    int i  = t >> 2;
    int jb = (t & 3) * 32;

    float cmax = g_bhmax[0];
    #pragma unroll
    for (int q=1; q<BH_; q++) cmax = fmaxf(cmax, g_bhmax[q]);
    float rinv = 1.f / cmax;

    const float* Kg = g_k2 + (size_t)bh*NL_*NL_;
    #pragma unroll 4
    for (int j=0; j<32; j++)
        Vs[i*128 + jb + j] = Kg[(jb+j)*128 + i] * rinv;
    __syncthreads();

    float acc[32];
    for (int iter=0; iter<6; iter++){
        #pragma unroll
        for (int j=0;j<32;j++) acc[j]=0.f;
        for (int k0=0; k0<128; k0+=16){
            #pragma unroll
            for (int r=0; r<4; r++){
                int idx = t + r*512;
                int ii = idx >> 4, kk = idx & 15;
                Ks[ii*17 + kk] = Kg[ii*128 + k0 + kk];
            }
            __syncthreads();
            #pragma unroll
            for (int kk=0; kk<16; kk++){
                float kv = Ks[i*17 + kk];
                const float4* vr = (const float4*)(Vs + (k0+kk)*128 + jb);
                #pragma unroll
                for (int j4=0;j4<8;j4++){
                    float4 rv = vr[j4];
                    acc[j4*4+0] += kv*rv.x;
                    acc[j4*4+1] += kv*rv.y;
                    acc[j4*4+2] += kv*rv.z;
                    acc[j4*4+3] += kv*rv.w;
                }
            }
            __syncthreads();
        }
        #pragma unroll
        for (int j=0;j<32;j++) As[i*128 + jb + j] = acc[j];
        __syncthreads();

        mm128(acc, As, As, i, jb);
        #pragma unroll
        for (int j=0;j<32;j++) Cs[i*128 + jb + j] = 7.f*As[i*128 + jb + j] - acc[j];
        __syncthreads();

        mm128(acc, As, Cs, i, jb);
        __syncthreads();
        #pragma unroll
        for (int j=0;j<32;j++) Cs[i*128 + jb + j] = 15.f*As[i*128 + jb + j] - acc[j];
        __syncthreads();

        mm128(acc, Vs, Cs, i, jb);
        __syncthreads();
        #pragma unroll
        for (int j=0;j<32;j++)
            Vs[i*128 + jb + j] = 0.25f*(13.f*Vs[i*128 + jb + j] - acc[j]);
        __syncthreads();
    }

    float* Ns = As;
    for (int idx = t; idx < 128*64; idx += 512) Ns[idx] = g_k3V[(size_t)bh*8192 + idx];
    __syncthreads();
    int jb2 = (t & 3) * 16;
    float accw[16];
    #pragma unroll
    for (int j=0;j<16;j++) accw[j]=0.f;
    #pragma unroll 4
    for (int k=0; k<128; k++){
        float v = Vs[i*128 + k];
        const float* nr = Ns + k*64 + jb2;
        #pragma unroll
        for (int j=0;j<16;j++) accw[j] += v * nr[j];
    }
    #pragma unroll
    for (int j=0;j<16;j++) g_W2[(size_t)bh*8192 + i*64 + jb2 + j] = accw[j];
}

// ---------------- k1 fused: ctx = softmax(Q @ Kl^T) @ W2 -----------------------
__global__ __launch_bounds__(256, 4)
void k1_kernel(){
    extern __shared__ float sm[];
    float* Klt = sm;            // [64][128] transposed
    float* W2s = sm + 8192;     // [128][64]
    float* ps  = sm + 16384;    // [8][128]
    int chunk = blockIdx.x;     // 0..7 (512 rows each)
    int bh = blockIdx.y;
    int tid = threadIdx.x;
    int w = tid >> 5, lane = tid & 31;

    for (int idx = tid; idx < 8192; idx += 256){
        int l = idx >> 6, d = idx & 63;
        Klt[d*128 + l] = g_Kl[(size_t)bh*8192 + idx];
    }
    for (int idx = tid; idx < 8192; idx += 256)
        W2s[idx] = g_W2[(size_t)bh*8192 + idx];
    __syncthreads();

    int b = bh >> 4, h = bh & 15;
    for (int it=0; it<64; it++){
        int s = chunk*512 + it*8 + w;
        const float4* Q4 = (const float4*)(g_Q + ((size_t)bh*S_ + s)*HD_);
        float a0=0.f,a1=0.f,a2=0.f,a3=0.f;
        #pragma unroll
        for (int d4=0; d4<16; d4++){
            float4 q = Q4[d4];
            const float* kb = Klt + (d4*4)*128 + lane*4;
            float4 k0 = *(const float4*)(kb);
            float4 k1 = *(const float4*)(kb + 128);
            float4 k2 = *(const float4*)(kb + 256);
            float4 k3 = *(const float4*)(kb + 384);
            a0 += q.x*k0.x + q.y*k1.x + q.z*k2.x + q.w*k3.x;
            a1 += q.x*k0.y + q.y*k1.y + q.z*k2.y + q.w*k3.y;
            a2 += q.x*k0.z + q.y*k1.z + q.z*k2.z + q.w*k3.z;
            a3 += q.x*k0.w + q.y*k1.w + q.z*k2.w + q.w*k3.w;
        }
        float mx = fmaxf(fmaxf(a0,a1), fmaxf(a2,a3));
        #pragma unroll
        for (int off=16; off; off>>=1) mx = fmaxf(mx, __shfl_xor_sync(0xffffffffu, mx, off));
        float p0=__expf(a0-mx), p1=__expf(a1-mx), p2=__expf(a2-mx), p3=__expf(a3-mx);
        float zs = p0+p1+p2+p3;
        #pragma unroll
        for (int off=16; off; off>>=1) zs += __shfl_xor_sync(0xffffffffu, zs, off);
        float zi = 1.f/zs;
        *(float4*)&ps[w*128 + lane*4] = make_float4(p0*zi, p1*zi, p2*zi, p3*zi);
        __syncwarp();

        float o0=0.f, o1=0.f;
        const float4* P4 = (const float4*)(ps + w*128);
        #pragma unroll 8
        for (int l4=0; l4<32; l4++){
            float4 p = P4[l4];
            const float* wrow = W2s + l4*4*64;
            o0 += p.x*wrow[lane]      + p.y*wrow[64+lane]
                + p.z*wrow[128+lane]  + p.w*wrow[192+lane];
            o1 += p.x*wrow[32+lane]   + p.y*wrow[96+lane]
                + p.z*wrow[160+lane]  + p.w*wrow[224+lane];
        }
        float* orow = g_ctx + ((size_t)(b*S_ + s))*D_ + h*64;
        orow[lane]      = o0;
        orow[lane + 32] = o1;
        __syncwarp();
    }
}

// ---------------- launch -------------------------------------------------------
extern "C" void kernel_launch(void* const* d_in, const int* in_sizes, int n_in,
                              void* d_out, int out_size)
{
    const float* X    = (const float*)d_in[0];
    const float* mask = (const float*)d_in[1];
    const float* Wq   = (const float*)d_in[2];
    const float* bq   = (const float*)d_in[3];
    const float* Wk   = (const float*)d_in[4];
    const float* bk   = (const float*)d_in[5];
    const float* Wv   = (const float*)d_in[6];
    const float* bv   = (const float*)d_in[7];
    const float* Wo   = (const float*)d_in[8];
    const float* bo   = (const float*)d_in[9];
    float* out = (float*)d_out;

    void *pQ, *pK, *pV, *pctx;
    cudaGetSymbolAddress(&pQ, g_Q);
    cudaGetSymbolAddress(&pK, g_K);
    cudaGetSymbolAddress(&pV, g_V);
    cudaGetSymbolAddress(&pctx, g_ctx);

    static const int GEMM_SMEM = 2 * STAGE_B;             // 49,152 B
    static const int INV_SMEM = (16384*3 + 128*17) * 4;   // 205,312 B
    static const int K1_SMEM  = (8192 + 8192 + 1024) * 4; // 69,632 B
    cudaFuncSetAttribute(gemm_mma, cudaFuncAttributeMaxDynamicSharedMemorySize, GEMM_SMEM);
    cudaFuncSetAttribute(inv_kernel, cudaFuncAttributeMaxDynamicSharedMemorySize, INV_SMEM);
    cudaFuncSetAttribute(k1_kernel,  cudaFuncAttributeMaxDynamicSharedMemorySize, K1_SMEM);

    dim3 gg(8, 64);   // 1024/128 x 8192/128
    gemm_mma<<<gg, 256, GEMM_SMEM>>>(X, Wq, bq, mask, SCALE_, (float*)pQ, 1);
    gemm_mma<<<gg, 256, GEMM_SMEM>>>(X, Wk, bk, mask, SCALE_, (float*)pK, 1);
    gemm_mma<<<gg, 256, GEMM_SMEM>>>(X, Wv, bv, nullptr, 1.0f, (float*)pV, 1);

    landmark_kernel<<<(BH_*NL_*HD_)/256, 256>>>();
    k2_kernel<<<dim3(NL_, BH_), 128>>>();
    colmax_kernel<<<BH_, 128>>>();
    k3_kernel<<<dim3(8, BH_), 256>>>(mask);
    inv_kernel<<<BH_, 512, INV_SMEM>>>();
    k1_kernel<<<dim3(8, BH_), 256, K1_SMEM>>>();

    gemm_mma<<<gg, 256, GEMM_SMEM>>>((const float*)pctx, Wo, bo, nullptr, 1.0f, out, 0);
}

// round 8
// speedup vs baseline: 1.2450x; 1.0029x over previous
#include <cuda_runtime.h>
#include <cuda_bf16.h>

// Problem constants
#define B_  2
#define S_  4096
#define HID_ 1024
#define NH_ 16
#define HD_ 64
#define NL_ 128
#define BH_ (B_*NH_)          // 32
#define SEG_ (S_/NL_)         // 32
#define D_ (NH_*HD_)          // 1024
#define SCALE_ 0.35355339059327373f  // HD^-0.25

// ---------------- device scratch -----------------------------------------------
__device__ float g_Q[B_*NH_*S_*HD_];     // (b,h,s,d) scaled+masked
__device__ float g_K[B_*NH_*S_*HD_];
__device__ float g_V[B_*NH_*S_*HD_];
__device__ float g_Ql[BH_*NL_*HD_];
__device__ float g_Kl[BH_*NL_*HD_];
__device__ float g_k2[BH_*NL_*NL_];
__device__ float g_bhmax[BH_];
__device__ float g_k3V[BH_*NL_*HD_];
__device__ float g_W2[BH_*NL_*HD_];
__device__ __align__(256) __nv_bfloat16 g_Xh[8192*1024];
__device__ __align__(256) __nv_bfloat16 g_Xl[8192*1024];
__device__ __align__(256) __nv_bfloat16 g_Wth[4*1024*1024];   // [4][n][k] q,k,v,o
__device__ __align__(256) __nv_bfloat16 g_Wtl[4*1024*1024];
__device__ __align__(256) __nv_bfloat16 g_ctxh[8192*1024];
__device__ __align__(256) __nv_bfloat16 g_ctxl[8192*1024];

typedef unsigned long long u64;
__device__ __forceinline__ u64 pack2(float x, float y){
    u64 r; asm("mov.b64 %0, {%1, %2};" : "=l"(r) : "f"(x), "f"(y)); return r;
}
__device__ __forceinline__ void unpack2(u64 v, float& x, float& y){
    asm("mov.b64 {%0, %1}, %2;" : "=f"(x), "=f"(y) : "l"(v));
}
__device__ __forceinline__ void fma2(u64& d, u64 a, u64 b){
    asm("fma.rn.f32x2 %0, %1, %2, %0;" : "+l"(d) : "l"(a), "l"(b));
}
__device__ __forceinline__ unsigned smem_u32(const void* p){
    unsigned a;
    asm("{ .reg .u64 t; cvta.to.shared.u64 t, %1; cvt.u32.u64 %0, t; }" : "=r"(a) : "l"(p));
    return a;
}
__device__ __forceinline__ void ldsm4(unsigned& r0, unsigned& r1, unsigned& r2, unsigned& r3,
                                      unsigned addr){
    asm volatile("ldmatrix.sync.aligned.m8n8.x4.shared.b16 {%0,%1,%2,%3}, [%4];"
        : "=r"(r0), "=r"(r1), "=r"(r2), "=r"(r3) : "r"(addr));
}
__device__ __forceinline__ void mma16816(float* c, const unsigned* a, const unsigned* b){
    asm volatile(
        "mma.sync.aligned.m16n8k16.row.col.f32.bf16.bf16.f32 "
        "{%0,%1,%2,%3}, {%4,%5,%6,%7}, {%8,%9}, {%0,%1,%2,%3};"
        : "+f"(c[0]), "+f"(c[1]), "+f"(c[2]), "+f"(c[3])
        : "r"(a[0]), "r"(a[1]), "r"(a[2]), "r"(a[3]), "r"(b[0]), "r"(b[1]));
}
__device__ __forceinline__ void cp16(unsigned dst, const void* src){
    asm volatile("cp.async.cg.shared.global [%0], [%1], 16;" :: "r"(dst), "l"(src));
}
__device__ __forceinline__ void cpcommit(){ asm volatile("cp.async.commit_group;" ::: "memory"); }
template<int N> __device__ __forceinline__ void cpwait(){
    asm volatile("cp.async.wait_group %0;" :: "n"(N) : "memory");
}

// ---------------- prep: split X into bf16 hi/lo --------------------------------
__global__ void convX_kernel(const float* __restrict__ X){
    size_t i4 = (size_t)blockIdx.x * blockDim.x + threadIdx.x;  // float4 index
    float4 v = ((const float4*)X)[i4];
    float vs[4] = {v.x, v.y, v.z, v.w};
    __nv_bfloat16 hi[4], lo[4];
    #pragma unroll
    for (int c = 0; c < 4; c++){
        hi[c] = __float2bfloat16(vs[c]);
        lo[c] = __float2bfloat16(vs[c] - __bfloat162float(hi[c]));
    }
    *(uint2*)&g_Xh[i4*4] = *(uint2*)hi;
    *(uint2*)&g_Xl[i4*4] = *(uint2*)lo;
}

// ---------------- prep: transpose+split weights -> [n][k] bf16 hi/lo -----------
__global__ void convW_kernel(const float* __restrict__ Wq, const float* __restrict__ Wk,
                             const float* __restrict__ Wv, const float* __restrict__ Wo){
    __shared__ float t[32][33];
    int z = blockIdx.z;
    const float* W = (z==0) ? Wq : (z==1) ? Wk : (z==2) ? Wv : Wo;
    int n0 = blockIdx.x * 32, k0 = blockIdx.y * 32;
    int tx = threadIdx.x & 31, ty = threadIdx.x >> 5;   // 256 threads
    #pragma unroll
    for (int r = 0; r < 4; r++){
        int ky = ty + r*8;
        t[ky][tx] = W[(size_t)(k0 + ky)*1024 + n0 + tx];
    }
    __syncthreads();
    #pragma unroll
    for (int r = 0; r < 4; r++){
        int ny = ty + r*8;
        float v = t[tx][ny];
        __nv_bfloat16 hi = __float2bfloat16(v);
        __nv_bfloat16 lo = __float2bfloat16(v - __bfloat162float(hi));
        size_t o = (size_t)z*1048576 + (size_t)(n0 + ny)*1024 + k0 + tx;
        g_Wth[o] = hi; g_Wtl[o] = lo;
    }
}

// ================= bf16 HMMA GEMM mainloop =====================================
// A: [M][1024] bf16 hi/lo row-major; B: [n][1024] bf16 hi/lo row-major (B^T layout).
// CTA 128x128, K staged 32, 2-stage cp.async pipeline, 3 split-products.
#define ROWBY 80                 // 32 bf16 data + 8 pad = 80 bytes/row
#define TILEB (128*ROWBY)        // 10240
#define STAGEB (4*TILEB)         // 40960 (Ah,Al,Bh,Bl)
#define GSMEM (2*STAGEB)         // 81920

__device__ __forceinline__ void gemm_main(
    const __nv_bfloat16* __restrict__ Ah, const __nv_bfloat16* __restrict__ Al,
    const __nv_bfloat16* __restrict__ Bh, const __nv_bfloat16* __restrict__ Bl,
    unsigned smb, float acc[2][8][4])
{
    const int tid = threadIdx.x, lane = tid & 31, w = tid >> 5;
    const int wr = w & 3, wc = w >> 2;

    unsigned aoff[2], boff[4];
    {
        int i = lane & 7, t8 = lane >> 3;
        #pragma unroll
        for (int t = 0; t < 2; t++)
            aoff[t] = (unsigned)((wr*32 + t*16 + (t8 & 1)*8 + i) * ROWBY + (t8 >> 1) * 16);
        #pragma unroll
        for (int q = 0; q < 4; q++)
            boff[q] = (unsigned)((wc*64 + q*16 + (t8 >> 1)*8 + i) * ROWBY + (t8 & 1) * 16);
    }

    auto issue = [&](int buf, int k0){
        #pragma unroll
        for (int r = 0; r < 8; r++){
            int idx = r*256 + tid;
            int c = idx & 3, row = (idx >> 2) & 127, tile = idx >> 9;
            const __nv_bfloat16* src =
                (tile == 0) ? Ah + (size_t)row*1024 + k0 + c*8 :
                (tile == 1) ? Al + (size_t)row*1024 + k0 + c*8 :
                (tile == 2) ? Bh + (size_t)row*1024 + k0 + c*8 :
                              Bl + (size_t)row*1024 + k0 + c*8;
            cp16(smb + buf*STAGEB + tile*TILEB + row*ROWBY + c*16, src);
        }
        cpcommit();
    };

    issue(0, 0);
    for (int s = 0; s < 32; s++){
        __syncthreads();
        if (s < 31){ issue((s+1) & 1, (s+1)*32); cpwait<1>(); }
        else       { cpwait<0>(); }
        __syncthreads();

        unsigned base = smb + (s & 1)*STAGEB;
        #pragma unroll
        for (int kb = 0; kb < 2; kb++){
            unsigned ko = kb * 32;
            unsigned aH[2][4], aL[2][4], bX[4][4];
            #pragma unroll
            for (int t = 0; t < 2; t++){
                ldsm4(aH[t][0], aH[t][1], aH[t][2], aH[t][3], base + aoff[t] + ko);
                ldsm4(aL[t][0], aL[t][1], aL[t][2], aL[t][3], base + TILEB + aoff[t] + ko);
            }
            #pragma unroll
            for (int q = 0; q < 4; q++)
                ldsm4(bX[q][0], bX[q][1], bX[q][2], bX[q][3], base + 2*TILEB + boff[q] + ko);
            #pragma unroll
            for (int t = 0; t < 2; t++)
                #pragma unroll
                for (int q = 0; q < 4; q++){
                    mma16816(acc[t][2*q],   aH[t], &bX[q][0]);
                    mma16816(acc[t][2*q+1], aH[t], &bX[q][2]);
                    mma16816(acc[t][2*q],   aL[t], &bX[q][0]);
                    mma16816(acc[t][2*q+1], aL[t], &bX[q][2]);
                }
            #pragma unroll
            for (int q = 0; q < 4; q++)
                ldsm4(bX[q][0], bX[q][1], bX[q][2], bX[q][3], base + 3*TILEB + boff[q] + ko);
            #pragma unroll
            for (int t = 0; t < 2; t++)
                #pragma unroll
                for (int q = 0; q < 4; q++){
                    mma16816(acc[t][2*q],   aH[t], &bX[q][0]);
                    mma16816(acc[t][2*q+1], aH[t], &bX[q][2]);
                }
        }
    }
}

// fused Q/K/V projection GEMM: grid (24, 64)
__global__ __launch_bounds__(256, 2)
void gemm_qkv(const float* __restrict__ bq, const float* __restrict__ bk,
              const float* __restrict__ bv, const float* __restrict__ mask,
              float* __restrict__ oq, float* __restrict__ okk, float* __restrict__ ov)
{
    extern __shared__ __align__(16) char smem[];
    unsigned smb = smem_u32(smem);
    int wsel = blockIdx.x >> 3, colt = blockIdx.x & 7;
    const __nv_bfloat16* Ah = g_Xh + (size_t)blockIdx.y*128*1024;
    const __nv_bfloat16* Al = g_Xl + (size_t)blockIdx.y*128*1024;
    const __nv_bfloat16* Bh = g_Wth + ((size_t)wsel*1024 + colt*128)*1024;
    const __nv_bfloat16* Bl = g_Wtl + ((size_t)wsel*1024 + colt*128)*1024;

    float acc[2][8][4];
    #pragma unroll
    for (int t=0;t<2;t++)
        #pragma unroll
        for (int j=0;j<8;j++)
            #pragma unroll
            for (int e=0;e<4;e++) acc[t][j][e] = 0.f;

    gemm_main(Ah, Al, Bh, Bl, smb, acc);

    const float* bias = (wsel==0) ? bq : (wsel==1) ? bk : bv;
    float* out = (wsel==0) ? oq : (wsel==1) ? okk : ov;
    const bool scaled = (wsel < 2);

    int lane = threadIdx.x & 31, w = threadIdx.x >> 5;
    int wr = w & 3, wc = w >> 2;
    int g = lane >> 2, tg = lane & 3;
    #pragma unroll
    for (int t = 0; t < 2; t++){
        #pragma unroll
        for (int half = 0; half < 2; half++){
            int row = blockIdx.y*128 + wr*32 + t*16 + g + half*8;
            float rs = scaled ? SCALE_ * mask[row] : 1.0f;
            int bb = row >> 12, sI = row & 4095;
            #pragma unroll
            for (int j = 0; j < 8; j++){
                int col = colt*128 + wc*64 + j*8 + tg*2;
                float c0 = (acc[t][j][half*2]   + bias[col])   * rs;
                float c1 = (acc[t][j][half*2+1] + bias[col+1]) * rs;
                int h = col >> 6, d = col & 63;
                *(float2*)(out + ((size_t)(bb*NH_ + h)*S_ + sI)*HD_ + d) = make_float2(c0, c1);
            }
        }
    }
}

// output projection GEMM: grid (8, 64), plain row-major out
__global__ __launch_bounds__(256, 2)
void gemm_out(const float* __restrict__ bias, float* __restrict__ out)
{
    extern __shared__ __align__(16) char smem[];
    unsigned smb = smem_u32(smem);
    const __nv_bfloat16* Ah = g_ctxh + (size_t)blockIdx.y*128*1024;
    const __nv_bfloat16* Al = g_ctxl + (size_t)blockIdx.y*128*1024;
    const __nv_bfloat16* Bh = g_Wth + (size_t)3*1048576 + (size_t)blockIdx.x*128*1024;
    const __nv_bfloat16* Bl = g_Wtl + (size_t)3*1048576 + (size_t)blockIdx.x*128*1024;

    float acc[2][8][4];
    #pragma unroll
    for (int t=0;t<2;t++)
        #pragma unroll
        for (int j=0;j<8;j++)
            #pragma unroll
            for (int e=0;e<4;e++) acc[t][j][e] = 0.f;

    gemm_main(Ah, Al, Bh, Bl, smb, acc);

    int lane = threadIdx.x & 31, w = threadIdx.x >> 5;
    int wr = w & 3, wc = w >> 2;
    int g = lane >> 2, tg = lane & 3;
    #pragma unroll
    for (int t = 0; t < 2; t++){
        #pragma unroll
        for (int half = 0; half < 2; half++){
            int row = blockIdx.y*128 + wr*32 + t*16 + g + half*8;
            #pragma unroll
            for (int j = 0; j < 8; j++){
                int col = blockIdx.x*128 + wc*64 + j*8 + tg*2;
                float c0 = acc[t][j][half*2]   + bias[col];
                float c1 = acc[t][j][half*2+1] + bias[col+1];
                *(float2*)(out + (size_t)row*1024 + col) = make_float2(c0, c1);
            }
        }
    }
}

// ---------------- landmarks: Ql/Kl = segment means ------------------------------
__global__ void landmark_kernel(){
    int idx = blockIdx.x*blockDim.x + threadIdx.x;   // < 32*128*64
    int d  = idx & 63;
    int l  = (idx >> 6) & 127;
    int bh = idx >> 13;
    const float* q = g_Q + ((size_t)bh*S_ + l*SEG_)*HD_ + d;
    const float* k = g_K + ((size_t)bh*S_ + l*SEG_)*HD_ + d;
    float sq = 0.f, sk = 0.f;
    #pragma unroll
    for (int j=0; j<SEG_; j++){ sq += q[j*HD_]; sk += k[j*HD_]; }
    g_Ql[idx] = sq * (1.f/SEG_);
    g_Kl[idx] = sk * (1.f/SEG_);
}

// ---------------- k2 = softmax(Ql @ Kl^T) --------------------------------------
__global__ void k2_kernel(){
    int l = blockIdx.x, bh = blockIdx.y, m = threadIdx.x;
    const float4* ql = (const float4*)(g_Ql + ((size_t)bh*NL_ + l)*HD_);
    const float4* kl = (const float4*)(g_Kl + ((size_t)bh*NL_ + m)*HD_);
    float acc = 0.f;
    #pragma unroll
    for (int d4=0; d4<16; d4++){
        float4 a = ql[d4], b = kl[d4];
        acc += a.x*b.x + a.y*b.y + a.z*b.z + a.w*b.w;
    }
    __shared__ float red[128];
    red[m] = acc; __syncthreads();
    for (int off=64; off>0; off>>=1){
        if (m < off) red[m] = fmaxf(red[m], red[m+off]);
        __syncthreads();
    }
    float mx = red[0]; __syncthreads();
    float p = __expf(acc - mx);
    red[m] = p; __syncthreads();
    for (int off=64; off>0; off>>=1){
        if (m < off) red[m] += red[m+off];
        __syncthreads();
    }
    g_k2[((size_t)bh*NL_ + l)*NL_ + m] = p / red[0];
}

// ---------------- column sums of k2 -> per-bh max ------------------------------
__global__ void colmax_kernel(){
    int bh = blockIdx.x, m = threadIdx.x;
    float s = 0.f;
    for (int l=0; l<NL_; l++) s += g_k2[((size_t)bh*NL_ + l)*NL_ + m];
    __shared__ float red[128];
    red[m] = s; __syncthreads();
    for (int off=64; off>0; off>>=1){
        if (m < off) red[m] = fmaxf(red[m], red[m+off]);
        __syncthreads();
    }
    if (m == 0) g_bhmax[bh] = red[0];
}

// ---------------- k3V = softmax(Ql@K^T - 1e9(1-mask)) @ V ----------------------
__global__ void k3_kernel(const float* __restrict__ mask){
    __shared__ float Qls[16*64];
    __shared__ float Kt[64*65];
    __shared__ float Vc[64*64];
    __shared__ float psm[8*2*64];
    int lg = blockIdx.x;
    int bh = blockIdx.y;
    int tid = threadIdx.x;
    int w = tid >> 5, lane = tid & 31;
    int b = bh >> 4;
    int l0 = lg * 16;

    for (int i = tid; i < 16*64; i += 256)
        Qls[i] = g_Ql[((size_t)bh*NL_ + l0)*HD_ + i];
    __syncthreads();

    const float* Kbh = g_K + (size_t)bh*S_*HD_;
    const float* Vbh = g_V + (size_t)bh*S_*HD_;
    const float* mrow = mask + (size_t)b*S_;

    float m0=-1e30f, m1=-1e30f, z0=0.f, z1=0.f;
    float o00=0.f,o01=0.f,o10=0.f,o11=0.f;
    const float* q0 = Qls + (w*2+0)*64;
    const float* q1 = Qls + (w*2+1)*64;

    for (int c=0; c<S_/64; c++){
        int s0 = c*64;
        #pragma unroll
        for (int r=0; r<4; r++){
            int idx = tid + r*256;
            int s = idx >> 4, d4 = idx & 15;
            float4 kv = *(const float4*)(Kbh + (size_t)(s0+s)*HD_ + d4*4);
            Kt[(d4*4+0)*65 + s] = kv.x;
            Kt[(d4*4+1)*65 + s] = kv.y;
            Kt[(d4*4+2)*65 + s] = kv.z;
            Kt[(d4*4+3)*65 + s] = kv.w;
            float4 vv = *(const float4*)(Vbh + (size_t)(s0+s)*HD_ + d4*4);
            *(float4*)&Vc[s*64 + d4*4] = vv;
        }
        __syncthreads();

        float sc00=0.f,sc01=0.f,sc10=0.f,sc11=0.f;
        #pragma unroll 8
        for (int d=0; d<64; d++){
            float k0v = Kt[d*65 + lane];
            float k1v = Kt[d*65 + lane + 32];
            float a = q0[d], bb = q1[d];
            sc00 += a*k0v;  sc01 += a*k1v;
            sc10 += bb*k0v; sc11 += bb*k1v;
        }
        float mk0 = mrow[s0 + lane], mk1 = mrow[s0 + lane + 32];
        float pen0 = -1e9f*(1.f-mk0), pen1 = -1e9f*(1.f-mk1);
        sc00 += pen0; sc01 += pen1; sc10 += pen0; sc11 += pen1;

        {
            float cm = fmaxf(sc00, sc01);
            #pragma unroll
            for (int off=16; off; off>>=1) cm = fmaxf(cm, __shfl_xor_sync(0xffffffffu, cm, off));
            float mn = fmaxf(m0, cm);
            float corr = __expf(m0 - mn);
            m0 = mn; z0 *= corr; o00 *= corr; o01 *= corr;
            float p0 = __expf(sc00 - mn), p1 = __expf(sc01 - mn);
            float pz = p0 + p1;
            #pragma unroll
            for (int off=16; off; off>>=1) pz += __shfl_xor_sync(0xffffffffu, pz, off);
            z0 += pz;
            psm[(w*2+0)*64 + lane]      = p0;
            psm[(w*2+0)*64 + lane + 32] = p1;
        }
        {
            float cm = fmaxf(sc10, sc11);
            #pragma unroll
            for (int off=16; off; off>>=1) cm = fmaxf(cm, __shfl_xor_sync(0xffffffffu, cm, off));
            float mn = fmaxf(m1, cm);
            float corr = __expf(m1 - mn);
            m1 = mn; z1 *= corr; o10 *= corr; o11 *= corr;
            float p0 = __expf(sc10 - mn), p1 = __expf(sc11 - mn);
            float pz = p0 + p1;
            #pragma unroll
            for (int off=16; off; off>>=1) pz += __shfl_xor_sync(0xffffffffu, pz, off);
            z1 += pz;
            psm[(w*2+1)*64 + lane]      = p0;
            psm[(w*2+1)*64 + lane + 32] = p1;
        }
        __syncwarp();
        #pragma unroll 8
        for (int s=0; s<64; s++){
            float pa = psm[(w*2+0)*64 + s];
            float pb = psm[(w*2+1)*64 + s];
            float v0 = Vc[s*64 + lane], v1 = Vc[s*64 + lane + 32];
            o00 += pa*v0; o01 += pa*v1;
            o10 += pb*v0; o11 += pb*v1;
        }
        __syncwarp();
        __syncthreads();
    }
    int l = l0 + w*2;
    g_k3V[((size_t)bh*NL_ + l)*HD_ + lane]        = o00 / z0;
    g_k3V[((size_t)bh*NL_ + l)*HD_ + lane + 32]   = o01 / z0;
    g_k3V[((size_t)bh*NL_ + l+1)*HD_ + lane]      = o10 / z1;
    g_k3V[((size_t)bh*NL_ + l+1)*HD_ + lane + 32] = o11 / z1;
}

// ---------------- Newton inverse (f32x2) + W2 = inv @ k3V ----------------------
__device__ __forceinline__ void mmx2(u64 acc[16], const float* __restrict__ L,
                                     const float* __restrict__ R, int i, int jb){
    #pragma unroll
    for (int j=0;j<16;j++) acc[j]=0ULL;
    #pragma unroll 2
    for (int k=0;k<128;k++){
        float lv = L[i*128 + k];
        u64 l2 = pack2(lv, lv);
        const u64* rr = (const u64*)(R + k*128 + jb);
        #pragma unroll
        for (int j=0;j<16;j++) fma2(acc[j], l2, rr[j]);
    }
}

__global__ __launch_bounds__(512, 1)
void inv_kernel(){
    extern __shared__ float sm[];
    float* Vs = sm;               // 128*128
    float* As = sm + 16384;
    float* Cs = sm + 32768;
    float* Ks = sm + 49152;       // 128*17
    int bh = blockIdx.x;
    int t = threadIdx.x;          // 512
    int i  = t >> 2;
    int jb = (t & 3) * 32;

    float cmax = g_bhmax[0];
    #pragma unroll
    for (int q=1; q<BH_; q++) cmax = fmaxf(cmax, g_bhmax[q]);
    float rinv = 1.f / cmax;

    const float* Kg = g_k2 + (size_t)bh*NL_*NL_;
    #pragma unroll 4
    for (int j=0; j<32; j++)
        Vs[i*128 + jb + j] = Kg[(jb+j)*128 + i] * rinv;
    __syncthreads();

    u64 acc[16];
    for (int iter=0; iter<6; iter++){
        // A = K @ V
        #pragma unroll
        for (int j=0;j<16;j++) acc[j]=0ULL;
        for (int k0=0; k0<128; k0+=16){
            #pragma unroll
            for (int r=0; r<4; r++){
                int idx = t + r*512;
                int ii = idx >> 4, kk = idx & 15;
                Ks[ii*17 + kk] = Kg[ii*128 + k0 + kk];
            }
            __syncthreads();
            #pragma unroll
            for (int kk=0; kk<16; kk++){
                float kv = Ks[i*17 + kk];
                u64 l2 = pack2(kv, kv);
                const u64* vr = (const u64*)(Vs + (k0+kk)*128 + jb);
                #pragma unroll
                for (int j=0;j<16;j++) fma2(acc[j], l2, vr[j]);
            }
            __syncthreads();
        }
        #pragma unroll
        for (int j=0;j<16;j++){
            float x, y; unpack2(acc[j], x, y);
            As[i*128 + jb + 2*j]     = x;
            As[i*128 + jb + 2*j + 1] = y;
        }
        __syncthreads();

        // C = 7A - A@A
        mmx2(acc, As, As, i, jb);
        #pragma unroll
        for (int j=0;j<16;j++){
            float x, y; unpack2(acc[j], x, y);
            Cs[i*128 + jb + 2*j]     = 7.f*As[i*128 + jb + 2*j]     - x;
            Cs[i*128 + jb + 2*j + 1] = 7.f*As[i*128 + jb + 2*j + 1] - y;
        }
        __syncthreads();

        // E = 15A - A@C  (overwrite Cs)
        mmx2(acc, As, Cs, i, jb);
        __syncthreads();
        #pragma unroll
        for (int j=0;j<16;j++){
            float x, y; unpack2(acc[j], x, y);
            Cs[i*128 + jb + 2*j]     = 15.f*As[i*128 + jb + 2*j]     - x;
            Cs[i*128 + jb + 2*j + 1] = 15.f*As[i*128 + jb + 2*j + 1] - y;
        }
        __syncthreads();

        // V = 0.25*(13V - V@E)
        mmx2(acc, Vs, Cs, i, jb);
        __syncthreads();
        #pragma unroll
        for (int j=0;j<16;j++){
            float x, y; unpack2(acc[j], x, y);
            Vs[i*128 + jb + 2*j]     = 0.25f*(13.f*Vs[i*128 + jb + 2*j]     - x);
            Vs[i*128 + jb + 2*j + 1] = 0.25f*(13.f*Vs[i*128 + jb + 2*j + 1] - y);
        }
        __syncthreads();
    }

    // W2 = inv @ k3V  (128x128 @ 128x64)
    float* Ns = As;
    for (int idx = t; idx < 128*64; idx += 512) Ns[idx] = g_k3V[(size_t)bh*8192 + idx];
    __syncthreads();
    int jb2 = (t & 3) * 16;
    u64 accw[8];
    #pragma unroll
    for (int j=0;j<8;j++) accw[j]=0ULL;
    #pragma unroll 2
    for (int k=0; k<128; k++){
        float v = Vs[i*128 + k];
        u64 v2 = pack2(v, v);
        const u64* nr = (const u64*)(Ns + k*64 + jb2);
        #pragma unroll
        for (int j=0;j<8;j++) fma2(accw[j], v2, nr[j]);
    }
    #pragma unroll
    for (int j=0;j<8;j++){
        float x, y; unpack2(accw[j], x, y);
        g_W2[(size_t)bh*8192 + i*64 + jb2 + 2*j]     = x;
        g_W2[(size_t)bh*8192 + i*64 + jb2 + 2*j + 1] = y;
    }
}

// ---------------- k1 fused: ctx = softmax(Q @ Kl^T) @ W2 (bf16 hi/lo out) ------
__global__ __launch_bounds__(256, 4)
void k1_kernel(){
    extern __shared__ float sm[];
    float* Klt = sm;            // [64][128]
    float* W2s = sm + 8192;     // [128][64]
    float* ps  = sm + 16384;    // [8][128]
    int chunk = blockIdx.x;
    int bh = blockIdx.y;
    int tid = threadIdx.x;
    int w = tid >> 5, lane = tid & 31;

    for (int idx = tid; idx < 8192; idx += 256){
        int l = idx >> 6, d = idx & 63;
        Klt[d*128 + l] = g_Kl[(size_t)bh*8192 + idx];
    }
    for (int idx = tid; idx < 8192; idx += 256)
        W2s[idx] = g_W2[(size_t)bh*8192 + idx];
    __syncthreads();

    int b = bh >> 4, h = bh & 15;
    for (int it=0; it<64; it++){
        int s = chunk*512 + it*8 + w;
        const float4* Q4 = (const float4*)(g_Q + ((size_t)bh*S_ + s)*HD_);
        float a0=0.f,a1=0.f,a2=0.f,a3=0.f;
        #pragma unroll
        for (int d4=0; d4<16; d4++){
            float4 q = Q4[d4];
            const float* kb = Klt + (d4*4)*128 + lane*4;
            float4 k0 = *(const float4*)(kb);
            float4 k1 = *(const float4*)(kb + 128);
            float4 k2 = *(const float4*)(kb + 256);
            float4 k3 = *(const float4*)(kb + 384);
            a0 += q.x*k0.x + q.y*k1.x + q.z*k2.x + q.w*k3.x;
            a1 += q.x*k0.y + q.y*k1.y + q.z*k2.y + q.w*k3.y;
            a2 += q.x*k0.z + q.y*k1.z + q.z*k2.z + q.w*k3.z;
            a3 += q.x*k0.w + q.y*k1.w + q.z*k2.w + q.w*k3.w;
        }
        float mx = fmaxf(fmaxf(a0,a1), fmaxf(a2,a3));
        #pragma unroll
        for (int off=16; off; off>>=1) mx = fmaxf(mx, __shfl_xor_sync(0xffffffffu, mx, off));
        float p0=__expf(a0-mx), p1=__expf(a1-mx), p2=__expf(a2-mx), p3=__expf(a3-mx);
        float zs = p0+p1+p2+p3;
        #pragma unroll
        for (int off=16; off; off>>=1) zs += __shfl_xor_sync(0xffffffffu, zs, off);
        float zi = 1.f/zs;
        *(float4*)&ps[w*128 + lane*4] = make_float4(p0*zi, p1*zi, p2*zi, p3*zi);
        __syncwarp();

        float o0=0.f, o1=0.f;
        const float4* P4 = (const float4*)(ps + w*128);
        #pragma unroll 8
        for (int l4=0; l4<32; l4++){
            float4 p = P4[l4];
            const float* wrow = W2s + l4*4*64;
            o0 += p.x*wrow[lane]      + p.y*wrow[64+lane]
                + p.z*wrow[128+lane]  + p.w*wrow[192+lane];
            o1 += p.x*wrow[32+lane]   + p.y*wrow[96+lane]
                + p.z*wrow[160+lane]  + p.w*wrow[224+lane];
        }
        size_t obase = ((size_t)(b*S_ + s))*D_ + h*64;
        __nv_bfloat16 h0 = __float2bfloat16(o0);
        __nv_bfloat16 h1 = __float2bfloat16(o1);
        g_ctxh[obase + lane]      = h0;
        g_ctxh[obase + lane + 32] = h1;
        g_ctxl[obase + lane]      = __float2bfloat16(o0 - __bfloat162float(h0));
        g_ctxl[obase + lane + 32] = __float2bfloat16(o1 - __bfloat162float(h1));
        __syncwarp();
    }
}

// ---------------- launch -------------------------------------------------------
extern "C" void kernel_launch(void* const* d_in, const int* in_sizes, int n_in,
                              void* d_out, int out_size)
{
    const float* X    = (const float*)d_in[0];
    const float* mask = (const float*)d_in[1];
    const float* Wq   = (const float*)d_in[2];
    const float* bq   = (const float*)d_in[3];
    const float* Wk   = (const float*)d_in[4];
    const float* bk   = (const float*)d_in[5];
    const float* Wv   = (const float*)d_in[6];
    const float* bv   = (const float*)d_in[7];
    const float* Wo   = (const float*)d_in[8];
    const float* bo   = (const float*)d_in[9];
    float* out = (float*)d_out;

    void *pQ, *pK, *pV;
    cudaGetSymbolAddress(&pQ, g_Q);
    cudaGetSymbolAddress(&pK, g_K);
    cudaGetSymbolAddress(&pV, g_V);

    static const int INV_SMEM = (16384*3 + 128*17) * 4;   // 205,312 B
    static const int K1_SMEM  = (8192 + 8192 + 1024) * 4; // 69,632 B
    cudaFuncSetAttribute(gemm_qkv, cudaFuncAttributeMaxDynamicSharedMemorySize, GSMEM);
    cudaFuncSetAttribute(gemm_out, cudaFuncAttributeMaxDynamicSharedMemorySize, GSMEM);
    cudaFuncSetAttribute(inv_kernel, cudaFuncAttributeMaxDynamicSharedMemorySize, INV_SMEM);
    cudaFuncSetAttribute(k1_kernel,  cudaFuncAttributeMaxDynamicSharedMemorySize, K1_SMEM);

    convX_kernel<<<8192, 256>>>(X);                       // 8192*1024/4/256
    convW_kernel<<<dim3(32,32,4), 256>>>(Wq, Wk, Wv, Wo);

    gemm_qkv<<<dim3(24,64), 256, GSMEM>>>(bq, bk, bv, mask,
                                          (float*)pQ, (float*)pK, (float*)pV);

    landmark_kernel<<<(BH_*NL_*HD_)/256, 256>>>();
    k2_kernel<<<dim3(NL_, BH_), 128>>>();
    colmax_kernel<<<BH_, 128>>>();
    k3_kernel<<<dim3(8, BH_), 256>>>(mask);
    inv_kernel<<<BH_, 512, INV_SMEM>>>();
    k1_kernel<<<dim3(8, BH_), 256, K1_SMEM>>>();

    gemm_out<<<dim3(8,64), 256, GSMEM>>>(bo, out);
}

// round 9
// speedup vs baseline: 3.9933x; 3.2075x over previous
#include <cuda_runtime.h>
#include <cuda_bf16.h>

// Problem constants
#define B_  2
#define S_  4096
#define HID_ 1024
#define NH_ 16
#define HD_ 64
#define NL_ 128
#define BH_ (B_*NH_)          // 32
#define SEG_ (S_/NL_)         // 32
#define D_ (NH_*HD_)          // 1024
#define SCALE_ 0.35355339059327373f  // HD^-0.25

// ---------------- device scratch -----------------------------------------------
__device__ float g_Q[B_*NH_*S_*HD_];     // (b,h,s,d) scaled+masked
__device__ float g_K[B_*NH_*S_*HD_];
__device__ float g_V[B_*NH_*S_*HD_];
__device__ float g_Ql[BH_*NL_*HD_];
__device__ float g_Kl[BH_*NL_*HD_];
__device__ float g_k2[BH_*NL_*NL_];
__device__ float g_bhmax[BH_];
__device__ float g_k3V[BH_*NL_*HD_];
__device__ float g_W2[BH_*NL_*HD_];
__device__ __align__(256) __nv_bfloat16 g_Xh[8192*1024];
__device__ __align__(256) __nv_bfloat16 g_Xl[8192*1024];
__device__ __align__(256) __nv_bfloat16 g_Wth[4*1024*1024];   // [4][n][k] q,k,v,o
__device__ __align__(256) __nv_bfloat16 g_Wtl[4*1024*1024];
__device__ __align__(256) __nv_bfloat16 g_ctxh[8192*1024];
__device__ __align__(256) __nv_bfloat16 g_ctxl[8192*1024];

__device__ __forceinline__ unsigned smem_u32(const void* p){
    unsigned a;
    asm("{ .reg .u64 t; cvta.to.shared.u64 t, %1; cvt.u32.u64 %0, t; }" : "=r"(a) : "l"(p));
    return a;
}
__device__ __forceinline__ void ldsm4(unsigned& r0, unsigned& r1, unsigned& r2, unsigned& r3,
                                      unsigned addr){
    asm volatile("ldmatrix.sync.aligned.m8n8.x4.shared.b16 {%0,%1,%2,%3}, [%4];"
        : "=r"(r0), "=r"(r1), "=r"(r2), "=r"(r3) : "r"(addr));
}
__device__ __forceinline__ void ldsm4t(unsigned& r0, unsigned& r1, unsigned& r2, unsigned& r3,
                                       unsigned addr){
    asm volatile("ldmatrix.sync.aligned.m8n8.x4.trans.shared.b16 {%0,%1,%2,%3}, [%4];"
        : "=r"(r0), "=r"(r1), "=r"(r2), "=r"(r3) : "r"(addr));
}
__device__ __forceinline__ void mma16816(float* c, const unsigned* a, const unsigned* b){
    asm volatile(
        "mma.sync.aligned.m16n8k16.row.col.f32.bf16.bf16.f32 "
        "{%0,%1,%2,%3}, {%4,%5,%6,%7}, {%8,%9}, {%0,%1,%2,%3};"
        : "+f"(c[0]), "+f"(c[1]), "+f"(c[2]), "+f"(c[3])
        : "r"(a[0]), "r"(a[1]), "r"(a[2]), "r"(a[3]), "r"(b[0]), "r"(b[1]));
}
__device__ __forceinline__ unsigned pack_hi(float x, float y, float& lx, float& ly){
    __nv_bfloat162 h = __floats2bfloat162_rn(x, y);
    lx = x - __bfloat162float(h.x);
    ly = y - __bfloat162float(h.y);
    return *(unsigned*)&h;
}
__device__ __forceinline__ unsigned pack_bf2(float x, float y){
    __nv_bfloat162 h = __floats2bfloat162_rn(x, y);
    return *(unsigned*)&h;
}
__device__ __forceinline__ void cp16(unsigned dst, const void* src){
    asm volatile("cp.async.cg.shared.global [%0], [%1], 16;" :: "r"(dst), "l"(src));
}
__device__ __forceinline__ void cpcommit(){ asm volatile("cp.async.commit_group;" ::: "memory"); }
template<int N> __device__ __forceinline__ void cpwait(){
    asm volatile("cp.async.wait_group %0;" :: "n"(N) : "memory");
}

// ---------------- probe (diagnostic: shifts gemm_qkv into ncu capture slot) -----
__global__ void probe_kernel(){
    if (threadIdx.x < BH_) g_bhmax[threadIdx.x] = 0.f;
}

// ---------------- prep: split X into bf16 hi/lo --------------------------------
__global__ void convX_kernel(const float* __restrict__ X){
    size_t i4 = (size_t)blockIdx.x * blockDim.x + threadIdx.x;
    float4 v = ((const float4*)X)[i4];
    float vs[4] = {v.x, v.y, v.z, v.w};
    __nv_bfloat16 hi[4], lo[4];
    #pragma unroll
    for (int c = 0; c < 4; c++){
        hi[c] = __float2bfloat16(vs[c]);
        lo[c] = __float2bfloat16(vs[c] - __bfloat162float(hi[c]));
    }
    *(uint2*)&g_Xh[i4*4] = *(uint2*)hi;
    *(uint2*)&g_Xl[i4*4] = *(uint2*)lo;
}

// ---------------- prep: transpose+split weights -> [n][k] bf16 hi/lo -----------
__global__ void convW_kernel(const float* __restrict__ Wq, const float* __restrict__ Wk,
                             const float* __restrict__ Wv, const float* __restrict__ Wo){
    __shared__ float t[32][33];
    int z = blockIdx.z;
    const float* W = (z==0) ? Wq : (z==1) ? Wk : (z==2) ? Wv : Wo;
    int n0 = blockIdx.x * 32, k0 = blockIdx.y * 32;
    int tx = threadIdx.x & 31, ty = threadIdx.x >> 5;
    #pragma unroll
    for (int r = 0; r < 4; r++){
        int ky = ty + r*8;
        t[ky][tx] = W[(size_t)(k0 + ky)*1024 + n0 + tx];
    }
    __syncthreads();
    #pragma unroll
    for (int r = 0; r < 4; r++){
        int ny = ty + r*8;
        float v = t[tx][ny];
        __nv_bfloat16 hi = __float2bfloat16(v);
        __nv_bfloat16 lo = __float2bfloat16(v - __bfloat162float(hi));
        size_t o = (size_t)z*1048576 + (size_t)(n0 + ny)*1024 + k0 + tx;
        g_Wth[o] = hi; g_Wtl[o] = lo;
    }
}

// ================= bf16 HMMA GEMM mainloop =====================================
#define ROWBY 80
#define TILEB (128*ROWBY)
#define STAGEB (4*TILEB)
#define GSMEM (2*STAGEB)

__device__ __forceinline__ void gemm_main(
    const __nv_bfloat16* __restrict__ Ah, const __nv_bfloat16* __restrict__ Al,
    const __nv_bfloat16* __restrict__ Bh, const __nv_bfloat16* __restrict__ Bl,
    unsigned smb, float acc[2][8][4])
{
    const int tid = threadIdx.x, lane = tid & 31, w = tid >> 5;
    const int wr = w & 3, wc = w >> 2;

    unsigned aoff[2], boff[4];
    {
        int i = lane & 7, t8 = lane >> 3;
        #pragma unroll
        for (int t = 0; t < 2; t++)
            aoff[t] = (unsigned)((wr*32 + t*16 + (t8 & 1)*8 + i) * ROWBY + (t8 >> 1) * 16);
        #pragma unroll
        for (int q = 0; q < 4; q++)
            boff[q] = (unsigned)((wc*64 + q*16 + (t8 >> 1)*8 + i) * ROWBY + (t8 & 1) * 16);
    }

    auto issue = [&](int buf, int k0){
        #pragma unroll
        for (int r = 0; r < 8; r++){
            int idx = r*256 + tid;
            int c = idx & 3, row = (idx >> 2) & 127, tile = idx >> 9;
            const __nv_bfloat16* src =
                (tile == 0) ? Ah + (size_t)row*1024 + k0 + c*8 :
                (tile == 1) ? Al + (size_t)row*1024 + k0 + c*8 :
                (tile == 2) ? Bh + (size_t)row*1024 + k0 + c*8 :
                              Bl + (size_t)row*1024 + k0 + c*8;
            cp16(smb + buf*STAGEB + tile*TILEB + row*ROWBY + c*16, src);
        }
        cpcommit();
    };

    issue(0, 0);
    for (int s = 0; s < 32; s++){
        __syncthreads();
        if (s < 31){ issue((s+1) & 1, (s+1)*32); cpwait<1>(); }
        else       { cpwait<0>(); }
        __syncthreads();

        unsigned base = smb + (s & 1)*STAGEB;
        #pragma unroll
        for (int kb = 0; kb < 2; kb++){
            unsigned ko = kb * 32;
            unsigned aH[2][4], aL[2][4], bX[4][4];
            #pragma unroll
            for (int t = 0; t < 2; t++){
                ldsm4(aH[t][0], aH[t][1], aH[t][2], aH[t][3], base + aoff[t] + ko);
                ldsm4(aL[t][0], aL[t][1], aL[t][2], aL[t][3], base + TILEB + aoff[t] + ko);
            }
            #pragma unroll
            for (int q = 0; q < 4; q++)
                ldsm4(bX[q][0], bX[q][1], bX[q][2], bX[q][3], base + 2*TILEB + boff[q] + ko);
            #pragma unroll
            for (int t = 0; t < 2; t++)
                #pragma unroll
                for (int q = 0; q < 4; q++){
                    mma16816(acc[t][2*q],   aH[t], &bX[q][0]);
                    mma16816(acc[t][2*q+1], aH[t], &bX[q][2]);
                    mma16816(acc[t][2*q],   aL[t], &bX[q][0]);
                    mma16816(acc[t][2*q+1], aL[t], &bX[q][2]);
                }
            #pragma unroll
            for (int q = 0; q < 4; q++)
                ldsm4(bX[q][0], bX[q][1], bX[q][2], bX[q][3], base + 3*TILEB + boff[q] + ko);
            #pragma unroll
            for (int t = 0; t < 2; t++)
                #pragma unroll
                for (int q = 0; q < 4; q++){
                    mma16816(acc[t][2*q],   aH[t], &bX[q][0]);
                    mma16816(acc[t][2*q+1], aH[t], &bX[q][2]);
                }
        }
    }
}

__global__ __launch_bounds__(256, 2)
void gemm_qkv(const float* __restrict__ bq, const float* __restrict__ bk,
              const float* __restrict__ bv, const float* __restrict__ mask,
              float* __restrict__ oq, float* __restrict__ okk, float* __restrict__ ov)
{
    extern __shared__ __align__(16) char smem[];
    unsigned smb = smem_u32(smem);
    int wsel = blockIdx.x >> 3, colt = blockIdx.x & 7;
    const __nv_bfloat16* Ah = g_Xh + (size_t)blockIdx.y*128*1024;
    const __nv_bfloat16* Al = g_Xl + (size_t)blockIdx.y*128*1024;
    const __nv_bfloat16* Bh = g_Wth + ((size_t)wsel*1024 + colt*128)*1024;
    const __nv_bfloat16* Bl = g_Wtl + ((size_t)wsel*1024 + colt*128)*1024;

    float acc[2][8][4];
    #pragma unroll
    for (int t=0;t<2;t++)
        #pragma unroll
        for (int j=0;j<8;j++)
            #pragma unroll
            for (int e=0;e<4;e++) acc[t][j][e] = 0.f;

    gemm_main(Ah, Al, Bh, Bl, smb, acc);

    const float* bias = (wsel==0) ? bq : (wsel==1) ? bk : bv;
    float* out = (wsel==0) ? oq : (wsel==1) ? okk : ov;
    const bool scaled = (wsel < 2);

    int lane = threadIdx.x & 31, w = threadIdx.x >> 5;
    int wr = w & 3, wc = w >> 2;
    int g = lane >> 2, tg = lane & 3;
    #pragma unroll
    for (int t = 0; t < 2; t++){
        #pragma unroll
        for (int half = 0; half < 2; half++){
            int row = blockIdx.y*128 + wr*32 + t*16 + g + half*8;
            float rs = scaled ? SCALE_ * mask[row] : 1.0f;
            int bb = row >> 12, sI = row & 4095;
            #pragma unroll
            for (int j = 0; j < 8; j++){
                int col = colt*128 + wc*64 + j*8 + tg*2;
                float c0 = (acc[t][j][half*2]   + bias[col])   * rs;
                float c1 = (acc[t][j][half*2+1] + bias[col+1]) * rs;
                int h = col >> 6, d = col & 63;
                *(float2*)(out + ((size_t)(bb*NH_ + h)*S_ + sI)*HD_ + d) = make_float2(c0, c1);
            }
        }
    }
}

__global__ __launch_bounds__(256, 2)
void gemm_out(const float* __restrict__ bias, float* __restrict__ out)
{
    extern __shared__ __align__(16) char smem[];
    unsigned smb = smem_u32(smem);
    const __nv_bfloat16* Ah = g_ctxh + (size_t)blockIdx.y*128*1024;
    const __nv_bfloat16* Al = g_ctxl + (size_t)blockIdx.y*128*1024;
    const __nv_bfloat16* Bh = g_Wth + (size_t)3*1048576 + (size_t)blockIdx.x*128*1024;
    const __nv_bfloat16* Bl = g_Wtl + (size_t)3*1048576 + (size_t)blockIdx.x*128*1024;

    float acc[2][8][4];
    #pragma unroll
    for (int t=0;t<2;t++)
        #pragma unroll
        for (int j=0;j<8;j++)
            #pragma unroll
            for (int e=0;e<4;e++) acc[t][j][e] = 0.f;

    gemm_main(Ah, Al, Bh, Bl, smb, acc);

    int lane = threadIdx.x & 31, w = threadIdx.x >> 5;
    int wr = w & 3, wc = w >> 2;
    int g = lane >> 2, tg = lane & 3;
    #pragma unroll
    for (int t = 0; t < 2; t++){
        #pragma unroll
        for (int half = 0; half < 2; half++){
            int row = blockIdx.y*128 + wr*32 + t*16 + g + half*8;
            #pragma unroll
            for (int j = 0; j < 8; j++){
                int col = blockIdx.x*128 + wc*64 + j*8 + tg*2;
                float c0 = acc[t][j][half*2]   + bias[col];
                float c1 = acc[t][j][half*2+1] + bias[col+1];
                *(float2*)(out + (size_t)row*1024 + col) = make_float2(c0, c1);
            }
        }
    }
}

// ---------------- landmarks ----------------------------------------------------
__global__ void landmark_kernel(){
    int idx = blockIdx.x*blockDim.x + threadIdx.x;
    int d  = idx & 63;
    int l  = (idx >> 6) & 127;
    int bh = idx >> 13;
    const float* q = g_Q + ((size_t)bh*S_ + l*SEG_)*HD_ + d;
    const float* k = g_K + ((size_t)bh*S_ + l*SEG_)*HD_ + d;
    float sq = 0.f, sk = 0.f;
    #pragma unroll
    for (int j=0; j<SEG_; j++){ sq += q[j*HD_]; sk += k[j*HD_]; }
    g_Ql[idx] = sq * (1.f/SEG_);
    g_Kl[idx] = sk * (1.f/SEG_);
}

// ---------------- k2 = softmax(Ql @ Kl^T) --------------------------------------
__global__ void k2_kernel(){
    int l = blockIdx.x, bh = blockIdx.y, m = threadIdx.x;
    const float4* ql = (const float4*)(g_Ql + ((size_t)bh*NL_ + l)*HD_);
    const float4* kl = (const float4*)(g_Kl + ((size_t)bh*NL_ + m)*HD_);
    float acc = 0.f;
    #pragma unroll
    for (int d4=0; d4<16; d4++){
        float4 a = ql[d4], b = kl[d4];
        acc += a.x*b.x + a.y*b.y + a.z*b.z + a.w*b.w;
    }
    __shared__ float red[128];
    red[m] = acc; __syncthreads();
    for (int off=64; off>0; off>>=1){
        if (m < off) red[m] = fmaxf(red[m], red[m+off]);
        __syncthreads();
    }
    float mx = red[0]; __syncthreads();
    float p = __expf(acc - mx);
    red[m] = p; __syncthreads();
    for (int off=64; off>0; off>>=1){
        if (m < off) red[m] += red[m+off];
        __syncthreads();
    }
    g_k2[((size_t)bh*NL_ + l)*NL_ + m] = p / red[0];
}

// ---------------- column sums of k2 -> per-bh max ------------------------------
__global__ void colmax_kernel(){
    int bh = blockIdx.x, m = threadIdx.x;
    float s = 0.f;
    for (int l=0; l<NL_; l++) s += g_k2[((size_t)bh*NL_ + l)*NL_ + m];
    __shared__ float red[128];
    red[m] = s; __syncthreads();
    for (int off=64; off>0; off>>=1){
        if (m < off) red[m] = fmaxf(red[m], red[m+off]);
        __syncthreads();
    }
    if (m == 0) g_bhmax[bh] = red[0];
}

// ---------------- k3V = softmax(Ql@K^T - 1e9(1-mask)) @ V ----------------------
__global__ void k3_kernel(const float* __restrict__ mask){
    __shared__ float Qls[16*64];
    __shared__ float Kt[64*65];
    __shared__ float Vc[64*64];
    __shared__ float psm[8*2*64];
    int lg = blockIdx.x;
    int bh = blockIdx.y;
    int tid = threadIdx.x;
    int w = tid >> 5, lane = tid & 31;
    int b = bh >> 4;
    int l0 = lg * 16;

    for (int i = tid; i < 16*64; i += 256)
        Qls[i] = g_Ql[((size_t)bh*NL_ + l0)*HD_ + i];
    __syncthreads();

    const float* Kbh = g_K + (size_t)bh*S_*HD_;
    const float* Vbh = g_V + (size_t)bh*S_*HD_;
    const float* mrow = mask + (size_t)b*S_;

    float m0=-1e30f, m1=-1e30f, z0=0.f, z1=0.f;
    float o00=0.f,o01=0.f,o10=0.f,o11=0.f;
    const float* q0 = Qls + (w*2+0)*64;
    const float* q1 = Qls + (w*2+1)*64;

    for (int c=0; c<S_/64; c++){
        int s0 = c*64;
        #pragma unroll
        for (int r=0; r<4; r++){
            int idx = tid + r*256;
            int s = idx >> 4, d4 = idx & 15;
            float4 kv = *(const float4*)(Kbh + (size_t)(s0+s)*HD_ + d4*4);
            Kt[(d4*4+0)*65 + s] = kv.x;
            Kt[(d4*4+1)*65 + s] = kv.y;
            Kt[(d4*4+2)*65 + s] = kv.z;
            Kt[(d4*4+3)*65 + s] = kv.w;
            float4 vv = *(const float4*)(Vbh + (size_t)(s0+s)*HD_ + d4*4);
            *(float4*)&Vc[s*64 + d4*4] = vv;
        }
        __syncthreads();

        float sc00=0.f,sc01=0.f,sc10=0.f,sc11=0.f;
        #pragma unroll 8
        for (int d=0; d<64; d++){
            float k0v = Kt[d*65 + lane];
            float k1v = Kt[d*65 + lane + 32];
            float a = q0[d], bb = q1[d];
            sc00 += a*k0v;  sc01 += a*k1v;
            sc10 += bb*k0v; sc11 += bb*k1v;
        }
        float mk0 = mrow[s0 + lane], mk1 = mrow[s0 + lane + 32];
        float pen0 = -1e9f*(1.f-mk0), pen1 = -1e9f*(1.f-mk1);
        sc00 += pen0; sc01 += pen1; sc10 += pen0; sc11 += pen1;

        {
            float cm = fmaxf(sc00, sc01);
            #pragma unroll
            for (int off=16; off; off>>=1) cm = fmaxf(cm, __shfl_xor_sync(0xffffffffu, cm, off));
            float mn = fmaxf(m0, cm);
            float corr = __expf(m0 - mn);
            m0 = mn; z0 *= corr; o00 *= corr; o01 *= corr;
            float p0 = __expf(sc00 - mn), p1 = __expf(sc01 - mn);
            float pz = p0 + p1;
            #pragma unroll
            for (int off=16; off; off>>=1) pz += __shfl_xor_sync(0xffffffffu, pz, off);
            z0 += pz;
            psm[(w*2+0)*64 + lane]      = p0;
            psm[(w*2+0)*64 + lane + 32] = p1;
        }
        {
            float cm = fmaxf(sc10, sc11);
            #pragma unroll
            for (int off=16; off; off>>=1) cm = fmaxf(cm, __shfl_xor_sync(0xffffffffu, cm, off));
            float mn = fmaxf(m1, cm);
            float corr = __expf(m1 - mn);
            m1 = mn; z1 *= corr; o10 *= corr; o11 *= corr;
            float p0 = __expf(sc10 - mn), p1 = __expf(sc11 - mn);
            float pz = p0 + p1;
            #pragma unroll
            for (int off=16; off; off>>=1) pz += __shfl_xor_sync(0xffffffffu, pz, off);
            z1 += pz;
            psm[(w*2+1)*64 + lane]      = p0;
            psm[(w*2+1)*64 + lane + 32] = p1;
        }
        __syncwarp();
        #pragma unroll 8
        for (int s=0; s<64; s++){
            float pa = psm[(w*2+0)*64 + s];
            float pb = psm[(w*2+1)*64 + s];
            float v0 = Vc[s*64 + lane], v1 = Vc[s*64 + lane + 32];
            o00 += pa*v0; o01 += pa*v1;
            o10 += pb*v0; o11 += pb*v1;
        }
        __syncwarp();
        __syncthreads();
    }
    int l = l0 + w*2;
    g_k3V[((size_t)bh*NL_ + l)*HD_ + lane]        = o00 / z0;
    g_k3V[((size_t)bh*NL_ + l)*HD_ + lane + 32]   = o01 / z0;
    g_k3V[((size_t)bh*NL_ + l+1)*HD_ + lane]      = o10 / z1;
    g_k3V[((size_t)bh*NL_ + l+1)*HD_ + lane + 32] = o11 / z1;
}

// ---------------- Newton inverse on HMMA (bf16 hi/lo, 3-product) ---------------
// smem slots (row stride 272B, 128 rows each): 0:Vh 1:Vl 2:Ah 3:Al 4:Ch 5:Cl
#define IRS  272
#define IMAT 34816
#define INV_SMEM (6*IMAT)   // 208896

__global__ __launch_bounds__(256, 1)
void inv_kernel(){
    extern __shared__ __align__(16) char ismem[];
    const unsigned smb = smem_u32(ismem);
    const int bh = blockIdx.x, tid = threadIdx.x;
    const int lane = tid & 31, w = tid >> 5;
    const int mw = w & 3, nw = w >> 2;
    const int m0 = mw*32, nb = nw*64;
    const int g = lane >> 2, tg = lane & 3;

    float cmax = g_bhmax[0];
    #pragma unroll
    for (int q=1; q<BH_; q++) cmax = fmaxf(cmax, g_bhmax[q]);
    const float rinv = 1.f / cmax;
    const float* Kg = g_k2 + (size_t)bh*NL_*NL_;

    // V0 = K^T * rinv  (hi/lo bf16 into slots 0/1)
    {
        int i = tid >> 1, h0 = (tid & 1) * 64;
        for (int j = 0; j < 64; j++){
            float v = Kg[(h0 + j)*128 + i] * rinv;
            __nv_bfloat16 hi = __float2bfloat16(v);
            __nv_bfloat16 lo = __float2bfloat16(v - __bfloat162float(hi));
            *(__nv_bfloat16*)(ismem + 0*IMAT + i*IRS + (h0+j)*2) = hi;
            *(__nv_bfloat16*)(ismem + 1*IMAT + i*IRS + (h0+j)*2) = lo;
        }
    }
    __syncthreads();

    unsigned aoff[2], boff[4];
    {
        int i8 = lane & 7, t8 = lane >> 3;
        aoff[0] = (unsigned)((m0 + (t8&1)*8 + i8)*IRS + (t8>>1)*16);
        aoff[1] = aoff[0] + 16*IRS;
        #pragma unroll
        for (int q = 0; q < 4; q++)
            boff[q] = (unsigned)(((t8&1)*8 + i8)*IRS + (nb + q*16 + (t8>>1)*8)*2);
    }

    float P[2][8][4], Aa[2][8][4];

    // P = L(slots Lh,Lh+1) @ R(slots Rh,Rh+1), 3-product
    auto mm_ss = [&](int Lh, int Rh){
        #pragma unroll
        for (int t=0;t<2;t++)
            #pragma unroll
            for (int j=0;j<8;j++)
                #pragma unroll
                for (int e=0;e<4;e++) P[t][j][e] = 0.f;
        unsigned Lb = smb + (unsigned)Lh*IMAT;
        unsigned Rb = smb + (unsigned)Rh*IMAT;
        #pragma unroll
        for (int k = 0; k < 8; k++){
            unsigned aH[2][4], aL[2][4];
            #pragma unroll
            for (int t = 0; t < 2; t++){
                ldsm4(aH[t][0],aH[t][1],aH[t][2],aH[t][3], Lb + aoff[t] + k*32);
                ldsm4(aL[t][0],aL[t][1],aL[t][2],aL[t][3], Lb + IMAT + aoff[t] + k*32);
            }
            #pragma unroll
            for (int q = 0; q < 4; q++){
                unsigned bH[4], bL[4];
                ldsm4t(bH[0],bH[1],bH[2],bH[3], Rb + boff[q] + k*16*IRS);
                ldsm4t(bL[0],bL[1],bL[2],bL[3], Rb + IMAT + boff[q] + k*16*IRS);
                #pragma unroll
                for (int t = 0; t < 2; t++){
                    mma16816(P[t][2*q],   aH[t], bH);
                    mma16816(P[t][2*q+1], aH[t], bH+2);
                    mma16816(P[t][2*q],   aL[t], bH);
                    mma16816(P[t][2*q+1], aL[t], bH+2);
                    mma16816(P[t][2*q],   aH[t], bL);
                    mma16816(P[t][2*q+1], aH[t], bL+2);
                }
            }
        }
    };

    // P = K(global fp32) @ V(slots 0/1)
    auto mm_KV = [&](){
        #pragma unroll
        for (int t=0;t<2;t++)
            #pragma unroll
            for (int j=0;j<8;j++)
                #pragma unroll
                for (int e=0;e<4;e++) P[t][j][e] = 0.f;
        unsigned Rb = smb;
        #pragma unroll
        for (int k = 0; k < 8; k++){
            int k0 = k*16;
            unsigned aH[2][4], aL[2][4];
            #pragma unroll
            for (int t = 0; t < 2; t++){
                int r = m0 + t*16 + g, c = k0 + tg*2;
                float2 v0 = *(const float2*)&Kg[(size_t)r*128 + c];
                float2 v1 = *(const float2*)&Kg[(size_t)(r+8)*128 + c];
                float2 v2 = *(const float2*)&Kg[(size_t)r*128 + c + 8];
                float2 v3 = *(const float2*)&Kg[(size_t)(r+8)*128 + c + 8];
                float lx, ly;
                aH[t][0] = pack_hi(v0.x, v0.y, lx, ly); aL[t][0] = pack_bf2(lx, ly);
                aH[t][1] = pack_hi(v1.x, v1.y, lx, ly); aL[t][1] = pack_bf2(lx, ly);
                aH[t][2] = pack_hi(v2.x, v2.y, lx, ly); aL[t][2] = pack_bf2(lx, ly);
                aH[t][3] = pack_hi(v3.x, v3.y, lx, ly); aL[t][3] = pack_bf2(lx, ly);
            }
            #pragma unroll
            for (int q = 0; q < 4; q++){
                unsigned bH[4], bL[4];
                ldsm4t(bH[0],bH[1],bH[2],bH[3], Rb + boff[q] + k*16*IRS);
                ldsm4t(bL[0],bL[1],bL[2],bL[3], Rb + IMAT + boff[q] + k*16*IRS);
                #pragma unroll
                for (int t = 0; t < 2; t++){
                    mma16816(P[t][2*q],   aH[t], bH);
                    mma16816(P[t][2*q+1], aH[t], bH+2);
                    mma16816(P[t][2*q],   aL[t], bH);
                    mma16816(P[t][2*q+1], aL[t], bH+2);
                    mma16816(P[t][2*q],   aH[t], bL);
                    mma16816(P[t][2*q+1], aH[t], bL+2);
                }
            }
        }
    };

    // store F into slot/slot+1 as hi/lo
    auto store_mat = [&](int slot, float (*F)[8][4]){
        #pragma unroll
        for (int t = 0; t < 2; t++)
            #pragma unroll
            for (int half = 0; half < 2; half++){
                int r = m0 + t*16 + g + half*8;
                #pragma unroll
                for (int j = 0; j < 8; j++){
                    int c = nb + j*8 + tg*2;
                    float x = F[t][j][half*2], y = F[t][j][half*2+1];
                    float lx, ly;
                    unsigned hp = pack_hi(x, y, lx, ly);
                    unsigned lp = pack_bf2(lx, ly);
                    *(unsigned*)(ismem + slot*IMAT + r*IRS + c*2) = hp;
                    *(unsigned*)(ismem + (slot+1)*IMAT + r*IRS + c*2) = lp;
                }
            }
    };

    for (int it = 0; it < 6; it++){
        // A = K @ V
        mm_KV();
        #pragma unroll
        for (int t=0;t<2;t++)
            #pragma unroll
            for (int j=0;j<8;j++)
                #pragma unroll
                for (int e=0;e<4;e++) Aa[t][j][e] = P[t][j][e];
        __syncthreads();
        store_mat(2, Aa);
        __syncthreads();

        // C = 7A - A@A
        mm_ss(2, 2);
        #pragma unroll
        for (int t=0;t<2;t++)
            #pragma unroll
            for (int j=0;j<8;j++)
                #pragma unroll
                for (int e=0;e<4;e++) P[t][j][e] = 7.f*Aa[t][j][e] - P[t][j][e];
        __syncthreads();
        store_mat(4, P);
        __syncthreads();

        // E = 15A - A@C  (overwrite C slot)
        mm_ss(2, 4);
        #pragma unroll
        for (int t=0;t<2;t++)
            #pragma unroll
            for (int j=0;j<8;j++)
                #pragma unroll
                for (int e=0;e<4;e++) P[t][j][e] = 15.f*Aa[t][j][e] - P[t][j][e];
        __syncthreads();
        store_mat(4, P);
        __syncthreads();

        // V = 3.25V - 0.25 * V@E
        mm_ss(0, 4);
        __syncthreads();
        #pragma unroll
        for (int t = 0; t < 2; t++)
            #pragma unroll
            for (int half = 0; half < 2; half++){
                int r = m0 + t*16 + g + half*8;
                #pragma unroll
                for (int j = 0; j < 8; j++){
                    int c = nb + j*8 + tg*2;
                    unsigned hp = *(unsigned*)(ismem + 0*IMAT + r*IRS + c*2);
                    unsigned lp = *(unsigned*)(ismem + 1*IMAT + r*IRS + c*2);
                    __nv_bfloat162 hb = *(__nv_bfloat162*)&hp;
                    __nv_bfloat162 lb = *(__nv_bfloat162*)&lp;
                    float vx = __bfloat162float(hb.x) + __bfloat162float(lb.x);
                    float vy = __bfloat162float(hb.y) + __bfloat162float(lb.y);
                    P[t][j][half*2]   = 3.25f*vx - 0.25f*P[t][j][half*2];
                    P[t][j][half*2+1] = 3.25f*vy - 0.25f*P[t][j][half*2+1];
                }
            }
        store_mat(0, P);
        __syncthreads();
    }

    // W2 = V @ k3V   (128x128 @ 128x64)
    {
        int i = tid >> 1, h0 = (tid & 1) * 32;
        const float* Ng = g_k3V + (size_t)bh*8192;
        for (int j = 0; j < 32; j++){
            float v = Ng[i*64 + h0 + j];
            __nv_bfloat16 hi = __float2bfloat16(v);
            __nv_bfloat16 lo = __float2bfloat16(v - __bfloat162float(hi));
            *(__nv_bfloat16*)(ismem + 2*IMAT + i*IRS + (h0+j)*2) = hi;
            *(__nv_bfloat16*)(ismem + 3*IMAT + i*IRS + (h0+j)*2) = lo;
        }
    }
    __syncthreads();
    {
        unsigned boffW[2];
        int i8 = lane & 7, t8 = lane >> 3;
        int nbW = nw * 32;
        #pragma unroll
        for (int q = 0; q < 2; q++)
            boffW[q] = (unsigned)(((t8&1)*8 + i8)*IRS + (nbW + q*16 + (t8>>1)*8)*2);

        float Pw[2][4][4];
        #pragma unroll
        for (int t=0;t<2;t++)
            #pragma unroll
            for (int j=0;j<4;j++)
                #pragma unroll
                for (int e=0;e<4;e++) Pw[t][j][e] = 0.f;

        #pragma unroll
        for (int k = 0; k < 8; k++){
            unsigned aH[2][4], aL[2][4];
            #pragma unroll
            for (int t = 0; t < 2; t++){
                ldsm4(aH[t][0],aH[t][1],aH[t][2],aH[t][3], smb + aoff[t] + k*32);
                ldsm4(aL[t][0],aL[t][1],aL[t][2],aL[t][3], smb + IMAT + aoff[t] + k*32);
            }
            #pragma unroll
            for (int q = 0; q < 2; q++){
                unsigned bH[4], bL[4];
                ldsm4t(bH[0],bH[1],bH[2],bH[3], smb + 2*IMAT + boffW[q] + k*16*IRS);
                ldsm4t(bL[0],bL[1],bL[2],bL[3], smb + 3*IMAT + boffW[q] + k*16*IRS);
                #pragma unroll
                for (int t = 0; t < 2; t++){
                    mma16816(Pw[t][2*q],   aH[t], bH);
                    mma16816(Pw[t][2*q+1], aH[t], bH+2);
                    mma16816(Pw[t][2*q],   aL[t], bH);
                    mma16816(Pw[t][2*q+1], aL[t], bH+2);
                    mma16816(Pw[t][2*q],   aH[t], bL);
                    mma16816(Pw[t][2*q+1], aH[t], bL+2);
                }
            }
        }
        float* Wg = g_W2 + (size_t)bh*8192;
        #pragma unroll
        for (int t = 0; t < 2; t++)
            #pragma unroll
            for (int half = 0; half < 2; half++){
                int r = m0 + t*16 + g + half*8;
                #pragma unroll
                for (int j = 0; j < 4; j++){
                    int c = nbW + j*8 + tg*2;
                    *(float2*)&Wg[r*64 + c] =
                        make_float2(Pw[t][j][half*2], Pw[t][j][half*2+1]);
                }
            }
    }
}

// ---------------- k1 fused: ctx = softmax(Q @ Kl^T) @ W2 (bf16 hi/lo out) ------
__global__ __launch_bounds__(256, 4)
void k1_kernel(){
    extern __shared__ float sm[];
    float* Klt = sm;            // [64][128]
    float* W2s = sm + 8192;     // [128][64]
    float* ps  = sm + 16384;    // [8][128]
    int chunk = blockIdx.x;
    int bh = blockIdx.y;
    int tid = threadIdx.x;
    int w = tid >> 5, lane = tid & 31;

    for (int idx = tid; idx < 8192; idx += 256){
        int l = idx >> 6, d = idx & 63;
        Klt[d*128 + l] = g_Kl[(size_t)bh*8192 + idx];
    }
    for (int idx = tid; idx < 8192; idx += 256)
        W2s[idx] = g_W2[(size_t)bh*8192 + idx];
    __syncthreads();

    int b = bh >> 4, h = bh & 15;
    for (int it=0; it<64; it++){
        int s = chunk*512 + it*8 + w;
        const float4* Q4 = (const float4*)(g_Q + ((size_t)bh*S_ + s)*HD_);
        float a0=0.f,a1=0.f,a2=0.f,a3=0.f;
        #pragma unroll
        for (int d4=0; d4<16; d4++){
            float4 q = Q4[d4];
            const float* kb = Klt + (d4*4)*128 + lane*4;
            float4 k0 = *(const float4*)(kb);
            float4 k1 = *(const float4*)(kb + 128);
            float4 k2 = *(const float4*)(kb + 256);
            float4 k3 = *(const float4*)(kb + 384);
            a0 += q.x*k0.x + q.y*k1.x + q.z*k2.x + q.w*k3.x;
            a1 += q.x*k0.y + q.y*k1.y + q.z*k2.y + q.w*k3.y;
            a2 += q.x*k0.z + q.y*k1.z + q.z*k2.z + q.w*k3.z;
            a3 += q.x*k0.w + q.y*k1.w + q.z*k2.w + q.w*k3.w;
        }
        float mx = fmaxf(fmaxf(a0,a1), fmaxf(a2,a3));
        #pragma unroll
        for (int off=16; off; off>>=1) mx = fmaxf(mx, __shfl_xor_sync(0xffffffffu, mx, off));
        float p0=__expf(a0-mx), p1=__expf(a1-mx), p2=__expf(a2-mx), p3=__expf(a3-mx);
        float zs = p0+p1+p2+p3;
        #pragma unroll
        for (int off=16; off; off>>=1) zs += __shfl_xor_sync(0xffffffffu, zs, off);
        float zi = 1.f/zs;
        *(float4*)&ps[w*128 + lane*4] = make_float4(p0*zi, p1*zi, p2*zi, p3*zi);
        __syncwarp();

        float o0=0.f, o1=0.f;
        const float4* P4 = (const float4*)(ps + w*128);
        #pragma unroll 8
        for (int l4=0; l4<32; l4++){
            float4 p = P4[l4];
            const float* wrow = W2s + l4*4*64;
            o0 += p.x*wrow[lane]      + p.y*wrow[64+lane]
                + p.z*wrow[128+lane]  + p.w*wrow[192+lane];
            o1 += p.x*wrow[32+lane]   + p.y*wrow[96+lane]
                + p.z*wrow[160+lane]  + p.w*wrow[224+lane];
        }
        size_t obase = ((size_t)(b*S_ + s))*D_ + h*64;
        __nv_bfloat16 h0 = __float2bfloat16(o0);
        __nv_bfloat16 h1 = __float2bfloat16(o1);
        g_ctxh[obase + lane]      = h0;
        g_ctxh[obase + lane + 32] = h1;
        g_ctxl[obase + lane]      = __float2bfloat16(o0 - __bfloat162float(h0));
        g_ctxl[obase + lane + 32] = __float2bfloat16(o1 - __bfloat162float(h1));
        __syncwarp();
    }
}

// ---------------- launch -------------------------------------------------------
extern "C" void kernel_launch(void* const* d_in, const int* in_sizes, int n_in,
                              void* d_out, int out_size)
{
    const float* X    = (const float*)d_in[0];
    const float* mask = (const float*)d_in[1];
    const float* Wq   = (const float*)d_in[2];
    const float* bq   = (const float*)d_in[3];
    const float* Wk   = (const float*)d_in[4];
    const float* bk   = (const float*)d_in[5];
    const float* Wv   = (const float*)d_in[6];
    const float* bv   = (const float*)d_in[7];
    const float* Wo   = (const float*)d_in[8];
    const float* bo   = (const float*)d_in[9];
    float* out = (float*)d_out;

    void *pQ, *pK, *pV;
    cudaGetSymbolAddress(&pQ, g_Q);
    cudaGetSymbolAddress(&pK, g_K);
    cudaGetSymbolAddress(&pV, g_V);

    static const int K1_SMEM  = (8192 + 8192 + 1024) * 4; // 69,632 B
    cudaFuncSetAttribute(gemm_qkv, cudaFuncAttributeMaxDynamicSharedMemorySize, GSMEM);
    cudaFuncSetAttribute(gemm_out, cudaFuncAttributeMaxDynamicSharedMemorySize, GSMEM);
    cudaFuncSetAttribute(inv_kernel, cudaFuncAttributeMaxDynamicSharedMemorySize, INV_SMEM);
    cudaFuncSetAttribute(k1_kernel,  cudaFuncAttributeMaxDynamicSharedMemorySize, K1_SMEM);

    convX_kernel<<<8192, 256>>>(X);                       // launch 1
    convW_kernel<<<dim3(32,32,4), 256>>>(Wq, Wk, Wv, Wo); // launch 2
    probe_kernel<<<1, 32>>>();                            // launch 3 (shifts slot)
    gemm_qkv<<<dim3(24,64), 256, GSMEM>>>(bq, bk, bv, mask,
                                          (float*)pQ, (float*)pK, (float*)pV); // launch 4 <- ncu

    landmark_kernel<<<(BH_*NL_*HD_)/256, 256>>>();
    k2_kernel<<<dim3(NL_, BH_), 128>>>();
    colmax_kernel<<<BH_, 128>>>();
    k3_kernel<<<dim3(8, BH_), 256>>>(mask);
    inv_kernel<<<BH_, 256, INV_SMEM>>>();
    k1_kernel<<<dim3(8, BH_), 256, K1_SMEM>>>();

    gemm_out<<<dim3(8,64), 256, GSMEM>>>(bo, out);
}

// round 10
// speedup vs baseline: 5.1328x; 1.2854x over previous
#include <cuda_runtime.h>
#include <cuda_bf16.h>

// Problem constants
#define B_  2
#define S_  4096
#define HID_ 1024
#define NH_ 16
#define HD_ 64
#define NL_ 128
#define BH_ (B_*NH_)          // 32
#define SEG_ (S_/NL_)         // 32
#define D_ (NH_*HD_)          // 1024
#define SCALE_ 0.35355339059327373f  // HD^-0.25

// ---------------- device scratch -----------------------------------------------
__device__ float g_Q[B_*NH_*S_*HD_];     // (b,h,s,d) scaled+masked
__device__ float g_K[B_*NH_*S_*HD_];
__device__ float g_V[B_*NH_*S_*HD_];
__device__ float g_Ql[BH_*NL_*HD_];
__device__ float g_Kl[BH_*NL_*HD_];
__device__ float g_k2[BH_*NL_*NL_];
__device__ float g_bhmax[BH_];
__device__ float g_k3V[BH_*NL_*HD_];
__device__ float g_W2[BH_*NL_*HD_];
__device__ __align__(256) __nv_bfloat16 g_Xh[8192*1024];
__device__ __align__(256) __nv_bfloat16 g_Xl[8192*1024];
__device__ __align__(256) __nv_bfloat16 g_Wth[4*1024*1024];   // [4][n][k] q,k,v,o
__device__ __align__(256) __nv_bfloat16 g_Wtl[4*1024*1024];
__device__ __align__(256) __nv_bfloat16 g_ctxh[8192*1024];
__device__ __align__(256) __nv_bfloat16 g_ctxl[8192*1024];

__device__ __forceinline__ unsigned smem_u32(const void* p){
    unsigned a;
    asm("{ .reg .u64 t; cvta.to.shared.u64 t, %1; cvt.u32.u64 %0, t; }" : "=r"(a) : "l"(p));
    return a;
}
__device__ __forceinline__ void ldsm4(unsigned& r0, unsigned& r1, unsigned& r2, unsigned& r3,
                                      unsigned addr){
    asm volatile("ldmatrix.sync.aligned.m8n8.x4.shared.b16 {%0,%1,%2,%3}, [%4];"
        : "=r"(r0), "=r"(r1), "=r"(r2), "=r"(r3) : "r"(addr));
}
__device__ __forceinline__ void ldsm4t(unsigned& r0, unsigned& r1, unsigned& r2, unsigned& r3,
                                       unsigned addr){
    asm volatile("ldmatrix.sync.aligned.m8n8.x4.trans.shared.b16 {%0,%1,%2,%3}, [%4];"
        : "=r"(r0), "=r"(r1), "=r"(r2), "=r"(r3) : "r"(addr));
}
__device__ __forceinline__ void mma16816(float* c, const unsigned* a, const unsigned* b){
    asm volatile(
        "mma.sync.aligned.m16n8k16.row.col.f32.bf16.bf16.f32 "
        "{%0,%1,%2,%3}, {%4,%5,%6,%7}, {%8,%9}, {%0,%1,%2,%3};"
        : "+f"(c[0]), "+f"(c[1]), "+f"(c[2]), "+f"(c[3])
        : "r"(a[0]), "r"(a[1]), "r"(a[2]), "r"(a[3]), "r"(b[0]), "r"(b[1]));
}
__device__ __forceinline__ unsigned pack_hi(float x, float y, float& lx, float& ly){
    __nv_bfloat162 h = __floats2bfloat162_rn(x, y);
    lx = x - __bfloat162float(h.x);
    ly = y - __bfloat162float(h.y);
    return *(unsigned*)&h;
}
__device__ __forceinline__ unsigned pack_bf2(float x, float y){
    __nv_bfloat162 h = __floats2bfloat162_rn(x, y);
    return *(unsigned*)&h;
}
__device__ __forceinline__ void cp16(unsigned dst, const void* src){
    asm volatile("cp.async.cg.shared.global [%0], [%1], 16;" :: "r"(dst), "l"(src));
}
__device__ __forceinline__ void cpcommit(){ asm volatile("cp.async.commit_group;" ::: "memory"); }
template<int N> __device__ __forceinline__ void cpwait(){
    asm volatile("cp.async.wait_group %0;" :: "n"(N) : "memory");
}

// ---------------- probe (keeps gemm_qkv in the profiled 4th slot) --------------
__global__ void probe_kernel(){
    if (threadIdx.x < BH_) g_bhmax[threadIdx.x] = 0.f;
}

// ---------------- prep: split X into bf16 hi/lo --------------------------------
__global__ void convX_kernel(const float* __restrict__ X){
    size_t i4 = (size_t)blockIdx.x * blockDim.x + threadIdx.x;
    float4 v = ((const float4*)X)[i4];
    float vs[4] = {v.x, v.y, v.z, v.w};
    __nv_bfloat16 hi[4], lo[4];
    #pragma unroll
    for (int c = 0; c < 4; c++){
        hi[c] = __float2bfloat16(vs[c]);
        lo[c] = __float2bfloat16(vs[c] - __bfloat162float(hi[c]));
    }
    *(uint2*)&g_Xh[i4*4] = *(uint2*)hi;
    *(uint2*)&g_Xl[i4*4] = *(uint2*)lo;
}

// ---------------- prep: transpose+split weights -> [n][k] bf16 hi/lo -----------
__global__ void convW_kernel(const float* __restrict__ Wq, const float* __restrict__ Wk,
                             const float* __restrict__ Wv, const float* __restrict__ Wo){
    __shared__ float t[32][33];
    int z = blockIdx.z;
    const float* W = (z==0) ? Wq : (z==1) ? Wk : (z==2) ? Wv : Wo;
    int n0 = blockIdx.x * 32, k0 = blockIdx.y * 32;
    int tx = threadIdx.x & 31, ty = threadIdx.x >> 5;
    #pragma unroll
    for (int r = 0; r < 4; r++){
        int ky = ty + r*8;
        t[ky][tx] = W[(size_t)(k0 + ky)*1024 + n0 + tx];
    }
    __syncthreads();
    #pragma unroll
    for (int r = 0; r < 4; r++){
        int ny = ty + r*8;
        float v = t[tx][ny];
        __nv_bfloat16 hi = __float2bfloat16(v);
        __nv_bfloat16 lo = __float2bfloat16(v - __bfloat162float(hi));
        size_t o = (size_t)z*1048576 + (size_t)(n0 + ny)*1024 + k0 + tx;
        g_Wth[o] = hi; g_Wtl[o] = lo;
    }
}

// ================= bf16 HMMA GEMM mainloop (unchanged from R9) =================
#define ROWBY 80
#define TILEB (128*ROWBY)
#define STAGEB (4*TILEB)
#define GSMEM (2*STAGEB)

__device__ __forceinline__ void gemm_main(
    const __nv_bfloat16* __restrict__ Ah, const __nv_bfloat16* __restrict__ Al,
    const __nv_bfloat16* __restrict__ Bh, const __nv_bfloat16* __restrict__ Bl,
    unsigned smb, float acc[2][8][4])
{
    const int tid = threadIdx.x, lane = tid & 31, w = tid >> 5;
    const int wr = w & 3, wc = w >> 2;

    unsigned aoff[2], boff[4];
    {
        int i = lane & 7, t8 = lane >> 3;
        #pragma unroll
        for (int t = 0; t < 2; t++)
            aoff[t] = (unsigned)((wr*32 + t*16 + (t8 & 1)*8 + i) * ROWBY + (t8 >> 1) * 16);
        #pragma unroll
        for (int q = 0; q < 4; q++)
            boff[q] = (unsigned)((wc*64 + q*16 + (t8 >> 1)*8 + i) * ROWBY + (t8 & 1) * 16);
    }

    auto issue = [&](int buf, int k0){
        #pragma unroll
        for (int r = 0; r < 8; r++){
            int idx = r*256 + tid;
            int c = idx & 3, row = (idx >> 2) & 127, tile = idx >> 9;
            const __nv_bfloat16* src =
                (tile == 0) ? Ah + (size_t)row*1024 + k0 + c*8 :
                (tile == 1) ? Al + (size_t)row*1024 + k0 + c*8 :
                (tile == 2) ? Bh + (size_t)row*1024 + k0 + c*8 :
                              Bl + (size_t)row*1024 + k0 + c*8;
            cp16(smb + buf*STAGEB + tile*TILEB + row*ROWBY + c*16, src);
        }
        cpcommit();
    };

    issue(0, 0);
    for (int s = 0; s < 32; s++){
        __syncthreads();
        if (s < 31){ issue((s+1) & 1, (s+1)*32); cpwait<1>(); }
        else       { cpwait<0>(); }
        __syncthreads();

        unsigned base = smb + (s & 1)*STAGEB;
        #pragma unroll
        for (int kb = 0; kb < 2; kb++){
            unsigned ko = kb * 32;
            unsigned aH[2][4], aL[2][4], bX[4][4];
            #pragma unroll
            for (int t = 0; t < 2; t++){
                ldsm4(aH[t][0], aH[t][1], aH[t][2], aH[t][3], base + aoff[t] + ko);
                ldsm4(aL[t][0], aL[t][1], aL[t][2], aL[t][3], base + TILEB + aoff[t] + ko);
            }
            #pragma unroll
            for (int q = 0; q < 4; q++)
                ldsm4(bX[q][0], bX[q][1], bX[q][2], bX[q][3], base + 2*TILEB + boff[q] + ko);
            #pragma unroll
            for (int t = 0; t < 2; t++)
                #pragma unroll
                for (int q = 0; q < 4; q++){
                    mma16816(acc[t][2*q],   aH[t], &bX[q][0]);
                    mma16816(acc[t][2*q+1], aH[t], &bX[q][2]);
                    mma16816(acc[t][2*q],   aL[t], &bX[q][0]);
                    mma16816(acc[t][2*q+1], aL[t], &bX[q][2]);
                }
            #pragma unroll
            for (int q = 0; q < 4; q++)
                ldsm4(bX[q][0], bX[q][1], bX[q][2], bX[q][3], base + 3*TILEB + boff[q] + ko);
            #pragma unroll
            for (int t = 0; t < 2; t++)
                #pragma unroll
                for (int q = 0; q < 4; q++){
                    mma16816(acc[t][2*q],   aH[t], &bX[q][0]);
                    mma16816(acc[t][2*q+1], aH[t], &bX[q][2]);
                }
        }
    }
}

__global__ __launch_bounds__(256, 2)
void gemm_qkv(const float* __restrict__ bq, const float* __restrict__ bk,
              const float* __restrict__ bv, const float* __restrict__ mask,
              float* __restrict__ oq, float* __restrict__ okk, float* __restrict__ ov)
{
    extern __shared__ __align__(16) char smem[];
    unsigned smb = smem_u32(smem);
    int wsel = blockIdx.x >> 3, colt = blockIdx.x & 7;
    const __nv_bfloat16* Ah = g_Xh + (size_t)blockIdx.y*128*1024;
    const __nv_bfloat16* Al = g_Xl + (size_t)blockIdx.y*128*1024;
    const __nv_bfloat16* Bh = g_Wth + ((size_t)wsel*1024 + colt*128)*1024;
    const __nv_bfloat16* Bl = g_Wtl + ((size_t)wsel*1024 + colt*128)*1024;

    float acc[2][8][4];
    #pragma unroll
    for (int t=0;t<2;t++)
        #pragma unroll
        for (int j=0;j<8;j++)
            #pragma unroll
            for (int e=0;e<4;e++) acc[t][j][e] = 0.f;

    gemm_main(Ah, Al, Bh, Bl, smb, acc);

    const float* bias = (wsel==0) ? bq : (wsel==1) ? bk : bv;
    float* out = (wsel==0) ? oq : (wsel==1) ? okk : ov;
    const bool scaled = (wsel < 2);

    int lane = threadIdx.x & 31, w = threadIdx.x >> 5;
    int wr = w & 3, wc = w >> 2;
    int g = lane >> 2, tg = lane & 3;
    #pragma unroll
    for (int t = 0; t < 2; t++){
        #pragma unroll
        for (int half = 0; half < 2; half++){
            int row = blockIdx.y*128 + wr*32 + t*16 + g + half*8;
            float rs = scaled ? SCALE_ * mask[row] : 1.0f;
            int bb = row >> 12, sI = row & 4095;
            #pragma unroll
            for (int j = 0; j < 8; j++){
                int col = colt*128 + wc*64 + j*8 + tg*2;
                float c0 = (acc[t][j][half*2]   + bias[col])   * rs;
                float c1 = (acc[t][j][half*2+1] + bias[col+1]) * rs;
                int h = col >> 6, d = col & 63;
                *(float2*)(out + ((size_t)(bb*NH_ + h)*S_ + sI)*HD_ + d) = make_float2(c0, c1);
            }
        }
    }
}

__global__ __launch_bounds__(256, 2)
void gemm_out(const float* __restrict__ bias, float* __restrict__ out)
{
    extern __shared__ __align__(16) char smem[];
    unsigned smb = smem_u32(smem);
    const __nv_bfloat16* Ah = g_ctxh + (size_t)blockIdx.y*128*1024;
    const __nv_bfloat16* Al = g_ctxl + (size_t)blockIdx.y*128*1024;
    const __nv_bfloat16* Bh = g_Wth + (size_t)3*1048576 + (size_t)blockIdx.x*128*1024;
    const __nv_bfloat16* Bl = g_Wtl + (size_t)3*1048576 + (size_t)blockIdx.x*128*1024;

    float acc[2][8][4];
    #pragma unroll
    for (int t=0;t<2;t++)
        #pragma unroll
        for (int j=0;j<8;j++)
            #pragma unroll
            for (int e=0;e<4;e++) acc[t][j][e] = 0.f;

    gemm_main(Ah, Al, Bh, Bl, smb, acc);

    int lane = threadIdx.x & 31, w = threadIdx.x >> 5;
    int wr = w & 3, wc = w >> 2;
    int g = lane >> 2, tg = lane & 3;
    #pragma unroll
    for (int t = 0; t < 2; t++){
        #pragma unroll
        for (int half = 0; half < 2; half++){
            int row = blockIdx.y*128 + wr*32 + t*16 + g + half*8;
            #pragma unroll
            for (int j = 0; j < 8; j++){
                int col = blockIdx.x*128 + wc*64 + j*8 + tg*2;
                float c0 = acc[t][j][half*2]   + bias[col];
                float c1 = acc[t][j][half*2+1] + bias[col+1];
                *(float2*)(out + (size_t)row*1024 + col) = make_float2(c0, c1);
            }
        }
    }
}

// ---------------- landmarks ----------------------------------------------------
__global__ void landmark_kernel(){
    int idx = blockIdx.x*blockDim.x + threadIdx.x;
    int d  = idx & 63;
    int l  = (idx >> 6) & 127;
    int bh = idx >> 13;
    const float* q = g_Q + ((size_t)bh*S_ + l*SEG_)*HD_ + d;
    const float* k = g_K + ((size_t)bh*S_ + l*SEG_)*HD_ + d;
    float sq = 0.f, sk = 0.f;
    #pragma unroll
    for (int j=0; j<SEG_; j++){ sq += q[j*HD_]; sk += k[j*HD_]; }
    g_Ql[idx] = sq * (1.f/SEG_);
    g_Kl[idx] = sk * (1.f/SEG_);
}

// ---------------- k2 = softmax(Ql @ Kl^T) --------------------------------------
__global__ void k2_kernel(){
    int l = blockIdx.x, bh = blockIdx.y, m = threadIdx.x;
    const float4* ql = (const float4*)(g_Ql + ((size_t)bh*NL_ + l)*HD_);
    const float4* kl = (const float4*)(g_Kl + ((size_t)bh*NL_ + m)*HD_);
    float acc = 0.f;
    #pragma unroll
    for (int d4=0; d4<16; d4++){
        float4 a = ql[d4], b = kl[d4];
        acc += a.x*b.x + a.y*b.y + a.z*b.z + a.w*b.w;
    }
    __shared__ float red[128];
    red[m] = acc; __syncthreads();
    for (int off=64; off>0; off>>=1){
        if (m < off) red[m] = fmaxf(red[m], red[m+off]);
        __syncthreads();
    }
    float mx = red[0]; __syncthreads();
    float p = __expf(acc - mx);
    red[m] = p; __syncthreads();
    for (int off=64; off>0; off>>=1){
        if (m < off) red[m] += red[m+off];
        __syncthreads();
    }
    g_k2[((size_t)bh*NL_ + l)*NL_ + m] = p / red[0];
}

// ---------------- column sums of k2 -> per-bh max ------------------------------
__global__ void colmax_kernel(){
    int bh = blockIdx.x, m = threadIdx.x;
    float s = 0.f;
    for (int l=0; l<NL_; l++) s += g_k2[((size_t)bh*NL_ + l)*NL_ + m];
    __shared__ float red[128];
    red[m] = s; __syncthreads();
    for (int off=64; off>0; off>>=1){
        if (m < off) red[m] = fmaxf(red[m], red[m+off]);
        __syncthreads();
    }
    if (m == 0) g_bhmax[bh] = red[0];
}

// ---------------- k3V = softmax(Ql@K^T - 1e9(1-mask)) @ V (SIMT, unchanged) ----
__global__ void k3_kernel(const float* __restrict__ mask){
    __shared__ float Qls[16*64];
    __shared__ float Kt[64*65];
    __shared__ float Vc[64*64];
    __shared__ float psm[8*2*64];
    int lg = blockIdx.x;
    int bh = blockIdx.y;
    int tid = threadIdx.x;
    int w = tid >> 5, lane = tid & 31;
    int b = bh >> 4;
    int l0 = lg * 16;

    for (int i = tid; i < 16*64; i += 256)
        Qls[i] = g_Ql[((size_t)bh*NL_ + l0)*HD_ + i];
    __syncthreads();

    const float* Kbh = g_K + (size_t)bh*S_*HD_;
    const float* Vbh = g_V + (size_t)bh*S_*HD_;
    const float* mrow = mask + (size_t)b*S_;

    float m0=-1e30f, m1=-1e30f, z0=0.f, z1=0.f;
    float o00=0.f,o01=0.f,o10=0.f,o11=0.f;
    const float* q0 = Qls + (w*2+0)*64;
    const float* q1 = Qls + (w*2+1)*64;

    for (int c=0; c<S_/64; c++){
        int s0 = c*64;
        #pragma unroll
        for (int r=0; r<4; r++){
            int idx = tid + r*256;
            int s = idx >> 4, d4 = idx & 15;
            float4 kv = *(const float4*)(Kbh + (size_t)(s0+s)*HD_ + d4*4);
            Kt[(d4*4+0)*65 + s] = kv.x;
            Kt[(d4*4+1)*65 + s] = kv.y;
            Kt[(d4*4+2)*65 + s] = kv.z;
            Kt[(d4*4+3)*65 + s] = kv.w;
            float4 vv = *(const float4*)(Vbh + (size_t)(s0+s)*HD_ + d4*4);
            *(float4*)&Vc[s*64 + d4*4] = vv;
        }
        __syncthreads();

        float sc00=0.f,sc01=0.f,sc10=0.f,sc11=0.f;
        #pragma unroll 8
        for (int d=0; d<64; d++){
            float k0v = Kt[d*65 + lane];
            float k1v = Kt[d*65 + lane + 32];
            float a = q0[d], bb = q1[d];
            sc00 += a*k0v;  sc01 += a*k1v;
            sc10 += bb*k0v; sc11 += bb*k1v;
        }
        float mk0 = mrow[s0 + lane], mk1 = mrow[s0 + lane + 32];
        float pen0 = -1e9f*(1.f-mk0), pen1 = -1e9f*(1.f-mk1);
        sc00 += pen0; sc01 += pen1; sc10 += pen0; sc11 += pen1;

        {
            float cm = fmaxf(sc00, sc01);
            #pragma unroll
            for (int off=16; off; off>>=1) cm = fmaxf(cm, __shfl_xor_sync(0xffffffffu, cm, off));
            float mn = fmaxf(m0, cm);
            float corr = __expf(m0 - mn);
            m0 = mn; z0 *= corr; o00 *= corr; o01 *= corr;
            float p0 = __expf(sc00 - mn), p1 = __expf(sc01 - mn);
            float pz = p0 + p1;
            #pragma unroll
            for (int off=16; off; off>>=1) pz += __shfl_xor_sync(0xffffffffu, pz, off);
            z0 += pz;
            psm[(w*2+0)*64 + lane]      = p0;
            psm[(w*2+0)*64 + lane + 32] = p1;
        }
        {
            float cm = fmaxf(sc10, sc11);
            #pragma unroll
            for (int off=16; off; off>>=1) cm = fmaxf(cm, __shfl_xor_sync(0xffffffffu, cm, off));
            float mn = fmaxf(m1, cm);
            float corr = __expf(m1 - mn);
            m1 = mn; z1 *= corr; o10 *= corr; o11 *= corr;
            float p0 = __expf(sc10 - mn), p1 = __expf(sc11 - mn);
            float pz = p0 + p1;
            #pragma unroll
            for (int off=16; off; off>>=1) pz += __shfl_xor_sync(0xffffffffu, pz, off);
            z1 += pz;
            psm[(w*2+1)*64 + lane]      = p0;
            psm[(w*2+1)*64 + lane + 32] = p1;
        }
        __syncwarp();
        #pragma unroll 8
        for (int s=0; s<64; s++){
            float pa = psm[(w*2+0)*64 + s];
            float pb = psm[(w*2+1)*64 + s];
            float v0 = Vc[s*64 + lane], v1 = Vc[s*64 + lane + 32];
            o00 += pa*v0; o01 += pa*v1;
            o10 += pb*v0; o11 += pb*v1;
        }
        __syncwarp();
        __syncthreads();
    }
    int l = l0 + w*2;
    g_k3V[((size_t)bh*NL_ + l)*HD_ + lane]        = o00 / z0;
    g_k3V[((size_t)bh*NL_ + l)*HD_ + lane + 32]   = o01 / z0;
    g_k3V[((size_t)bh*NL_ + l+1)*HD_ + lane]      = o10 / z1;
    g_k3V[((size_t)bh*NL_ + l+1)*HD_ + lane + 32] = o11 / z1;
}

// ---------------- Newton inverse on HMMA: 512 threads, 16 warps ----------------
// smem slots (row stride 272B, 128 rows each): 0:Vh 1:Vl 2:Ah 3:Al 4:Ch 5:Cl
#define IRS  272
#define IMAT 34816
#define INV_SMEM (6*IMAT)   // 208896

__global__ __launch_bounds__(512, 1)
void inv_kernel(){
    extern __shared__ __align__(16) char ismem[];
    const unsigned smb = smem_u32(ismem);
    const int bh = blockIdx.x, tid = threadIdx.x;
    const int lane = tid & 31, w = tid >> 5;      // 16 warps
    const int mw = w & 7, nw = w >> 3;            // 8 x 2 warp grid
    const int m0 = mw*16, nb = nw*64;
    const int g = lane >> 2, tg = lane & 3;
    const int i8 = lane & 7, t8 = lane >> 3;

    float cmax = g_bhmax[0];
    #pragma unroll
    for (int q=1; q<BH_; q++) cmax = fmaxf(cmax, g_bhmax[q]);
    const float rinv = 1.f / cmax;
    const float* Kg = g_k2 + (size_t)bh*NL_*NL_;

    // V0 = K^T * rinv  (hi/lo bf16 into slots 0/1)
    {
        int i = tid >> 2, h0 = (tid & 3) * 32;
        for (int j = 0; j < 32; j++){
            float v = Kg[(h0 + j)*128 + i] * rinv;
            __nv_bfloat16 hi = __float2bfloat16(v);
            __nv_bfloat16 lo = __float2bfloat16(v - __bfloat162float(hi));
            *(__nv_bfloat16*)(ismem + 0*IMAT + i*IRS + (h0+j)*2) = hi;
            *(__nv_bfloat16*)(ismem + 1*IMAT + i*IRS + (h0+j)*2) = lo;
        }
    }
    __syncthreads();

    unsigned aoff = (unsigned)((m0 + (t8&1)*8 + i8)*IRS + (t8>>1)*16);
    unsigned boff[4];
    #pragma unroll
    for (int q = 0; q < 4; q++)
        boff[q] = (unsigned)(((t8&1)*8 + i8)*IRS + (nb + q*16 + (t8>>1)*8)*2);

    float P[8][4], Aa[8][4];

    auto mm_ss = [&](int Lh, int Rh){
        #pragma unroll
        for (int j=0;j<8;j++)
            #pragma unroll
            for (int e=0;e<4;e++) P[j][e] = 0.f;
        unsigned Lb = smb + (unsigned)Lh*IMAT;
        unsigned Rb = smb + (unsigned)Rh*IMAT;
        #pragma unroll
        for (int k = 0; k < 8; k++){
            unsigned aH[4], aL[4];
            ldsm4(aH[0],aH[1],aH[2],aH[3], Lb + aoff + k*32);
            ldsm4(aL[0],aL[1],aL[2],aL[3], Lb + IMAT + aoff + k*32);
            #pragma unroll
            for (int q = 0; q < 4; q++){
                unsigned bH[4], bL[4];
                ldsm4t(bH[0],bH[1],bH[2],bH[3], Rb + boff[q] + k*16*IRS);
                ldsm4t(bL[0],bL[1],bL[2],bL[3], Rb + IMAT + boff[q] + k*16*IRS);
                mma16816(P[2*q],   aH, bH);
                mma16816(P[2*q+1], aH, bH+2);
                mma16816(P[2*q],   aL, bH);
                mma16816(P[2*q+1], aL, bH+2);
                mma16816(P[2*q],   aH, bL);
                mma16816(P[2*q+1], aH, bL+2);
            }
        }
    };

    auto mm_KV = [&](){
        #pragma unroll
        for (int j=0;j<8;j++)
            #pragma unroll
            for (int e=0;e<4;e++) P[j][e] = 0.f;
        unsigned Rb = smb;
        #pragma unroll
        for (int k = 0; k < 8; k++){
            int k0 = k*16;
            int r = m0 + g, c = k0 + tg*2;
            float2 v0 = *(const float2*)&Kg[(size_t)r*128 + c];
            float2 v1 = *(const float2*)&Kg[(size_t)(r+8)*128 + c];
            float2 v2 = *(const float2*)&Kg[(size_t)r*128 + c + 8];
            float2 v3 = *(const float2*)&Kg[(size_t)(r+8)*128 + c + 8];
            unsigned aH[4], aL[4]; float lx, ly;
            aH[0] = pack_hi(v0.x, v0.y, lx, ly); aL[0] = pack_bf2(lx, ly);
            aH[1] = pack_hi(v1.x, v1.y, lx, ly); aL[1] = pack_bf2(lx, ly);
            aH[2] = pack_hi(v2.x, v2.y, lx, ly); aL[2] = pack_bf2(lx, ly);
            aH[3] = pack_hi(v3.x, v3.y, lx, ly); aL[3] = pack_bf2(lx, ly);
            #pragma unroll
            for (int q = 0; q < 4; q++){
                unsigned bH[4], bL[4];
                ldsm4t(bH[0],bH[1],bH[2],bH[3], Rb + boff[q] + k*16*IRS);
                ldsm4t(bL[0],bL[1],bL[2],bL[3], Rb + IMAT + boff[q] + k*16*IRS);
                mma16816(P[2*q],   aH, bH);
                mma16816(P[2*q+1], aH, bH+2);
                mma16816(P[2*q],   aL, bH);
                mma16816(P[2*q+1], aL, bH+2);
                mma16816(P[2*q],   aH, bL);
                mma16816(P[2*q+1], aH, bL+2);
            }
        }
    };

    auto store_mat = [&](int slot, float (*F)[4]){
        #pragma unroll
        for (int half = 0; half < 2; half++){
            int r = m0 + g + half*8;
            #pragma unroll
            for (int j = 0; j < 8; j++){
                int c = nb + j*8 + tg*2;
                float x = F[j][half*2], y = F[j][half*2+1];
                float lx, ly;
                unsigned hp = pack_hi(x, y, lx, ly);
                unsigned lp = pack_bf2(lx, ly);
                *(unsigned*)(ismem + slot*IMAT + r*IRS + c*2) = hp;
                *(unsigned*)(ismem + (slot+1)*IMAT + r*IRS + c*2) = lp;
            }
        }
    };

    for (int it = 0; it < 6; it++){
        // A = K @ V
        mm_KV();
        #pragma unroll
        for (int j=0;j<8;j++)
            #pragma unroll
            for (int e=0;e<4;e++) Aa[j][e] = P[j][e];
        __syncthreads();
        store_mat(2, Aa);
        __syncthreads();

        // C = 7A - A@A
        mm_ss(2, 2);
        #pragma unroll
        for (int j=0;j<8;j++)
            #pragma unroll
            for (int e=0;e<4;e++) P[j][e] = 7.f*Aa[j][e] - P[j][e];
        __syncthreads();
        store_mat(4, P);
        __syncthreads();

        // E = 15A - A@C
        mm_ss(2, 4);
        #pragma unroll
        for (int j=0;j<8;j++)
            #pragma unroll
            for (int e=0;e<4;e++) P[j][e] = 15.f*Aa[j][e] - P[j][e];
        __syncthreads();
        store_mat(4, P);
        __syncthreads();

        // V = 3.25V - 0.25 * V@E
        mm_ss(0, 4);
        __syncthreads();
        #pragma unroll
        for (int half = 0; half < 2; half++){
            int r = m0 + g + half*8;
            #pragma unroll
            for (int j = 0; j < 8; j++){
                int c = nb + j*8 + tg*2;
                unsigned hp = *(unsigned*)(ismem + 0*IMAT + r*IRS + c*2);
                unsigned lp = *(unsigned*)(ismem + 1*IMAT + r*IRS + c*2);
                __nv_bfloat162 hb = *(__nv_bfloat162*)&hp;
                __nv_bfloat162 lb = *(__nv_bfloat162*)&lp;
                float vx = __bfloat162float(hb.x) + __bfloat162float(lb.x);
                float vy = __bfloat162float(hb.y) + __bfloat162float(lb.y);
                P[j][half*2]   = 3.25f*vx - 0.25f*P[j][half*2];
                P[j][half*2+1] = 3.25f*vy - 0.25f*P[j][half*2+1];
            }
        }
        store_mat(0, P);
        __syncthreads();
    }

    // W2 = V @ k3V  (128x128 @ 128x64)
    {
        int i = tid >> 2, h0 = (tid & 3) * 16;
        const float* Ng = g_k3V + (size_t)bh*8192;
        for (int j = 0; j < 16; j++){
            float v = Ng[i*64 + h0 + j];
            __nv_bfloat16 hi = __float2bfloat16(v);
            __nv_bfloat16 lo = __float2bfloat16(v - __bfloat162float(hi));
            *(__nv_bfloat16*)(ismem + 2*IMAT + i*IRS + (h0+j)*2) = hi;
            *(__nv_bfloat16*)(ismem + 3*IMAT + i*IRS + (h0+j)*2) = lo;
        }
    }
    __syncthreads();
    {
        int nbW = nw * 32;
        unsigned boffW[2];
        #pragma unroll
        for (int q = 0; q < 2; q++)
            boffW[q] = (unsigned)(((t8&1)*8 + i8)*IRS + (nbW + q*16 + (t8>>1)*8)*2);

        float Pw[4][4];
        #pragma unroll
        for (int j=0;j<4;j++)
            #pragma unroll
            for (int e=0;e<4;e++) Pw[j][e] = 0.f;

        #pragma unroll
        for (int k = 0; k < 8; k++){
            unsigned aH[4], aL[4];
            ldsm4(aH[0],aH[1],aH[2],aH[3], smb + aoff + k*32);
            ldsm4(aL[0],aL[1],aL[2],aL[3], smb + IMAT + aoff + k*32);
            #pragma unroll
            for (int q = 0; q < 2; q++){
                unsigned bH[4], bL[4];
                ldsm4t(bH[0],bH[1],bH[2],bH[3], smb + 2*IMAT + boffW[q] + k*16*IRS);
                ldsm4t(bL[0],bL[1],bL[2],bL[3], smb + 3*IMAT + boffW[q] + k*16*IRS);
                mma16816(Pw[2*q],   aH, bH);
                mma16816(Pw[2*q+1], aH, bH+2);
                mma16816(Pw[2*q],   aL, bH);
                mma16816(Pw[2*q+1], aL, bH+2);
                mma16816(Pw[2*q],   aH, bL);
                mma16816(Pw[2*q+1], aH, bL+2);
            }
        }
        float* Wg = g_W2 + (size_t)bh*8192;
        #pragma unroll
        for (int half = 0; half < 2; half++){
            int r = m0 + g + half*8;
            #pragma unroll
            for (int j = 0; j < 4; j++){
                int c = nbW + j*8 + tg*2;
                *(float2*)&Wg[r*64 + c] = make_float2(Pw[j][half*2], Pw[j][half*2+1]);
            }
        }
    }
}

// ---------------- k1 on HMMA: ctx = softmax(Q @ Kl^T) @ W2 ---------------------
// smem: KlH [128][64] | KlL | W2H [128][64] | W2L, row stride 144B
#define KLRS 144
#define K1MAT 18432
#define K1_SMEM (4*K1MAT)   // 73728

__global__ __launch_bounds__(256, 2)
void k1_kernel(){
    extern __shared__ __align__(16) char ksm[];
    const unsigned smb = smem_u32(ksm);
    const int sblk = blockIdx.x, bh = blockIdx.y;
    const int tid = threadIdx.x, lane = tid & 31, w = tid >> 5;
    const int g = lane >> 2, tg = lane & 3;
    const int i8 = lane & 7, t8 = lane >> 3;
    const int m0 = w * 16;

    // load Kl, W2 -> bf16 hi/lo smem
    const float* Klg = g_Kl + (size_t)bh*8192;
    const float* W2g = g_W2 + (size_t)bh*8192;
    for (int idx = tid; idx < 8192; idx += 256){
        int r = idx >> 6, c = idx & 63;
        float v = Klg[idx];
        __nv_bfloat16 hi = __float2bfloat16(v);
        __nv_bfloat16 lo = __float2bfloat16(v - __bfloat162float(hi));
        *(__nv_bfloat16*)(ksm + 0*K1MAT + r*KLRS + c*2) = hi;
        *(__nv_bfloat16*)(ksm + 1*K1MAT + r*KLRS + c*2) = lo;
        v = W2g[idx];
        hi = __float2bfloat16(v);
        lo = __float2bfloat16(v - __bfloat162float(hi));
        *(__nv_bfloat16*)(ksm + 2*K1MAT + r*KLRS + c*2) = hi;
        *(__nv_bfloat16*)(ksm + 3*K1MAT + r*KLRS + c*2) = lo;
    }
    __syncthreads();

    // scores: st[16 ntiles][4] = Q(rows) @ Kl^T, 3-product
    const float* Qg = g_Q + ((size_t)bh*S_ + sblk*128)*HD_;
    float st[16][4];
    #pragma unroll
    for (int nt=0;nt<16;nt++)
        #pragma unroll
        for (int e=0;e<4;e++) st[nt][e] = 0.f;

    #pragma unroll
    for (int kc = 0; kc < 4; kc++){
        int r = m0 + g, c = kc*16 + tg*2;
        float2 v0 = *(const float2*)&Qg[(size_t)r*64 + c];
        float2 v1 = *(const float2*)&Qg[(size_t)(r+8)*64 + c];
        float2 v2 = *(const float2*)&Qg[(size_t)r*64 + c + 8];
        float2 v3 = *(const float2*)&Qg[(size_t)(r+8)*64 + c + 8];
        unsigned aH[4], aL[4]; float lx, ly;
        aH[0] = pack_hi(v0.x, v0.y, lx, ly); aL[0] = pack_bf2(lx, ly);
        aH[1] = pack_hi(v1.x, v1.y, lx, ly); aL[1] = pack_bf2(lx, ly);
        aH[2] = pack_hi(v2.x, v2.y, lx, ly); aL[2] = pack_bf2(lx, ly);
        aH[3] = pack_hi(v3.x, v3.y, lx, ly); aL[3] = pack_bf2(lx, ly);
        #pragma unroll
        for (int q = 0; q < 8; q++){
            unsigned kOff = (unsigned)((q*16 + (t8>>1)*8 + i8)*KLRS + (t8&1)*16 + kc*32);
            unsigned bH[4], bL[4];
            ldsm4(bH[0],bH[1],bH[2],bH[3], smb + 0*K1MAT + kOff);
            ldsm4(bL[0],bL[1],bL[2],bL[3], smb + 1*K1MAT + kOff);
            mma16816(st[2*q],   aH, bH);
            mma16816(st[2*q+1], aH, bH+2);
            mma16816(st[2*q],   aL, bH);
            mma16816(st[2*q+1], aL, bH+2);
            mma16816(st[2*q],   aH, bL);
            mma16816(st[2*q+1], aH, bL+2);
        }
    }

    // softmax over 128 landmarks (rows m0+g and m0+g+8)
    float mx0 = -1e30f, mx1 = -1e30f;
    #pragma unroll
    for (int nt = 0; nt < 16; nt++){
        mx0 = fmaxf(mx0, fmaxf(st[nt][0], st[nt][1]));
        mx1 = fmaxf(mx1, fmaxf(st[nt][2], st[nt][3]));
    }
    mx0 = fmaxf(mx0, __shfl_xor_sync(0xffffffffu, mx0, 1));
    mx0 = fmaxf(mx0, __shfl_xor_sync(0xffffffffu, mx0, 2));
    mx1 = fmaxf(mx1, __shfl_xor_sync(0xffffffffu, mx1, 1));
    mx1 = fmaxf(mx1, __shfl_xor_sync(0xffffffffu, mx1, 2));
    float z0 = 0.f, z1 = 0.f;
    #pragma unroll
    for (int nt = 0; nt < 16; nt++){
        st[nt][0] = __expf(st[nt][0] - mx0);
        st[nt][1] = __expf(st[nt][1] - mx0);
        st[nt][2] = __expf(st[nt][2] - mx1);
        st[nt][3] = __expf(st[nt][3] - mx1);
        z0 += st[nt][0] + st[nt][1];
        z1 += st[nt][2] + st[nt][3];
    }
    z0 += __shfl_xor_sync(0xffffffffu, z0, 1);
    z0 += __shfl_xor_sync(0xffffffffu, z0, 2);
    z1 += __shfl_xor_sync(0xffffffffu, z1, 1);
    z1 += __shfl_xor_sync(0xffffffffu, z1, 2);
    float zi0 = 1.f/z0, zi1 = 1.f/z1;
    #pragma unroll
    for (int nt = 0; nt < 16; nt++){
        st[nt][0] *= zi0; st[nt][1] *= zi0;
        st[nt][2] *= zi1; st[nt][3] *= zi1;
    }

    // out = P @ W2, 3-product (W2^T via ldsm.trans)
    float o[8][4];
    #pragma unroll
    for (int j=0;j<8;j++)
        #pragma unroll
        for (int e=0;e<4;e++) o[j][e] = 0.f;

    #pragma unroll
    for (int kc = 0; kc < 8; kc++){
        unsigned aH[4], aL[4]; float lx, ly;
        aH[0] = pack_hi(st[2*kc][0],   st[2*kc][1],   lx, ly); aL[0] = pack_bf2(lx, ly);
        aH[1] = pack_hi(st[2*kc][2],   st[2*kc][3],   lx, ly); aL[1] = pack_bf2(lx, ly);
        aH[2] = pack_hi(st[2*kc+1][0], st[2*kc+1][1], lx, ly); aL[2] = pack_bf2(lx, ly);
        aH[3] = pack_hi(st[2*kc+1][2], st[2*kc+1][3], lx, ly); aL[3] = pack_bf2(lx, ly);
        #pragma unroll
        for (int q = 0; q < 4; q++){
            unsigned wOff = (unsigned)(((t8&1)*8 + i8 + kc*16)*KLRS + (q*16 + (t8>>1)*8)*2);
            unsigned bH[4], bL[4];
            ldsm4t(bH[0],bH[1],bH[2],bH[3], smb + 2*K1MAT + wOff);
            ldsm4t(bL[0],bL[1],bL[2],bL[3], smb + 3*K1MAT + wOff);
            mma16816(o[2*q],   aH, bH);
            mma16816(o[2*q+1], aH, bH+2);
            mma16816(o[2*q],   aL, bH);
            mma16816(o[2*q+1], aL, bH+2);
            mma16816(o[2*q],   aH, bL);
            mma16816(o[2*q+1], aH, bL+2);
        }
    }

    // epilogue: write ctx bf16 hi/lo
    int b = bh >> 4, h = bh & 15;
    #pragma unroll
    for (int half = 0; half < 2; half++){
        int sI = sblk*128 + m0 + g + half*8;
        size_t obase = ((size_t)(b*S_ + sI))*D_ + h*64;
        #pragma unroll
        for (int nt = 0; nt < 8; nt++){
            int d = nt*8 + tg*2;
            float x = o[nt][half*2], y = o[nt][half*2+1];
            float lx, ly;
            unsigned hp = pack_hi(x, y, lx, ly);
            unsigned lp = pack_bf2(lx, ly);
            *(unsigned*)&g_ctxh[obase + d] = hp;
            *(unsigned*)&g_ctxl[obase + d] = lp;
        }
    }
}

// ---------------- launch -------------------------------------------------------
extern "C" void kernel_launch(void* const* d_in, const int* in_sizes, int n_in,
                              void* d_out, int out_size)
{
    const float* X    = (const float*)d_in[0];
    const float* mask = (const float*)d_in[1];
    const float* Wq   = (const float*)d_in[2];
    const float* bq   = (const float*)d_in[3];
    const float* Wk   = (const float*)d_in[4];
    const float* bk   = (const float*)d_in[5];
    const float* Wv   = (const float*)d_in[6];
    const float* bv   = (const float*)d_in[7];
    const float* Wo   = (const float*)d_in[8];
    const float* bo   = (const float*)d_in[9];
    float* out = (float*)d_out;

    void *pQ, *pK, *pV;
    cudaGetSymbolAddress(&pQ, g_Q);
    cudaGetSymbolAddress(&pK, g_K);
    cudaGetSymbolAddress(&pV, g_V);

    cudaFuncSetAttribute(gemm_qkv, cudaFuncAttributeMaxDynamicSharedMemorySize, GSMEM);
    cudaFuncSetAttribute(gemm_out, cudaFuncAttributeMaxDynamicSharedMemorySize, GSMEM);
    cudaFuncSetAttribute(inv_kernel, cudaFuncAttributeMaxDynamicSharedMemorySize, INV_SMEM);
    cudaFuncSetAttribute(k1_kernel,  cudaFuncAttributeMaxDynamicSharedMemorySize, K1_SMEM);

    convX_kernel<<<8192, 256>>>(X);                       // 1
    convW_kernel<<<dim3(32,32,4), 256>>>(Wq, Wk, Wv, Wo); // 2
    probe_kernel<<<1, 32>>>();                            // 3
    gemm_qkv<<<dim3(24,64), 256, GSMEM>>>(bq, bk, bv, mask,
                                          (float*)pQ, (float*)pK, (float*)pV); // 4 <- ncu

    landmark_kernel<<<(BH_*NL_*HD_)/256, 256>>>();
    k2_kernel<<<dim3(NL_, BH_), 128>>>();
    colmax_kernel<<<BH_, 128>>>();
    k3_kernel<<<dim3(8, BH_), 256>>>(mask);
    inv_kernel<<<BH_, 512, INV_SMEM>>>();
    k1_kernel<<<dim3(32, BH_), 256, K1_SMEM>>>();

    gemm_out<<<dim3(8,64), 256, GSMEM>>>(bo, out);
}

// round 12
// speedup vs baseline: 6.1980x; 1.2075x over previous
#include <cuda_runtime.h>
#include <cuda_bf16.h>

// Problem constants
#define B_  2
#define S_  4096
#define HID_ 1024
#define NH_ 16
#define HD_ 64
#define NL_ 128
#define BH_ (B_*NH_)          // 32
#define SEG_ (S_/NL_)         // 32
#define D_ (NH_*HD_)          // 1024
#define SCALE_ 0.35355339059327373f  // HD^-0.25

// ---------------- device scratch -----------------------------------------------
__device__ float g_Q[B_*NH_*S_*HD_];     // (b,h,s,d) scaled+masked
__device__ float g_K[B_*NH_*S_*HD_];
__device__ float g_V[B_*NH_*S_*HD_];
__device__ float g_Ql[BH_*NL_*HD_];
__device__ float g_Kl[BH_*NL_*HD_];
__device__ float g_k2[BH_*NL_*NL_];
__device__ float g_bhmax[BH_];
__device__ float g_k3V[BH_*NL_*HD_];
__device__ float g_W2[BH_*NL_*HD_];
__device__ float g_k3o[BH_*8*NL_*HD_];   // split-K partials
__device__ float g_k3mz[BH_*8*NL_*2];
__device__ __align__(256) __nv_bfloat16 g_Xh[8192*1024];
__device__ __align__(256) __nv_bfloat16 g_Xl[8192*1024];
__device__ __align__(256) __nv_bfloat16 g_Wth[4*1024*1024];   // [4][n][k] q,k,v,o
__device__ __align__(256) __nv_bfloat16 g_Wtl[4*1024*1024];
__device__ __align__(256) __nv_bfloat16 g_ctxh[8192*1024];
__device__ __align__(256) __nv_bfloat16 g_ctxl[8192*1024];

__device__ __forceinline__ unsigned smem_u32(const void* p){
    unsigned a;
    asm("{ .reg .u64 t; cvta.to.shared.u64 t, %1; cvt.u32.u64 %0, t; }" : "=r"(a) : "l"(p));
    return a;
}
__device__ __forceinline__ void ldsm4(unsigned& r0, unsigned& r1, unsigned& r2, unsigned& r3,
                                      unsigned addr){
    asm volatile("ldmatrix.sync.aligned.m8n8.x4.shared.b16 {%0,%1,%2,%3}, [%4];"
        : "=r"(r0), "=r"(r1), "=r"(r2), "=r"(r3) : "r"(addr));
}
__device__ __forceinline__ void ldsm4t(unsigned& r0, unsigned& r1, unsigned& r2, unsigned& r3,
                                       unsigned addr){
    asm volatile("ldmatrix.sync.aligned.m8n8.x4.trans.shared.b16 {%0,%1,%2,%3}, [%4];"
        : "=r"(r0), "=r"(r1), "=r"(r2), "=r"(r3) : "r"(addr));
}
__device__ __forceinline__ void mma16816(float* c, const unsigned* a, const unsigned* b){
    asm volatile(
        "mma.sync.aligned.m16n8k16.row.col.f32.bf16.bf16.f32 "
        "{%0,%1,%2,%3}, {%4,%5,%6,%7}, {%8,%9}, {%0,%1,%2,%3};"
        : "+f"(c[0]), "+f"(c[1]), "+f"(c[2]), "+f"(c[3])
        : "r"(a[0]), "r"(a[1]), "r"(a[2]), "r"(a[3]), "r"(b[0]), "r"(b[1]));
}
__device__ __forceinline__ unsigned pack_hi(float x, float y, float& lx, float& ly){
    __nv_bfloat162 h = __floats2bfloat162_rn(x, y);
    lx = x - __bfloat162float(h.x);
    ly = y - __bfloat162float(h.y);
    return *(unsigned*)&h;
}
__device__ __forceinline__ unsigned pack_bf2(float x, float y){
    __nv_bfloat162 h = __floats2bfloat162_rn(x, y);
    return *(unsigned*)&h;
}
__device__ __forceinline__ void cp16(unsigned dst, const void* src){
    asm volatile("cp.async.cg.shared.global [%0], [%1], 16;" :: "r"(dst), "l"(src));
}
__device__ __forceinline__ void cpcommit(){ asm volatile("cp.async.commit_group;" ::: "memory"); }
template<int N> __device__ __forceinline__ void cpwait(){
    asm volatile("cp.async.wait_group %0;" :: "n"(N) : "memory");
}

// ---------------- probe (keeps gemm_qkv in the profiled 4th slot) --------------
__global__ void probe_kernel(){
    if (threadIdx.x < BH_) g_bhmax[threadIdx.x] = 0.f;
}

// ---------------- prep: split X into bf16 hi/lo --------------------------------
__global__ void convX_kernel(const float* __restrict__ X){
    size_t i4 = (size_t)blockIdx.x * blockDim.x + threadIdx.x;
    float4 v = ((const float4*)X)[i4];
    float vs[4] = {v.x, v.y, v.z, v.w};
    __nv_bfloat16 hi[4], lo[4];
    #pragma unroll
    for (int c = 0; c < 4; c++){
        hi[c] = __float2bfloat16(vs[c]);
        lo[c] = __float2bfloat16(vs[c] - __bfloat162float(hi[c]));
    }
    *(uint2*)&g_Xh[i4*4] = *(uint2*)hi;
    *(uint2*)&g_Xl[i4*4] = *(uint2*)lo;
}

// ---------------- prep: transpose+split weights -> [n][k] bf16 hi/lo -----------
__global__ void convW_kernel(const float* __restrict__ Wq, const float* __restrict__ Wk,
                             const float* __restrict__ Wv, const float* __restrict__ Wo){
    __shared__ float t[32][33];
    int z = blockIdx.z;
    const float* W = (z==0) ? Wq : (z==1) ? Wk : (z==2) ? Wv : Wo;
    int n0 = blockIdx.x * 32, k0 = blockIdx.y * 32;
    int tx = threadIdx.x & 31, ty = threadIdx.x >> 5;
    #pragma unroll
    for (int r = 0; r < 4; r++){
        int ky = ty + r*8;
        t[ky][tx] = W[(size_t)(k0 + ky)*1024 + n0 + tx];
    }
    __syncthreads();
    #pragma unroll
    for (int r = 0; r < 4; r++){
        int ny = ty + r*8;
        float v = t[tx][ny];
        __nv_bfloat16 hi = __float2bfloat16(v);
        __nv_bfloat16 lo = __float2bfloat16(v - __bfloat162float(hi));
        size_t o = (size_t)z*1048576 + (size_t)(n0 + ny)*1024 + k0 + tx;
        g_Wth[o] = hi; g_Wtl[o] = lo;
    }
}

// ================= bf16 HMMA GEMM mainloop (unchanged) =========================
#define ROWBY 80
#define TILEB (128*ROWBY)
#define STAGEB (4*TILEB)
#define GSMEM (2*STAGEB)

__device__ __forceinline__ void gemm_main(
    const __nv_bfloat16* __restrict__ Ah, const __nv_bfloat16* __restrict__ Al,
    const __nv_bfloat16* __restrict__ Bh, const __nv_bfloat16* __restrict__ Bl,
    unsigned smb, float acc[2][8][4])
{
    const int tid = threadIdx.x, lane = tid & 31, w = tid >> 5;
    const int wr = w & 3, wc = w >> 2;

    unsigned aoff[2], boff[4];
    {
        int i = lane & 7, t8 = lane >> 3;
        #pragma unroll
        for (int t = 0; t < 2; t++)
            aoff[t] = (unsigned)((wr*32 + t*16 + (t8 & 1)*8 + i) * ROWBY + (t8 >> 1) * 16);
        #pragma unroll
        for (int q = 0; q < 4; q++)
            boff[q] = (unsigned)((wc*64 + q*16 + (t8 >> 1)*8 + i) * ROWBY + (t8 & 1) * 16);
    }

    auto issue = [&](int buf, int k0){
        #pragma unroll
        for (int r = 0; r < 8; r++){
            int idx = r*256 + tid;
            int c = idx & 3, row = (idx >> 2) & 127, tile = idx >> 9;
            const __nv_bfloat16* src =
                (tile == 0) ? Ah + (size_t)row*1024 + k0 + c*8 :
                (tile == 1) ? Al + (size_t)row*1024 + k0 + c*8 :
                (tile == 2) ? Bh + (size_t)row*1024 + k0 + c*8 :
                              Bl + (size_t)row*1024 + k0 + c*8;
            cp16(smb + buf*STAGEB + tile*TILEB + row*ROWBY + c*16, src);
        }
        cpcommit();
    };

    issue(0, 0);
    for (int s = 0; s < 32; s++){
        __syncthreads();
        if (s < 31){ issue((s+1) & 1, (s+1)*32); cpwait<1>(); }
        else       { cpwait<0>(); }
        __syncthreads();

        unsigned base = smb + (s & 1)*STAGEB;
        #pragma unroll
        for (int kb = 0; kb < 2; kb++){
            unsigned ko = kb * 32;
            unsigned aH[2][4], aL[2][4], bX[4][4];
            #pragma unroll
            for (int t = 0; t < 2; t++){
                ldsm4(aH[t][0], aH[t][1], aH[t][2], aH[t][3], base + aoff[t] + ko);
                ldsm4(aL[t][0], aL[t][1], aL[t][2], aL[t][3], base + TILEB + aoff[t] + ko);
            }
            #pragma unroll
            for (int q = 0; q < 4; q++)
                ldsm4(bX[q][0], bX[q][1], bX[q][2], bX[q][3], base + 2*TILEB + boff[q] + ko);
            #pragma unroll
            for (int t = 0; t < 2; t++)
                #pragma unroll
                for (int q = 0; q < 4; q++){
                    mma16816(acc[t][2*q],   aH[t], &bX[q][0]);
                    mma16816(acc[t][2*q+1], aH[t], &bX[q][2]);
                    mma16816(acc[t][2*q],   aL[t], &bX[q][0]);
                    mma16816(acc[t][2*q+1], aL[t], &bX[q][2]);
                }
            #pragma unroll
            for (int q = 0; q < 4; q++)
                ldsm4(bX[q][0], bX[q][1], bX[q][2], bX[q][3], base + 3*TILEB + boff[q] + ko);
            #pragma unroll
            for (int t = 0; t < 2; t++)
                #pragma unroll
                for (int q = 0; q < 4; q++){
                    mma16816(acc[t][2*q],   aH[t], &bX[q][0]);
                    mma16816(acc[t][2*q+1], aH[t], &bX[q][2]);
                }
        }
    }
}

__global__ __launch_bounds__(256, 2)
void gemm_qkv(const float* __restrict__ bq, const float* __restrict__ bk,
              const float* __restrict__ bv, const float* __restrict__ mask,
              float* __restrict__ oq, float* __restrict__ okk, float* __restrict__ ov)
{
    extern __shared__ __align__(16) char smem[];
    unsigned smb = smem_u32(smem);
    int wsel = blockIdx.x >> 3, colt = blockIdx.x & 7;
    const __nv_bfloat16* Ah = g_Xh + (size_t)blockIdx.y*128*1024;
    const __nv_bfloat16* Al = g_Xl + (size_t)blockIdx.y*128*1024;
    const __nv_bfloat16* Bh = g_Wth + ((size_t)wsel*1024 + colt*128)*1024;
    const __nv_bfloat16* Bl = g_Wtl + ((size_t)wsel*1024 + colt*128)*1024;

    float acc[2][8][4];
    #pragma unroll
    for (int t=0;t<2;t++)
        #pragma unroll
        for (int j=0;j<8;j++)
            #pragma unroll
            for (int e=0;e<4;e++) acc[t][j][e] = 0.f;

    gemm_main(Ah, Al, Bh, Bl, smb, acc);

    const float* bias = (wsel==0) ? bq : (wsel==1) ? bk : bv;
    float* out = (wsel==0) ? oq : (wsel==1) ? okk : ov;
    const bool scaled = (wsel < 2);

    int lane = threadIdx.x & 31, w = threadIdx.x >> 5;
    int wr = w & 3, wc = w >> 2;
    int g = lane >> 2, tg = lane & 3;
    #pragma unroll
    for (int t = 0; t < 2; t++){
        #pragma unroll
        for (int half = 0; half < 2; half++){
            int row = blockIdx.y*128 + wr*32 + t*16 + g + half*8;
            float rs = scaled ? SCALE_ * mask[row] : 1.0f;
            int bb = row >> 12, sI = row & 4095;
            #pragma unroll
            for (int j = 0; j < 8; j++){
                int col = colt*128 + wc*64 + j*8 + tg*2;
                float c0 = (acc[t][j][half*2]   + bias[col])   * rs;
                float c1 = (acc[t][j][half*2+1] + bias[col+1]) * rs;
                int h = col >> 6, d = col & 63;
                *(float2*)(out + ((size_t)(bb*NH_ + h)*S_ + sI)*HD_ + d) = make_float2(c0, c1);
            }
        }
    }
}

__global__ __launch_bounds__(256, 2)
void gemm_out(const float* __restrict__ bias, float* __restrict__ out)
{
    extern __shared__ __align__(16) char smem[];
    unsigned smb = smem_u32(smem);
    const __nv_bfloat16* Ah = g_ctxh + (size_t)blockIdx.y*128*1024;
    const __nv_bfloat16* Al = g_ctxl + (size_t)blockIdx.y*128*1024;
    const __nv_bfloat16* Bh = g_Wth + (size_t)3*1048576 + (size_t)blockIdx.x*128*1024;
    const __nv_bfloat16* Bl = g_Wtl + (size_t)3*1048576 + (size_t)blockIdx.x*128*1024;

    float acc[2][8][4];
    #pragma unroll
    for (int t=0;t<2;t++)
        #pragma unroll
        for (int j=0;j<8;j++)
            #pragma unroll
            for (int e=0;e<4;e++) acc[t][j][e] = 0.f;

    gemm_main(Ah, Al, Bh, Bl, smb, acc);

    int lane = threadIdx.x & 31, w = threadIdx.x >> 5;
    int wr = w & 3, wc = w >> 2;
    int g = lane >> 2, tg = lane & 3;
    #pragma unroll
    for (int t = 0; t < 2; t++){
        #pragma unroll
        for (int half = 0; half < 2; half++){
            int row = blockIdx.y*128 + wr*32 + t*16 + g + half*8;
            #pragma unroll
            for (int j = 0; j < 8; j++){
                int col = blockIdx.x*128 + wc*64 + j*8 + tg*2;
                float c0 = acc[t][j][half*2]   + bias[col];
                float c1 = acc[t][j][half*2+1] + bias[col+1];
                *(float2*)(out + (size_t)row*1024 + col) = make_float2(c0, c1);
            }
        }
    }
}

// ---------------- landmarks ----------------------------------------------------
__global__ void landmark_kernel(){
    int idx = blockIdx.x*blockDim.x + threadIdx.x;
    int d  = idx & 63;
    int l  = (idx >> 6) & 127;
    int bh = idx >> 13;
    const float* q = g_Q + ((size_t)bh*S_ + l*SEG_)*HD_ + d;
    const float* k = g_K + ((size_t)bh*S_ + l*SEG_)*HD_ + d;
    float sq = 0.f, sk = 0.f;
    #pragma unroll
    for (int j=0; j<SEG_; j++){ sq += q[j*HD_]; sk += k[j*HD_]; }
    g_Ql[idx] = sq * (1.f/SEG_);
    g_Kl[idx] = sk * (1.f/SEG_);
}

// ---------------- k2 = softmax(Ql @ Kl^T) --------------------------------------
__global__ void k2_kernel(){
    int l = blockIdx.x, bh = blockIdx.y, m = threadIdx.x;
    const float4* ql = (const float4*)(g_Ql + ((size_t)bh*NL_ + l)*HD_);
    const float4* kl = (const float4*)(g_Kl + ((size_t)bh*NL_ + m)*HD_);
    float acc = 0.f;
    #pragma unroll
    for (int d4=0; d4<16; d4++){
        float4 a = ql[d4], b = kl[d4];
        acc += a.x*b.x + a.y*b.y + a.z*b.z + a.w*b.w;
    }
    __shared__ float red[128];
    red[m] = acc; __syncthreads();
    for (int off=64; off>0; off>>=1){
        if (m < off) red[m] = fmaxf(red[m], red[m+off]);
        __syncthreads();
    }
    float mx = red[0]; __syncthreads();
    float p = __expf(acc - mx);
    red[m] = p; __syncthreads();
    for (int off=64; off>0; off>>=1){
        if (m < off) red[m] += red[m+off];
        __syncthreads();
    }
    g_k2[((size_t)bh*NL_ + l)*NL_ + m] = p / red[0];
}

// ---------------- column sums of k2 -> per-bh max ------------------------------
__global__ void colmax_kernel(){
    int bh = blockIdx.x, m = threadIdx.x;
    float s = 0.f;
    for (int l=0; l<NL_; l++) s += g_k2[((size_t)bh*NL_ + l)*NL_ + m];
    __shared__ float red[128];
    red[m] = s; __syncthreads();
    for (int off=64; off>0; off>>=1){
        if (m < off) red[m] = fmaxf(red[m], red[m+off]);
        __syncthreads();
    }
    if (m == 0) g_bhmax[bh] = red[0];
}

// ---------------- k3 on HMMA: flash-style split-K ------------------------------
// smem slots (row stride 144B, 128 rows): 0:QlH 1:QlL 2:KH 3:KL 4:VH 5:VL + mask
#define K3RS  144
#define K3MAT 18432
#define K3_SMEM (6*K3MAT + 512)

__global__ __launch_bounds__(256, 1)
void k3_mma(const float* __restrict__ mask){
    extern __shared__ __align__(16) char ksm[];
    const unsigned smb = smem_u32(ksm);
    const int chunk = blockIdx.x, bh = blockIdx.y;
    const int tid = threadIdx.x, lane = tid & 31, w = tid >> 5;
    const int g = lane >> 2, tg = lane & 3;
    const int i8 = lane & 7, t8 = lane >> 3;
    const int m0 = w * 16;
    float* msk = (float*)(ksm + 6*K3MAT);

    // Ql -> slots 0/1 (bf16 hi/lo)
    const float* Qlg = g_Ql + (size_t)bh*8192;
    for (int idx = tid; idx < 8192; idx += 256){
        int r = idx >> 6, c = idx & 63;
        float v = Qlg[idx];
        __nv_bfloat16 hi = __float2bfloat16(v);
        __nv_bfloat16 lo = __float2bfloat16(v - __bfloat162float(hi));
        *(__nv_bfloat16*)(ksm + 0*K3MAT + r*K3RS + c*2) = hi;
        *(__nv_bfloat16*)(ksm + 1*K3MAT + r*K3RS + c*2) = lo;
    }

    const float* Kbh = g_K + (size_t)bh*S_*HD_;
    const float* Vbh = g_V + (size_t)bh*S_*HD_;
    const float* mrow = mask + (size_t)(bh >> 4)*S_;

    const unsigned aoff = (unsigned)((m0 + (t8&1)*8 + i8)*K3RS + (t8>>1)*16);

    float mr0 = -1e30f, mr1 = -1e30f, z0 = 0.f, z1 = 0.f;
    float o[8][4];
    #pragma unroll
    for (int j=0;j<8;j++)
        #pragma unroll
        for (int e=0;e<4;e++) o[j][e] = 0.f;

    for (int it = 0; it < 4; it++){
        int sbase = chunk*512 + it*128;
        __syncthreads();
        for (int idx = tid; idx < 8192; idx += 256){
            int r = idx >> 6, c = idx & 63;
            float v = Kbh[(size_t)(sbase + r)*HD_ + c];
            __nv_bfloat16 hi = __float2bfloat16(v);
            __nv_bfloat16 lo = __float2bfloat16(v - __bfloat162float(hi));
            *(__nv_bfloat16*)(ksm + 2*K3MAT + r*K3RS + c*2) = hi;
            *(__nv_bfloat16*)(ksm + 3*K3MAT + r*K3RS + c*2) = lo;
            v = Vbh[(size_t)(sbase + r)*HD_ + c];
            hi = __float2bfloat16(v);
            lo = __float2bfloat16(v - __bfloat162float(hi));
            *(__nv_bfloat16*)(ksm + 4*K3MAT + r*K3RS + c*2) = hi;
            *(__nv_bfloat16*)(ksm + 5*K3MAT + r*K3RS + c*2) = lo;
        }
        if (tid < 128) msk[tid] = mrow[sbase + tid];
        __syncthreads();

        // scores: 128 rows (this warp: m0..m0+15) x 128 cols
        float st[16][4];
        #pragma unroll
        for (int nt=0;nt<16;nt++)
            #pragma unroll
            for (int e=0;e<4;e++) st[nt][e] = 0.f;

        #pragma unroll
        for (int kc = 0; kc < 4; kc++){
            unsigned aH[4], aL[4];
            ldsm4(aH[0],aH[1],aH[2],aH[3], smb + 0*K3MAT + aoff + kc*32);
            ldsm4(aL[0],aL[1],aL[2],aL[3], smb + 1*K3MAT + aoff + kc*32);
            #pragma unroll
            for (int q = 0; q < 8; q++){
                unsigned kOff = (unsigned)((q*16 + (t8>>1)*8 + i8)*K3RS + (t8&1)*16 + kc*32);
                unsigned bH[4], bL[4];
                ldsm4(bH[0],bH[1],bH[2],bH[3], smb + 2*K3MAT + kOff);
                ldsm4(bL[0],bL[1],bL[2],bL[3], smb + 3*K3MAT + kOff);
                mma16816(st[2*q],   aH, bH);
                mma16816(st[2*q+1], aH, bH+2);
                mma16816(st[2*q],   aL, bH);
                mma16816(st[2*q+1], aL, bH+2);
                mma16816(st[2*q],   aH, bL);
                mma16816(st[2*q+1], aH, bL+2);
            }
        }

        // mask penalty
        #pragma unroll
        for (int nt = 0; nt < 16; nt++){
            int c0 = nt*8 + tg*2;
            float p0 = -1e9f*(1.f - msk[c0]);
            float p1 = -1e9f*(1.f - msk[c0+1]);
            st[nt][0] += p0; st[nt][1] += p1;
            st[nt][2] += p0; st[nt][3] += p1;
        }

        // online softmax (rows m0+g and m0+g+8)
        float cm0 = -1e30f, cm1 = -1e30f;
        #pragma unroll
        for (int nt = 0; nt < 16; nt++){
            cm0 = fmaxf(cm0, fmaxf(st[nt][0], st[nt][1]));
            cm1 = fmaxf(cm1, fmaxf(st[nt][2], st[nt][3]));
        }
        cm0 = fmaxf(cm0, __shfl_xor_sync(0xffffffffu, cm0, 1));
        cm0 = fmaxf(cm0, __shfl_xor_sync(0xffffffffu, cm0, 2));
        cm1 = fmaxf(cm1, __shfl_xor_sync(0xffffffffu, cm1, 1));
        cm1 = fmaxf(cm1, __shfl_xor_sync(0xffffffffu, cm1, 2));
        float mn0 = fmaxf(mr0, cm0), mn1 = fmaxf(mr1, cm1);
        float cr0 = __expf(mr0 - mn0), cr1 = __expf(mr1 - mn1);
        mr0 = mn0; mr1 = mn1;
        z0 *= cr0; z1 *= cr1;
        #pragma unroll
        for (int j = 0; j < 8; j++){
            o[j][0] *= cr0; o[j][1] *= cr0;
            o[j][2] *= cr1; o[j][3] *= cr1;
        }
        float ps0 = 0.f, ps1 = 0.f;
        #pragma unroll
        for (int nt = 0; nt < 16; nt++){
            st[nt][0] = __expf(st[nt][0] - mn0);
            st[nt][1] = __expf(st[nt][1] - mn0);
            st[nt][2] = __expf(st[nt][2] - mn1);
            st[nt][3] = __expf(st[nt][3] - mn1);
            ps0 += st[nt][0] + st[nt][1];
            ps1 += st[nt][2] + st[nt][3];
        }
        ps0 += __shfl_xor_sync(0xffffffffu, ps0, 1);
        ps0 += __shfl_xor_sync(0xffffffffu, ps0, 2);
        ps1 += __shfl_xor_sync(0xffffffffu, ps1, 1);
        ps1 += __shfl_xor_sync(0xffffffffu, ps1, 2);
        z0 += ps0; z1 += ps1;

        // o += P @ V  (3-product, V^T via ldsm.trans)
        #pragma unroll
        for (int kc = 0; kc < 8; kc++){
            unsigned aH[4], aL[4]; float lx, ly;
            aH[0] = pack_hi(st[2*kc][0],   st[2*kc][1],   lx, ly); aL[0] = pack_bf2(lx, ly);
            aH[1] = pack_hi(st[2*kc][2],   st[2*kc][3],   lx, ly); aL[1] = pack_bf2(lx, ly);
            aH[2] = pack_hi(st[2*kc+1][0], st[2*kc+1][1], lx, ly); aL[2] = pack_bf2(lx, ly);
            aH[3] = pack_hi(st[2*kc+1][2], st[2*kc+1][3], lx, ly); aL[3] = pack_bf2(lx, ly);
            #pragma unroll
            for (int q = 0; q < 4; q++){
                unsigned wOff = (unsigned)(((t8&1)*8 + i8 + kc*16)*K3RS + (q*16 + (t8>>1)*8)*2);
                unsigned bH[4], bL[4];
                ldsm4t(bH[0],bH[1],bH[2],bH[3], smb + 4*K3MAT + wOff);
                ldsm4t(bL[0],bL[1],bL[2],bL[3], smb + 5*K3MAT + wOff);
                mma16816(o[2*q],   aH, bH);
                mma16816(o[2*q+1], aH, bH+2);
                mma16816(o[2*q],   aL, bH);
                mma16816(o[2*q+1], aL, bH+2);
                mma16816(o[2*q],   aH, bL);
                mma16816(o[2*q+1], aH, bL+2);
            }
        }
    }

    // write split-K partials
    size_t pbase = ((size_t)(bh*8 + chunk))*128;
    #pragma unroll
    for (int j = 0; j < 8; j++){
        int c = j*8 + tg*2;
        *(float2*)&g_k3o[(pbase + m0 + g)*64 + c]     = make_float2(o[j][0], o[j][1]);
        *(float2*)&g_k3o[(pbase + m0 + g + 8)*64 + c] = make_float2(o[j][2], o[j][3]);
    }
    if (tg == 0){
        g_k3mz[(pbase + m0 + g)*2]       = mr0;
        g_k3mz[(pbase + m0 + g)*2 + 1]   = z0;
        g_k3mz[(pbase + m0 + g + 8)*2]     = mr1;
        g_k3mz[(pbase + m0 + g + 8)*2 + 1] = z1;
    }
}

__global__ void k3_combine(){
    int bh = blockIdx.x, l = threadIdx.x;   // 128 threads
    float m[8], z[8], M = -1e30f;
    #pragma unroll
    for (int c = 0; c < 8; c++){
        m[c] = g_k3mz[((size_t)(bh*8 + c)*128 + l)*2];
        z[c] = g_k3mz[((size_t)(bh*8 + c)*128 + l)*2 + 1];
        M = fmaxf(M, m[c]);
    }
    float coef[8], Z = 0.f;
    #pragma unroll
    for (int c = 0; c < 8; c++){
        coef[c] = __expf(m[c] - M);
        Z += z[c]*coef[c];
    }
    float Zi = 1.f / Z;
    #pragma unroll
    for (int d4 = 0; d4 < 16; d4++){
        float4 acc = make_float4(0.f, 0.f, 0.f, 0.f);
        #pragma unroll
        for (int c = 0; c < 8; c++){
            float4 ov = *(const float4*)&g_k3o[((size_t)(bh*8 + c)*128 + l)*64 + d4*4];
            acc.x += coef[c]*ov.x; acc.y += coef[c]*ov.y;
            acc.z += coef[c]*ov.z; acc.w += coef[c]*ov.w;
        }
        acc.x *= Zi; acc.y *= Zi; acc.z *= Zi; acc.w *= Zi;
        *(float4*)&g_k3V[(size_t)bh*8192 + l*64 + d4*4] = acc;
    }
}

// ---------------- Newton inverse on HMMA: 512 threads, 16 warps ----------------
#define IRS  272
#define IMAT 34816
#define INV_SMEM (6*IMAT)

__global__ __launch_bounds__(512, 1)
void inv_kernel(){
    extern __shared__ __align__(16) char ismem[];
    const unsigned smb = smem_u32(ismem);
    const int bh = blockIdx.x, tid = threadIdx.x;
    const int lane = tid & 31, w = tid >> 5;
    const int mw = w & 7, nw = w >> 3;
    const int m0 = mw*16, nb = nw*64;
    const int g = lane >> 2, tg = lane & 3;
    const int i8 = lane & 7, t8 = lane >> 3;

    float cmax = g_bhmax[0];
    #pragma unroll
    for (int q=1; q<BH_; q++) cmax = fmaxf(cmax, g_bhmax[q]);
    const float rinv = 1.f / cmax;
    const float* Kg = g_k2 + (size_t)bh*NL_*NL_;

    {
        int i = tid >> 2, h0 = (tid & 3) * 32;
        for (int j = 0; j < 32; j++){
            float v = Kg[(h0 + j)*128 + i] * rinv;
            __nv_bfloat16 hi = __float2bfloat16(v);
            __nv_bfloat16 lo = __float2bfloat16(v - __bfloat162float(hi));
            *(__nv_bfloat16*)(ismem + 0*IMAT + i*IRS + (h0+j)*2) = hi;
            *(__nv_bfloat16*)(ismem + 1*IMAT + i*IRS + (h0+j)*2) = lo;
        }
    }
    __syncthreads();

    unsigned aoff = (unsigned)((m0 + (t8&1)*8 + i8)*IRS + (t8>>1)*16);
    unsigned boff[4];
    #pragma unroll
    for (int q = 0; q < 4; q++)
        boff[q] = (unsigned)(((t8&1)*8 + i8)*IRS + (nb + q*16 + (t8>>1)*8)*2);

    float P[8][4], Aa[8][4];

    auto mm_ss = [&](int Lh, int Rh){
        #pragma unroll
        for (int j=0;j<8;j++)
            #pragma unroll
            for (int e=0;e<4;e++) P[j][e] = 0.f;
        unsigned Lb = smb + (unsigned)Lh*IMAT;
        unsigned Rb = smb + (unsigned)Rh*IMAT;
        #pragma unroll
        for (int k = 0; k < 8; k++){
            unsigned aH[4], aL[4];
            ldsm4(aH[0],aH[1],aH[2],aH[3], Lb + aoff + k*32);
            ldsm4(aL[0],aL[1],aL[2],aL[3], Lb + IMAT + aoff + k*32);
            #pragma unroll
            for (int q = 0; q < 4; q++){
                unsigned bH[4], bL[4];
                ldsm4t(bH[0],bH[1],bH[2],bH[3], Rb + boff[q] + k*16*IRS);
                ldsm4t(bL[0],bL[1],bL[2],bL[3], Rb + IMAT + boff[q] + k*16*IRS);
                mma16816(P[2*q],   aH, bH);
                mma16816(P[2*q+1], aH, bH+2);
                mma16816(P[2*q],   aL, bH);
                mma16816(P[2*q+1], aL, bH+2);
                mma16816(P[2*q],   aH, bL);
                mma16816(P[2*q+1], aH, bL+2);
            }
        }
    };

    auto mm_KV = [&](){
        #pragma unroll
        for (int j=0;j<8;j++)
            #pragma unroll
            for (int e=0;e<4;e++) P[j][e] = 0.f;
        unsigned Rb = smb;
        #pragma unroll
        for (int k = 0; k < 8; k++){
            int k0 = k*16;
            int r = m0 + g, c = k0 + tg*2;
            float2 v0 = *(const float2*)&Kg[(size_t)r*128 + c];
            float2 v1 = *(const float2*)&Kg[(size_t)(r+8)*128 + c];
            float2 v2 = *(const float2*)&Kg[(size_t)r*128 + c + 8];
            float2 v3 = *(const float2*)&Kg[(size_t)(r+8)*128 + c + 8];
            unsigned aH[4], aL[4]; float lx, ly;
            aH[0] = pack_hi(v0.x, v0.y, lx, ly); aL[0] = pack_bf2(lx, ly);
            aH[1] = pack_hi(v1.x, v1.y, lx, ly); aL[1] = pack_bf2(lx, ly);
            aH[2] = pack_hi(v2.x, v2.y, lx, ly); aL[2] = pack_bf2(lx, ly);
            aH[3] = pack_hi(v3.x, v3.y, lx, ly); aL[3] = pack_bf2(lx, ly);
            #pragma unroll
            for (int q = 0; q < 4; q++){
                unsigned bH[4], bL[4];
                ldsm4t(bH[0],bH[1],bH[2],bH[3], Rb + boff[q] + k*16*IRS);
                ldsm4t(bL[0],bL[1],bL[2],bL[3], Rb + IMAT + boff[q] + k*16*IRS);
                mma16816(P[2*q],   aH, bH);
                mma16816(P[2*q+1], aH, bH+2);
                mma16816(P[2*q],   aL, bH);
                mma16816(P[2*q+1], aL, bH+2);
                mma16816(P[2*q],   aH, bL);
                mma16816(P[2*q+1], aH, bL+2);
            }
        }
    };

    auto store_mat = [&](int slot, float (*F)[4]){
        #pragma unroll
        for (int half = 0; half < 2; half++){
            int r = m0 + g + half*8;
            #pragma unroll
            for (int j = 0; j < 8; j++){
                int c = nb + j*8 + tg*2;
                float x = F[j][half*2], y = F[j][half*2+1];
                float lx, ly;
                unsigned hp = pack_hi(x, y, lx, ly);
                unsigned lp = pack_bf2(lx, ly);
                *(unsigned*)(ismem + slot*IMAT + r*IRS + c*2) = hp;
                *(unsigned*)(ismem + (slot+1)*IMAT + r*IRS + c*2) = lp;
            }
        }
    };

    for (int it = 0; it < 6; it++){
        mm_KV();
        #pragma unroll
        for (int j=0;j<8;j++)
            #pragma unroll
            for (int e=0;e<4;e++) Aa[j][e] = P[j][e];
        __syncthreads();
        store_mat(2, Aa);
        __syncthreads();

        mm_ss(2, 2);
        #pragma unroll
        for (int j=0;j<8;j++)
            #pragma unroll
            for (int e=0;e<4;e++) P[j][e] = 7.f*Aa[j][e] - P[j][e];
        __syncthreads();
        store_mat(4, P);
        __syncthreads();

        mm_ss(2, 4);
        #pragma unroll
        for (int j=0;j<8;j++)
            #pragma unroll
            for (int e=0;e<4;e++) P[j][e] = 15.f*Aa[j][e] - P[j][e];
        __syncthreads();
        store_mat(4, P);
        __syncthreads();

        mm_ss(0, 4);
        __syncthreads();
        #pragma unroll
        for (int half = 0; half < 2; half++){
            int r = m0 + g + half*8;
            #pragma unroll
            for (int j = 0; j < 8; j++){
                int c = nb + j*8 + tg*2;
                unsigned hp = *(unsigned*)(ismem + 0*IMAT + r*IRS + c*2);
                unsigned lp = *(unsigned*)(ismem + 1*IMAT + r*IRS + c*2);
                __nv_bfloat162 hb = *(__nv_bfloat162*)&hp;
                __nv_bfloat162 lb = *(__nv_bfloat162*)&lp;
                float vx = __bfloat162float(hb.x) + __bfloat162float(lb.x);
                float vy = __bfloat162float(hb.y) + __bfloat162float(lb.y);
                P[j][half*2]   = 3.25f*vx - 0.25f*P[j][half*2];
                P[j][half*2+1] = 3.25f*vy - 0.25f*P[j][half*2+1];
            }
        }
        store_mat(0, P);
        __syncthreads();
    }

    {
        int i = tid >> 2, h0 = (tid & 3) * 16;
        const float* Ng = g_k3V + (size_t)bh*8192;
        for (int j = 0; j < 16; j++){
            float v = Ng[i*64 + h0 + j];
            __nv_bfloat16 hi = __float2bfloat16(v);
            __nv_bfloat16 lo = __float2bfloat16(v - __bfloat162float(hi));
            *(__nv_bfloat16*)(ismem + 2*IMAT + i*IRS + (h0+j)*2) = hi;
            *(__nv_bfloat16*)(ismem + 3*IMAT + i*IRS + (h0+j)*2) = lo;
        }
    }
    __syncthreads();
    {
        int nbW = nw * 32;
        unsigned boffW[2];
        #pragma unroll
        for (int q = 0; q < 2; q++)
            boffW[q] = (unsigned)(((t8&1)*8 + i8)*IRS + (nbW + q*16 + (t8>>1)*8)*2);

        float Pw[4][4];
        #pragma unroll
        for (int j=0;j<4;j++)
            #pragma unroll
            for (int e=0;e<4;e++) Pw[j][e] = 0.f;

        #pragma unroll
        for (int k = 0; k < 8; k++){
            unsigned aH[4], aL[4];
            ldsm4(aH[0],aH[1],aH[2],aH[3], smb + aoff + k*32);
            ldsm4(aL[0],aL[1],aL[2],aL[3], smb + IMAT + aoff + k*32);
            #pragma unroll
            for (int q = 0; q < 2; q++){
                unsigned bH[4], bL[4];
                ldsm4t(bH[0],bH[1],bH[2],bH[3], smb + 2*IMAT + boffW[q] + k*16*IRS);
                ldsm4t(bL[0],bL[1],bL[2],bL[3], smb + 3*IMAT + boffW[q] + k*16*IRS);
                mma16816(Pw[2*q],   aH, bH);
                mma16816(Pw[2*q+1], aH, bH+2);
                mma16816(Pw[2*q],   aL, bH);
                mma16816(Pw[2*q+1], aL, bH+2);
                mma16816(Pw[2*q],   aH, bL);
                mma16816(Pw[2*q+1], aH, bL+2);
            }
        }
        float* Wg = g_W2 + (size_t)bh*8192;
        #pragma unroll
        for (int half = 0; half < 2; half++){
            int r = m0 + g + half*8;
            #pragma unroll
            for (int j = 0; j < 4; j++){
                int c = nbW + j*8 + tg*2;
                *(float2*)&Wg[r*64 + c] = make_float2(Pw[j][half*2], Pw[j][half*2+1]);
            }
        }
    }
}

// ---------------- k1 on HMMA: ctx = softmax(Q @ Kl^T) @ W2 ---------------------
#define KLRS 144
#define K1MAT 18432
#define K1_SMEM (4*K1MAT)

__global__ __launch_bounds__(256, 2)
void k1_kernel(){
    extern __shared__ __align__(16) char ksm[];
    const unsigned smb = smem_u32(ksm);
    const int sblk = blockIdx.x, bh = blockIdx.y;
    const int tid = threadIdx.x, lane = tid & 31, w = tid >> 5;
    const int g = lane >> 2, tg = lane & 3;
    const int i8 = lane & 7, t8 = lane >> 3;
    const int m0 = w * 16;

    const float* Klg = g_Kl + (size_t)bh*8192;
    const float* W2g = g_W2 + (size_t)bh*8192;
    for (int idx = tid; idx < 8192; idx += 256){
        int r = idx >> 6, c = idx & 63;
        float v = Klg[idx];
        __nv_bfloat16 hi = __float2bfloat16(v);
        __nv_bfloat16 lo = __float2bfloat16(v - __bfloat162float(hi));
        *(__nv_bfloat16*)(ksm + 0*K1MAT + r*KLRS + c*2) = hi;
        *(__nv_bfloat16*)(ksm + 1*K1MAT + r*KLRS + c*2) = lo;
        v = W2g[idx];
        hi = __float2bfloat16(v);
        lo = __float2bfloat16(v - __bfloat162float(hi));
        *(__nv_bfloat16*)(ksm + 2*K1MAT + r*KLRS + c*2) = hi;
        *(__nv_bfloat16*)(ksm + 3*K1MAT + r*KLRS + c*2) = lo;
    }
    __syncthreads();

    const float* Qg = g_Q + ((size_t)bh*S_ + sblk*128)*HD_;
    float st[16][4];
    #pragma unroll
    for (int nt=0;nt<16;nt++)
        #pragma unroll
        for (int e=0;e<4;e++) st[nt][e] = 0.f;

    #pragma unroll
    for (int kc = 0; kc < 4; kc++){
        int r = m0 + g, c = kc*16 + tg*2;
        float2 v0 = *(const float2*)&Qg[(size_t)r*64 + c];
        float2 v1 = *(const float2*)&Qg[(size_t)(r+8)*64 + c];
        float2 v2 = *(const float2*)&Qg[(size_t)r*64 + c + 8];
        float2 v3 = *(const float2*)&Qg[(size_t)(r+8)*64 + c + 8];
        unsigned aH[4], aL[4]; float lx, ly;
        aH[0] = pack_hi(v0.x, v0.y, lx, ly); aL[0] = pack_bf2(lx, ly);
        aH[1] = pack_hi(v1.x, v1.y, lx, ly); aL[1] = pack_bf2(lx, ly);
        aH[2] = pack_hi(v2.x, v2.y, lx, ly); aL[2] = pack_bf2(lx, ly);
        aH[3] = pack_hi(v3.x, v3.y, lx, ly); aL[3] = pack_bf2(lx, ly);
        #pragma unroll
        for (int q = 0; q < 8; q++){
            unsigned kOff = (unsigned)((q*16 + (t8>>1)*8 + i8)*KLRS + (t8&1)*16 + kc*32);
            unsigned bH[4], bL[4];
            ldsm4(bH[0],bH[1],bH[2],bH[3], smb + 0*K1MAT + kOff);
            ldsm4(bL[0],bL[1],bL[2],bL[3], smb + 1*K1MAT + kOff);
            mma16816(st[2*q],   aH, bH);
            mma16816(st[2*q+1], aH, bH+2);
            mma16816(st[2*q],   aL, bH);
            mma16816(st[2*q+1], aL, bH+2);
            mma16816(st[2*q],   aH, bL);
            mma16816(st[2*q+1], aH, bL+2);
        }
    }

    float mx0 = -1e30f, mx1 = -1e30f;
    #pragma unroll
    for (int nt = 0; nt < 16; nt++){
        mx0 = fmaxf(mx0, fmaxf(st[nt][0], st[nt][1]));
        mx1 = fmaxf(mx1, fmaxf(st[nt][2], st[nt][3]));
    }
    mx0 = fmaxf(mx0, __shfl_xor_sync(0xffffffffu, mx0, 1));
    mx0 = fmaxf(mx0, __shfl_xor_sync(0xffffffffu, mx0, 2));
    mx1 = fmaxf(mx1, __shfl_xor_sync(0xffffffffu, mx1, 1));
    mx1 = fmaxf(mx1, __shfl_xor_sync(0xffffffffu, mx1, 2));
    float z0 = 0.f, z1 = 0.f;
    #pragma unroll
    for (int nt = 0; nt < 16; nt++){
        st[nt][0] = __expf(st[nt][0] - mx0);
        st[nt][1] = __expf(st[nt][1] - mx0);
        st[nt][2] = __expf(st[nt][2] - mx1);
        st[nt][3] = __expf(st[nt][3] - mx1);
        z0 += st[nt][0] + st[nt][1];
        z1 += st[nt][2] + st[nt][3];
    }
    z0 += __shfl_xor_sync(0xffffffffu, z0, 1);
    z0 += __shfl_xor_sync(0xffffffffu, z0, 2);
    z1 += __shfl_xor_sync(0xffffffffu, z1, 1);
    z1 += __shfl_xor_sync(0xffffffffu, z1, 2);
    float zi0 = 1.f/z0, zi1 = 1.f/z1;
    #pragma unroll
    for (int nt = 0; nt < 16; nt++){
        st[nt][0] *= zi0; st[nt][1] *= zi0;
        st[nt][2] *= zi1; st[nt][3] *= zi1;
    }

    float o[8][4];
    #pragma unroll
    for (int j=0;j<8;j++)
        #pragma unroll
        for (int e=0;e<4;e++) o[j][e] = 0.f;

    #pragma unroll
    for (int kc = 0; kc < 8; kc++){
        unsigned aH[4], aL[4]; float lx, ly;
        aH[0] = pack_hi(st[2*kc][0],   st[2*kc][1],   lx, ly); aL[0] = pack_bf2(lx, ly);
        aH[1] = pack_hi(st[2*kc][2],   st[2*kc][3],   lx, ly); aL[1] = pack_bf2(lx, ly);
        aH[2] = pack_hi(st[2*kc+1][0], st[2*kc+1][1], lx, ly); aL[2] = pack_bf2(lx, ly);
        aH[3] = pack_hi(st[2*kc+1][2], st[2*kc+1][3], lx, ly); aL[3] = pack_bf2(lx, ly);
        #pragma unroll
        for (int q = 0; q < 4; q++){
            unsigned wOff = (unsigned)(((t8&1)*8 + i8 + kc*16)*KLRS + (q*16 + (t8>>1)*8)*2);
            unsigned bH[4], bL[4];
            ldsm4t(bH[0],bH[1],bH[2],bH[3], smb + 2*K1MAT + wOff);
            ldsm4t(bL[0],bL[1],bL[2],bL[3], smb + 3*K1MAT + wOff);
            mma16816(o[2*q],   aH, bH);
            mma16816(o[2*q+1], aH, bH+2);
            mma16816(o[2*q],   aL, bH);
            mma16816(o[2*q+1], aL, bH+2);
            mma16816(o[2*q],   aH, bL);
            mma16816(o[2*q+1], aH, bL+2);
        }
    }

    int b = bh >> 4, h = bh & 15;
    #pragma unroll
    for (int half = 0; half < 2; half++){
        int sI = sblk*128 + m0 + g + half*8;
        size_t obase = ((size_t)(b*S_ + sI))*D_ + h*64;
        #pragma unroll
        for (int nt = 0; nt < 8; nt++){
            int d = nt*8 + tg*2;
            float x = o[nt][half*2], y = o[nt][half*2+1];
            float lx, ly;
            unsigned hp = pack_hi(x, y, lx, ly);
            unsigned lp = pack_bf2(lx, ly);
            *(unsigned*)&g_ctxh[obase + d] = hp;
            *(unsigned*)&g_ctxl[obase + d] = lp;
        }
    }
}

// ---------------- launch -------------------------------------------------------
extern "C" void kernel_launch(void* const* d_in, const int* in_sizes, int n_in,
                              void* d_out, int out_size)
{
    const float* X    = (const float*)d_in[0];
    const float* mask = (const float*)d_in[1];
    const float* Wq   = (const float*)d_in[2];
    const float* bq   = (const float*)d_in[3];
    const float* Wk   = (const float*)d_in[4];
    const float* bk   = (const float*)d_in[5];
    const float* Wv   = (const float*)d_in[6];
    const float* bv   = (const float*)d_in[7];
    const float* Wo   = (const float*)d_in[8];
    const float* bo   = (const float*)d_in[9];
    float* out = (float*)d_out;

    void *pQ, *pK, *pV;
    cudaGetSymbolAddress(&pQ, g_Q);
    cudaGetSymbolAddress(&pK, g_K);
    cudaGetSymbolAddress(&pV, g_V);

    cudaFuncSetAttribute(gemm_qkv, cudaFuncAttributeMaxDynamicSharedMemorySize, GSMEM);
    cudaFuncSetAttribute(gemm_out, cudaFuncAttributeMaxDynamicSharedMemorySize, GSMEM);
    cudaFuncSetAttribute(inv_kernel, cudaFuncAttributeMaxDynamicSharedMemorySize, INV_SMEM);
    cudaFuncSetAttribute(k1_kernel,  cudaFuncAttributeMaxDynamicSharedMemorySize, K1_SMEM);
    cudaFuncSetAttribute(k3_mma,     cudaFuncAttributeMaxDynamicSharedMemorySize, K3_SMEM);

    convX_kernel<<<8192, 256>>>(X);                       // 1
    convW_kernel<<<dim3(32,32,4), 256>>>(Wq, Wk, Wv, Wo); // 2
    probe_kernel<<<1, 32>>>();                            // 3
    gemm_qkv<<<dim3(24,64), 256, GSMEM>>>(bq, bk, bv, mask,
                                          (float*)pQ, (float*)pK, (float*)pV); // 4 <- ncu

    landmark_kernel<<<(BH_*NL_*HD_)/256, 256>>>();
    k2_kernel<<<dim3(NL_, BH_), 128>>>();
    colmax_kernel<<<BH_, 128>>>();
    k3_mma<<<dim3(8, BH_), 256, K3_SMEM>>>(mask);
    k3_combine<<<BH_, 128>>>();
    inv_kernel<<<BH_, 512, INV_SMEM>>>();
    k1_kernel<<<dim3(32, BH_), 256, K1_SMEM>>>();

    gemm_out<<<dim3(8,64), 256, GSMEM>>>(bo, out);
}

// round 13
// speedup vs baseline: 6.2120x; 1.0023x over previous
#include <cuda_runtime.h>
#include <cuda_bf16.h>

// Problem constants
#define B_  2
#define S_  4096
#define HID_ 1024
#define NH_ 16
#define HD_ 64
#define NL_ 128
#define BH_ (B_*NH_)          // 32
#define SEG_ (S_/NL_)         // 32
#define D_ (NH_*HD_)          // 1024
#define SCALE_ 0.35355339059327373f  // HD^-0.25

// ---------------- device scratch -----------------------------------------------
__device__ float g_Q[B_*NH_*S_*HD_];     // (b,h,s,d) scaled+masked
__device__ float g_K[B_*NH_*S_*HD_];
__device__ float g_V[B_*NH_*S_*HD_];
__device__ float g_Ql[BH_*NL_*HD_];
__device__ float g_Kl[BH_*NL_*HD_];
__device__ float g_k2[BH_*NL_*NL_];
__device__ float g_bhmax[BH_];
__device__ float g_k3V[BH_*NL_*HD_];
__device__ float g_W2[BH_*NL_*HD_];
__device__ float g_k3o[BH_*8*NL_*HD_];   // split-K partials
__device__ float g_k3mz[BH_*8*NL_*2];
__device__ __align__(256) __nv_bfloat16 g_Xh[8192*1024];
__device__ __align__(256) __nv_bfloat16 g_Xl[8192*1024];
__device__ __align__(256) __nv_bfloat16 g_Wth[4*1024*1024];   // [4][n][k] q,k,v,o
__device__ __align__(256) __nv_bfloat16 g_Wtl[4*1024*1024];
__device__ __align__(256) __nv_bfloat16 g_ctxh[8192*1024];
__device__ __align__(256) __nv_bfloat16 g_ctxl[8192*1024];

__device__ __forceinline__ unsigned smem_u32(const void* p){
    unsigned a;
    asm("{ .reg .u64 t; cvta.to.shared.u64 t, %1; cvt.u32.u64 %0, t; }" : "=r"(a) : "l"(p));
    return a;
}
__device__ __forceinline__ void ldsm4(unsigned& r0, unsigned& r1, unsigned& r2, unsigned& r3,
                                      unsigned addr){
    asm volatile("ldmatrix.sync.aligned.m8n8.x4.shared.b16 {%0,%1,%2,%3}, [%4];"
        : "=r"(r0), "=r"(r1), "=r"(r2), "=r"(r3) : "r"(addr));
}
__device__ __forceinline__ void ldsm4t(unsigned& r0, unsigned& r1, unsigned& r2, unsigned& r3,
                                       unsigned addr){
    asm volatile("ldmatrix.sync.aligned.m8n8.x4.trans.shared.b16 {%0,%1,%2,%3}, [%4];"
        : "=r"(r0), "=r"(r1), "=r"(r2), "=r"(r3) : "r"(addr));
}
__device__ __forceinline__ void mma16816(float* c, const unsigned* a, const unsigned* b){
    asm volatile(
        "mma.sync.aligned.m16n8k16.row.col.f32.bf16.bf16.f32 "
        "{%0,%1,%2,%3}, {%4,%5,%6,%7}, {%8,%9}, {%0,%1,%2,%3};"
        : "+f"(c[0]), "+f"(c[1]), "+f"(c[2]), "+f"(c[3])
        : "r"(a[0]), "r"(a[1]), "r"(a[2]), "r"(a[3]), "r"(b[0]), "r"(b[1]));
}
__device__ __forceinline__ unsigned pack_hi(float x, float y, float& lx, float& ly){
    __nv_bfloat162 h = __floats2bfloat162_rn(x, y);
    lx = x - __bfloat162float(h.x);
    ly = y - __bfloat162float(h.y);
    return *(unsigned*)&h;
}
__device__ __forceinline__ unsigned pack_bf2(float x, float y){
    __nv_bfloat162 h = __floats2bfloat162_rn(x, y);
    return *(unsigned*)&h;
}
__device__ __forceinline__ void cp16(unsigned dst, const void* src){
    asm volatile("cp.async.cg.shared.global [%0], [%1], 16;" :: "r"(dst), "l"(src));
}
__device__ __forceinline__ void cpcommit(){ asm volatile("cp.async.commit_group;" ::: "memory"); }
template<int N> __device__ __forceinline__ void cpwait(){
    asm volatile("cp.async.wait_group %0;" :: "n"(N) : "memory");
}

// ---------------- probe (keeps gemm_qkv in the profiled 4th slot) --------------
__global__ void probe_kernel(){
    if (threadIdx.x < BH_) g_bhmax[threadIdx.x] = 0.f;
}

// ---------------- prep: split X into bf16 hi/lo --------------------------------
__global__ void convX_kernel(const float* __restrict__ X){
    size_t i4 = (size_t)blockIdx.x * blockDim.x + threadIdx.x;
    float4 v = ((const float4*)X)[i4];
    float vs[4] = {v.x, v.y, v.z, v.w};
    __nv_bfloat16 hi[4], lo[4];
    #pragma unroll
    for (int c = 0; c < 4; c++){
        hi[c] = __float2bfloat16(vs[c]);
        lo[c] = __float2bfloat16(vs[c] - __bfloat162float(hi[c]));
    }
    *(uint2*)&g_Xh[i4*4] = *(uint2*)hi;
    *(uint2*)&g_Xl[i4*4] = *(uint2*)lo;
}

// ---------------- prep: transpose+split weights -> [n][k] bf16 hi/lo -----------
__global__ void convW_kernel(const float* __restrict__ Wq, const float* __restrict__ Wk,
                             const float* __restrict__ Wv, const float* __restrict__ Wo){
    __shared__ float t[32][33];
    int z = blockIdx.z;
    const float* W = (z==0) ? Wq : (z==1) ? Wk : (z==2) ? Wv : Wo;
    int n0 = blockIdx.x * 32, k0 = blockIdx.y * 32;
    int tx = threadIdx.x & 31, ty = threadIdx.x >> 5;
    #pragma unroll
    for (int r = 0; r < 4; r++){
        int ky = ty + r*8;
        t[ky][tx] = W[(size_t)(k0 + ky)*1024 + n0 + tx];
    }
    __syncthreads();
    #pragma unroll
    for (int r = 0; r < 4; r++){
        int ny = ty + r*8;
        float v = t[tx][ny];
        __nv_bfloat16 hi = __float2bfloat16(v);
        __nv_bfloat16 lo = __float2bfloat16(v - __bfloat162float(hi));
        size_t o = (size_t)z*1048576 + (size_t)(n0 + ny)*1024 + k0 + tx;
        g_Wth[o] = hi; g_Wtl[o] = lo;
    }
}

// ================= bf16 HMMA GEMM mainloop =====================================
// R13: mma schedule reordered into 3 full sweeps so each accumulator's reuse
// distance is 16 issues instead of 2 (accumulator RAW interlock was stalling
// the tensor pipe at 60%). Per-accumulator op order unchanged -> bit-identical.
#define ROWBY 80
#define TILEB (128*ROWBY)
#define STAGEB (4*TILEB)
#define GSMEM (2*STAGEB)

__device__ __forceinline__ void gemm_main(
    const __nv_bfloat16* __restrict__ Ah, const __nv_bfloat16* __restrict__ Al,
    const __nv_bfloat16* __restrict__ Bh, const __nv_bfloat16* __restrict__ Bl,
    unsigned smb, float acc[2][8][4])
{
    const int tid = threadIdx.x, lane = tid & 31, w = tid >> 5;
    const int wr = w & 3, wc = w >> 2;

    unsigned aoff[2], boff[4];
    {
        int i = lane & 7, t8 = lane >> 3;
        #pragma unroll
        for (int t = 0; t < 2; t++)
            aoff[t] = (unsigned)((wr*32 + t*16 + (t8 & 1)*8 + i) * ROWBY + (t8 >> 1) * 16);
        #pragma unroll
        for (int q = 0; q < 4; q++)
            boff[q] = (unsigned)((wc*64 + q*16 + (t8 >> 1)*8 + i) * ROWBY + (t8 & 1) * 16);
    }

    auto issue = [&](int buf, int k0){
        #pragma unroll
        for (int r = 0; r < 8; r++){
            int idx = r*256 + tid;
            int c = idx & 3, row = (idx >> 2) & 127, tile = idx >> 9;
            const __nv_bfloat16* src =
                (tile == 0) ? Ah + (size_t)row*1024 + k0 + c*8 :
                (tile == 1) ? Al + (size_t)row*1024 + k0 + c*8 :
                (tile == 2) ? Bh + (size_t)row*1024 + k0 + c*8 :
                              Bl + (size_t)row*1024 + k0 + c*8;
            cp16(smb + buf*STAGEB + tile*TILEB + row*ROWBY + c*16, src);
        }
        cpcommit();
    };

    issue(0, 0);
    for (int s = 0; s < 32; s++){
        __syncthreads();
        if (s < 31){ issue((s+1) & 1, (s+1)*32); cpwait<1>(); }
        else       { cpwait<0>(); }
        __syncthreads();

        unsigned base = smb + (s & 1)*STAGEB;
        #pragma unroll
        for (int kb = 0; kb < 2; kb++){
            unsigned ko = kb * 32;
            unsigned aH[2][4], aL[2][4], bX[4][4];
            #pragma unroll
            for (int t = 0; t < 2; t++){
                ldsm4(aH[t][0], aH[t][1], aH[t][2], aH[t][3], base + aoff[t] + ko);
                ldsm4(aL[t][0], aL[t][1], aL[t][2], aL[t][3], base + TILEB + aoff[t] + ko);
            }
            #pragma unroll
            for (int q = 0; q < 4; q++)
                ldsm4(bX[q][0], bX[q][1], bX[q][2], bX[q][3], base + 2*TILEB + boff[q] + ko);
            // pass 1: aH * bH  (each accumulator touched exactly once)
            #pragma unroll
            for (int t = 0; t < 2; t++)
                #pragma unroll
                for (int q = 0; q < 4; q++){
                    mma16816(acc[t][2*q],   aH[t], &bX[q][0]);
                    mma16816(acc[t][2*q+1], aH[t], &bX[q][2]);
                }
            // pass 2: aL * bH
            #pragma unroll
            for (int t = 0; t < 2; t++)
                #pragma unroll
                for (int q = 0; q < 4; q++){
                    mma16816(acc[t][2*q],   aL[t], &bX[q][0]);
                    mma16816(acc[t][2*q+1], aL[t], &bX[q][2]);
                }
            // pass 3: aH * bL
            #pragma unroll
            for (int q = 0; q < 4; q++)
                ldsm4(bX[q][0], bX[q][1], bX[q][2], bX[q][3], base + 3*TILEB + boff[q] + ko);
            #pragma unroll
            for (int t = 0; t < 2; t++)
                #pragma unroll
                for (int q = 0; q < 4; q++){
                    mma16816(acc[t][2*q],   aH[t], &bX[q][0]);
                    mma16816(acc[t][2*q+1], aH[t], &bX[q][2]);
                }
        }
    }
}

__global__ __launch_bounds__(256, 2)
void gemm_qkv(const float* __restrict__ bq, const float* __restrict__ bk,
              const float* __restrict__ bv, const float* __restrict__ mask,
              float* __restrict__ oq, float* __restrict__ okk, float* __restrict__ ov)
{
    extern __shared__ __align__(16) char smem[];
    unsigned smb = smem_u32(smem);
    int wsel = blockIdx.x >> 3, colt = blockIdx.x & 7;
    const __nv_bfloat16* Ah = g_Xh + (size_t)blockIdx.y*128*1024;
    const __nv_bfloat16* Al = g_Xl + (size_t)blockIdx.y*128*1024;
    const __nv_bfloat16* Bh = g_Wth + ((size_t)wsel*1024 + colt*128)*1024;
    const __nv_bfloat16* Bl = g_Wtl + ((size_t)wsel*1024 + colt*128)*1024;

    float acc[2][8][4];
    #pragma unroll
    for (int t=0;t<2;t++)
        #pragma unroll
        for (int j=0;j<8;j++)
            #pragma unroll
            for (int e=0;e<4;e++) acc[t][j][e] = 0.f;

    gemm_main(Ah, Al, Bh, Bl, smb, acc);

    const float* bias = (wsel==0) ? bq : (wsel==1) ? bk : bv;
    float* out = (wsel==0) ? oq : (wsel==1) ? okk : ov;
    const bool scaled = (wsel < 2);

    int lane = threadIdx.x & 31, w = threadIdx.x >> 5;
    int wr = w & 3, wc = w >> 2;
    int g = lane >> 2, tg = lane & 3;
    #pragma unroll
    for (int t = 0; t < 2; t++){
        #pragma unroll
        for (int half = 0; half < 2; half++){
            int row = blockIdx.y*128 + wr*32 + t*16 + g + half*8;
            float rs = scaled ? SCALE_ * mask[row] : 1.0f;
            int bb = row >> 12, sI = row & 4095;
            #pragma unroll
            for (int j = 0; j < 8; j++){
                int col = colt*128 + wc*64 + j*8 + tg*2;
                float c0 = (acc[t][j][half*2]   + bias[col])   * rs;
                float c1 = (acc[t][j][half*2+1] + bias[col+1]) * rs;
                int h = col >> 6, d = col & 63;
                *(float2*)(out + ((size_t)(bb*NH_ + h)*S_ + sI)*HD_ + d) = make_float2(c0, c1);
            }
        }
    }
}

__global__ __launch_bounds__(256, 2)
void gemm_out(const float* __restrict__ bias, float* __restrict__ out)
{
    extern __shared__ __align__(16) char smem[];
    unsigned smb = smem_u32(smem);
    const __nv_bfloat16* Ah = g_ctxh + (size_t)blockIdx.y*128*1024;
    const __nv_bfloat16* Al = g_ctxl + (size_t)blockIdx.y*128*1024;
    const __nv_bfloat16* Bh = g_Wth + (size_t)3*1048576 + (size_t)blockIdx.x*128*1024;
    const __nv_bfloat16* Bl = g_Wtl + (size_t)3*1048576 + (size_t)blockIdx.x*128*1024;

    float acc[2][8][4];
    #pragma unroll
    for (int t=0;t<2;t++)
        #pragma unroll
        for (int j=0;j<8;j++)
            #pragma unroll
            for (int e=0;e<4;e++) acc[t][j][e] = 0.f;

    gemm_main(Ah, Al, Bh, Bl, smb, acc);

    int lane = threadIdx.x & 31, w = threadIdx.x >> 5;
    int wr = w & 3, wc = w >> 2;
    int g = lane >> 2, tg = lane & 3;
    #pragma unroll
    for (int t = 0; t < 2; t++){
        #pragma unroll
        for (int half = 0; half < 2; half++){
            int row = blockIdx.y*128 + wr*32 + t*16 + g + half*8;
            #pragma unroll
            for (int j = 0; j < 8; j++){
                int col = blockIdx.x*128 + wc*64 + j*8 + tg*2;
                float c0 = acc[t][j][half*2]   + bias[col];
                float c1 = acc[t][j][half*2+1] + bias[col+1];
                *(float2*)(out + (size_t)row*1024 + col) = make_float2(c0, c1);
            }
        }
    }
}

// ---------------- landmarks ----------------------------------------------------
__global__ void landmark_kernel(){
    int idx = blockIdx.x*blockDim.x + threadIdx.x;
    int d  = idx & 63;
    int l  = (idx >> 6) & 127;
    int bh = idx >> 13;
    const float* q = g_Q + ((size_t)bh*S_ + l*SEG_)*HD_ + d;
    const float* k = g_K + ((size_t)bh*S_ + l*SEG_)*HD_ + d;
    float sq = 0.f, sk = 0.f;
    #pragma unroll
    for (int j=0; j<SEG_; j++){ sq += q[j*HD_]; sk += k[j*HD_]; }
    g_Ql[idx] = sq * (1.f/SEG_);
    g_Kl[idx] = sk * (1.f/SEG_);
}

// ---------------- k2 = softmax(Ql @ Kl^T) --------------------------------------
__global__ void k2_kernel(){
    int l = blockIdx.x, bh = blockIdx.y, m = threadIdx.x;
    const float4* ql = (const float4*)(g_Ql + ((size_t)bh*NL_ + l)*HD_);
    const float4* kl = (const float4*)(g_Kl + ((size_t)bh*NL_ + m)*HD_);
    float acc = 0.f;
    #pragma unroll
    for (int d4=0; d4<16; d4++){
        float4 a = ql[d4], b = kl[d4];
        acc += a.x*b.x + a.y*b.y + a.z*b.z + a.w*b.w;
    }
    __shared__ float red[128];
    red[m] = acc; __syncthreads();
    for (int off=64; off>0; off>>=1){
        if (m < off) red[m] = fmaxf(red[m], red[m+off]);
        __syncthreads();
    }
    float mx = red[0]; __syncthreads();
    float p = __expf(acc - mx);
    red[m] = p; __syncthreads();
    for (int off=64; off>0; off>>=1){
        if (m < off) red[m] += red[m+off];
        __syncthreads();
    }
    g_k2[((size_t)bh*NL_ + l)*NL_ + m] = p / red[0];
}

// ---------------- column sums of k2 -> per-bh max ------------------------------
__global__ void colmax_kernel(){
    int bh = blockIdx.x, m = threadIdx.x;
    float s = 0.f;
    for (int l=0; l<NL_; l++) s += g_k2[((size_t)bh*NL_ + l)*NL_ + m];
    __shared__ float red[128];
    red[m] = s; __syncthreads();
    for (int off=64; off>0; off>>=1){
        if (m < off) red[m] = fmaxf(red[m], red[m+off]);
        __syncthreads();
    }
    if (m == 0) g_bhmax[bh] = red[0];
}

// ---------------- k3 on HMMA: flash-style split-K ------------------------------
#define K3RS  144
#define K3MAT 18432
#define K3_SMEM (6*K3MAT + 512)

__global__ __launch_bounds__(256, 1)
void k3_mma(const float* __restrict__ mask){
    extern __shared__ __align__(16) char ksm[];
    const unsigned smb = smem_u32(ksm);
    const int chunk = blockIdx.x, bh = blockIdx.y;
    const int tid = threadIdx.x, lane = tid & 31, w = tid >> 5;
    const int g = lane >> 2, tg = lane & 3;
    const int i8 = lane & 7, t8 = lane >> 3;
    const int m0 = w * 16;
    float* msk = (float*)(ksm + 6*K3MAT);

    const float* Qlg = g_Ql + (size_t)bh*8192;
    for (int idx = tid; idx < 8192; idx += 256){
        int r = idx >> 6, c = idx & 63;
        float v = Qlg[idx];
        __nv_bfloat16 hi = __float2bfloat16(v);
        __nv_bfloat16 lo = __float2bfloat16(v - __bfloat162float(hi));
        *(__nv_bfloat16*)(ksm + 0*K3MAT + r*K3RS + c*2) = hi;
        *(__nv_bfloat16*)(ksm + 1*K3MAT + r*K3RS + c*2) = lo;
    }

    const float* Kbh = g_K + (size_t)bh*S_*HD_;
    const float* Vbh = g_V + (size_t)bh*S_*HD_;
    const float* mrow = mask + (size_t)(bh >> 4)*S_;

    const unsigned aoff = (unsigned)((m0 + (t8&1)*8 + i8)*K3RS + (t8>>1)*16);

    float mr0 = -1e30f, mr1 = -1e30f, z0 = 0.f, z1 = 0.f;
    float o[8][4];
    #pragma unroll
    for (int j=0;j<8;j++)
        #pragma unroll
        for (int e=0;e<4;e++) o[j][e] = 0.f;

    for (int it = 0; it < 4; it++){
        int sbase = chunk*512 + it*128;
        __syncthreads();
        for (int idx = tid; idx < 8192; idx += 256){
            int r = idx >> 6, c = idx & 63;
            float v = Kbh[(size_t)(sbase + r)*HD_ + c];
            __nv_bfloat16 hi = __float2bfloat16(v);
            __nv_bfloat16 lo = __float2bfloat16(v - __bfloat162float(hi));
            *(__nv_bfloat16*)(ksm + 2*K3MAT + r*K3RS + c*2) = hi;
            *(__nv_bfloat16*)(ksm + 3*K3MAT + r*K3RS + c*2) = lo;
            v = Vbh[(size_t)(sbase + r)*HD_ + c];
            hi = __float2bfloat16(v);
            lo = __float2bfloat16(v - __bfloat162float(hi));
            *(__nv_bfloat16*)(ksm + 4*K3MAT + r*K3RS + c*2) = hi;
            *(__nv_bfloat16*)(ksm + 5*K3MAT + r*K3RS + c*2) = lo;
        }
        if (tid < 128) msk[tid] = mrow[sbase + tid];
        __syncthreads();

        float st[16][4];
        #pragma unroll
        for (int nt=0;nt<16;nt++)
            #pragma unroll
            for (int e=0;e<4;e++) st[nt][e] = 0.f;

        #pragma unroll
        for (int kc = 0; kc < 4; kc++){
            unsigned aH[4], aL[4];
            ldsm4(aH[0],aH[1],aH[2],aH[3], smb + 0*K3MAT + aoff + kc*32);
            ldsm4(aL[0],aL[1],aL[2],aL[3], smb + 1*K3MAT + aoff + kc*32);
            #pragma unroll
            for (int q = 0; q < 8; q++){
                unsigned kOff = (unsigned)((q*16 + (t8>>1)*8 + i8)*K3RS + (t8&1)*16 + kc*32);
                unsigned bH[4], bL[4];
                ldsm4(bH[0],bH[1],bH[2],bH[3], smb + 2*K3MAT + kOff);
                ldsm4(bL[0],bL[1],bL[2],bL[3], smb + 3*K3MAT + kOff);
                mma16816(st[2*q],   aH, bH);
                mma16816(st[2*q+1], aH, bH+2);
                mma16816(st[2*q],   aL, bH);
                mma16816(st[2*q+1], aL, bH+2);
                mma16816(st[2*q],   aH, bL);
                mma16816(st[2*q+1], aH, bL+2);
            }
        }

        #pragma unroll
        for (int nt = 0; nt < 16; nt++){
            int c0 = nt*8 + tg*2;
            float p0 = -1e9f*(1.f - msk[c0]);
            float p1 = -1e9f*(1.f - msk[c0+1]);
            st[nt][0] += p0; st[nt][1] += p1;
            st[nt][2] += p0; st[nt][3] += p1;
        }

        float cm0 = -1e30f, cm1 = -1e30f;
        #pragma unroll
        for (int nt = 0; nt < 16; nt++){
            cm0 = fmaxf(cm0, fmaxf(st[nt][0], st[nt][1]));
            cm1 = fmaxf(cm1, fmaxf(st[nt][2], st[nt][3]));
        }
        cm0 = fmaxf(cm0, __shfl_xor_sync(0xffffffffu, cm0, 1));
        cm0 = fmaxf(cm0, __shfl_xor_sync(0xffffffffu, cm0, 2));
        cm1 = fmaxf(cm1, __shfl_xor_sync(0xffffffffu, cm1, 1));
        cm1 = fmaxf(cm1, __shfl_xor_sync(0xffffffffu, cm1, 2));
        float mn0 = fmaxf(mr0, cm0), mn1 = fmaxf(mr1, cm1);
        float cr0 = __expf(mr0 - mn0), cr1 = __expf(mr1 - mn1);
        mr0 = mn0; mr1 = mn1;
        z0 *= cr0; z1 *= cr1;
        #pragma unroll
        for (int j = 0; j < 8; j++){
            o[j][0] *= cr0; o[j][1] *= cr0;
            o[j][2] *= cr1; o[j][3] *= cr1;
        }
        float ps0 = 0.f, ps1 = 0.f;
        #pragma unroll
        for (int nt = 0; nt < 16; nt++){
            st[nt][0] = __expf(st[nt][0] - mn0);
            st[nt][1] = __expf(st[nt][1] - mn0);
            st[nt][2] = __expf(st[nt][2] - mn1);
            st[nt][3] = __expf(st[nt][3] - mn1);
            ps0 += st[nt][0] + st[nt][1];
            ps1 += st[nt][2] + st[nt][3];
        }
        ps0 += __shfl_xor_sync(0xffffffffu, ps0, 1);
        ps0 += __shfl_xor_sync(0xffffffffu, ps0, 2);
        ps1 += __shfl_xor_sync(0xffffffffu, ps1, 1);
        ps1 += __shfl_xor_sync(0xffffffffu, ps1, 2);
        z0 += ps0; z1 += ps1;

        #pragma unroll
        for (int kc = 0; kc < 8; kc++){
            unsigned aH[4], aL[4]; float lx, ly;
            aH[0] = pack_hi(st[2*kc][0],   st[2*kc][1],   lx, ly); aL[0] = pack_bf2(lx, ly);
            aH[1] = pack_hi(st[2*kc][2],   st[2*kc][3],   lx, ly); aL[1] = pack_bf2(lx, ly);
            aH[2] = pack_hi(st[2*kc+1][0], st[2*kc+1][1], lx, ly); aL[2] = pack_bf2(lx, ly);
            aH[3] = pack_hi(st[2*kc+1][2], st[2*kc+1][3], lx, ly); aL[3] = pack_bf2(lx, ly);
            #pragma unroll
            for (int q = 0; q < 4; q++){
                unsigned wOff = (unsigned)(((t8&1)*8 + i8 + kc*16)*K3RS + (q*16 + (t8>>1)*8)*2);
                unsigned bH[4], bL[4];
                ldsm4t(bH[0],bH[1],bH[2],bH[3], smb + 4*K3MAT + wOff);
                ldsm4t(bL[0],bL[1],bL[2],bL[3], smb + 5*K3MAT + wOff);
                mma16816(o[2*q],   aH, bH);
                mma16816(o[2*q+1], aH, bH+2);
                mma16816(o[2*q],   aL, bH);
                mma16816(o[2*q+1], aL, bH+2);
                mma16816(o[2*q],   aH, bL);
                mma16816(o[2*q+1], aH, bL+2);
            }
        }
    }

    size_t pbase = ((size_t)(bh*8 + chunk))*128;
    #pragma unroll
    for (int j = 0; j < 8; j++){
        int c = j*8 + tg*2;
        *(float2*)&g_k3o[(pbase + m0 + g)*64 + c]     = make_float2(o[j][0], o[j][1]);
        *(float2*)&g_k3o[(pbase + m0 + g + 8)*64 + c] = make_float2(o[j][2], o[j][3]);
    }
    if (tg == 0){
        g_k3mz[(pbase + m0 + g)*2]       = mr0;
        g_k3mz[(pbase + m0 + g)*2 + 1]   = z0;
        g_k3mz[(pbase + m0 + g + 8)*2]     = mr1;
        g_k3mz[(pbase + m0 + g + 8)*2 + 1] = z1;
    }
}

__global__ void k3_combine(){
    int bh = blockIdx.x, l = threadIdx.x;   // 128 threads
    float m[8], z[8], M = -1e30f;
    #pragma unroll
    for (int c = 0; c < 8; c++){
        m[c] = g_k3mz[((size_t)(bh*8 + c)*128 + l)*2];
        z[c] = g_k3mz[((size_t)(bh*8 + c)*128 + l)*2 + 1];
        M = fmaxf(M, m[c]);
    }
    float coef[8], Z = 0.f;
    #pragma unroll
    for (int c = 0; c < 8; c++){
        coef[c] = __expf(m[c] - M);
        Z += z[c]*coef[c];
    }
    float Zi = 1.f / Z;
    #pragma unroll
    for (int d4 = 0; d4 < 16; d4++){
        float4 acc = make_float4(0.f, 0.f, 0.f, 0.f);
        #pragma unroll
        for (int c = 0; c < 8; c++){
            float4 ov = *(const float4*)&g_k3o[((size_t)(bh*8 + c)*128 + l)*64 + d4*4];
            acc.x += coef[c]*ov.x; acc.y += coef[c]*ov.y;
            acc.z += coef[c]*ov.z; acc.w += coef[c]*ov.w;
        }
        acc.x *= Zi; acc.y *= Zi; acc.z *= Zi; acc.w *= Zi;
        *(float4*)&g_k3V[(size_t)bh*8192 + l*64 + d4*4] = acc;
    }
}

// ---------------- Newton inverse on HMMA: 512 threads, 16 warps ----------------
#define IRS  272
#define IMAT 34816
#define INV_SMEM (6*IMAT)

__global__ __launch_bounds__(512, 1)
void inv_kernel(){
    extern __shared__ __align__(16) char ismem[];
    const unsigned smb = smem_u32(ismem);
    const int bh = blockIdx.x, tid = threadIdx.x;
    const int lane = tid & 31, w = tid >> 5;
    const int mw = w & 7, nw = w >> 3;
    const int m0 = mw*16, nb = nw*64;
    const int g = lane >> 2, tg = lane & 3;
    const int i8 = lane & 7, t8 = lane >> 3;

    float cmax = g_bhmax[0];
    #pragma unroll
    for (int q=1; q<BH_; q++) cmax = fmaxf(cmax, g_bhmax[q]);
    const float rinv = 1.f / cmax;
    const float* Kg = g_k2 + (size_t)bh*NL_*NL_;

    {
        int i = tid >> 2, h0 = (tid & 3) * 32;
        for (int j = 0; j < 32; j++){
            float v = Kg[(h0 + j)*128 + i] * rinv;
            __nv_bfloat16 hi = __float2bfloat16(v);
            __nv_bfloat16 lo = __float2bfloat16(v - __bfloat162float(hi));
            *(__nv_bfloat16*)(ismem + 0*IMAT + i*IRS + (h0+j)*2) = hi;
            *(__nv_bfloat16*)(ismem + 1*IMAT + i*IRS + (h0+j)*2) = lo;
        }
    }
    __syncthreads();

    unsigned aoff = (unsigned)((m0 + (t8&1)*8 + i8)*IRS + (t8>>1)*16);
    unsigned boff[4];
    #pragma unroll
    for (int q = 0; q < 4; q++)
        boff[q] = (unsigned)(((t8&1)*8 + i8)*IRS + (nb + q*16 + (t8>>1)*8)*2);

    float P[8][4], Aa[8][4];

    auto mm_ss = [&](int Lh, int Rh){
        #pragma unroll
        for (int j=0;j<8;j++)
            #pragma unroll
            for (int e=0;e<4;e++) P[j][e] = 0.f;
        unsigned Lb = smb + (unsigned)Lh*IMAT;
        unsigned Rb = smb + (unsigned)Rh*IMAT;
        #pragma unroll
        for (int k = 0; k < 8; k++){
            unsigned aH[4], aL[4];
            ldsm4(aH[0],aH[1],aH[2],aH[3], Lb + aoff + k*32);
            ldsm4(aL[0],aL[1],aL[2],aL[3], Lb + IMAT + aoff + k*32);
            #pragma unroll
            for (int q = 0; q < 4; q++){
                unsigned bH[4], bL[4];
                ldsm4t(bH[0],bH[1],bH[2],bH[3], Rb + boff[q] + k*16*IRS);
                ldsm4t(bL[0],bL[1],bL[2],bL[3], Rb + IMAT + boff[q] + k*16*IRS);
                mma16816(P[2*q],   aH, bH);
                mma16816(P[2*q+1], aH, bH+2);
                mma16816(P[2*q],   aL, bH);
                mma16816(P[2*q+1], aL, bH+2);
                mma16816(P[2*q],   aH, bL);
                mma16816(P[2*q+1], aH, bL+2);
            }
        }
    };

    auto mm_KV = [&](){
        #pragma unroll
        for (int j=0;j<8;j++)
            #pragma unroll
            for (int e=0;e<4;e++) P[j][e] = 0.f;
        unsigned Rb = smb;
        #pragma unroll
        for (int k = 0; k < 8; k++){
            int k0 = k*16;
            int r = m0 + g, c = k0 + tg*2;
            float2 v0 = *(const float2*)&Kg[(size_t)r*128 + c];
            float2 v1 = *(const float2*)&Kg[(size_t)(r+8)*128 + c];
            float2 v2 = *(const float2*)&Kg[(size_t)r*128 + c + 8];
            float2 v3 = *(const float2*)&Kg[(size_t)(r+8)*128 + c + 8];
            unsigned aH[4], aL[4]; float lx, ly;
            aH[0] = pack_hi(v0.x, v0.y, lx, ly); aL[0] = pack_bf2(lx, ly);
            aH[1] = pack_hi(v1.x, v1.y, lx, ly); aL[1] = pack_bf2(lx, ly);
            aH[2] = pack_hi(v2.x, v2.y, lx, ly); aL[2] = pack_bf2(lx, ly);
            aH[3] = pack_hi(v3.x, v3.y, lx, ly); aL[3] = pack_bf2(lx, ly);
            #pragma unroll
            for (int q = 0; q < 4; q++){
                unsigned bH[4], bL[4];
                ldsm4t(bH[0],bH[1],bH[2],bH[3], Rb + boff[q] + k*16*IRS);
                ldsm4t(bL[0],bL[1],bL[2],bL[3], Rb + IMAT + boff[q] + k*16*IRS);
                mma16816(P[2*q],   aH, bH);
                mma16816(P[2*q+1], aH, bH+2);
                mma16816(P[2*q],   aL, bH);
                mma16816(P[2*q+1], aL, bH+2);
                mma16816(P[2*q],   aH, bL);
                mma16816(P[2*q+1], aH, bL+2);
            }
        }
    };

    auto store_mat = [&](int slot, float (*F)[4]){
        #pragma unroll
        for (int half = 0; half < 2; half++){
            int r = m0 + g + half*8;
            #pragma unroll
            for (int j = 0; j < 8; j++){
                int c = nb + j*8 + tg*2;
                float x = F[j][half*2], y = F[j][half*2+1];
                float lx, ly;
                unsigned hp = pack_hi(x, y, lx, ly);
                unsigned lp = pack_bf2(lx, ly);
                *(unsigned*)(ismem + slot*IMAT + r*IRS + c*2) = hp;
                *(unsigned*)(ismem + (slot+1)*IMAT + r*IRS + c*2) = lp;
            }
        }
    };

    for (int it = 0; it < 6; it++){
        mm_KV();
        #pragma unroll
        for (int j=0;j<8;j++)
            #pragma unroll
            for (int e=0;e<4;e++) Aa[j][e] = P[j][e];
        __syncthreads();
        store_mat(2, Aa);
        __syncthreads();

        mm_ss(2, 2);
        #pragma unroll
        for (int j=0;j<8;j++)
            #pragma unroll
            for (int e=0;e<4;e++) P[j][e] = 7.f*Aa[j][e] - P[j][e];
        __syncthreads();
        store_mat(4, P);
        __syncthreads();

        mm_ss(2, 4);
        #pragma unroll
        for (int j=0;j<8;j++)
            #pragma unroll
            for (int e=0;e<4;e++) P[j][e] = 15.f*Aa[j][e] - P[j][e];
        __syncthreads();
        store_mat(4, P);
        __syncthreads();

        mm_ss(0, 4);
        __syncthreads();
        #pragma unroll
        for (int half = 0; half < 2; half++){
            int r = m0 + g + half*8;
            #pragma unroll
            for (int j = 0; j < 8; j++){
                int c = nb + j*8 + tg*2;
                unsigned hp = *(unsigned*)(ismem + 0*IMAT + r*IRS + c*2);
                unsigned lp = *(unsigned*)(ismem + 1*IMAT + r*IRS + c*2);
                __nv_bfloat162 hb = *(__nv_bfloat162*)&hp;
                __nv_bfloat162 lb = *(__nv_bfloat162*)&lp;
                float vx = __bfloat162float(hb.x) + __bfloat162float(lb.x);
                float vy = __bfloat162float(hb.y) + __bfloat162float(lb.y);
                P[j][half*2]   = 3.25f*vx - 0.25f*P[j][half*2];
                P[j][half*2+1] = 3.25f*vy - 0.25f*P[j][half*2+1];
            }
        }
        store_mat(0, P);
        __syncthreads();
    }

    {
        int i = tid >> 2, h0 = (tid & 3) * 16;
        const float* Ng = g_k3V + (size_t)bh*8192;
        for (int j = 0; j < 16; j++){
            float v = Ng[i*64 + h0 + j];
            __nv_bfloat16 hi = __float2bfloat16(v);
            __nv_bfloat16 lo = __float2bfloat16(v - __bfloat162float(hi));
            *(__nv_bfloat16*)(ismem + 2*IMAT + i*IRS + (h0+j)*2) = hi;
            *(__nv_bfloat16*)(ismem + 3*IMAT + i*IRS + (h0+j)*2) = lo;
        }
    }
    __syncthreads();
    {
        int nbW = nw * 32;
        unsigned boffW[2];
        #pragma unroll
        for (int q = 0; q < 2; q++)
            boffW[q] = (unsigned)(((t8&1)*8 + i8)*IRS + (nbW + q*16 + (t8>>1)*8)*2);

        float Pw[4][4];
        #pragma unroll
        for (int j=0;j<4;j++)
            #pragma unroll
            for (int e=0;e<4;e++) Pw[j][e] = 0.f;

        #pragma unroll
        for (int k = 0; k < 8; k++){
            unsigned aH[4], aL[4];
            ldsm4(aH[0],aH[1],aH[2],aH[3], smb + aoff + k*32);
            ldsm4(aL[0],aL[1],aL[2],aL[3], smb + IMAT + aoff + k*32);
            #pragma unroll
            for (int q = 0; q < 2; q++){
                unsigned bH[4], bL[4];
                ldsm4t(bH[0],bH[1],bH[2],bH[3], smb + 2*IMAT + boffW[q] + k*16*IRS);
                ldsm4t(bL[0],bL[1],bL[2],bL[3], smb + 3*IMAT + boffW[q] + k*16*IRS);
                mma16816(Pw[2*q],   aH, bH);
                mma16816(Pw[2*q+1], aH, bH+2);
                mma16816(Pw[2*q],   aL, bH);
                mma16816(Pw[2*q+1], aL, bH+2);
                mma16816(Pw[2*q],   aH, bL);
                mma16816(Pw[2*q+1], aH, bL+2);
            }
        }
        float* Wg = g_W2 + (size_t)bh*8192;
        #pragma unroll
        for (int half = 0; half < 2; half++){
            int r = m0 + g + half*8;
            #pragma unroll
            for (int j = 0; j < 4; j++){
                int c = nbW + j*8 + tg*2;
                *(float2*)&Wg[r*64 + c] = make_float2(Pw[j][half*2], Pw[j][half*2+1]);
            }
        }
    }
}

// ---------------- k1 on HMMA: ctx = softmax(Q @ Kl^T) @ W2 ---------------------
#define KLRS 144
#define K1MAT 18432
#define K1_SMEM (4*K1MAT)

__global__ __launch_bounds__(256, 2)
void k1_kernel(){
    extern __shared__ __align__(16) char ksm[];
    const unsigned smb = smem_u32(ksm);
    const int sblk = blockIdx.x, bh = blockIdx.y;
    const int tid = threadIdx.x, lane = tid & 31, w = tid >> 5;
    const int g = lane >> 2, tg = lane & 3;
    const int i8 = lane & 7, t8 = lane >> 3;
    const int m0 = w * 16;

    const float* Klg = g_Kl + (size_t)bh*8192;
    const float* W2g = g_W2 + (size_t)bh*8192;
    for (int idx = tid; idx < 8192; idx += 256){
        int r = idx >> 6, c = idx & 63;
        float v = Klg[idx];
        __nv_bfloat16 hi = __float2bfloat16(v);
        __nv_bfloat16 lo = __float2bfloat16(v - __bfloat162float(hi));
        *(__nv_bfloat16*)(ksm + 0*K1MAT + r*KLRS + c*2) = hi;
        *(__nv_bfloat16*)(ksm + 1*K1MAT + r*KLRS + c*2) = lo;
        v = W2g[idx];
        hi = __float2bfloat16(v);
        lo = __float2bfloat16(v - __bfloat162float(hi));
        *(__nv_bfloat16*)(ksm + 2*K1MAT + r*KLRS + c*2) = hi;
        *(__nv_bfloat16*)(ksm + 3*K1MAT + r*KLRS + c*2) = lo;
    }
    __syncthreads();

    const float* Qg = g_Q + ((size_t)bh*S_ + sblk*128)*HD_;
    float st[16][4];
    #pragma unroll
    for (int nt=0;nt<16;nt++)
        #pragma unroll
        for (int e=0;e<4;e++) st[nt][e] = 0.f;

    #pragma unroll
    for (int kc = 0; kc < 4; kc++){
        int r = m0 + g, c = kc*16 + tg*2;
        float2 v0 = *(const float2*)&Qg[(size_t)r*64 + c];
        float2 v1 = *(const float2*)&Qg[(size_t)(r+8)*64 + c];
        float2 v2 = *(const float2*)&Qg[(size_t)r*64 + c + 8];
        float2 v3 = *(const float2*)&Qg[(size_t)(r+8)*64 + c + 8];
        unsigned aH[4], aL[4]; float lx, ly;
        aH[0] = pack_hi(v0.x, v0.y, lx, ly); aL[0] = pack_bf2(lx, ly);
        aH[1] = pack_hi(v1.x, v1.y, lx, ly); aL[1] = pack_bf2(lx, ly);
        aH[2] = pack_hi(v2.x, v2.y, lx, ly); aL[2] = pack_bf2(lx, ly);
        aH[3] = pack_hi(v3.x, v3.y, lx, ly); aL[3] = pack_bf2(lx, ly);
        #pragma unroll
        for (int q = 0; q < 8; q++){
            unsigned kOff = (unsigned)((q*16 + (t8>>1)*8 + i8)*KLRS + (t8&1)*16 + kc*32);
            unsigned bH[4], bL[4];
            ldsm4(bH[0],bH[1],bH[2],bH[3], smb + 0*K1MAT + kOff);
            ldsm4(bL[0],bL[1],bL[2],bL[3], smb + 1*K1MAT + kOff);
            mma16816(st[2*q],   aH, bH);
            mma16816(st[2*q+1], aH, bH+2);
            mma16816(st[2*q],   aL, bH);
            mma16816(st[2*q+1], aL, bH+2);
            mma16816(st[2*q],   aH, bL);
            mma16816(st[2*q+1], aH, bL+2);
        }
    }

    float mx0 = -1e30f, mx1 = -1e30f;
    #pragma unroll
    for (int nt = 0; nt < 16; nt++){
        mx0 = fmaxf(mx0, fmaxf(st[nt][0], st[nt][1]));
        mx1 = fmaxf(mx1, fmaxf(st[nt][2], st[nt][3]));
    }
    mx0 = fmaxf(mx0, __shfl_xor_sync(0xffffffffu, mx0, 1));
    mx0 = fmaxf(mx0, __shfl_xor_sync(0xffffffffu, mx0, 2));
    mx1 = fmaxf(mx1, __shfl_xor_sync(0xffffffffu, mx1, 1));
    mx1 = fmaxf(mx1, __shfl_xor_sync(0xffffffffu, mx1, 2));
    float z0 = 0.f, z1 = 0.f;
    #pragma unroll
    for (int nt = 0; nt < 16; nt++){
        st[nt][0] = __expf(st[nt][0] - mx0);
        st[nt][1] = __expf(st[nt][1] - mx0);
        st[nt][2] = __expf(st[nt][2] - mx1);
        st[nt][3] = __expf(st[nt][3] - mx1);
        z0 += st[nt][0] + st[nt][1];
        z1 += st[nt][2] + st[nt][3];
    }
    z0 += __shfl_xor_sync(0xffffffffu, z0, 1);
    z0 += __shfl_xor_sync(0xffffffffu, z0, 2);
    z1 += __shfl_xor_sync(0xffffffffu, z1, 1);
    z1 += __shfl_xor_sync(0xffffffffu, z1, 2);
    float zi0 = 1.f/z0, zi1 = 1.f/z1;
    #pragma unroll
    for (int nt = 0; nt < 16; nt++){
        st[nt][0] *= zi0; st[nt][1] *= zi0;
        st[nt][2] *= zi1; st[nt][3] *= zi1;
    }

    float o[8][4];
    #pragma unroll
    for (int j=0;j<8;j++)
        #pragma unroll
        for (int e=0;e<4;e++) o[j][e] = 0.f;

    #pragma unroll
    for (int kc = 0; kc < 8; kc++){
        unsigned aH[4], aL[4]; float lx, ly;
        aH[0] = pack_hi(st[2*kc][0],   st[2*kc][1],   lx, ly); aL[0] = pack_bf2(lx, ly);
        aH[1] = pack_hi(st[2*kc][2],   st[2*kc][3],   lx, ly); aL[1] = pack_bf2(lx, ly);
        aH[2] = pack_hi(st[2*kc+1][0], st[2*kc+1][1], lx, ly); aL[2] = pack_bf2(lx, ly);
        aH[3] = pack_hi(st[2*kc+1][2], st[2*kc+1][3], lx, ly); aL[3] = pack_bf2(lx, ly);
        #pragma unroll
        for (int q = 0; q < 4; q++){
            unsigned wOff = (unsigned)(((t8&1)*8 + i8 + kc*16)*KLRS + (q*16 + (t8>>1)*8)*2);
            unsigned bH[4], bL[4];
            ldsm4t(bH[0],bH[1],bH[2],bH[3], smb + 2*K1MAT + wOff);
            ldsm4t(bL[0],bL[1],bL[2],bL[3], smb + 3*K1MAT + wOff);
            mma16816(o[2*q],   aH, bH);
            mma16816(o[2*q+1], aH, bH+2);
            mma16816(o[2*q],   aL, bH);
            mma16816(o[2*q+1], aL, bH+2);
            mma16816(o[2*q],   aH, bL);
            mma16816(o[2*q+1], aH, bL+2);
        }
    }

    int b = bh >> 4, h = bh & 15;
    #pragma unroll
    for (int half = 0; half < 2; half++){
        int sI = sblk*128 + m0 + g + half*8;
        size_t obase = ((size_t)(b*S_ + sI))*D_ + h*64;
        #pragma unroll
        for (int nt = 0; nt < 8; nt++){
            int d = nt*8 + tg*2;
            float x = o[nt][half*2], y = o[nt][half*2+1];
            float lx, ly;
            unsigned hp = pack_hi(x, y, lx, ly);
            unsigned lp = pack_bf2(lx, ly);
            *(unsigned*)&g_ctxh[obase + d] = hp;
            *(unsigned*)&g_ctxl[obase + d] = lp;
        }
    }
}

// ---------------- launch -------------------------------------------------------
extern "C" void kernel_launch(void* const* d_in, const int* in_sizes, int n_in,
                              void* d_out, int out_size)
{
    const float* X    = (const float*)d_in[0];
    const float* mask = (const float*)d_in[1];
    const float* Wq   = (const float*)d_in[2];
    const float* bq   = (const float*)d_in[3];
    const float* Wk   = (const float*)d_in[4];
    const float* bk   = (const float*)d_in[5];
    const float* Wv   = (const float*)d_in[6];
    const float* bv   = (const float*)d_in[7];
    const float* Wo   = (const float*)d_in[8];
    const float* bo   = (const float*)d_in[9];
    float* out = (float*)d_out;

    void *pQ, *pK, *pV;
    cudaGetSymbolAddress(&pQ, g_Q);
    cudaGetSymbolAddress(&pK, g_K);
    cudaGetSymbolAddress(&pV, g_V);

    cudaFuncSetAttribute(gemm_qkv, cudaFuncAttributeMaxDynamicSharedMemorySize, GSMEM);
    cudaFuncSetAttribute(gemm_out, cudaFuncAttributeMaxDynamicSharedMemorySize, GSMEM);
    cudaFuncSetAttribute(inv_kernel, cudaFuncAttributeMaxDynamicSharedMemorySize, INV_SMEM);
    cudaFuncSetAttribute(k1_kernel,  cudaFuncAttributeMaxDynamicSharedMemorySize, K1_SMEM);
    cudaFuncSetAttribute(k3_mma,     cudaFuncAttributeMaxDynamicSharedMemorySize, K3_SMEM);

    convX_kernel<<<8192, 256>>>(X);                       // 1
    convW_kernel<<<dim3(32,32,4), 256>>>(Wq, Wk, Wv, Wo); // 2
    probe_kernel<<<1, 32>>>();                            // 3
    gemm_qkv<<<dim3(24,64), 256, GSMEM>>>(bq, bk, bv, mask,
                                          (float*)pQ, (float*)pK, (float*)pV); // 4 <- ncu

    landmark_kernel<<<(BH_*NL_*HD_)/256, 256>>>();
    k2_kernel<<<dim3(NL_, BH_), 128>>>();
    colmax_kernel<<<BH_, 128>>>();
    k3_mma<<<dim3(8, BH_), 256, K3_SMEM>>>(mask);
    k3_combine<<<BH_, 128>>>();
    inv_kernel<<<BH_, 512, INV_SMEM>>>();
    k1_kernel<<<dim3(32, BH_), 256, K1_SMEM>>>();

    gemm_out<<<dim3(8,64), 256, GSMEM>>>(bo, out);
}

// round 14
// speedup vs baseline: 7.7475x; 1.2472x over previous
#include <cuda_runtime.h>
#include <cuda_bf16.h>
#include <cuda_fp16.h>

// Problem constants
#define B_  2
#define S_  4096
#define HID_ 1024
#define NH_ 16
#define HD_ 64
#define NL_ 128
#define BH_ (B_*NH_)          // 32
#define SEG_ (S_/NL_)         // 32
#define D_ (NH_*HD_)          // 1024
#define SCALE_ 0.35355339059327373f  // HD^-0.25

// ---------------- device scratch -----------------------------------------------
__device__ float g_Q[B_*NH_*S_*HD_];     // (b,h,s,d) scaled+masked
__device__ float g_K[B_*NH_*S_*HD_];
__device__ float g_V[B_*NH_*S_*HD_];
__device__ float g_Ql[BH_*NL_*HD_];
__device__ float g_Kl[BH_*NL_*HD_];
__device__ float g_k2[BH_*NL_*NL_];
__device__ float g_bhmax[BH_];
__device__ float g_k3V[BH_*NL_*HD_];
__device__ float g_W2[BH_*NL_*HD_];
__device__ float g_k3o[BH_*8*NL_*HD_];   // split-K partials
__device__ float g_k3mz[BH_*8*NL_*2];
__device__ __align__(256) __half g_Xh[8192*1024];
__device__ __align__(256) __half g_Xl[8192*1024];
__device__ __align__(256) __half g_Wth[4*1024*1024];   // [4][n][k] q,k,v,o (fp16 hi only)
__device__ __align__(256) __half g_ctxh[8192*1024];
__device__ __align__(256) __half g_ctxl[8192*1024];

__device__ __forceinline__ unsigned smem_u32(const void* p){
    unsigned a;
    asm("{ .reg .u64 t; cvta.to.shared.u64 t, %1; cvt.u32.u64 %0, t; }" : "=r"(a) : "l"(p));
    return a;
}
__device__ __forceinline__ void ldsm4(unsigned& r0, unsigned& r1, unsigned& r2, unsigned& r3,
                                      unsigned addr){
    asm volatile("ldmatrix.sync.aligned.m8n8.x4.shared.b16 {%0,%1,%2,%3}, [%4];"
        : "=r"(r0), "=r"(r1), "=r"(r2), "=r"(r3) : "r"(addr));
}
__device__ __forceinline__ void ldsm4t(unsigned& r0, unsigned& r1, unsigned& r2, unsigned& r3,
                                       unsigned addr){
    asm volatile("ldmatrix.sync.aligned.m8n8.x4.trans.shared.b16 {%0,%1,%2,%3}, [%4];"
        : "=r"(r0), "=r"(r1), "=r"(r2), "=r"(r3) : "r"(addr));
}
// bf16 mma (attention mid-section)
__device__ __forceinline__ void mma16816(float* c, const unsigned* a, const unsigned* b){
    asm volatile(
        "mma.sync.aligned.m16n8k16.row.col.f32.bf16.bf16.f32 "
        "{%0,%1,%2,%3}, {%4,%5,%6,%7}, {%8,%9}, {%0,%1,%2,%3};"
        : "+f"(c[0]), "+f"(c[1]), "+f"(c[2]), "+f"(c[3])
        : "r"(a[0]), "r"(a[1]), "r"(a[2]), "r"(a[3]), "r"(b[0]), "r"(b[1]));
}
// fp16 mma (big GEMMs)
__device__ __forceinline__ void mma16816h(float* c, const unsigned* a, const unsigned* b){
    asm volatile(
        "mma.sync.aligned.m16n8k16.row.col.f32.f16.f16.f32 "
        "{%0,%1,%2,%3}, {%4,%5,%6,%7}, {%8,%9}, {%0,%1,%2,%3};"
        : "+f"(c[0]), "+f"(c[1]), "+f"(c[2]), "+f"(c[3])
        : "r"(a[0]), "r"(a[1]), "r"(a[2]), "r"(a[3]), "r"(b[0]), "r"(b[1]));
}
__device__ __forceinline__ unsigned pack_hi(float x, float y, float& lx, float& ly){
    __nv_bfloat162 h = __floats2bfloat162_rn(x, y);
    lx = x - __bfloat162float(h.x);
    ly = y - __bfloat162float(h.y);
    return *(unsigned*)&h;
}
__device__ __forceinline__ unsigned pack_bf2(float x, float y){
    __nv_bfloat162 h = __floats2bfloat162_rn(x, y);
    return *(unsigned*)&h;
}
__device__ __forceinline__ void cp16(unsigned dst, const void* src){
    asm volatile("cp.async.cg.shared.global [%0], [%1], 16;" :: "r"(dst), "l"(src));
}
__device__ __forceinline__ void cpcommit(){ asm volatile("cp.async.commit_group;" ::: "memory"); }
template<int N> __device__ __forceinline__ void cpwait(){
    asm volatile("cp.async.wait_group %0;" :: "n"(N) : "memory");
}

// ---------------- probe (keeps gemm_qkv in the profiled 4th slot) --------------
__global__ void probe_kernel(){
    if (threadIdx.x < BH_) g_bhmax[threadIdx.x] = 0.f;
}

// ---------------- prep: split X into fp16 hi/lo --------------------------------
__global__ void convX_kernel(const float* __restrict__ X){
    size_t i4 = (size_t)blockIdx.x * blockDim.x + threadIdx.x;
    float4 v = ((const float4*)X)[i4];
    float vs[4] = {v.x, v.y, v.z, v.w};
    __half hi[4], lo[4];
    #pragma unroll
    for (int c = 0; c < 4; c++){
        hi[c] = __float2half_rn(vs[c]);
        lo[c] = __float2half_rn(vs[c] - __half2float(hi[c]));
    }
    *(uint2*)&g_Xh[i4*4] = *(uint2*)hi;
    *(uint2*)&g_Xl[i4*4] = *(uint2*)lo;
}

// ---------------- prep: transpose weights -> [n][k] fp16 hi -------------------
__global__ void convW_kernel(const float* __restrict__ Wq, const float* __restrict__ Wk,
                             const float* __restrict__ Wv, const float* __restrict__ Wo){
    __shared__ float t[32][33];
    int z = blockIdx.z;
    const float* W = (z==0) ? Wq : (z==1) ? Wk : (z==2) ? Wv : Wo;
    int n0 = blockIdx.x * 32, k0 = blockIdx.y * 32;
    int tx = threadIdx.x & 31, ty = threadIdx.x >> 5;
    #pragma unroll
    for (int r = 0; r < 4; r++){
        int ky = ty + r*8;
        t[ky][tx] = W[(size_t)(k0 + ky)*1024 + n0 + tx];
    }
    __syncthreads();
    #pragma unroll
    for (int r = 0; r < 4; r++){
        int ny = ty + r*8;
        size_t o = (size_t)z*1048576 + (size_t)(n0 + ny)*1024 + k0 + tx;
        g_Wth[o] = __float2half_rn(t[tx][ny]);
    }
}

// ================= fp16 HMMA GEMM mainloop =====================================
// R14: fp16 operands, A 2-split (exact to 2^-22), B single fp16 (err 2^-12).
// 2 products instead of 3 -> 32 mma per kb (was 48). Stage = 3 tiles (Ah,Al,Bh).
#define ROWBY 80
#define TILEB (128*ROWBY)
#define STAGEB (3*TILEB)      // 30720
#define GSMEM (2*STAGEB)      // 61440

__device__ __forceinline__ void gemm_main(
    const __half* __restrict__ Ah, const __half* __restrict__ Al,
    const __half* __restrict__ Bh,
    unsigned smb, float acc[2][8][4])
{
    const int tid = threadIdx.x, lane = tid & 31, w = tid >> 5;
    const int wr = w & 3, wc = w >> 2;

    unsigned aoff[2], boff[4];
    {
        int i = lane & 7, t8 = lane >> 3;
        #pragma unroll
        for (int t = 0; t < 2; t++)
            aoff[t] = (unsigned)((wr*32 + t*16 + (t8 & 1)*8 + i) * ROWBY + (t8 >> 1) * 16);
        #pragma unroll
        for (int q = 0; q < 4; q++)
            boff[q] = (unsigned)((wc*64 + q*16 + (t8 >> 1)*8 + i) * ROWBY + (t8 & 1) * 16);
    }

    auto issue = [&](int buf, int k0){
        #pragma unroll
        for (int r = 0; r < 6; r++){
            int idx = r*256 + tid;
            int c = idx & 3, row = (idx >> 2) & 127, tile = idx >> 9;
            const __half* src =
                (tile == 0) ? Ah + (size_t)row*1024 + k0 + c*8 :
                (tile == 1) ? Al + (size_t)row*1024 + k0 + c*8 :
                              Bh + (size_t)row*1024 + k0 + c*8;
            cp16(smb + buf*STAGEB + tile*TILEB + row*ROWBY + c*16, src);
        }
        cpcommit();
    };

    issue(0, 0);
    for (int s = 0; s < 32; s++){
        __syncthreads();
        if (s < 31){ issue((s+1) & 1, (s+1)*32); cpwait<1>(); }
        else       { cpwait<0>(); }
        __syncthreads();

        unsigned base = smb + (s & 1)*STAGEB;
        #pragma unroll
        for (int kb = 0; kb < 2; kb++){
            unsigned ko = kb * 32;
            unsigned aH[2][4], aL[2][4], bX[4][4];
            #pragma unroll
            for (int t = 0; t < 2; t++){
                ldsm4(aH[t][0], aH[t][1], aH[t][2], aH[t][3], base + aoff[t] + ko);
                ldsm4(aL[t][0], aL[t][1], aL[t][2], aL[t][3], base + TILEB + aoff[t] + ko);
            }
            #pragma unroll
            for (int q = 0; q < 4; q++)
                ldsm4(bX[q][0], bX[q][1], bX[q][2], bX[q][3], base + 2*TILEB + boff[q] + ko);
            // pass 1: aH * bH
            #pragma unroll
            for (int t = 0; t < 2; t++)
                #pragma unroll
                for (int q = 0; q < 4; q++){
                    mma16816h(acc[t][2*q],   aH[t], &bX[q][0]);
                    mma16816h(acc[t][2*q+1], aH[t], &bX[q][2]);
                }
            // pass 2: aL * bH
            #pragma unroll
            for (int t = 0; t < 2; t++)
                #pragma unroll
                for (int q = 0; q < 4; q++){
                    mma16816h(acc[t][2*q],   aL[t], &bX[q][0]);
                    mma16816h(acc[t][2*q+1], aL[t], &bX[q][2]);
                }
        }
    }
}

__global__ __launch_bounds__(256, 2)
void gemm_qkv(const float* __restrict__ bq, const float* __restrict__ bk,
              const float* __restrict__ bv, const float* __restrict__ mask,
              float* __restrict__ oq, float* __restrict__ okk, float* __restrict__ ov)
{
    extern __shared__ __align__(16) char smem[];
    unsigned smb = smem_u32(smem);
    int wsel = blockIdx.x >> 3, colt = blockIdx.x & 7;
    const __half* Ah = g_Xh + (size_t)blockIdx.y*128*1024;
    const __half* Al = g_Xl + (size_t)blockIdx.y*128*1024;
    const __half* Bh = g_Wth + ((size_t)wsel*1024 + colt*128)*1024;

    float acc[2][8][4];
    #pragma unroll
    for (int t=0;t<2;t++)
        #pragma unroll
        for (int j=0;j<8;j++)
            #pragma unroll
            for (int e=0;e<4;e++) acc[t][j][e] = 0.f;

    gemm_main(Ah, Al, Bh, smb, acc);

    const float* bias = (wsel==0) ? bq : (wsel==1) ? bk : bv;
    float* out = (wsel==0) ? oq : (wsel==1) ? okk : ov;
    const bool scaled = (wsel < 2);

    int lane = threadIdx.x & 31, w = threadIdx.x >> 5;
    int wr = w & 3, wc = w >> 2;
    int g = lane >> 2, tg = lane & 3;
    #pragma unroll
    for (int t = 0; t < 2; t++){
        #pragma unroll
        for (int half = 0; half < 2; half++){
            int row = blockIdx.y*128 + wr*32 + t*16 + g + half*8;
            float rs = scaled ? SCALE_ * mask[row] : 1.0f;
            int bb = row >> 12, sI = row & 4095;
            #pragma unroll
            for (int j = 0; j < 8; j++){
                int col = colt*128 + wc*64 + j*8 + tg*2;
                float c0 = (acc[t][j][half*2]   + bias[col])   * rs;
                float c1 = (acc[t][j][half*2+1] + bias[col+1]) * rs;
                int h = col >> 6, d = col & 63;
                *(float2*)(out + ((size_t)(bb*NH_ + h)*S_ + sI)*HD_ + d) = make_float2(c0, c1);
            }
        }
    }
}

__global__ __launch_bounds__(256, 2)
void gemm_out(const float* __restrict__ bias, float* __restrict__ out)
{
    extern __shared__ __align__(16) char smem[];
    unsigned smb = smem_u32(smem);
    const __half* Ah = g_ctxh + (size_t)blockIdx.y*128*1024;
    const __half* Al = g_ctxl + (size_t)blockIdx.y*128*1024;
    const __half* Bh = g_Wth + (size_t)3*1048576 + (size_t)blockIdx.x*128*1024;

    float acc[2][8][4];
    #pragma unroll
    for (int t=0;t<2;t++)
        #pragma unroll
        for (int j=0;j<8;j++)
            #pragma unroll
            for (int e=0;e<4;e++) acc[t][j][e] = 0.f;

    gemm_main(Ah, Al, Bh, smb, acc);

    int lane = threadIdx.x & 31, w = threadIdx.x >> 5;
    int wr = w & 3, wc = w >> 2;
    int g = lane >> 2, tg = lane & 3;
    #pragma unroll
    for (int t = 0; t < 2; t++){
        #pragma unroll
        for (int half = 0; half < 2; half++){
            int row = blockIdx.y*128 + wr*32 + t*16 + g + half*8;
            #pragma unroll
            for (int j = 0; j < 8; j++){
                int col = blockIdx.x*128 + wc*64 + j*8 + tg*2;
                float c0 = acc[t][j][half*2]   + bias[col];
                float c1 = acc[t][j][half*2+1] + bias[col+1];
                *(float2*)(out + (size_t)row*1024 + col) = make_float2(c0, c1);
            }
        }
    }
}

// ---------------- landmarks ----------------------------------------------------
__global__ void landmark_kernel(){
    int idx = blockIdx.x*blockDim.x + threadIdx.x;
    int d  = idx & 63;
    int l  = (idx >> 6) & 127;
    int bh = idx >> 13;
    const float* q = g_Q + ((size_t)bh*S_ + l*SEG_)*HD_ + d;
    const float* k = g_K + ((size_t)bh*S_ + l*SEG_)*HD_ + d;
    float sq = 0.f, sk = 0.f;
    #pragma unroll
    for (int j=0; j<SEG_; j++){ sq += q[j*HD_]; sk += k[j*HD_]; }
    g_Ql[idx] = sq * (1.f/SEG_);
    g_Kl[idx] = sk * (1.f/SEG_);
}

// ---------------- k2 = softmax(Ql @ Kl^T) --------------------------------------
__global__ void k2_kernel(){
    int l = blockIdx.x, bh = blockIdx.y, m = threadIdx.x;
    const float4* ql = (const float4*)(g_Ql + ((size_t)bh*NL_ + l)*HD_);
    const float4* kl = (const float4*)(g_Kl + ((size_t)bh*NL_ + m)*HD_);
    float acc = 0.f;
    #pragma unroll
    for (int d4=0; d4<16; d4++){
        float4 a = ql[d4], b = kl[d4];
        acc += a.x*b.x + a.y*b.y + a.z*b.z + a.w*b.w;
    }
    __shared__ float red[128];
    red[m] = acc; __syncthreads();
    for (int off=64; off>0; off>>=1){
        if (m < off) red[m] = fmaxf(red[m], red[m+off]);
        __syncthreads();
    }
    float mx = red[0]; __syncthreads();
    float p = __expf(acc - mx);
    red[m] = p; __syncthreads();
    for (int off=64; off>0; off>>=1){
        if (m < off) red[m] += red[m+off];
        __syncthreads();
    }
    g_k2[((size_t)bh*NL_ + l)*NL_ + m] = p / red[0];
}

// ---------------- column sums of k2 -> per-bh max ------------------------------
__global__ void colmax_kernel(){
    int bh = blockIdx.x, m = threadIdx.x;
    float s = 0.f;
    for (int l=0; l<NL_; l++) s += g_k2[((size_t)bh*NL_ + l)*NL_ + m];
    __shared__ float red[128];
    red[m] = s; __syncthreads();
    for (int off=64; off>0; off>>=1){
        if (m < off) red[m] = fmaxf(red[m], red[m+off]);
        __syncthreads();
    }
    if (m == 0) g_bhmax[bh] = red[0];
}

// ---------------- k3 on HMMA: flash-style split-K ------------------------------
#define K3RS  144
#define K3MAT 18432
#define K3_SMEM (6*K3MAT + 512)

__global__ __launch_bounds__(256, 1)
void k3_mma(const float* __restrict__ mask){
    extern __shared__ __align__(16) char ksm[];
    const unsigned smb = smem_u32(ksm);
    const int chunk = blockIdx.x, bh = blockIdx.y;
    const int tid = threadIdx.x, lane = tid & 31, w = tid >> 5;
    const int g = lane >> 2, tg = lane & 3;
    const int i8 = lane & 7, t8 = lane >> 3;
    const int m0 = w * 16;
    float* msk = (float*)(ksm + 6*K3MAT);

    const float* Qlg = g_Ql + (size_t)bh*8192;
    for (int idx = tid; idx < 8192; idx += 256){
        int r = idx >> 6, c = idx & 63;
        float v = Qlg[idx];
        __nv_bfloat16 hi = __float2bfloat16(v);
        __nv_bfloat16 lo = __float2bfloat16(v - __bfloat162float(hi));
        *(__nv_bfloat16*)(ksm + 0*K3MAT + r*K3RS + c*2) = hi;
        *(__nv_bfloat16*)(ksm + 1*K3MAT + r*K3RS + c*2) = lo;
    }

    const float* Kbh = g_K + (size_t)bh*S_*HD_;
    const float* Vbh = g_V + (size_t)bh*S_*HD_;
    const float* mrow = mask + (size_t)(bh >> 4)*S_;

    const unsigned aoff = (unsigned)((m0 + (t8&1)*8 + i8)*K3RS + (t8>>1)*16);

    float mr0 = -1e30f, mr1 = -1e30f, z0 = 0.f, z1 = 0.f;
    float o[8][4];
    #pragma unroll
    for (int j=0;j<8;j++)
        #pragma unroll
        for (int e=0;e<4;e++) o[j][e] = 0.f;

    for (int it = 0; it < 4; it++){
        int sbase = chunk*512 + it*128;
        __syncthreads();
        for (int idx = tid; idx < 8192; idx += 256){
            int r = idx >> 6, c = idx & 63;
            float v = Kbh[(size_t)(sbase + r)*HD_ + c];
            __nv_bfloat16 hi = __float2bfloat16(v);
            __nv_bfloat16 lo = __float2bfloat16(v - __bfloat162float(hi));
            *(__nv_bfloat16*)(ksm + 2*K3MAT + r*K3RS + c*2) = hi;
            *(__nv_bfloat16*)(ksm + 3*K3MAT + r*K3RS + c*2) = lo;
            v = Vbh[(size_t)(sbase + r)*HD_ + c];
            hi = __float2bfloat16(v);
            lo = __float2bfloat16(v - __bfloat162float(hi));
            *(__nv_bfloat16*)(ksm + 4*K3MAT + r*K3RS + c*2) = hi;
            *(__nv_bfloat16*)(ksm + 5*K3MAT + r*K3RS + c*2) = lo;
        }
        if (tid < 128) msk[tid] = mrow[sbase + tid];
        __syncthreads();

        float st[16][4];
        #pragma unroll
        for (int nt=0;nt<16;nt++)
            #pragma unroll
            for (int e=0;e<4;e++) st[nt][e] = 0.f;

        #pragma unroll
        for (int kc = 0; kc < 4; kc++){
            unsigned aH[4], aL[4];
            ldsm4(aH[0],aH[1],aH[2],aH[3], smb + 0*K3MAT + aoff + kc*32);
            ldsm4(aL[0],aL[1],aL[2],aL[3], smb + 1*K3MAT + aoff + kc*32);
            #pragma unroll
            for (int q = 0; q < 8; q++){
                unsigned kOff = (unsigned)((q*16 + (t8>>1)*8 + i8)*K3RS + (t8&1)*16 + kc*32);
                unsigned bH[4], bL[4];
                ldsm4(bH[0],bH[1],bH[2],bH[3], smb + 2*K3MAT + kOff);
                ldsm4(bL[0],bL[1],bL[2],bL[3], smb + 3*K3MAT + kOff);
                mma16816(st[2*q],   aH, bH);
                mma16816(st[2*q+1], aH, bH+2);
                mma16816(st[2*q],   aL, bH);
                mma16816(st[2*q+1], aL, bH+2);
                mma16816(st[2*q],   aH, bL);
                mma16816(st[2*q+1], aH, bL+2);
            }
        }

        #pragma unroll
        for (int nt = 0; nt < 16; nt++){
            int c0 = nt*8 + tg*2;
            float p0 = -1e9f*(1.f - msk[c0]);
            float p1 = -1e9f*(1.f - msk[c0+1]);
            st[nt][0] += p0; st[nt][1] += p1;
            st[nt][2] += p0; st[nt][3] += p1;
        }

        float cm0 = -1e30f, cm1 = -1e30f;
        #pragma unroll
        for (int nt = 0; nt < 16; nt++){
            cm0 = fmaxf(cm0, fmaxf(st[nt][0], st[nt][1]));
            cm1 = fmaxf(cm1, fmaxf(st[nt][2], st[nt][3]));
        }
        cm0 = fmaxf(cm0, __shfl_xor_sync(0xffffffffu, cm0, 1));
        cm0 = fmaxf(cm0, __shfl_xor_sync(0xffffffffu, cm0, 2));
        cm1 = fmaxf(cm1, __shfl_xor_sync(0xffffffffu, cm1, 1));
        cm1 = fmaxf(cm1, __shfl_xor_sync(0xffffffffu, cm1, 2));
        float mn0 = fmaxf(mr0, cm0), mn1 = fmaxf(mr1, cm1);
        float cr0 = __expf(mr0 - mn0), cr1 = __expf(mr1 - mn1);
        mr0 = mn0; mr1 = mn1;
        z0 *= cr0; z1 *= cr1;
        #pragma unroll
        for (int j = 0; j < 8; j++){
            o[j][0] *= cr0; o[j][1] *= cr0;
            o[j][2] *= cr1; o[j][3] *= cr1;
        }
        float ps0 = 0.f, ps1 = 0.f;
        #pragma unroll
        for (int nt = 0; nt < 16; nt++){
            st[nt][0] = __expf(st[nt][0] - mn0);
            st[nt][1] = __expf(st[nt][1] - mn0);
            st[nt][2] = __expf(st[nt][2] - mn1);
            st[nt][3] = __expf(st[nt][3] - mn1);
            ps0 += st[nt][0] + st[nt][1];
            ps1 += st[nt][2] + st[nt][3];
        }
        ps0 += __shfl_xor_sync(0xffffffffu, ps0, 1);
        ps0 += __shfl_xor_sync(0xffffffffu, ps0, 2);
        ps1 += __shfl_xor_sync(0xffffffffu, ps1, 1);
        ps1 += __shfl_xor_sync(0xffffffffu, ps1, 2);
        z0 += ps0; z1 += ps1;

        #pragma unroll
        for (int kc = 0; kc < 8; kc++){
            unsigned aH[4], aL[4]; float lx, ly;
            aH[0] = pack_hi(st[2*kc][0],   st[2*kc][1],   lx, ly); aL[0] = pack_bf2(lx, ly);
            aH[1] = pack_hi(st[2*kc][2],   st[2*kc][3],   lx, ly); aL[1] = pack_bf2(lx, ly);
            aH[2] = pack_hi(st[2*kc+1][0], st[2*kc+1][1], lx, ly); aL[2] = pack_bf2(lx, ly);
            aH[3] = pack_hi(st[2*kc+1][2], st[2*kc+1][3], lx, ly); aL[3] = pack_bf2(lx, ly);
            #pragma unroll
            for (int q = 0; q < 4; q++){
                unsigned wOff = (unsigned)(((t8&1)*8 + i8 + kc*16)*K3RS + (q*16 + (t8>>1)*8)*2);
                unsigned bH[4], bL[4];
                ldsm4t(bH[0],bH[1],bH[2],bH[3], smb + 4*K3MAT + wOff);
                ldsm4t(bL[0],bL[1],bL[2],bL[3], smb + 5*K3MAT + wOff);
                mma16816(o[2*q],   aH, bH);
                mma16816(o[2*q+1], aH, bH+2);
                mma16816(o[2*q],   aL, bH);
                mma16816(o[2*q+1], aL, bH+2);
                mma16816(o[2*q],   aH, bL);
                mma16816(o[2*q+1], aH, bL+2);
            }
        }
    }

    size_t pbase = ((size_t)(bh*8 + chunk))*128;
    #pragma unroll
    for (int j = 0; j < 8; j++){
        int c = j*8 + tg*2;
        *(float2*)&g_k3o[(pbase + m0 + g)*64 + c]     = make_float2(o[j][0], o[j][1]);
        *(float2*)&g_k3o[(pbase + m0 + g + 8)*64 + c] = make_float2(o[j][2], o[j][3]);
    }
    if (tg == 0){
        g_k3mz[(pbase + m0 + g)*2]       = mr0;
        g_k3mz[(pbase + m0 + g)*2 + 1]   = z0;
        g_k3mz[(pbase + m0 + g + 8)*2]     = mr1;
        g_k3mz[(pbase + m0 + g + 8)*2 + 1] = z1;
    }
}

__global__ void k3_combine(){
    int bh = blockIdx.x, l = threadIdx.x;   // 128 threads
    float m[8], z[8], M = -1e30f;
    #pragma unroll
    for (int c = 0; c < 8; c++){
        m[c] = g_k3mz[((size_t)(bh*8 + c)*128 + l)*2];
        z[c] = g_k3mz[((size_t)(bh*8 + c)*128 + l)*2 + 1];
        M = fmaxf(M, m[c]);
    }
    float coef[8], Z = 0.f;
    #pragma unroll
    for (int c = 0; c < 8; c++){
        coef[c] = __expf(m[c] - M);
        Z += z[c]*coef[c];
    }
    float Zi = 1.f / Z;
    #pragma unroll
    for (int d4 = 0; d4 < 16; d4++){
        float4 acc = make_float4(0.f, 0.f, 0.f, 0.f);
        #pragma unroll
        for (int c = 0; c < 8; c++){
            float4 ov = *(const float4*)&g_k3o[((size_t)(bh*8 + c)*128 + l)*64 + d4*4];
            acc.x += coef[c]*ov.x; acc.y += coef[c]*ov.y;
            acc.z += coef[c]*ov.z; acc.w += coef[c]*ov.w;
        }
        acc.x *= Zi; acc.y *= Zi; acc.z *= Zi; acc.w *= Zi;
        *(float4*)&g_k3V[(size_t)bh*8192 + l*64 + d4*4] = acc;
    }
}

// ---------------- Newton inverse on HMMA: 512 threads, 16 warps ----------------
#define IRS  272
#define IMAT 34816
#define INV_SMEM (6*IMAT)

__global__ __launch_bounds__(512, 1)
void inv_kernel(){
    extern __shared__ __align__(16) char ismem[];
    const unsigned smb = smem_u32(ismem);
    const int bh = blockIdx.x, tid = threadIdx.x;
    const int lane = tid & 31, w = tid >> 5;
    const int mw = w & 7, nw = w >> 3;
    const int m0 = mw*16, nb = nw*64;
    const int g = lane >> 2, tg = lane & 3;
    const int i8 = lane & 7, t8 = lane >> 3;

    float cmax = g_bhmax[0];
    #pragma unroll
    for (int q=1; q<BH_; q++) cmax = fmaxf(cmax, g_bhmax[q]);
    const float rinv = 1.f / cmax;
    const float* Kg = g_k2 + (size_t)bh*NL_*NL_;

    {
        int i = tid >> 2, h0 = (tid & 3) * 32;
        for (int j = 0; j < 32; j++){
            float v = Kg[(h0 + j)*128 + i] * rinv;
            __nv_bfloat16 hi = __float2bfloat16(v);
            __nv_bfloat16 lo = __float2bfloat16(v - __bfloat162float(hi));
            *(__nv_bfloat16*)(ismem + 0*IMAT + i*IRS + (h0+j)*2) = hi;
            *(__nv_bfloat16*)(ismem + 1*IMAT + i*IRS + (h0+j)*2) = lo;
        }
    }
    __syncthreads();

    unsigned aoff = (unsigned)((m0 + (t8&1)*8 + i8)*IRS + (t8>>1)*16);
    unsigned boff[4];
    #pragma unroll
    for (int q = 0; q < 4; q++)
        boff[q] = (unsigned)(((t8&1)*8 + i8)*IRS + (nb + q*16 + (t8>>1)*8)*2);

    float P[8][4], Aa[8][4];

    auto mm_ss = [&](int Lh, int Rh){
        #pragma unroll
        for (int j=0;j<8;j++)
            #pragma unroll
            for (int e=0;e<4;e++) P[j][e] = 0.f;
        unsigned Lb = smb + (unsigned)Lh*IMAT;
        unsigned Rb = smb + (unsigned)Rh*IMAT;
        #pragma unroll
        for (int k = 0; k < 8; k++){
            unsigned aH[4], aL[4];
            ldsm4(aH[0],aH[1],aH[2],aH[3], Lb + aoff + k*32);
            ldsm4(aL[0],aL[1],aL[2],aL[3], Lb + IMAT + aoff + k*32);
            #pragma unroll
            for (int q = 0; q < 4; q++){
                unsigned bH[4], bL[4];
                ldsm4t(bH[0],bH[1],bH[2],bH[3], Rb + boff[q] + k*16*IRS);
                ldsm4t(bL[0],bL[1],bL[2],bL[3], Rb + IMAT + boff[q] + k*16*IRS);
                mma16816(P[2*q],   aH, bH);
                mma16816(P[2*q+1], aH, bH+2);
                mma16816(P[2*q],   aL, bH);
                mma16816(P[2*q+1], aL, bH+2);
                mma16816(P[2*q],   aH, bL);
                mma16816(P[2*q+1], aH, bL+2);
            }
        }
    };

    auto mm_KV = [&](){
        #pragma unroll
        for (int j=0;j<8;j++)
            #pragma unroll
            for (int e=0;e<4;e++) P[j][e] = 0.f;
        unsigned Rb = smb;
        #pragma unroll
        for (int k = 0; k < 8; k++){
            int k0 = k*16;
            int r = m0 + g, c = k0 + tg*2;
            float2 v0 = *(const float2*)&Kg[(size_t)r*128 + c];
            float2 v1 = *(const float2*)&Kg[(size_t)(r+8)*128 + c];
            float2 v2 = *(const float2*)&Kg[(size_t)r*128 + c + 8];
            float2 v3 = *(const float2*)&Kg[(size_t)(r+8)*128 + c + 8];
            unsigned aH[4], aL[4]; float lx, ly;
            aH[0] = pack_hi(v0.x, v0.y, lx, ly); aL[0] = pack_bf2(lx, ly);
            aH[1] = pack_hi(v1.x, v1.y, lx, ly); aL[1] = pack_bf2(lx, ly);
            aH[2] = pack_hi(v2.x, v2.y, lx, ly); aL[2] = pack_bf2(lx, ly);
            aH[3] = pack_hi(v3.x, v3.y, lx, ly); aL[3] = pack_bf2(lx, ly);
            #pragma unroll
            for (int q = 0; q < 4; q++){
                unsigned bH[4], bL[4];
                ldsm4t(bH[0],bH[1],bH[2],bH[3], Rb + boff[q] + k*16*IRS);
                ldsm4t(bL[0],bL[1],bL[2],bL[3], Rb + IMAT + boff[q] + k*16*IRS);
                mma16816(P[2*q],   aH, bH);
                mma16816(P[2*q+1], aH, bH+2);
                mma16816(P[2*q],   aL, bH);
                mma16816(P[2*q+1], aL, bH+2);
                mma16816(P[2*q],   aH, bL);
                mma16816(P[2*q+1], aH, bL+2);
            }
        }
    };

    auto store_mat = [&](int slot, float (*F)[4]){
        #pragma unroll
        for (int half = 0; half < 2; half++){
            int r = m0 + g + half*8;
            #pragma unroll
            for (int j = 0; j < 8; j++){
                int c = nb + j*8 + tg*2;
                float x = F[j][half*2], y = F[j][half*2+1];
                float lx, ly;
                unsigned hp = pack_hi(x, y, lx, ly);
                unsigned lp = pack_bf2(lx, ly);
                *(unsigned*)(ismem + slot*IMAT + r*IRS + c*2) = hp;
                *(unsigned*)(ismem + (slot+1)*IMAT + r*IRS + c*2) = lp;
            }
        }
    };

    for (int it = 0; it < 6; it++){
        mm_KV();
        #pragma unroll
        for (int j=0;j<8;j++)
            #pragma unroll
            for (int e=0;e<4;e++) Aa[j][e] = P[j][e];
        __syncthreads();
        store_mat(2, Aa);
        __syncthreads();

        mm_ss(2, 2);
        #pragma unroll
        for (int j=0;j<8;j++)
            #pragma unroll
            for (int e=0;e<4;e++) P[j][e] = 7.f*Aa[j][e] - P[j][e];
        __syncthreads();
        store_mat(4, P);
        __syncthreads();

        mm_ss(2, 4);
        #pragma unroll
        for (int j=0;j<8;j++)
            #pragma unroll
            for (int e=0;e<4;e++) P[j][e] = 15.f*Aa[j][e] - P[j][e];
        __syncthreads();
        store_mat(4, P);
        __syncthreads();

        mm_ss(0, 4);
        __syncthreads();
        #pragma unroll
        for (int half = 0; half < 2; half++){
            int r = m0 + g + half*8;
            #pragma unroll
            for (int j = 0; j < 8; j++){
                int c = nb + j*8 + tg*2;
                unsigned hp = *(unsigned*)(ismem + 0*IMAT + r*IRS + c*2);
                unsigned lp = *(unsigned*)(ismem + 1*IMAT + r*IRS + c*2);
                __nv_bfloat162 hb = *(__nv_bfloat162*)&hp;
                __nv_bfloat162 lb = *(__nv_bfloat162*)&lp;
                float vx = __bfloat162float(hb.x) + __bfloat162float(lb.x);
                float vy = __bfloat162float(hb.y) + __bfloat162float(lb.y);
                P[j][half*2]   = 3.25f*vx - 0.25f*P[j][half*2];
                P[j][half*2+1] = 3.25f*vy - 0.25f*P[j][half*2+1];
            }
        }
        store_mat(0, P);
        __syncthreads();
    }

    {
        int i = tid >> 2, h0 = (tid & 3) * 16;
        const float* Ng = g_k3V + (size_t)bh*8192;
        for (int j = 0; j < 16; j++){
            float v = Ng[i*64 + h0 + j];
            __nv_bfloat16 hi = __float2bfloat16(v);
            __nv_bfloat16 lo = __float2bfloat16(v - __bfloat162float(hi));
            *(__nv_bfloat16*)(ismem + 2*IMAT + i*IRS + (h0+j)*2) = hi;
            *(__nv_bfloat16*)(ismem + 3*IMAT + i*IRS + (h0+j)*2) = lo;
        }
    }
    __syncthreads();
    {
        int nbW = nw * 32;
        unsigned boffW[2];
        #pragma unroll
        for (int q = 0; q < 2; q++)
            boffW[q] = (unsigned)(((t8&1)*8 + i8)*IRS + (nbW + q*16 + (t8>>1)*8)*2);

        float Pw[4][4];
        #pragma unroll
        for (int j=0;j<4;j++)
            #pragma unroll
            for (int e=0;e<4;e++) Pw[j][e] = 0.f;

        #pragma unroll
        for (int k = 0; k < 8; k++){
            unsigned aH[4], aL[4];
            ldsm4(aH[0],aH[1],aH[2],aH[3], smb + aoff + k*32);
            ldsm4(aL[0],aL[1],aL[2],aL[3], smb + IMAT + aoff + k*32);
            #pragma unroll
            for (int q = 0; q < 2; q++){
                unsigned bH[4], bL[4];
                ldsm4t(bH[0],bH[1],bH[2],bH[3], smb + 2*IMAT + boffW[q] + k*16*IRS);
                ldsm4t(bL[0],bL[1],bL[2],bL[3], smb + 3*IMAT + boffW[q] + k*16*IRS);
                mma16816(Pw[2*q],   aH, bH);
                mma16816(Pw[2*q+1], aH, bH+2);
                mma16816(Pw[2*q],   aL, bH);
                mma16816(Pw[2*q+1], aL, bH+2);
                mma16816(Pw[2*q],   aH, bL);
                mma16816(Pw[2*q+1], aH, bL+2);
            }
        }
        float* Wg = g_W2 + (size_t)bh*8192;
        #pragma unroll
        for (int half = 0; half < 2; half++){
            int r = m0 + g + half*8;
            #pragma unroll
            for (int j = 0; j < 4; j++){
                int c = nbW + j*8 + tg*2;
                *(float2*)&Wg[r*64 + c] = make_float2(Pw[j][half*2], Pw[j][half*2+1]);
            }
        }
    }
}

// ---------------- k1 on HMMA: ctx = softmax(Q @ Kl^T) @ W2 ---------------------
#define KLRS 144
#define K1MAT 18432
#define K1_SMEM (4*K1MAT)

__global__ __launch_bounds__(256, 2)
void k1_kernel(){
    extern __shared__ __align__(16) char ksm[];
    const unsigned smb = smem_u32(ksm);
    const int sblk = blockIdx.x, bh = blockIdx.y;
    const int tid = threadIdx.x, lane = tid & 31, w = tid >> 5;
    const int g = lane >> 2, tg = lane & 3;
    const int i8 = lane & 7, t8 = lane >> 3;
    const int m0 = w * 16;

    const float* Klg = g_Kl + (size_t)bh*8192;
    const float* W2g = g_W2 + (size_t)bh*8192;
    for (int idx = tid; idx < 8192; idx += 256){
        int r = idx >> 6, c = idx & 63;
        float v = Klg[idx];
        __nv_bfloat16 hi = __float2bfloat16(v);
        __nv_bfloat16 lo = __float2bfloat16(v - __bfloat162float(hi));
        *(__nv_bfloat16*)(ksm + 0*K1MAT + r*KLRS + c*2) = hi;
        *(__nv_bfloat16*)(ksm + 1*K1MAT + r*KLRS + c*2) = lo;
        v = W2g[idx];
        hi = __float2bfloat16(v);
        lo = __float2bfloat16(v - __bfloat162float(hi));
        *(__nv_bfloat16*)(ksm + 2*K1MAT + r*KLRS + c*2) = hi;
        *(__nv_bfloat16*)(ksm + 3*K1MAT + r*KLRS + c*2) = lo;
    }
    __syncthreads();

    const float* Qg = g_Q + ((size_t)bh*S_ + sblk*128)*HD_;
    float st[16][4];
    #pragma unroll
    for (int nt=0;nt<16;nt++)
        #pragma unroll
        for (int e=0;e<4;e++) st[nt][e] = 0.f;

    #pragma unroll
    for (int kc = 0; kc < 4; kc++){
        int r = m0 + g, c = kc*16 + tg*2;
        float2 v0 = *(const float2*)&Qg[(size_t)r*64 + c];
        float2 v1 = *(const float2*)&Qg[(size_t)(r+8)*64 + c];
        float2 v2 = *(const float2*)&Qg[(size_t)r*64 + c + 8];
        float2 v3 = *(const float2*)&Qg[(size_t)(r+8)*64 + c + 8];
        unsigned aH[4], aL[4]; float lx, ly;
        aH[0] = pack_hi(v0.x, v0.y, lx, ly); aL[0] = pack_bf2(lx, ly);
        aH[1] = pack_hi(v1.x, v1.y, lx, ly); aL[1] = pack_bf2(lx, ly);
        aH[2] = pack_hi(v2.x, v2.y, lx, ly); aL[2] = pack_bf2(lx, ly);
        aH[3] = pack_hi(v3.x, v3.y, lx, ly); aL[3] = pack_bf2(lx, ly);
        #pragma unroll
        for (int q = 0; q < 8; q++){
            unsigned kOff = (unsigned)((q*16 + (t8>>1)*8 + i8)*KLRS + (t8&1)*16 + kc*32);
            unsigned bH[4], bL[4];
            ldsm4(bH[0],bH[1],bH[2],bH[3], smb + 0*K1MAT + kOff);
            ldsm4(bL[0],bL[1],bL[2],bL[3], smb + 1*K1MAT + kOff);
            mma16816(st[2*q],   aH, bH);
            mma16816(st[2*q+1], aH, bH+2);
            mma16816(st[2*q],   aL, bH);
            mma16816(st[2*q+1], aL, bH+2);
            mma16816(st[2*q],   aH, bL);
            mma16816(st[2*q+1], aH, bL+2);
        }
    }

    float mx0 = -1e30f, mx1 = -1e30f;
    #pragma unroll
    for (int nt = 0; nt < 16; nt++){
        mx0 = fmaxf(mx0, fmaxf(st[nt][0], st[nt][1]));
        mx1 = fmaxf(mx1, fmaxf(st[nt][2], st[nt][3]));
    }
    mx0 = fmaxf(mx0, __shfl_xor_sync(0xffffffffu, mx0, 1));
    mx0 = fmaxf(mx0, __shfl_xor_sync(0xffffffffu, mx0, 2));
    mx1 = fmaxf(mx1, __shfl_xor_sync(0xffffffffu, mx1, 1));
    mx1 = fmaxf(mx1, __shfl_xor_sync(0xffffffffu, mx1, 2));
    float z0 = 0.f, z1 = 0.f;
    #pragma unroll
    for (int nt = 0; nt < 16; nt++){
        st[nt][0] = __expf(st[nt][0] - mx0);
        st[nt][1] = __expf(st[nt][1] - mx0);
        st[nt][2] = __expf(st[nt][2] - mx1);
        st[nt][3] = __expf(st[nt][3] - mx1);
        z0 += st[nt][0] + st[nt][1];
        z1 += st[nt][2] + st[nt][3];
    }
    z0 += __shfl_xor_sync(0xffffffffu, z0, 1);
    z0 += __shfl_xor_sync(0xffffffffu, z0, 2);
    z1 += __shfl_xor_sync(0xffffffffu, z1, 1);
    z1 += __shfl_xor_sync(0xffffffffu, z1, 2);
    float zi0 = 1.f/z0, zi1 = 1.f/z1;
    #pragma unroll
    for (int nt = 0; nt < 16; nt++){
        st[nt][0] *= zi0; st[nt][1] *= zi0;
        st[nt][2] *= zi1; st[nt][3] *= zi1;
    }

    float o[8][4];
    #pragma unroll
    for (int j=0;j<8;j++)
        #pragma unroll
        for (int e=0;e<4;e++) o[j][e] = 0.f;

    #pragma unroll
    for (int kc = 0; kc < 8; kc++){
        unsigned aH[4], aL[4]; float lx, ly;
        aH[0] = pack_hi(st[2*kc][0],   st[2*kc][1],   lx, ly); aL[0] = pack_bf2(lx, ly);
        aH[1] = pack_hi(st[2*kc][2],   st[2*kc][3],   lx, ly); aL[1] = pack_bf2(lx, ly);
        aH[2] = pack_hi(st[2*kc+1][0], st[2*kc+1][1], lx, ly); aL[2] = pack_bf2(lx, ly);
        aH[3] = pack_hi(st[2*kc+1][2], st[2*kc+1][3], lx, ly); aL[3] = pack_bf2(lx, ly);
        #pragma unroll
        for (int q = 0; q < 4; q++){
            unsigned wOff = (unsigned)(((t8&1)*8 + i8 + kc*16)*KLRS + (q*16 + (t8>>1)*8)*2);
            unsigned bH[4], bL[4];
            ldsm4t(bH[0],bH[1],bH[2],bH[3], smb + 2*K1MAT + wOff);
            ldsm4t(bL[0],bL[1],bL[2],bL[3], smb + 3*K1MAT + wOff);
            mma16816(o[2*q],   aH, bH);
            mma16816(o[2*q+1], aH, bH+2);
            mma16816(o[2*q],   aL, bH);
            mma16816(o[2*q+1], aL, bH+2);
            mma16816(o[2*q],   aH, bL);
            mma16816(o[2*q+1], aH, bL+2);
        }
    }

    int b = bh >> 4, h = bh & 15;
    #pragma unroll
    for (int half = 0; half < 2; half++){
        int sI = sblk*128 + m0 + g + half*8;
        size_t obase = ((size_t)(b*S_ + sI))*D_ + h*64;
        #pragma unroll
        for (int nt = 0; nt < 8; nt++){
            int d = nt*8 + tg*2;
            float x = o[nt][half*2], y = o[nt][half*2+1];
            __half hx = __float2half_rn(x), hy = __float2half_rn(y);
            __half lxh = __float2half_rn(x - __half2float(hx));
            __half lyh = __float2half_rn(y - __half2float(hy));
            __half hv[2] = {hx, hy}, lv[2] = {lxh, lyh};
            *(unsigned*)&g_ctxh[obase + d] = *(unsigned*)hv;
            *(unsigned*)&g_ctxl[obase + d] = *(unsigned*)lv;
        }
    }
}

// ---------------- launch -------------------------------------------------------
extern "C" void kernel_launch(void* const* d_in, const int* in_sizes, int n_in,
                              void* d_out, int out_size)
{
    const float* X    = (const float*)d_in[0];
    const float* mask = (const float*)d_in[1];
    const float* Wq   = (const float*)d_in[2];
    const float* bq   = (const float*)d_in[3];
    const float* Wk   = (const float*)d_in[4];
    const float* bk   = (const float*)d_in[5];
    const float* Wv   = (const float*)d_in[6];
    const float* bv   = (const float*)d_in[7];
    const float* Wo   = (const float*)d_in[8];
    const float* bo   = (const float*)d_in[9];
    float* out = (float*)d_out;

    void *pQ, *pK, *pV;
    cudaGetSymbolAddress(&pQ, g_Q);
    cudaGetSymbolAddress(&pK, g_K);
    cudaGetSymbolAddress(&pV, g_V);

    cudaFuncSetAttribute(gemm_qkv, cudaFuncAttributeMaxDynamicSharedMemorySize, GSMEM);
    cudaFuncSetAttribute(gemm_out, cudaFuncAttributeMaxDynamicSharedMemorySize, GSMEM);
    cudaFuncSetAttribute(inv_kernel, cudaFuncAttributeMaxDynamicSharedMemorySize, INV_SMEM);
    cudaFuncSetAttribute(k1_kernel,  cudaFuncAttributeMaxDynamicSharedMemorySize, K1_SMEM);
    cudaFuncSetAttribute(k3_mma,     cudaFuncAttributeMaxDynamicSharedMemorySize, K3_SMEM);

    convX_kernel<<<8192, 256>>>(X);                       // 1
    convW_kernel<<<dim3(32,32,4), 256>>>(Wq, Wk, Wv, Wo); // 2
    probe_kernel<<<1, 32>>>();                            // 3
    gemm_qkv<<<dim3(24,64), 256, GSMEM>>>(bq, bk, bv, mask,
                                          (float*)pQ, (float*)pK, (float*)pV); // 4 <- ncu

    landmark_kernel<<<(BH_*NL_*HD_)/256, 256>>>();
    k2_kernel<<<dim3(NL_, BH_), 128>>>();
    colmax_kernel<<<BH_, 128>>>();
    k3_mma<<<dim3(8, BH_), 256, K3_SMEM>>>(mask);
    k3_combine<<<BH_, 128>>>();
    inv_kernel<<<BH_, 512, INV_SMEM>>>();
    k1_kernel<<<dim3(32, BH_), 256, K1_SMEM>>>();

    gemm_out<<<dim3(8,64), 256, GSMEM>>>(bo, out);
}

// round 15
// speedup vs baseline: 9.6283x; 1.2428x over previous
#include <cuda_runtime.h>
#include <cuda_bf16.h>
#include <cuda_fp16.h>

// Problem constants
#define B_  2
#define S_  4096
#define HID_ 1024
#define NH_ 16
#define HD_ 64
#define NL_ 128
#define BH_ (B_*NH_)          // 32
#define SEG_ (S_/NL_)         // 32
#define D_ (NH_*HD_)          // 1024
#define SCALE_ 0.35355339059327373f  // HD^-0.25

// ---------------- device scratch -----------------------------------------------
__device__ float g_Q[B_*NH_*S_*HD_];     // (b,h,s,d) scaled+masked
__device__ float g_K[B_*NH_*S_*HD_];
__device__ float g_V[B_*NH_*S_*HD_];
__device__ float g_Ql[BH_*NL_*HD_];
__device__ float g_Kl[BH_*NL_*HD_];
__device__ float g_k2[BH_*NL_*NL_];
__device__ float g_bhmax[BH_];
__device__ float g_k3V[BH_*NL_*HD_];
__device__ float g_W2[BH_*NL_*HD_];
__device__ float g_k3o[BH_*8*NL_*HD_];   // split-K partials
__device__ float g_k3mz[BH_*8*NL_*2];
__device__ __align__(256) __half g_Xh[8192*1024];
__device__ __align__(256) __half g_Wth[4*1024*1024];   // [4][n][k] q,k,v,o (fp16)
__device__ __align__(256) __half g_ctxh[8192*1024];

__device__ __forceinline__ unsigned smem_u32(const void* p){
    unsigned a;
    asm("{ .reg .u64 t; cvta.to.shared.u64 t, %1; cvt.u32.u64 %0, t; }" : "=r"(a) : "l"(p));
    return a;
}
__device__ __forceinline__ void ldsm4(unsigned& r0, unsigned& r1, unsigned& r2, unsigned& r3,
                                      unsigned addr){
    asm volatile("ldmatrix.sync.aligned.m8n8.x4.shared.b16 {%0,%1,%2,%3}, [%4];"
        : "=r"(r0), "=r"(r1), "=r"(r2), "=r"(r3) : "r"(addr));
}
__device__ __forceinline__ void ldsm4t(unsigned& r0, unsigned& r1, unsigned& r2, unsigned& r3,
                                       unsigned addr){
    asm volatile("ldmatrix.sync.aligned.m8n8.x4.trans.shared.b16 {%0,%1,%2,%3}, [%4];"
        : "=r"(r0), "=r"(r1), "=r"(r2), "=r"(r3) : "r"(addr));
}
// bf16 mma (attention mid-section)
__device__ __forceinline__ void mma16816(float* c, const unsigned* a, const unsigned* b){
    asm volatile(
        "mma.sync.aligned.m16n8k16.row.col.f32.bf16.bf16.f32 "
        "{%0,%1,%2,%3}, {%4,%5,%6,%7}, {%8,%9}, {%0,%1,%2,%3};"
        : "+f"(c[0]), "+f"(c[1]), "+f"(c[2]), "+f"(c[3])
        : "r"(a[0]), "r"(a[1]), "r"(a[2]), "r"(a[3]), "r"(b[0]), "r"(b[1]));
}
// fp16 mma (big GEMMs)
__device__ __forceinline__ void mma16816h(float* c, const unsigned* a, const unsigned* b){
    asm volatile(
        "mma.sync.aligned.m16n8k16.row.col.f32.f16.f16.f32 "
        "{%0,%1,%2,%3}, {%4,%5,%6,%7}, {%8,%9}, {%0,%1,%2,%3};"
        : "+f"(c[0]), "+f"(c[1]), "+f"(c[2]), "+f"(c[3])
        : "r"(a[0]), "r"(a[1]), "r"(a[2]), "r"(a[3]), "r"(b[0]), "r"(b[1]));
}
__device__ __forceinline__ unsigned pack_hi(float x, float y, float& lx, float& ly){
    __nv_bfloat162 h = __floats2bfloat162_rn(x, y);
    lx = x - __bfloat162float(h.x);
    ly = y - __bfloat162float(h.y);
    return *(unsigned*)&h;
}
__device__ __forceinline__ unsigned pack_bf2(float x, float y){
    __nv_bfloat162 h = __floats2bfloat162_rn(x, y);
    return *(unsigned*)&h;
}
__device__ __forceinline__ void cp16(unsigned dst, const void* src){
    asm volatile("cp.async.cg.shared.global [%0], [%1], 16;" :: "r"(dst), "l"(src));
}
__device__ __forceinline__ void cpcommit(){ asm volatile("cp.async.commit_group;" ::: "memory"); }
template<int N> __device__ __forceinline__ void cpwait(){
    asm volatile("cp.async.wait_group %0;" :: "n"(N) : "memory");
}

// ---------------- probe (keeps gemm_qkv in the profiled 4th slot) --------------
__global__ void probe_kernel(){
    if (threadIdx.x < BH_) g_bhmax[threadIdx.x] = 0.f;
}

// ---------------- prep: X -> fp16 ----------------------------------------------
__global__ void convX_kernel(const float* __restrict__ X){
    size_t i4 = (size_t)blockIdx.x * blockDim.x + threadIdx.x;
    float4 v = ((const float4*)X)[i4];
    __half h[4] = {__float2half_rn(v.x), __float2half_rn(v.y),
                   __float2half_rn(v.z), __float2half_rn(v.w)};
    *(uint2*)&g_Xh[i4*4] = *(uint2*)h;
}

// ---------------- prep: transpose weights -> [n][k] fp16 -----------------------
__global__ void convW_kernel(const float* __restrict__ Wq, const float* __restrict__ Wk,
                             const float* __restrict__ Wv, const float* __restrict__ Wo){
    __shared__ float t[32][33];
    int z = blockIdx.z;
    const float* W = (z==0) ? Wq : (z==1) ? Wk : (z==2) ? Wv : Wo;
    int n0 = blockIdx.x * 32, k0 = blockIdx.y * 32;
    int tx = threadIdx.x & 31, ty = threadIdx.x >> 5;
    #pragma unroll
    for (int r = 0; r < 4; r++){
        int ky = ty + r*8;
        t[ky][tx] = W[(size_t)(k0 + ky)*1024 + n0 + tx];
    }
    __syncthreads();
    #pragma unroll
    for (int r = 0; r < 4; r++){
        int ny = ty + r*8;
        size_t o = (size_t)z*1048576 + (size_t)(n0 + ny)*1024 + k0 + tx;
        g_Wth[o] = __float2half_rn(t[tx][ny]);
    }
}

// ================= fp16 HMMA GEMM mainloop =====================================
// R15: single product (A fp16, B fp16) -> 16 mma per kb. Stage = 2 tiles.
#define ROWBY 80
#define TILEB (128*ROWBY)
#define STAGEB (2*TILEB)      // 20480
#define GSMEM (2*STAGEB)      // 40960

__device__ __forceinline__ void gemm_main(
    const __half* __restrict__ Ah, const __half* __restrict__ Bh,
    unsigned smb, float acc[2][8][4])
{
    const int tid = threadIdx.x, lane = tid & 31, w = tid >> 5;
    const int wr = w & 3, wc = w >> 2;

    unsigned aoff[2], boff[4];
    {
        int i = lane & 7, t8 = lane >> 3;
        #pragma unroll
        for (int t = 0; t < 2; t++)
            aoff[t] = (unsigned)((wr*32 + t*16 + (t8 & 1)*8 + i) * ROWBY + (t8 >> 1) * 16);
        #pragma unroll
        for (int q = 0; q < 4; q++)
            boff[q] = (unsigned)((wc*64 + q*16 + (t8 >> 1)*8 + i) * ROWBY + (t8 & 1) * 16);
    }

    auto issue = [&](int buf, int k0){
        #pragma unroll
        for (int r = 0; r < 4; r++){
            int idx = r*256 + tid;
            int c = idx & 3, row = (idx >> 2) & 127, tile = idx >> 9;
            const __half* src =
                (tile == 0) ? Ah + (size_t)row*1024 + k0 + c*8 :
                              Bh + (size_t)row*1024 + k0 + c*8;
            cp16(smb + buf*STAGEB + tile*TILEB + row*ROWBY + c*16, src);
        }
        cpcommit();
    };

    issue(0, 0);
    for (int s = 0; s < 32; s++){
        __syncthreads();
        if (s < 31){ issue((s+1) & 1, (s+1)*32); cpwait<1>(); }
        else       { cpwait<0>(); }
        __syncthreads();

        unsigned base = smb + (s & 1)*STAGEB;
        #pragma unroll
        for (int kb = 0; kb < 2; kb++){
            unsigned ko = kb * 32;
            unsigned aH[2][4], bX[4][4];
            #pragma unroll
            for (int t = 0; t < 2; t++)
                ldsm4(aH[t][0], aH[t][1], aH[t][2], aH[t][3], base + aoff[t] + ko);
            #pragma unroll
            for (int q = 0; q < 4; q++)
                ldsm4(bX[q][0], bX[q][1], bX[q][2], bX[q][3], base + TILEB + boff[q] + ko);
            #pragma unroll
            for (int t = 0; t < 2; t++)
                #pragma unroll
                for (int q = 0; q < 4; q++){
                    mma16816h(acc[t][2*q],   aH[t], &bX[q][0]);
                    mma16816h(acc[t][2*q+1], aH[t], &bX[q][2]);
                }
        }
    }
}

__global__ __launch_bounds__(256, 2)
void gemm_qkv(const float* __restrict__ bq, const float* __restrict__ bk,
              const float* __restrict__ bv, const float* __restrict__ mask,
              float* __restrict__ oq, float* __restrict__ okk, float* __restrict__ ov)
{
    extern __shared__ __align__(16) char smem[];
    unsigned smb = smem_u32(smem);
    int wsel = blockIdx.x >> 3, colt = blockIdx.x & 7;
    const __half* Ah = g_Xh + (size_t)blockIdx.y*128*1024;
    const __half* Bh = g_Wth + ((size_t)wsel*1024 + colt*128)*1024;

    float acc[2][8][4];
    #pragma unroll
    for (int t=0;t<2;t++)
        #pragma unroll
        for (int j=0;j<8;j++)
            #pragma unroll
            for (int e=0;e<4;e++) acc[t][j][e] = 0.f;

    gemm_main(Ah, Bh, smb, acc);

    const float* bias = (wsel==0) ? bq : (wsel==1) ? bk : bv;
    float* out = (wsel==0) ? oq : (wsel==1) ? okk : ov;
    const bool scaled = (wsel < 2);

    int lane = threadIdx.x & 31, w = threadIdx.x >> 5;
    int wr = w & 3, wc = w >> 2;
    int g = lane >> 2, tg = lane & 3;
    #pragma unroll
    for (int t = 0; t < 2; t++){
        #pragma unroll
        for (int half = 0; half < 2; half++){
            int row = blockIdx.y*128 + wr*32 + t*16 + g + half*8;
            float rs = scaled ? SCALE_ * mask[row] : 1.0f;
            int bb = row >> 12, sI = row & 4095;
            #pragma unroll
            for (int j = 0; j < 8; j++){
                int col = colt*128 + wc*64 + j*8 + tg*2;
                float c0 = (acc[t][j][half*2]   + bias[col])   * rs;
                float c1 = (acc[t][j][half*2+1] + bias[col+1]) * rs;
                int h = col >> 6, d = col & 63;
                *(float2*)(out + ((size_t)(bb*NH_ + h)*S_ + sI)*HD_ + d) = make_float2(c0, c1);
            }
        }
    }
}

__global__ __launch_bounds__(256, 2)
void gemm_out(const float* __restrict__ bias, float* __restrict__ out)
{
    extern __shared__ __align__(16) char smem[];
    unsigned smb = smem_u32(smem);
    const __half* Ah = g_ctxh + (size_t)blockIdx.y*128*1024;
    const __half* Bh = g_Wth + (size_t)3*1048576 + (size_t)blockIdx.x*128*1024;

    float acc[2][8][4];
    #pragma unroll
    for (int t=0;t<2;t++)
        #pragma unroll
        for (int j=0;j<8;j++)
            #pragma unroll
            for (int e=0;e<4;e++) acc[t][j][e] = 0.f;

    gemm_main(Ah, Bh, smb, acc);

    int lane = threadIdx.x & 31, w = threadIdx.x >> 5;
    int wr = w & 3, wc = w >> 2;
    int g = lane >> 2, tg = lane & 3;
    #pragma unroll
    for (int t = 0; t < 2; t++){
        #pragma unroll
        for (int half = 0; half < 2; half++){
            int row = blockIdx.y*128 + wr*32 + t*16 + g + half*8;
            #pragma unroll
            for (int j = 0; j < 8; j++){
                int col = blockIdx.x*128 + wc*64 + j*8 + tg*2;
                float c0 = acc[t][j][half*2]   + bias[col];
                float c1 = acc[t][j][half*2+1] + bias[col+1];
                *(float2*)(out + (size_t)row*1024 + col) = make_float2(c0, c1);
            }
        }
    }
}

// ---------------- landmarks ----------------------------------------------------
__global__ void landmark_kernel(){
    int idx = blockIdx.x*blockDim.x + threadIdx.x;
    int d  = idx & 63;
    int l  = (idx >> 6) & 127;
    int bh = idx >> 13;
    const float* q = g_Q + ((size_t)bh*S_ + l*SEG_)*HD_ + d;
    const float* k = g_K + ((size_t)bh*S_ + l*SEG_)*HD_ + d;
    float sq = 0.f, sk = 0.f;
    #pragma unroll
    for (int j=0; j<SEG_; j++){ sq += q[j*HD_]; sk += k[j*HD_]; }
    g_Ql[idx] = sq * (1.f/SEG_);
    g_Kl[idx] = sk * (1.f/SEG_);
}

// ---------------- k2 = softmax(Ql @ Kl^T) --------------------------------------
__global__ void k2_kernel(){
    int l = blockIdx.x, bh = blockIdx.y, m = threadIdx.x;
    const float4* ql = (const float4*)(g_Ql + ((size_t)bh*NL_ + l)*HD_);
    const float4* kl = (const float4*)(g_Kl + ((size_t)bh*NL_ + m)*HD_);
    float acc = 0.f;
    #pragma unroll
    for (int d4=0; d4<16; d4++){
        float4 a = ql[d4], b = kl[d4];
        acc += a.x*b.x + a.y*b.y + a.z*b.z + a.w*b.w;
    }
    __shared__ float red[128];
    red[m] = acc; __syncthreads();
    for (int off=64; off>0; off>>=1){
        if (m < off) red[m] = fmaxf(red[m], red[m+off]);
        __syncthreads();
    }
    float mx = red[0]; __syncthreads();
    float p = __expf(acc - mx);
    red[m] = p; __syncthreads();
    for (int off=64; off>0; off>>=1){
        if (m < off) red[m] += red[m+off];
        __syncthreads();
    }
    g_k2[((size_t)bh*NL_ + l)*NL_ + m] = p / red[0];
}

// ---------------- column sums of k2 -> per-bh max ------------------------------
__global__ void colmax_kernel(){
    int bh = blockIdx.x, m = threadIdx.x;
    float s = 0.f;
    for (int l=0; l<NL_; l++) s += g_k2[((size_t)bh*NL_ + l)*NL_ + m];
    __shared__ float red[128];
    red[m] = s; __syncthreads();
    for (int off=64; off>0; off>>=1){
        if (m < off) red[m] = fmaxf(red[m], red[m+off]);
        __syncthreads();
    }
    if (m == 0) g_bhmax[bh] = red[0];
}

// ---------------- k3 on HMMA: flash-style split-K ------------------------------
#define K3RS  144
#define K3MAT 18432
#define K3_SMEM (6*K3MAT + 512)

__global__ __launch_bounds__(256, 1)
void k3_mma(const float* __restrict__ mask){
    extern __shared__ __align__(16) char ksm[];
    const unsigned smb = smem_u32(ksm);
    const int chunk = blockIdx.x, bh = blockIdx.y;
    const int tid = threadIdx.x, lane = tid & 31, w = tid >> 5;
    const int g = lane >> 2, tg = lane & 3;
    const int i8 = lane & 7, t8 = lane >> 3;
    const int m0 = w * 16;
    float* msk = (float*)(ksm + 6*K3MAT);

    const float* Qlg = g_Ql + (size_t)bh*8192;
    for (int idx = tid; idx < 8192; idx += 256){
        int r = idx >> 6, c = idx & 63;
        float v = Qlg[idx];
        __nv_bfloat16 hi = __float2bfloat16(v);
        __nv_bfloat16 lo = __float2bfloat16(v - __bfloat162float(hi));
        *(__nv_bfloat16*)(ksm + 0*K3MAT + r*K3RS + c*2) = hi;
        *(__nv_bfloat16*)(ksm + 1*K3MAT + r*K3RS + c*2) = lo;
    }

    const float* Kbh = g_K + (size_t)bh*S_*HD_;
    const float* Vbh = g_V + (size_t)bh*S_*HD_;
    const float* mrow = mask + (size_t)(bh >> 4)*S_;

    const unsigned aoff = (unsigned)((m0 + (t8&1)*8 + i8)*K3RS + (t8>>1)*16);

    float mr0 = -1e30f, mr1 = -1e30f, z0 = 0.f, z1 = 0.f;
    float o[8][4];
    #pragma unroll
    for (int j=0;j<8;j++)
        #pragma unroll
        for (int e=0;e<4;e++) o[j][e] = 0.f;

    for (int it = 0; it < 4; it++){
        int sbase = chunk*512 + it*128;
        __syncthreads();
        for (int idx = tid; idx < 8192; idx += 256){
            int r = idx >> 6, c = idx & 63;
            float v = Kbh[(size_t)(sbase + r)*HD_ + c];
            __nv_bfloat16 hi = __float2bfloat16(v);
            __nv_bfloat16 lo = __float2bfloat16(v - __bfloat162float(hi));
            *(__nv_bfloat16*)(ksm + 2*K3MAT + r*K3RS + c*2) = hi;
            *(__nv_bfloat16*)(ksm + 3*K3MAT + r*K3RS + c*2) = lo;
            v = Vbh[(size_t)(sbase + r)*HD_ + c];
            hi = __float2bfloat16(v);
            lo = __float2bfloat16(v - __bfloat162float(hi));
            *(__nv_bfloat16*)(ksm + 4*K3MAT + r*K3RS + c*2) = hi;
            *(__nv_bfloat16*)(ksm + 5*K3MAT + r*K3RS + c*2) = lo;
        }
        if (tid < 128) msk[tid] = mrow[sbase + tid];
        __syncthreads();

        float st[16][4];
        #pragma unroll
        for (int nt=0;nt<16;nt++)
            #pragma unroll
            for (int e=0;e<4;e++) st[nt][e] = 0.f;

        #pragma unroll
        for (int kc = 0; kc < 4; kc++){
            unsigned aH[4], aL[4];
            ldsm4(aH[0],aH[1],aH[2],aH[3], smb + 0*K3MAT + aoff + kc*32);
            ldsm4(aL[0],aL[1],aL[2],aL[3], smb + 1*K3MAT + aoff + kc*32);
            #pragma unroll
            for (int q = 0; q < 8; q++){
                unsigned kOff = (unsigned)((q*16 + (t8>>1)*8 + i8)*K3RS + (t8&1)*16 + kc*32);
                unsigned bH[4], bL[4];
                ldsm4(bH[0],bH[1],bH[2],bH[3], smb + 2*K3MAT + kOff);
                ldsm4(bL[0],bL[1],bL[2],bL[3], smb + 3*K3MAT + kOff);
                mma16816(st[2*q],   aH, bH);
                mma16816(st[2*q+1], aH, bH+2);
                mma16816(st[2*q],   aL, bH);
                mma16816(st[2*q+1], aL, bH+2);
                mma16816(st[2*q],   aH, bL);
                mma16816(st[2*q+1], aH, bL+2);
            }
        }

        #pragma unroll
        for (int nt = 0; nt < 16; nt++){
            int c0 = nt*8 + tg*2;
            float p0 = -1e9f*(1.f - msk[c0]);
            float p1 = -1e9f*(1.f - msk[c0+1]);
            st[nt][0] += p0; st[nt][1] += p1;
            st[nt][2] += p0; st[nt][3] += p1;
        }

        float cm0 = -1e30f, cm1 = -1e30f;
        #pragma unroll
        for (int nt = 0; nt < 16; nt++){
            cm0 = fmaxf(cm0, fmaxf(st[nt][0], st[nt][1]));
            cm1 = fmaxf(cm1, fmaxf(st[nt][2], st[nt][3]));
        }
        cm0 = fmaxf(cm0, __shfl_xor_sync(0xffffffffu, cm0, 1));
        cm0 = fmaxf(cm0, __shfl_xor_sync(0xffffffffu, cm0, 2));
        cm1 = fmaxf(cm1, __shfl_xor_sync(0xffffffffu, cm1, 1));
        cm1 = fmaxf(cm1, __shfl_xor_sync(0xffffffffu, cm1, 2));
        float mn0 = fmaxf(mr0, cm0), mn1 = fmaxf(mr1, cm1);
        float cr0 = __expf(mr0 - mn0), cr1 = __expf(mr1 - mn1);
        mr0 = mn0; mr1 = mn1;
        z0 *= cr0; z1 *= cr1;
        #pragma unroll
        for (int j = 0; j < 8; j++){
            o[j][0] *= cr0; o[j][1] *= cr0;
            o[j][2] *= cr1; o[j][3] *= cr1;
        }
        float ps0 = 0.f, ps1 = 0.f;
        #pragma unroll
        for (int nt = 0; nt < 16; nt++){
            st[nt][0] = __expf(st[nt][0] - mn0);
            st[nt][1] = __expf(st[nt][1] - mn0);
            st[nt][2] = __expf(st[nt][2] - mn1);
            st[nt][3] = __expf(st[nt][3] - mn1);
            ps0 += st[nt][0] + st[nt][1];
            ps1 += st[nt][2] + st[nt][3];
        }
        ps0 += __shfl_xor_sync(0xffffffffu, ps0, 1);
        ps0 += __shfl_xor_sync(0xffffffffu, ps0, 2);
        ps1 += __shfl_xor_sync(0xffffffffu, ps1, 1);
        ps1 += __shfl_xor_sync(0xffffffffu, ps1, 2);
        z0 += ps0; z1 += ps1;

        #pragma unroll
        for (int kc = 0; kc < 8; kc++){
            unsigned aH[4], aL[4]; float lx, ly;
            aH[0] = pack_hi(st[2*kc][0],   st[2*kc][1],   lx, ly); aL[0] = pack_bf2(lx, ly);
            aH[1] = pack_hi(st[2*kc][2],   st[2*kc][3],   lx, ly); aL[1] = pack_bf2(lx, ly);
            aH[2] = pack_hi(st[2*kc+1][0], st[2*kc+1][1], lx, ly); aL[2] = pack_bf2(lx, ly);
            aH[3] = pack_hi(st[2*kc+1][2], st[2*kc+1][3], lx, ly); aL[3] = pack_bf2(lx, ly);
            #pragma unroll
            for (int q = 0; q < 4; q++){
                unsigned wOff = (unsigned)(((t8&1)*8 + i8 + kc*16)*K3RS + (q*16 + (t8>>1)*8)*2);
                unsigned bH[4], bL[4];
                ldsm4t(bH[0],bH[1],bH[2],bH[3], smb + 4*K3MAT + wOff);
                ldsm4t(bL[0],bL[1],bL[2],bL[3], smb + 5*K3MAT + wOff);
                mma16816(o[2*q],   aH, bH);
                mma16816(o[2*q+1], aH, bH+2);
                mma16816(o[2*q],   aL, bH);
                mma16816(o[2*q+1], aL, bH+2);
                mma16816(o[2*q],   aH, bL);
                mma16816(o[2*q+1], aH, bL+2);
            }
        }
    }

    size_t pbase = ((size_t)(bh*8 + chunk))*128;
    #pragma unroll
    for (int j = 0; j < 8; j++){
        int c = j*8 + tg*2;
        *(float2*)&g_k3o[(pbase + m0 + g)*64 + c]     = make_float2(o[j][0], o[j][1]);
        *(float2*)&g_k3o[(pbase + m0 + g + 8)*64 + c] = make_float2(o[j][2], o[j][3]);
    }
    if (tg == 0){
        g_k3mz[(pbase + m0 + g)*2]       = mr0;
        g_k3mz[(pbase + m0 + g)*2 + 1]   = z0;
        g_k3mz[(pbase + m0 + g + 8)*2]     = mr1;
        g_k3mz[(pbase + m0 + g + 8)*2 + 1] = z1;
    }
}

__global__ void k3_combine(){
    int bh = blockIdx.x, l = threadIdx.x;   // 128 threads
    float m[8], z[8], M = -1e30f;
    #pragma unroll
    for (int c = 0; c < 8; c++){
        m[c] = g_k3mz[((size_t)(bh*8 + c)*128 + l)*2];
        z[c] = g_k3mz[((size_t)(bh*8 + c)*128 + l)*2 + 1];
        M = fmaxf(M, m[c]);
    }
    float coef[8], Z = 0.f;
    #pragma unroll
    for (int c = 0; c < 8; c++){
        coef[c] = __expf(m[c] - M);
        Z += z[c]*coef[c];
    }
    float Zi = 1.f / Z;
    #pragma unroll
    for (int d4 = 0; d4 < 16; d4++){
        float4 acc = make_float4(0.f, 0.f, 0.f, 0.f);
        #pragma unroll
        for (int c = 0; c < 8; c++){
            float4 ov = *(const float4*)&g_k3o[((size_t)(bh*8 + c)*128 + l)*64 + d4*4];
            acc.x += coef[c]*ov.x; acc.y += coef[c]*ov.y;
            acc.z += coef[c]*ov.z; acc.w += coef[c]*ov.w;
        }
        acc.x *= Zi; acc.y *= Zi; acc.z *= Zi; acc.w *= Zi;
        *(float4*)&g_k3V[(size_t)bh*8192 + l*64 + d4*4] = acc;
    }
}

// ---------------- Newton inverse on HMMA: 512 threads, 16 warps ----------------
#define IRS  272
#define IMAT 34816
#define INV_SMEM (6*IMAT)

__global__ __launch_bounds__(512, 1)
void inv_kernel(){
    extern __shared__ __align__(16) char ismem[];
    const unsigned smb = smem_u32(ismem);
    const int bh = blockIdx.x, tid = threadIdx.x;
    const int lane = tid & 31, w = tid >> 5;
    const int mw = w & 7, nw = w >> 3;
    const int m0 = mw*16, nb = nw*64;
    const int g = lane >> 2, tg = lane & 3;
    const int i8 = lane & 7, t8 = lane >> 3;

    float cmax = g_bhmax[0];
    #pragma unroll
    for (int q=1; q<BH_; q++) cmax = fmaxf(cmax, g_bhmax[q]);
    const float rinv = 1.f / cmax;
    const float* Kg = g_k2 + (size_t)bh*NL_*NL_;

    {
        int i = tid >> 2, h0 = (tid & 3) * 32;
        for (int j = 0; j < 32; j++){
            float v = Kg[(h0 + j)*128 + i] * rinv;
            __nv_bfloat16 hi = __float2bfloat16(v);
            __nv_bfloat16 lo = __float2bfloat16(v - __bfloat162float(hi));
            *(__nv_bfloat16*)(ismem + 0*IMAT + i*IRS + (h0+j)*2) = hi;
            *(__nv_bfloat16*)(ismem + 1*IMAT + i*IRS + (h0+j)*2) = lo;
        }
    }
    __syncthreads();

    unsigned aoff = (unsigned)((m0 + (t8&1)*8 + i8)*IRS + (t8>>1)*16);
    unsigned boff[4];
    #pragma unroll
    for (int q = 0; q < 4; q++)
        boff[q] = (unsigned)(((t8&1)*8 + i8)*IRS + (nb + q*16 + (t8>>1)*8)*2);

    float P[8][4], Aa[8][4];

    auto mm_ss = [&](int Lh, int Rh){
        #pragma unroll
        for (int j=0;j<8;j++)
            #pragma unroll
            for (int e=0;e<4;e++) P[j][e] = 0.f;
        unsigned Lb = smb + (unsigned)Lh*IMAT;
        unsigned Rb = smb + (unsigned)Rh*IMAT;
        #pragma unroll
        for (int k = 0; k < 8; k++){
            unsigned aH[4], aL[4];
            ldsm4(aH[0],aH[1],aH[2],aH[3], Lb + aoff + k*32);
            ldsm4(aL[0],aL[1],aL[2],aL[3], Lb + IMAT + aoff + k*32);
            #pragma unroll
            for (int q = 0; q < 4; q++){
                unsigned bH[4], bL[4];
                ldsm4t(bH[0],bH[1],bH[2],bH[3], Rb + boff[q] + k*16*IRS);
                ldsm4t(bL[0],bL[1],bL[2],bL[3], Rb + IMAT + boff[q] + k*16*IRS);
                mma16816(P[2*q],   aH, bH);
                mma16816(P[2*q+1], aH, bH+2);
                mma16816(P[2*q],   aL, bH);
                mma16816(P[2*q+1], aL, bH+2);
                mma16816(P[2*q],   aH, bL);
                mma16816(P[2*q+1], aH, bL+2);
            }
        }
    };

    auto mm_KV = [&](){
        #pragma unroll
        for (int j=0;j<8;j++)
            #pragma unroll
            for (int e=0;e<4;e++) P[j][e] = 0.f;
        unsigned Rb = smb;
        #pragma unroll
        for (int k = 0; k < 8; k++){
            int k0 = k*16;
            int r = m0 + g, c = k0 + tg*2;
            float2 v0 = *(const float2*)&Kg[(size_t)r*128 + c];
            float2 v1 = *(const float2*)&Kg[(size_t)(r+8)*128 + c];
            float2 v2 = *(const float2*)&Kg[(size_t)r*128 + c + 8];
            float2 v3 = *(const float2*)&Kg[(size_t)(r+8)*128 + c + 8];
            unsigned aH[4], aL[4]; float lx, ly;
            aH[0] = pack_hi(v0.x, v0.y, lx, ly); aL[0] = pack_bf2(lx, ly);
            aH[1] = pack_hi(v1.x, v1.y, lx, ly); aL[1] = pack_bf2(lx, ly);
            aH[2] = pack_hi(v2.x, v2.y, lx, ly); aL[2] = pack_bf2(lx, ly);
            aH[3] = pack_hi(v3.x, v3.y, lx, ly); aL[3] = pack_bf2(lx, ly);
            #pragma unroll
            for (int q = 0; q < 4; q++){
                unsigned bH[4], bL[4];
                ldsm4t(bH[0],bH[1],bH[2],bH[3], Rb + boff[q] + k*16*IRS);
                ldsm4t(bL[0],bL[1],bL[2],bL[3], Rb + IMAT + boff[q] + k*16*IRS);
                mma16816(P[2*q],   aH, bH);
                mma16816(P[2*q+1], aH, bH+2);
                mma16816(P[2*q],   aL, bH);
                mma16816(P[2*q+1], aL, bH+2);
                mma16816(P[2*q],   aH, bL);
                mma16816(P[2*q+1], aH, bL+2);
            }
        }
    };

    auto store_mat = [&](int slot, float (*F)[4]){
        #pragma unroll
        for (int half = 0; half < 2; half++){
            int r = m0 + g + half*8;
            #pragma unroll
            for (int j = 0; j < 8; j++){
                int c = nb + j*8 + tg*2;
                float x = F[j][half*2], y = F[j][half*2+1];
                float lx, ly;
                unsigned hp = pack_hi(x, y, lx, ly);
                unsigned lp = pack_bf2(lx, ly);
                *(unsigned*)(ismem + slot*IMAT + r*IRS + c*2) = hp;
                *(unsigned*)(ismem + (slot+1)*IMAT + r*IRS + c*2) = lp;
            }
        }
    };

    for (int it = 0; it < 6; it++){
        mm_KV();
        #pragma unroll
        for (int j=0;j<8;j++)
            #pragma unroll
            for (int e=0;e<4;e++) Aa[j][e] = P[j][e];
        __syncthreads();
        store_mat(2, Aa);
        __syncthreads();

        mm_ss(2, 2);
        #pragma unroll
        for (int j=0;j<8;j++)
            #pragma unroll
            for (int e=0;e<4;e++) P[j][e] = 7.f*Aa[j][e] - P[j][e];
        __syncthreads();
        store_mat(4, P);
        __syncthreads();

        mm_ss(2, 4);
        #pragma unroll
        for (int j=0;j<8;j++)
            #pragma unroll
            for (int e=0;e<4;e++) P[j][e] = 15.f*Aa[j][e] - P[j][e];
        __syncthreads();
        store_mat(4, P);
        __syncthreads();

        mm_ss(0, 4);
        __syncthreads();
        #pragma unroll
        for (int half = 0; half < 2; half++){
            int r = m0 + g + half*8;
            #pragma unroll
            for (int j = 0; j < 8; j++){
                int c = nb + j*8 + tg*2;
                unsigned hp = *(unsigned*)(ismem + 0*IMAT + r*IRS + c*2);
                unsigned lp = *(unsigned*)(ismem + 1*IMAT + r*IRS + c*2);
                __nv_bfloat162 hb = *(__nv_bfloat162*)&hp;
                __nv_bfloat162 lb = *(__nv_bfloat162*)&lp;
                float vx = __bfloat162float(hb.x) + __bfloat162float(lb.x);
                float vy = __bfloat162float(hb.y) + __bfloat162float(lb.y);
                P[j][half*2]   = 3.25f*vx - 0.25f*P[j][half*2];
                P[j][half*2+1] = 3.25f*vy - 0.25f*P[j][half*2+1];
            }
        }
        store_mat(0, P);
        __syncthreads();
    }

    {
        int i = tid >> 2, h0 = (tid & 3) * 16;
        const float* Ng = g_k3V + (size_t)bh*8192;
        for (int j = 0; j < 16; j++){
            float v = Ng[i*64 + h0 + j];
            __nv_bfloat16 hi = __float2bfloat16(v);
            __nv_bfloat16 lo = __float2bfloat16(v - __bfloat162float(hi));
            *(__nv_bfloat16*)(ismem + 2*IMAT + i*IRS + (h0+j)*2) = hi;
            *(__nv_bfloat16*)(ismem + 3*IMAT + i*IRS + (h0+j)*2) = lo;
        }
    }
    __syncthreads();
    {
        int nbW = nw * 32;
        unsigned boffW[2];
        #pragma unroll
        for (int q = 0; q < 2; q++)
            boffW[q] = (unsigned)(((t8&1)*8 + i8)*IRS + (nbW + q*16 + (t8>>1)*8)*2);

        float Pw[4][4];
        #pragma unroll
        for (int j=0;j<4;j++)
            #pragma unroll
            for (int e=0;e<4;e++) Pw[j][e] = 0.f;

        #pragma unroll
        for (int k = 0; k < 8; k++){
            unsigned aH[4], aL[4];
            ldsm4(aH[0],aH[1],aH[2],aH[3], smb + aoff + k*32);
            ldsm4(aL[0],aL[1],aL[2],aL[3], smb + IMAT + aoff + k*32);
            #pragma unroll
            for (int q = 0; q < 2; q++){
                unsigned bH[4], bL[4];
                ldsm4t(bH[0],bH[1],bH[2],bH[3], smb + 2*IMAT + boffW[q] + k*16*IRS);
                ldsm4t(bL[0],bL[1],bL[2],bL[3], smb + 3*IMAT + boffW[q] + k*16*IRS);
                mma16816(Pw[2*q],   aH, bH);
                mma16816(Pw[2*q+1], aH, bH+2);
                mma16816(Pw[2*q],   aL, bH);
                mma16816(Pw[2*q+1], aL, bH+2);
                mma16816(Pw[2*q],   aH, bL);
                mma16816(Pw[2*q+1], aH, bL+2);
            }
        }
        float* Wg = g_W2 + (size_t)bh*8192;
        #pragma unroll
        for (int half = 0; half < 2; half++){
            int r = m0 + g + half*8;
            #pragma unroll
            for (int j = 0; j < 4; j++){
                int c = nbW + j*8 + tg*2;
                *(float2*)&Wg[r*64 + c] = make_float2(Pw[j][half*2], Pw[j][half*2+1]);
            }
        }
    }
}

// ---------------- k1 on HMMA: ctx = softmax(Q @ Kl^T) @ W2 ---------------------
#define KLRS 144
#define K1MAT 18432
#define K1_SMEM (4*K1MAT)

__global__ __launch_bounds__(256, 2)
void k1_kernel(){
    extern __shared__ __align__(16) char ksm[];
    const unsigned smb = smem_u32(ksm);
    const int sblk = blockIdx.x, bh = blockIdx.y;
    const int tid = threadIdx.x, lane = tid & 31, w = tid >> 5;
    const int g = lane >> 2, tg = lane & 3;
    const int i8 = lane & 7, t8 = lane >> 3;
    const int m0 = w * 16;

    const float* Klg = g_Kl + (size_t)bh*8192;
    const float* W2g = g_W2 + (size_t)bh*8192;
    for (int idx = tid; idx < 8192; idx += 256){
        int r = idx >> 6, c = idx & 63;
        float v = Klg[idx];
        __nv_bfloat16 hi = __float2bfloat16(v);
        __nv_bfloat16 lo = __float2bfloat16(v - __bfloat162float(hi));
        *(__nv_bfloat16*)(ksm + 0*K1MAT + r*KLRS + c*2) = hi;
        *(__nv_bfloat16*)(ksm + 1*K1MAT + r*KLRS + c*2) = lo;
        v = W2g[idx];
        hi = __float2bfloat16(v);
        lo = __float2bfloat16(v - __bfloat162float(hi));
        *(__nv_bfloat16*)(ksm + 2*K1MAT + r*KLRS + c*2) = hi;
        *(__nv_bfloat16*)(ksm + 3*K1MAT + r*KLRS + c*2) = lo;
    }
    __syncthreads();

    const float* Qg = g_Q + ((size_t)bh*S_ + sblk*128)*HD_;
    float st[16][4];
    #pragma unroll
    for (int nt=0;nt<16;nt++)
        #pragma unroll
        for (int e=0;e<4;e++) st[nt][e] = 0.f;

    #pragma unroll
    for (int kc = 0; kc < 4; kc++){
        int r = m0 + g, c = kc*16 + tg*2;
        float2 v0 = *(const float2*)&Qg[(size_t)r*64 + c];
        float2 v1 = *(const float2*)&Qg[(size_t)(r+8)*64 + c];
        float2 v2 = *(const float2*)&Qg[(size_t)r*64 + c + 8];
        float2 v3 = *(const float2*)&Qg[(size_t)(r+8)*64 + c + 8];
        unsigned aH[4], aL[4]; float lx, ly;
        aH[0] = pack_hi(v0.x, v0.y, lx, ly); aL[0] = pack_bf2(lx, ly);
        aH[1] = pack_hi(v1.x, v1.y, lx, ly); aL[1] = pack_bf2(lx, ly);
        aH[2] = pack_hi(v2.x, v2.y, lx, ly); aL[2] = pack_bf2(lx, ly);
        aH[3] = pack_hi(v3.x, v3.y, lx, ly); aL[3] = pack_bf2(lx, ly);
        #pragma unroll
        for (int q = 0; q < 8; q++){
            unsigned kOff = (unsigned)((q*16 + (t8>>1)*8 + i8)*KLRS + (t8&1)*16 + kc*32);
            unsigned bH[4], bL[4];
            ldsm4(bH[0],bH[1],bH[2],bH[3], smb + 0*K1MAT + kOff);
            ldsm4(bL[0],bL[1],bL[2],bL[3], smb + 1*K1MAT + kOff);
            mma16816(st[2*q],   aH, bH);
            mma16816(st[2*q+1], aH, bH+2);
            mma16816(st[2*q],   aL, bH);
            mma16816(st[2*q+1], aL, bH+2);
            mma16816(st[2*q],   aH, bL);
            mma16816(st[2*q+1], aH, bL+2);
        }
    }

    float mx0 = -1e30f, mx1 = -1e30f;
    #pragma unroll
    for (int nt = 0; nt < 16; nt++){
        mx0 = fmaxf(mx0, fmaxf(st[nt][0], st[nt][1]));
        mx1 = fmaxf(mx1, fmaxf(st[nt][2], st[nt][3]));
    }
    mx0 = fmaxf(mx0, __shfl_xor_sync(0xffffffffu, mx0, 1));
    mx0 = fmaxf(mx0, __shfl_xor_sync(0xffffffffu, mx0, 2));
    mx1 = fmaxf(mx1, __shfl_xor_sync(0xffffffffu, mx1, 1));
    mx1 = fmaxf(mx1, __shfl_xor_sync(0xffffffffu, mx1, 2));
    float z0 = 0.f, z1 = 0.f;
    #pragma unroll
    for (int nt = 0; nt < 16; nt++){
        st[nt][0] = __expf(st[nt][0] - mx0);
        st[nt][1] = __expf(st[nt][1] - mx0);
        st[nt][2] = __expf(st[nt][2] - mx1);
        st[nt][3] = __expf(st[nt][3] - mx1);
        z0 += st[nt][0] + st[nt][1];
        z1 += st[nt][2] + st[nt][3];
    }
    z0 += __shfl_xor_sync(0xffffffffu, z0, 1);
    z0 += __shfl_xor_sync(0xffffffffu, z0, 2);
    z1 += __shfl_xor_sync(0xffffffffu, z1, 1);
    z1 += __shfl_xor_sync(0xffffffffu, z1, 2);
    float zi0 = 1.f/z0, zi1 = 1.f/z1;
    #pragma unroll
    for (int nt = 0; nt < 16; nt++){
        st[nt][0] *= zi0; st[nt][1] *= zi0;
        st[nt][2] *= zi1; st[nt][3] *= zi1;
    }

    float o[8][4];
    #pragma unroll
    for (int j=0;j<8;j++)
        #pragma unroll
        for (int e=0;e<4;e++) o[j][e] = 0.f;

    #pragma unroll
    for (int kc = 0; kc < 8; kc++){
        unsigned aH[4], aL[4]; float lx, ly;
        aH[0] = pack_hi(st[2*kc][0],   st[2*kc][1],   lx, ly); aL[0] = pack_bf2(lx, ly);
        aH[1] = pack_hi(st[2*kc][2],   st[2*kc][3],   lx, ly); aL[1] = pack_bf2(lx, ly);
        aH[2] = pack_hi(st[2*kc+1][0], st[2*kc+1][1], lx, ly); aL[2] = pack_bf2(lx, ly);
        aH[3] = pack_hi(st[2*kc+1][2], st[2*kc+1][3], lx, ly); aL[3] = pack_bf2(lx, ly);
        #pragma unroll
        for (int q = 0; q < 4; q++){
            unsigned wOff = (unsigned)(((t8&1)*8 + i8 + kc*16)*KLRS + (q*16 + (t8>>1)*8)*2);
            unsigned bH[4], bL[4];
            ldsm4t(bH[0],bH[1],bH[2],bH[3], smb + 2*K1MAT + wOff);
            ldsm4t(bL[0],bL[1],bL[2],bL[3], smb + 3*K1MAT + wOff);
            mma16816(o[2*q],   aH, bH);
            mma16816(o[2*q+1], aH, bH+2);
            mma16816(o[2*q],   aL, bH);
            mma16816(o[2*q+1], aL, bH+2);
            mma16816(o[2*q],   aH, bL);
            mma16816(o[2*q+1], aH, bL+2);
        }
    }

    int b = bh >> 4, h = bh & 15;
    #pragma unroll
    for (int half = 0; half < 2; half++){
        int sI = sblk*128 + m0 + g + half*8;
        size_t obase = ((size_t)(b*S_ + sI))*D_ + h*64;
        #pragma unroll
        for (int nt = 0; nt < 8; nt++){
            int d = nt*8 + tg*2;
            __half hv[2] = {__float2half_rn(o[nt][half*2]), __float2half_rn(o[nt][half*2+1])};
            *(unsigned*)&g_ctxh[obase + d] = *(unsigned*)hv;
        }
    }
}

// ---------------- launch -------------------------------------------------------
extern "C" void kernel_launch(void* const* d_in, const int* in_sizes, int n_in,
                              void* d_out, int out_size)
{
    const float* X    = (const float*)d_in[0];
    const float* mask = (const float*)d_in[1];
    const float* Wq   = (const float*)d_in[2];
    const float* bq   = (const float*)d_in[3];
    const float* Wk   = (const float*)d_in[4];
    const float* bk   = (const float*)d_in[5];
    const float* Wv   = (const float*)d_in[6];
    const float* bv   = (const float*)d_in[7];
    const float* Wo   = (const float*)d_in[8];
    const float* bo   = (const float*)d_in[9];
    float* out = (float*)d_out;

    void *pQ, *pK, *pV;
    cudaGetSymbolAddress(&pQ, g_Q);
    cudaGetSymbolAddress(&pK, g_K);
    cudaGetSymbolAddress(&pV, g_V);

    cudaFuncSetAttribute(gemm_qkv, cudaFuncAttributeMaxDynamicSharedMemorySize, GSMEM);
    cudaFuncSetAttribute(gemm_out, cudaFuncAttributeMaxDynamicSharedMemorySize, GSMEM);
    cudaFuncSetAttribute(inv_kernel, cudaFuncAttributeMaxDynamicSharedMemorySize, INV_SMEM);
    cudaFuncSetAttribute(k1_kernel,  cudaFuncAttributeMaxDynamicSharedMemorySize, K1_SMEM);
    cudaFuncSetAttribute(k3_mma,     cudaFuncAttributeMaxDynamicSharedMemorySize, K3_SMEM);

    convX_kernel<<<8192, 256>>>(X);                       // 1
    convW_kernel<<<dim3(32,32,4), 256>>>(Wq, Wk, Wv, Wo); // 2
    probe_kernel<<<1, 32>>>();                            // 3
    gemm_qkv<<<dim3(24,64), 256, GSMEM>>>(bq, bk, bv, mask,
                                          (float*)pQ, (float*)pK, (float*)pV); // 4 <- ncu

    landmark_kernel<<<(BH_*NL_*HD_)/256, 256>>>();
    k2_kernel<<<dim3(NL_, BH_), 128>>>();
    colmax_kernel<<<BH_, 128>>>();
    k3_mma<<<dim3(8, BH_), 256, K3_SMEM>>>(mask);
    k3_combine<<<BH_, 128>>>();
    inv_kernel<<<BH_, 512, INV_SMEM>>>();
    k1_kernel<<<dim3(32, BH_), 256, K1_SMEM>>>();

    gemm_out<<<dim3(8,64), 256, GSMEM>>>(bo, out);
}

// round 16
// speedup vs baseline: 10.1172x; 1.0508x over previous
#include <cuda_runtime.h>
#include <cuda_bf16.h>
#include <cuda_fp16.h>

// Problem constants
#define B_  2
#define S_  4096
#define HID_ 1024
#define NH_ 16
#define HD_ 64
#define NL_ 128
#define BH_ (B_*NH_)          // 32
#define SEG_ (S_/NL_)         // 32
#define D_ (NH_*HD_)          // 1024
#define SCALE_ 0.35355339059327373f  // HD^-0.25

// ---------------- device scratch -----------------------------------------------
__device__ float g_Q[B_*NH_*S_*HD_];     // (b,h,s,d) scaled+masked
__device__ float g_K[B_*NH_*S_*HD_];
__device__ float g_V[B_*NH_*S_*HD_];
__device__ float g_Ql[BH_*NL_*HD_];
__device__ float g_Kl[BH_*NL_*HD_];
__device__ float g_k2[BH_*NL_*NL_];
__device__ float g_bhmax[BH_];
__device__ float g_k3V[BH_*NL_*HD_];
__device__ float g_W2[BH_*NL_*HD_];
__device__ float g_k3o[BH_*8*NL_*HD_];   // split-K partials
__device__ float g_k3mz[BH_*8*NL_*2];
__device__ __align__(256) __half g_Xh[8192*1024];
__device__ __align__(256) __half g_Wth[4*1024*1024];   // [4][n][k] q,k,v,o (fp16)
__device__ __align__(256) __half g_ctxh[8192*1024];

__device__ __forceinline__ unsigned smem_u32(const void* p){
    unsigned a;
    asm("{ .reg .u64 t; cvta.to.shared.u64 t, %1; cvt.u32.u64 %0, t; }" : "=r"(a) : "l"(p));
    return a;
}
__device__ __forceinline__ void ldsm4(unsigned& r0, unsigned& r1, unsigned& r2, unsigned& r3,
                                      unsigned addr){
    asm volatile("ldmatrix.sync.aligned.m8n8.x4.shared.b16 {%0,%1,%2,%3}, [%4];"
        : "=r"(r0), "=r"(r1), "=r"(r2), "=r"(r3) : "r"(addr));
}
__device__ __forceinline__ void ldsm4t(unsigned& r0, unsigned& r1, unsigned& r2, unsigned& r3,
                                       unsigned addr){
    asm volatile("ldmatrix.sync.aligned.m8n8.x4.trans.shared.b16 {%0,%1,%2,%3}, [%4];"
        : "=r"(r0), "=r"(r1), "=r"(r2), "=r"(r3) : "r"(addr));
}
// bf16 mma (attention mid-section: k1, k3)
__device__ __forceinline__ void mma16816(float* c, const unsigned* a, const unsigned* b){
    asm volatile(
        "mma.sync.aligned.m16n8k16.row.col.f32.bf16.bf16.f32 "
        "{%0,%1,%2,%3}, {%4,%5,%6,%7}, {%8,%9}, {%0,%1,%2,%3};"
        : "+f"(c[0]), "+f"(c[1]), "+f"(c[2]), "+f"(c[3])
        : "r"(a[0]), "r"(a[1]), "r"(a[2]), "r"(a[3]), "r"(b[0]), "r"(b[1]));
}
// fp16 mma (big GEMMs + inv)
__device__ __forceinline__ void mma16816h(float* c, const unsigned* a, const unsigned* b){
    asm volatile(
        "mma.sync.aligned.m16n8k16.row.col.f32.f16.f16.f32 "
        "{%0,%1,%2,%3}, {%4,%5,%6,%7}, {%8,%9}, {%0,%1,%2,%3};"
        : "+f"(c[0]), "+f"(c[1]), "+f"(c[2]), "+f"(c[3])
        : "r"(a[0]), "r"(a[1]), "r"(a[2]), "r"(a[3]), "r"(b[0]), "r"(b[1]));
}
__device__ __forceinline__ unsigned pack_hi(float x, float y, float& lx, float& ly){
    __nv_bfloat162 h = __floats2bfloat162_rn(x, y);
    lx = x - __bfloat162float(h.x);
    ly = y - __bfloat162float(h.y);
    return *(unsigned*)&h;
}
__device__ __forceinline__ unsigned pack_bf2(float x, float y){
    __nv_bfloat162 h = __floats2bfloat162_rn(x, y);
    return *(unsigned*)&h;
}
__device__ __forceinline__ unsigned pack_hi_h(float x, float y, float& lx, float& ly){
    __half2 h = __floats2half2_rn(x, y);
    lx = x - __half2float(__low2half(h));
    ly = y - __half2float(__high2half(h));
    return *(unsigned*)&h;
}
__device__ __forceinline__ unsigned pack_h2(float x, float y){
    __half2 h = __floats2half2_rn(x, y);
    return *(unsigned*)&h;
}
__device__ __forceinline__ void cp16(unsigned dst, const void* src){
    asm volatile("cp.async.cg.shared.global [%0], [%1], 16;" :: "r"(dst), "l"(src));
}
__device__ __forceinline__ void cpcommit(){ asm volatile("cp.async.commit_group;" ::: "memory"); }
template<int N> __device__ __forceinline__ void cpwait(){
    asm volatile("cp.async.wait_group %0;" :: "n"(N) : "memory");
}

// ---------------- probe (keeps gemm_qkv in the profiled 4th slot) --------------
__global__ void probe_kernel(){
    if (threadIdx.x < BH_) g_bhmax[threadIdx.x] = 0.f;
}

// ---------------- prep: X -> fp16 ----------------------------------------------
__global__ void convX_kernel(const float* __restrict__ X){
    size_t i4 = (size_t)blockIdx.x * blockDim.x + threadIdx.x;
    float4 v = ((const float4*)X)[i4];
    __half h[4] = {__float2half_rn(v.x), __float2half_rn(v.y),
                   __float2half_rn(v.z), __float2half_rn(v.w)};
    *(uint2*)&g_Xh[i4*4] = *(uint2*)h;
}

// ---------------- prep: transpose weights -> [n][k] fp16 -----------------------
__global__ void convW_kernel(const float* __restrict__ Wq, const float* __restrict__ Wk,
                             const float* __restrict__ Wv, const float* __restrict__ Wo){
    __shared__ float t[32][33];
    int z = blockIdx.z;
    const float* W = (z==0) ? Wq : (z==1) ? Wk : (z==2) ? Wv : Wo;
    int n0 = blockIdx.x * 32, k0 = blockIdx.y * 32;
    int tx = threadIdx.x & 31, ty = threadIdx.x >> 5;
    #pragma unroll
    for (int r = 0; r < 4; r++){
        int ky = ty + r*8;
        t[ky][tx] = W[(size_t)(k0 + ky)*1024 + n0 + tx];
    }
    __syncthreads();
    #pragma unroll
    for (int r = 0; r < 4; r++){
        int ny = ty + r*8;
        size_t o = (size_t)z*1048576 + (size_t)(n0 + ny)*1024 + k0 + tx;
        g_Wth[o] = __float2half_rn(t[tx][ny]);
    }
}

// ================= fp16 HMMA GEMM mainloop =====================================
// R16: 3-stage cp.async pipeline, ONE __syncthreads per stage.
#define ROWBY 80
#define TILEB (128*ROWBY)
#define STAGEB (2*TILEB)      // 20480
#define GSMEM (3*STAGEB)      // 61440

__device__ __forceinline__ void gemm_main(
    const __half* __restrict__ Ah, const __half* __restrict__ Bh,
    unsigned smb, float acc[2][8][4])
{
    const int tid = threadIdx.x, lane = tid & 31, w = tid >> 5;
    const int wr = w & 3, wc = w >> 2;

    unsigned aoff[2], boff[4];
    {
        int i = lane & 7, t8 = lane >> 3;
        #pragma unroll
        for (int t = 0; t < 2; t++)
            aoff[t] = (unsigned)((wr*32 + t*16 + (t8 & 1)*8 + i) * ROWBY + (t8 >> 1) * 16);
        #pragma unroll
        for (int q = 0; q < 4; q++)
            boff[q] = (unsigned)((wc*64 + q*16 + (t8 >> 1)*8 + i) * ROWBY + (t8 & 1) * 16);
    }

    auto issue = [&](int buf, int k0){
        #pragma unroll
        for (int r = 0; r < 4; r++){
            int idx = r*256 + tid;
            int c = idx & 3, row = (idx >> 2) & 127, tile = idx >> 9;
            const __half* src =
                (tile == 0) ? Ah + (size_t)row*1024 + k0 + c*8 :
                              Bh + (size_t)row*1024 + k0 + c*8;
            cp16(smb + buf*STAGEB + tile*TILEB + row*ROWBY + c*16, src);
        }
        cpcommit();
    };

    issue(0, 0);
    issue(1, 32);
    for (int s = 0; s < 32; s++){
        cpwait<1>();            // stage s data landed (stage s+1 may be pending)
        __syncthreads();        // publish data; all warps done reading buf (s-1)%3
        if (s < 30) issue((s+2) % 3, (s+2)*32);

        unsigned base = smb + (s % 3)*STAGEB;
        #pragma unroll
        for (int kb = 0; kb < 2; kb++){
            unsigned ko = kb * 32;
            unsigned aH[2][4], bX[4][4];
            #pragma unroll
            for (int t = 0; t < 2; t++)
                ldsm4(aH[t][0], aH[t][1], aH[t][2], aH[t][3], base + aoff[t] + ko);
            #pragma unroll
            for (int q = 0; q < 4; q++)
                ldsm4(bX[q][0], bX[q][1], bX[q][2], bX[q][3], base + TILEB + boff[q] + ko);
            #pragma unroll
            for (int t = 0; t < 2; t++)
                #pragma unroll
                for (int q = 0; q < 4; q++){
                    mma16816h(acc[t][2*q],   aH[t], &bX[q][0]);
                    mma16816h(acc[t][2*q+1], aH[t], &bX[q][2]);
                }
        }
        __syncthreads();        // all warps done reading buf s%3 before it is refilled
    }
}

__global__ __launch_bounds__(256, 2)
void gemm_qkv(const float* __restrict__ bq, const float* __restrict__ bk,
              const float* __restrict__ bv, const float* __restrict__ mask,
              float* __restrict__ oq, float* __restrict__ okk, float* __restrict__ ov)
{
    extern __shared__ __align__(16) char smem[];
    unsigned smb = smem_u32(smem);
    int wsel = blockIdx.x >> 3, colt = blockIdx.x & 7;
    const __half* Ah = g_Xh + (size_t)blockIdx.y*128*1024;
    const __half* Bh = g_Wth + ((size_t)wsel*1024 + colt*128)*1024;

    float acc[2][8][4];
    #pragma unroll
    for (int t=0;t<2;t++)
        #pragma unroll
        for (int j=0;j<8;j++)
            #pragma unroll
            for (int e=0;e<4;e++) acc[t][j][e] = 0.f;

    gemm_main(Ah, Bh, smb, acc);

    const float* bias = (wsel==0) ? bq : (wsel==1) ? bk : bv;
    float* out = (wsel==0) ? oq : (wsel==1) ? okk : ov;
    const bool scaled = (wsel < 2);

    int lane = threadIdx.x & 31, w = threadIdx.x >> 5;
    int wr = w & 3, wc = w >> 2;
    int g = lane >> 2, tg = lane & 3;
    #pragma unroll
    for (int t = 0; t < 2; t++){
        #pragma unroll
        for (int half = 0; half < 2; half++){
            int row = blockIdx.y*128 + wr*32 + t*16 + g + half*8;
            float rs = scaled ? SCALE_ * mask[row] : 1.0f;
            int bb = row >> 12, sI = row & 4095;
            #pragma unroll
            for (int j = 0; j < 8; j++){
                int col = colt*128 + wc*64 + j*8 + tg*2;
                float c0 = (acc[t][j][half*2]   + bias[col])   * rs;
                float c1 = (acc[t][j][half*2+1] + bias[col+1]) * rs;
                int h = col >> 6, d = col & 63;
                *(float2*)(out + ((size_t)(bb*NH_ + h)*S_ + sI)*HD_ + d) = make_float2(c0, c1);
            }
        }
    }
}

__global__ __launch_bounds__(256, 2)
void gemm_out(const float* __restrict__ bias, float* __restrict__ out)
{
    extern __shared__ __align__(16) char smem[];
    unsigned smb = smem_u32(smem);
    const __half* Ah = g_ctxh + (size_t)blockIdx.y*128*1024;
    const __half* Bh = g_Wth + (size_t)3*1048576 + (size_t)blockIdx.x*128*1024;

    float acc[2][8][4];
    #pragma unroll
    for (int t=0;t<2;t++)
        #pragma unroll
        for (int j=0;j<8;j++)
            #pragma unroll
            for (int e=0;e<4;e++) acc[t][j][e] = 0.f;

    gemm_main(Ah, Bh, smb, acc);

    int lane = threadIdx.x & 31, w = threadIdx.x >> 5;
    int wr = w & 3, wc = w >> 2;
    int g = lane >> 2, tg = lane & 3;
    #pragma unroll
    for (int t = 0; t < 2; t++){
        #pragma unroll
        for (int half = 0; half < 2; half++){
            int row = blockIdx.y*128 + wr*32 + t*16 + g + half*8;
            #pragma unroll
            for (int j = 0; j < 8; j++){
                int col = blockIdx.x*128 + wc*64 + j*8 + tg*2;
                float c0 = acc[t][j][half*2]   + bias[col];
                float c1 = acc[t][j][half*2+1] + bias[col+1];
                *(float2*)(out + (size_t)row*1024 + col) = make_float2(c0, c1);
            }
        }
    }
}

// ---------------- landmarks ----------------------------------------------------
__global__ void landmark_kernel(){
    int idx = blockIdx.x*blockDim.x + threadIdx.x;
    int d  = idx & 63;
    int l  = (idx >> 6) & 127;
    int bh = idx >> 13;
    const float* q = g_Q + ((size_t)bh*S_ + l*SEG_)*HD_ + d;
    const float* k = g_K + ((size_t)bh*S_ + l*SEG_)*HD_ + d;
    float sq = 0.f, sk = 0.f;
    #pragma unroll
    for (int j=0; j<SEG_; j++){ sq += q[j*HD_]; sk += k[j*HD_]; }
    g_Ql[idx] = sq * (1.f/SEG_);
    g_Kl[idx] = sk * (1.f/SEG_);
}

// ---------------- k2 = softmax(Ql @ Kl^T) --------------------------------------
__global__ void k2_kernel(){
    int l = blockIdx.x, bh = blockIdx.y, m = threadIdx.x;
    const float4* ql = (const float4*)(g_Ql + ((size_t)bh*NL_ + l)*HD_);
    const float4* kl = (const float4*)(g_Kl + ((size_t)bh*NL_ + m)*HD_);
    float acc = 0.f;
    #pragma unroll
    for (int d4=0; d4<16; d4++){
        float4 a = ql[d4], b = kl[d4];
        acc += a.x*b.x + a.y*b.y + a.z*b.z + a.w*b.w;
    }
    __shared__ float red[128];
    red[m] = acc; __syncthreads();
    for (int off=64; off>0; off>>=1){
        if (m < off) red[m] = fmaxf(red[m], red[m+off]);
        __syncthreads();
    }
    float mx = red[0]; __syncthreads();
    float p = __expf(acc - mx);
    red[m] = p; __syncthreads();
    for (int off=64; off>0; off>>=1){
        if (m < off) red[m] += red[m+off];
        __syncthreads();
    }
    g_k2[((size_t)bh*NL_ + l)*NL_ + m] = p / red[0];
}

// ---------------- column sums of k2 -> per-bh max ------------------------------
__global__ void colmax_kernel(){
    int bh = blockIdx.x, m = threadIdx.x;
    float s = 0.f;
    for (int l=0; l<NL_; l++) s += g_k2[((size_t)bh*NL_ + l)*NL_ + m];
    __shared__ float red[128];
    red[m] = s; __syncthreads();
    for (int off=64; off>0; off>>=1){
        if (m < off) red[m] = fmaxf(red[m], red[m+off]);
        __syncthreads();
    }
    if (m == 0) g_bhmax[bh] = red[0];
}

// ---------------- k3 on HMMA: flash-style split-K (bf16 3-product) -------------
#define K3RS  144
#define K3MAT 18432
#define K3_SMEM (6*K3MAT + 512)

__global__ __launch_bounds__(256, 1)
void k3_mma(const float* __restrict__ mask){
    extern __shared__ __align__(16) char ksm[];
    const unsigned smb = smem_u32(ksm);
    const int chunk = blockIdx.x, bh = blockIdx.y;
    const int tid = threadIdx.x, lane = tid & 31, w = tid >> 5;
    const int g = lane >> 2, tg = lane & 3;
    const int i8 = lane & 7, t8 = lane >> 3;
    const int m0 = w * 16;
    float* msk = (float*)(ksm + 6*K3MAT);

    const float* Qlg = g_Ql + (size_t)bh*8192;
    for (int idx = tid; idx < 8192; idx += 256){
        int r = idx >> 6, c = idx & 63;
        float v = Qlg[idx];
        __nv_bfloat16 hi = __float2bfloat16(v);
        __nv_bfloat16 lo = __float2bfloat16(v - __bfloat162float(hi));
        *(__nv_bfloat16*)(ksm + 0*K3MAT + r*K3RS + c*2) = hi;
        *(__nv_bfloat16*)(ksm + 1*K3MAT + r*K3RS + c*2) = lo;
    }

    const float* Kbh = g_K + (size_t)bh*S_*HD_;
    const float* Vbh = g_V + (size_t)bh*S_*HD_;
    const float* mrow = mask + (size_t)(bh >> 4)*S_;

    const unsigned aoff = (unsigned)((m0 + (t8&1)*8 + i8)*K3RS + (t8>>1)*16);

    float mr0 = -1e30f, mr1 = -1e30f, z0 = 0.f, z1 = 0.f;
    float o[8][4];
    #pragma unroll
    for (int j=0;j<8;j++)
        #pragma unroll
        for (int e=0;e<4;e++) o[j][e] = 0.f;

    for (int it = 0; it < 4; it++){
        int sbase = chunk*512 + it*128;
        __syncthreads();
        for (int idx = tid; idx < 8192; idx += 256){
            int r = idx >> 6, c = idx & 63;
            float v = Kbh[(size_t)(sbase + r)*HD_ + c];
            __nv_bfloat16 hi = __float2bfloat16(v);
            __nv_bfloat16 lo = __float2bfloat16(v - __bfloat162float(hi));
            *(__nv_bfloat16*)(ksm + 2*K3MAT + r*K3RS + c*2) = hi;
            *(__nv_bfloat16*)(ksm + 3*K3MAT + r*K3RS + c*2) = lo;
            v = Vbh[(size_t)(sbase + r)*HD_ + c];
            hi = __float2bfloat16(v);
            lo = __float2bfloat16(v - __bfloat162float(hi));
            *(__nv_bfloat16*)(ksm + 4*K3MAT + r*K3RS + c*2) = hi;
            *(__nv_bfloat16*)(ksm + 5*K3MAT + r*K3RS + c*2) = lo;
        }
        if (tid < 128) msk[tid] = mrow[sbase + tid];
        __syncthreads();

        float st[16][4];
        #pragma unroll
        for (int nt=0;nt<16;nt++)
            #pragma unroll
            for (int e=0;e<4;e++) st[nt][e] = 0.f;

        #pragma unroll
        for (int kc = 0; kc < 4; kc++){
            unsigned aH[4], aL[4];
            ldsm4(aH[0],aH[1],aH[2],aH[3], smb + 0*K3MAT + aoff + kc*32);
            ldsm4(aL[0],aL[1],aL[2],aL[3], smb + 1*K3MAT + aoff + kc*32);
            #pragma unroll
            for (int q = 0; q < 8; q++){
                unsigned kOff = (unsigned)((q*16 + (t8>>1)*8 + i8)*K3RS + (t8&1)*16 + kc*32);
                unsigned bH[4], bL[4];
                ldsm4(bH[0],bH[1],bH[2],bH[3], smb + 2*K3MAT + kOff);
                ldsm4(bL[0],bL[1],bL[2],bL[3], smb + 3*K3MAT + kOff);
                mma16816(st[2*q],   aH, bH);
                mma16816(st[2*q+1], aH, bH+2);
                mma16816(st[2*q],   aL, bH);
                mma16816(st[2*q+1], aL, bH+2);
                mma16816(st[2*q],   aH, bL);
                mma16816(st[2*q+1], aH, bL+2);
            }
        }

        #pragma unroll
        for (int nt = 0; nt < 16; nt++){
            int c0 = nt*8 + tg*2;
            float p0 = -1e9f*(1.f - msk[c0]);
            float p1 = -1e9f*(1.f - msk[c0+1]);
            st[nt][0] += p0; st[nt][1] += p1;
            st[nt][2] += p0; st[nt][3] += p1;
        }

        float cm0 = -1e30f, cm1 = -1e30f;
        #pragma unroll
        for (int nt = 0; nt < 16; nt++){
            cm0 = fmaxf(cm0, fmaxf(st[nt][0], st[nt][1]));
            cm1 = fmaxf(cm1, fmaxf(st[nt][2], st[nt][3]));
        }
        cm0 = fmaxf(cm0, __shfl_xor_sync(0xffffffffu, cm0, 1));
        cm0 = fmaxf(cm0, __shfl_xor_sync(0xffffffffu, cm0, 2));
        cm1 = fmaxf(cm1, __shfl_xor_sync(0xffffffffu, cm1, 1));
        cm1 = fmaxf(cm1, __shfl_xor_sync(0xffffffffu, cm1, 2));
        float mn0 = fmaxf(mr0, cm0), mn1 = fmaxf(mr1, cm1);
        float cr0 = __expf(mr0 - mn0), cr1 = __expf(mr1 - mn1);
        mr0 = mn0; mr1 = mn1;
        z0 *= cr0; z1 *= cr1;
        #pragma unroll
        for (int j = 0; j < 8; j++){
            o[j][0] *= cr0; o[j][1] *= cr0;
            o[j][2] *= cr1; o[j][3] *= cr1;
        }
        float ps0 = 0.f, ps1 = 0.f;
        #pragma unroll
        for (int nt = 0; nt < 16; nt++){
            st[nt][0] = __expf(st[nt][0] - mn0);
            st[nt][1] = __expf(st[nt][1] - mn0);
            st[nt][2] = __expf(st[nt][2] - mn1);
            st[nt][3] = __expf(st[nt][3] - mn1);
            ps0 += st[nt][0] + st[nt][1];
            ps1 += st[nt][2] + st[nt][3];
        }
        ps0 += __shfl_xor_sync(0xffffffffu, ps0, 1);
        ps0 += __shfl_xor_sync(0xffffffffu, ps0, 2);
        ps1 += __shfl_xor_sync(0xffffffffu, ps1, 1);
        ps1 += __shfl_xor_sync(0xffffffffu, ps1, 2);
        z0 += ps0; z1 += ps1;

        #pragma unroll
        for (int kc = 0; kc < 8; kc++){
            unsigned aH[4], aL[4]; float lx, ly;
            aH[0] = pack_hi(st[2*kc][0],   st[2*kc][1],   lx, ly); aL[0] = pack_bf2(lx, ly);
            aH[1] = pack_hi(st[2*kc][2],   st[2*kc][3],   lx, ly); aL[1] = pack_bf2(lx, ly);
            aH[2] = pack_hi(st[2*kc+1][0], st[2*kc+1][1], lx, ly); aL[2] = pack_bf2(lx, ly);
            aH[3] = pack_hi(st[2*kc+1][2], st[2*kc+1][3], lx, ly); aL[3] = pack_bf2(lx, ly);
            #pragma unroll
            for (int q = 0; q < 4; q++){
                unsigned wOff = (unsigned)(((t8&1)*8 + i8 + kc*16)*K3RS + (q*16 + (t8>>1)*8)*2);
                unsigned bH[4], bL[4];
                ldsm4t(bH[0],bH[1],bH[2],bH[3], smb + 4*K3MAT + wOff);
                ldsm4t(bL[0],bL[1],bL[2],bL[3], smb + 5*K3MAT + wOff);
                mma16816(o[2*q],   aH, bH);
                mma16816(o[2*q+1], aH, bH+2);
                mma16816(o[2*q],   aL, bH);
                mma16816(o[2*q+1], aL, bH+2);
                mma16816(o[2*q],   aH, bL);
                mma16816(o[2*q+1], aH, bL+2);
            }
        }
    }

    size_t pbase = ((size_t)(bh*8 + chunk))*128;
    #pragma unroll
    for (int j = 0; j < 8; j++){
        int c = j*8 + tg*2;
        *(float2*)&g_k3o[(pbase + m0 + g)*64 + c]     = make_float2(o[j][0], o[j][1]);
        *(float2*)&g_k3o[(pbase + m0 + g + 8)*64 + c] = make_float2(o[j][2], o[j][3]);
    }
    if (tg == 0){
        g_k3mz[(pbase + m0 + g)*2]       = mr0;
        g_k3mz[(pbase + m0 + g)*2 + 1]   = z0;
        g_k3mz[(pbase + m0 + g + 8)*2]     = mr1;
        g_k3mz[(pbase + m0 + g + 8)*2 + 1] = z1;
    }
}

__global__ void k3_combine(){
    int bh = blockIdx.x, l = threadIdx.x;   // 128 threads
    float m[8], z[8], M = -1e30f;
    #pragma unroll
    for (int c = 0; c < 8; c++){
        m[c] = g_k3mz[((size_t)(bh*8 + c)*128 + l)*2];
        z[c] = g_k3mz[((size_t)(bh*8 + c)*128 + l)*2 + 1];
        M = fmaxf(M, m[c]);
    }
    float coef[8], Z = 0.f;
    #pragma unroll
    for (int c = 0; c < 8; c++){
        coef[c] = __expf(m[c] - M);
        Z += z[c]*coef[c];
    }
    float Zi = 1.f / Z;
    #pragma unroll
    for (int d4 = 0; d4 < 16; d4++){
        float4 acc = make_float4(0.f, 0.f, 0.f, 0.f);
        #pragma unroll
        for (int c = 0; c < 8; c++){
            float4 ov = *(const float4*)&g_k3o[((size_t)(bh*8 + c)*128 + l)*64 + d4*4];
            acc.x += coef[c]*ov.x; acc.y += coef[c]*ov.y;
            acc.z += coef[c]*ov.z; acc.w += coef[c]*ov.w;
        }
        acc.x *= Zi; acc.y *= Zi; acc.z *= Zi; acc.w *= Zi;
        *(float4*)&g_k3V[(size_t)bh*8192 + l*64 + d4*4] = acc;
    }
}

// ---------------- Newton inverse on HMMA: fp16 2-product -----------------------
// A-side split (hi/lo fp16, exact to 2^-22), B-side single fp16 (err 2^-12).
#define IRS  272
#define IMAT 34816
#define INV_SMEM (6*IMAT)

__global__ __launch_bounds__(512, 1)
void inv_kernel(){
    extern __shared__ __align__(16) char ismem[];
    const unsigned smb = smem_u32(ismem);
    const int bh = blockIdx.x, tid = threadIdx.x;
    const int lane = tid & 31, w = tid >> 5;
    const int mw = w & 7, nw = w >> 3;
    const int m0 = mw*16, nb = nw*64;
    const int g = lane >> 2, tg = lane & 3;
    const int i8 = lane & 7, t8 = lane >> 3;

    float cmax = g_bhmax[0];
    #pragma unroll
    for (int q=1; q<BH_; q++) cmax = fmaxf(cmax, g_bhmax[q]);
    const float rinv = 1.f / cmax;
    const float* Kg = g_k2 + (size_t)bh*NL_*NL_;

    {
        int i = tid >> 2, h0 = (tid & 3) * 32;
        for (int j = 0; j < 32; j++){
            float v = Kg[(h0 + j)*128 + i] * rinv;
            __half hi = __float2half_rn(v);
            __half lo = __float2half_rn(v - __half2float(hi));
            *(__half*)(ismem + 0*IMAT + i*IRS + (h0+j)*2) = hi;
            *(__half*)(ismem + 1*IMAT + i*IRS + (h0+j)*2) = lo;
        }
    }
    __syncthreads();

    unsigned aoff = (unsigned)((m0 + (t8&1)*8 + i8)*IRS + (t8>>1)*16);
    unsigned boff[4];
    #pragma unroll
    for (int q = 0; q < 4; q++)
        boff[q] = (unsigned)(((t8&1)*8 + i8)*IRS + (nb + q*16 + (t8>>1)*8)*2);

    float P[8][4], Aa[8][4];

    // P = L(hi/lo) @ R(hi): 2 products, fp16
    auto mm_ss = [&](int Lh, int Rh){
        #pragma unroll
        for (int j=0;j<8;j++)
            #pragma unroll
            for (int e=0;e<4;e++) P[j][e] = 0.f;
        unsigned Lb = smb + (unsigned)Lh*IMAT;
        unsigned Rb = smb + (unsigned)Rh*IMAT;
        #pragma unroll
        for (int k = 0; k < 8; k++){
            unsigned aH[4], aL[4];
            ldsm4(aH[0],aH[1],aH[2],aH[3], Lb + aoff + k*32);
            ldsm4(aL[0],aL[1],aL[2],aL[3], Lb + IMAT + aoff + k*32);
            #pragma unroll
            for (int q = 0; q < 4; q++){
                unsigned bH[4];
                ldsm4t(bH[0],bH[1],bH[2],bH[3], Rb + boff[q] + k*16*IRS);
                mma16816h(P[2*q],   aH, bH);
                mma16816h(P[2*q+1], aH, bH+2);
                mma16816h(P[2*q],   aL, bH);
                mma16816h(P[2*q+1], aL, bH+2);
            }
        }
    };

    auto mm_KV = [&](){
        #pragma unroll
        for (int j=0;j<8;j++)
            #pragma unroll
            for (int e=0;e<4;e++) P[j][e] = 0.f;
        unsigned Rb = smb;
        #pragma unroll
        for (int k = 0; k < 8; k++){
            int k0 = k*16;
            int r = m0 + g, c = k0 + tg*2;
            float2 v0 = *(const float2*)&Kg[(size_t)r*128 + c];
            float2 v1 = *(const float2*)&Kg[(size_t)(r+8)*128 + c];
            float2 v2 = *(const float2*)&Kg[(size_t)r*128 + c + 8];
            float2 v3 = *(const float2*)&Kg[(size_t)(r+8)*128 + c + 8];
            unsigned aH[4], aL[4]; float lx, ly;
            aH[0] = pack_hi_h(v0.x, v0.y, lx, ly); aL[0] = pack_h2(lx, ly);
            aH[1] = pack_hi_h(v1.x, v1.y, lx, ly); aL[1] = pack_h2(lx, ly);
            aH[2] = pack_hi_h(v2.x, v2.y, lx, ly); aL[2] = pack_h2(lx, ly);
            aH[3] = pack_hi_h(v3.x, v3.y, lx, ly); aL[3] = pack_h2(lx, ly);
            #pragma unroll
            for (int q = 0; q < 4; q++){
                unsigned bH[4];
                ldsm4t(bH[0],bH[1],bH[2],bH[3], Rb + boff[q] + k*16*IRS);
                mma16816h(P[2*q],   aH, bH);
                mma16816h(P[2*q+1], aH, bH+2);
                mma16816h(P[2*q],   aL, bH);
                mma16816h(P[2*q+1], aL, bH+2);
            }
        }
    };

    auto store_mat = [&](int slot, float (*F)[4]){
        #pragma unroll
        for (int half = 0; half < 2; half++){
            int r = m0 + g + half*8;
            #pragma unroll
            for (int j = 0; j < 8; j++){
                int c = nb + j*8 + tg*2;
                float x = F[j][half*2], y = F[j][half*2+1];
                float lx, ly;
                unsigned hp = pack_hi_h(x, y, lx, ly);
                unsigned lp = pack_h2(lx, ly);
                *(unsigned*)(ismem + slot*IMAT + r*IRS + c*2) = hp;
                *(unsigned*)(ismem + (slot+1)*IMAT + r*IRS + c*2) = lp;
            }
        }
    };

    for (int it = 0; it < 6; it++){
        mm_KV();
        #pragma unroll
        for (int j=0;j<8;j++)
            #pragma unroll
            for (int e=0;e<4;e++) Aa[j][e] = P[j][e];
        __syncthreads();
        store_mat(2, Aa);
        __syncthreads();

        mm_ss(2, 2);
        #pragma unroll
        for (int j=0;j<8;j++)
            #pragma unroll
            for (int e=0;e<4;e++) P[j][e] = 7.f*Aa[j][e] - P[j][e];
        __syncthreads();
        store_mat(4, P);
        __syncthreads();

        mm_ss(2, 4);
        #pragma unroll
        for (int j=0;j<8;j++)
            #pragma unroll
            for (int e=0;e<4;e++) P[j][e] = 15.f*Aa[j][e] - P[j][e];
        __syncthreads();
        store_mat(4, P);
        __syncthreads();

        mm_ss(0, 4);
        __syncthreads();
        #pragma unroll
        for (int half = 0; half < 2; half++){
            int r = m0 + g + half*8;
            #pragma unroll
            for (int j = 0; j < 8; j++){
                int c = nb + j*8 + tg*2;
                unsigned hp = *(unsigned*)(ismem + 0*IMAT + r*IRS + c*2);
                unsigned lp = *(unsigned*)(ismem + 1*IMAT + r*IRS + c*2);
                __half2 hb = *(__half2*)&hp;
                __half2 lb = *(__half2*)&lp;
                float vx = __half2float(__low2half(hb))  + __half2float(__low2half(lb));
                float vy = __half2float(__high2half(hb)) + __half2float(__high2half(lb));
                P[j][half*2]   = 3.25f*vx - 0.25f*P[j][half*2];
                P[j][half*2+1] = 3.25f*vy - 0.25f*P[j][half*2+1];
            }
        }
        store_mat(0, P);
        __syncthreads();
    }

    // W2 = V @ k3V
    {
        int i = tid >> 2, h0 = (tid & 3) * 16;
        const float* Ng = g_k3V + (size_t)bh*8192;
        for (int j = 0; j < 16; j++){
            float v = Ng[i*64 + h0 + j];
            *(__half*)(ismem + 2*IMAT + i*IRS + (h0+j)*2) = __float2half_rn(v);
        }
    }
    __syncthreads();
    {
        int nbW = nw * 32;
        unsigned boffW[2];
        #pragma unroll
        for (int q = 0; q < 2; q++)
            boffW[q] = (unsigned)(((t8&1)*8 + i8)*IRS + (nbW + q*16 + (t8>>1)*8)*2);

        float Pw[4][4];
        #pragma unroll
        for (int j=0;j<4;j++)
            #pragma unroll
            for (int e=0;e<4;e++) Pw[j][e] = 0.f;

        #pragma unroll
        for (int k = 0; k < 8; k++){
            unsigned aH[4], aL[4];
            ldsm4(aH[0],aH[1],aH[2],aH[3], smb + aoff + k*32);
            ldsm4(aL[0],aL[1],aL[2],aL[3], smb + IMAT + aoff + k*32);
            #pragma unroll
            for (int q = 0; q < 2; q++){
                unsigned bH[4];
                ldsm4t(bH[0],bH[1],bH[2],bH[3], smb + 2*IMAT + boffW[q] + k*16*IRS);
                mma16816h(Pw[2*q],   aH, bH);
                mma16816h(Pw[2*q+1], aH, bH+2);
                mma16816h(Pw[2*q],   aL, bH);
                mma16816h(Pw[2*q+1], aL, bH+2);
            }
        }
        float* Wg = g_W2 + (size_t)bh*8192;
        #pragma unroll
        for (int half = 0; half < 2; half++){
            int r = m0 + g + half*8;
            #pragma unroll
            for (int j = 0; j < 4; j++){
                int c = nbW + j*8 + tg*2;
                *(float2*)&Wg[r*64 + c] = make_float2(Pw[j][half*2], Pw[j][half*2+1]);
            }
        }
    }
}

// ---------------- k1 on HMMA: ctx = softmax(Q @ Kl^T) @ W2 (bf16 3-product) ----
#define KLRS 144
#define K1MAT 18432
#define K1_SMEM (4*K1MAT)

__global__ __launch_bounds__(256, 2)
void k1_kernel(){
    extern __shared__ __align__(16) char ksm[];
    const unsigned smb = smem_u32(ksm);
    const int sblk = blockIdx.x, bh = blockIdx.y;
    const int tid = threadIdx.x, lane = tid & 31, w = tid >> 5;
    const int g = lane >> 2, tg = lane & 3;
    const int i8 = lane & 7, t8 = lane >> 3;
    const int m0 = w * 16;

    const float* Klg = g_Kl + (size_t)bh*8192;
    const float* W2g = g_W2 + (size_t)bh*8192;
    for (int idx = tid; idx < 8192; idx += 256){
        int r = idx >> 6, c = idx & 63;
        float v = Klg[idx];
        __nv_bfloat16 hi = __float2bfloat16(v);
        __nv_bfloat16 lo = __float2bfloat16(v - __bfloat162float(hi));
        *(__nv_bfloat16*)(ksm + 0*K1MAT + r*KLRS + c*2) = hi;
        *(__nv_bfloat16*)(ksm + 1*K1MAT + r*KLRS + c*2) = lo;
        v = W2g[idx];
        hi = __float2bfloat16(v);
        lo = __float2bfloat16(v - __bfloat162float(hi));
        *(__nv_bfloat16*)(ksm + 2*K1MAT + r*KLRS + c*2) = hi;
        *(__nv_bfloat16*)(ksm + 3*K1MAT + r*KLRS + c*2) = lo;
    }
    __syncthreads();

    const float* Qg = g_Q + ((size_t)bh*S_ + sblk*128)*HD_;
    float st[16][4];
    #pragma unroll
    for (int nt=0;nt<16;nt++)
        #pragma unroll
        for (int e=0;e<4;e++) st[nt][e] = 0.f;

    #pragma unroll
    for (int kc = 0; kc < 4; kc++){
        int r = m0 + g, c = kc*16 + tg*2;
        float2 v0 = *(const float2*)&Qg[(size_t)r*64 + c];
        float2 v1 = *(const float2*)&Qg[(size_t)(r+8)*64 + c];
        float2 v2 = *(const float2*)&Qg[(size_t)r*64 + c + 8];
        float2 v3 = *(const float2*)&Qg[(size_t)(r+8)*64 + c + 8];
        unsigned aH[4], aL[4]; float lx, ly;
        aH[0] = pack_hi(v0.x, v0.y, lx, ly); aL[0] = pack_bf2(lx, ly);
        aH[1] = pack_hi(v1.x, v1.y, lx, ly); aL[1] = pack_bf2(lx, ly);
        aH[2] = pack_hi(v2.x, v2.y, lx, ly); aL[2] = pack_bf2(lx, ly);
        aH[3] = pack_hi(v3.x, v3.y, lx, ly); aL[3] = pack_bf2(lx, ly);
        #pragma unroll
        for (int q = 0; q < 8; q++){
            unsigned kOff = (unsigned)((q*16 + (t8>>1)*8 + i8)*KLRS + (t8&1)*16 + kc*32);
            unsigned bH[4], bL[4];
            ldsm4(bH[0],bH[1],bH[2],bH[3], smb + 0*K1MAT + kOff);
            ldsm4(bL[0],bL[1],bL[2],bL[3], smb + 1*K1MAT + kOff);
            mma16816(st[2*q],   aH, bH);
            mma16816(st[2*q+1], aH, bH+2);
            mma16816(st[2*q],   aL, bH);
            mma16816(st[2*q+1], aL, bH+2);
            mma16816(st[2*q],   aH, bL);
            mma16816(st[2*q+1], aH, bL+2);
        }
    }

    float mx0 = -1e30f, mx1 = -1e30f;
    #pragma unroll
    for (int nt = 0; nt < 16; nt++){
        mx0 = fmaxf(mx0, fmaxf(st[nt][0], st[nt][1]));
        mx1 = fmaxf(mx1, fmaxf(st[nt][2], st[nt][3]));
    }
    mx0 = fmaxf(mx0, __shfl_xor_sync(0xffffffffu, mx0, 1));
    mx0 = fmaxf(mx0, __shfl_xor_sync(0xffffffffu, mx0, 2));
    mx1 = fmaxf(mx1, __shfl_xor_sync(0xffffffffu, mx1, 1));
    mx1 = fmaxf(mx1, __shfl_xor_sync(0xffffffffu, mx1, 2));
    float z0 = 0.f, z1 = 0.f;
    #pragma unroll
    for (int nt = 0; nt < 16; nt++){
        st[nt][0] = __expf(st[nt][0] - mx0);
        st[nt][1] = __expf(st[nt][1] - mx0);
        st[nt][2] = __expf(st[nt][2] - mx1);
        st[nt][3] = __expf(st[nt][3] - mx1);
        z0 += st[nt][0] + st[nt][1];
        z1 += st[nt][2] + st[nt][3];
    }
    z0 += __shfl_xor_sync(0xffffffffu, z0, 1);
    z0 += __shfl_xor_sync(0xffffffffu, z0, 2);
    z1 += __shfl_xor_sync(0xffffffffu, z1, 1);
    z1 += __shfl_xor_sync(0xffffffffu, z1, 2);
    float zi0 = 1.f/z0, zi1 = 1.f/z1;
    #pragma unroll
    for (int nt = 0; nt < 16; nt++){
        st[nt][0] *= zi0; st[nt][1] *= zi0;
        st[nt][2] *= zi1; st[nt][3] *= zi1;
    }

    float o[8][4];
    #pragma unroll
    for (int j=0;j<8;j++)
        #pragma unroll
        for (int e=0;e<4;e++) o[j][e] = 0.f;

    #pragma unroll
    for (int kc = 0; kc < 8; kc++){
        unsigned aH[4], aL[4]; float lx, ly;
        aH[0] = pack_hi(st[2*kc][0],   st[2*kc][1],   lx, ly); aL[0] = pack_bf2(lx, ly);
        aH[1] = pack_hi(st[2*kc][2],   st[2*kc][3],   lx, ly); aL[1] = pack_bf2(lx, ly);
        aH[2] = pack_hi(st[2*kc+1][0], st[2*kc+1][1], lx, ly); aL[2] = pack_bf2(lx, ly);
        aH[3] = pack_hi(st[2*kc+1][2], st[2*kc+1][3], lx, ly); aL[3] = pack_bf2(lx, ly);
        #pragma unroll
        for (int q = 0; q < 4; q++){
            unsigned wOff = (unsigned)(((t8&1)*8 + i8 + kc*16)*KLRS + (q*16 + (t8>>1)*8)*2);
            unsigned bH[4], bL[4];
            ldsm4t(bH[0],bH[1],bH[2],bH[3], smb + 2*K1MAT + wOff);
            ldsm4t(bL[0],bL[1],bL[2],bL[3], smb + 3*K1MAT + wOff);
            mma16816(o[2*q],   aH, bH);
            mma16816(o[2*q+1], aH, bH+2);
            mma16816(o[2*q],   aL, bH);
            mma16816(o[2*q+1], aL, bH+2);
            mma16816(o[2*q],   aH, bL);
            mma16816(o[2*q+1], aH, bL+2);
        }
    }

    int b = bh >> 4, h = bh & 15;
    #pragma unroll
    for (int half = 0; half < 2; half++){
        int sI = sblk*128 + m0 + g + half*8;
        size_t obase = ((size_t)(b*S_ + sI))*D_ + h*64;
        #pragma unroll
        for (int nt = 0; nt < 8; nt++){
            int d = nt*8 + tg*2;
            __half hv[2] = {__float2half_rn(o[nt][half*2]), __float2half_rn(o[nt][half*2+1])};
            *(unsigned*)&g_ctxh[obase + d] = *(unsigned*)hv;
        }
    }
}

// ---------------- launch -------------------------------------------------------
extern "C" void kernel_launch(void* const* d_in, const int* in_sizes, int n_in,
                              void* d_out, int out_size)
{
    const float* X    = (const float*)d_in[0];
    const float* mask = (const float*)d_in[1];
    const float* Wq   = (const float*)d_in[2];
    const float* bq   = (const float*)d_in[3];
    const float* Wk   = (const float*)d_in[4];
    const float* bk   = (const float*)d_in[5];
    const float* Wv   = (const float*)d_in[6];
    const float* bv   = (const float*)d_in[7];
    const float* Wo   = (const float*)d_in[8];
    const float* bo   = (const float*)d_in[9];
    float* out = (float*)d_out;

    void *pQ, *pK, *pV;
    cudaGetSymbolAddress(&pQ, g_Q);
    cudaGetSymbolAddress(&pK, g_K);
    cudaGetSymbolAddress(&pV, g_V);

    cudaFuncSetAttribute(gemm_qkv, cudaFuncAttributeMaxDynamicSharedMemorySize, GSMEM);
    cudaFuncSetAttribute(gemm_out, cudaFuncAttributeMaxDynamicSharedMemorySize, GSMEM);
    cudaFuncSetAttribute(inv_kernel, cudaFuncAttributeMaxDynamicSharedMemorySize, INV_SMEM);
    cudaFuncSetAttribute(k1_kernel,  cudaFuncAttributeMaxDynamicSharedMemorySize, K1_SMEM);
    cudaFuncSetAttribute(k3_mma,     cudaFuncAttributeMaxDynamicSharedMemorySize, K3_SMEM);

    convX_kernel<<<8192, 256>>>(X);                       // 1
    convW_kernel<<<dim3(32,32,4), 256>>>(Wq, Wk, Wv, Wo); // 2
    probe_kernel<<<1, 32>>>();                            // 3
    gemm_qkv<<<dim3(24,64), 256, GSMEM>>>(bq, bk, bv, mask,
                                          (float*)pQ, (float*)pK, (float*)pV); // 4 <- ncu

    landmark_kernel<<<(BH_*NL_*HD_)/256, 256>>>();
    k2_kernel<<<dim3(NL_, BH_), 128>>>();
    colmax_kernel<<<BH_, 128>>>();
    k3_mma<<<dim3(8, BH_), 256, K3_SMEM>>>(mask);
    k3_combine<<<BH_, 128>>>();
    inv_kernel<<<BH_, 512, INV_SMEM>>>();
    k1_kernel<<<dim3(32, BH_), 256, K1_SMEM>>>();

    gemm_out<<<dim3(8,64), 256, GSMEM>>>(bo, out);
}

// round 17
// speedup vs baseline: 10.5342x; 1.0412x over previous
#include <cuda_runtime.h>
#include <cuda_bf16.h>
#include <cuda_fp16.h>

// Problem constants
#define B_  2
#define S_  4096
#define HID_ 1024
#define NH_ 16
#define HD_ 64
#define NL_ 128
#define BH_ (B_*NH_)          // 32
#define SEG_ (S_/NL_)         // 32
#define D_ (NH_*HD_)          // 1024
#define SCALE_ 0.35355339059327373f  // HD^-0.25

// ---------------- device scratch -----------------------------------------------
__device__ float g_Q[B_*NH_*S_*HD_];     // (b,h,s,d) scaled+masked
__device__ float g_K[B_*NH_*S_*HD_];
__device__ float g_V[B_*NH_*S_*HD_];
__device__ float g_Ql[BH_*NL_*HD_];
__device__ float g_Kl[BH_*NL_*HD_];
__device__ float g_k2[BH_*NL_*NL_];
__device__ float g_bhmax[BH_];
__device__ float g_k3V[BH_*NL_*HD_];
__device__ float g_W2[BH_*NL_*HD_];
__device__ float g_k3o[BH_*8*NL_*HD_];   // split-K partials
__device__ float g_k3mz[BH_*8*NL_*2];
__device__ __align__(256) __half g_Xh[8192*1024];
__device__ __align__(256) __half g_Wth[4*1024*1024];   // [4][n][k] q,k,v,o (fp16)
__device__ __align__(256) __half g_ctxh[8192*1024];

__device__ __forceinline__ unsigned smem_u32(const void* p){
    unsigned a;
    asm("{ .reg .u64 t; cvta.to.shared.u64 t, %1; cvt.u32.u64 %0, t; }" : "=r"(a) : "l"(p));
    return a;
}
__device__ __forceinline__ void ldsm4(unsigned& r0, unsigned& r1, unsigned& r2, unsigned& r3,
                                      unsigned addr){
    asm volatile("ldmatrix.sync.aligned.m8n8.x4.shared.b16 {%0,%1,%2,%3}, [%4];"
        : "=r"(r0), "=r"(r1), "=r"(r2), "=r"(r3) : "r"(addr));
}
__device__ __forceinline__ void ldsm4t(unsigned& r0, unsigned& r1, unsigned& r2, unsigned& r3,
                                       unsigned addr){
    asm volatile("ldmatrix.sync.aligned.m8n8.x4.trans.shared.b16 {%0,%1,%2,%3}, [%4];"
        : "=r"(r0), "=r"(r1), "=r"(r2), "=r"(r3) : "r"(addr));
}
// fp16 mma (all tensor kernels now)
__device__ __forceinline__ void mma16816h(float* c, const unsigned* a, const unsigned* b){
    asm volatile(
        "mma.sync.aligned.m16n8k16.row.col.f32.f16.f16.f32 "
        "{%0,%1,%2,%3}, {%4,%5,%6,%7}, {%8,%9}, {%0,%1,%2,%3};"
        : "+f"(c[0]), "+f"(c[1]), "+f"(c[2]), "+f"(c[3])
        : "r"(a[0]), "r"(a[1]), "r"(a[2]), "r"(a[3]), "r"(b[0]), "r"(b[1]));
}
__device__ __forceinline__ unsigned pack_hi_h(float x, float y, float& lx, float& ly){
    __half2 h = __floats2half2_rn(x, y);
    lx = x - __half2float(__low2half(h));
    ly = y - __half2float(__high2half(h));
    return *(unsigned*)&h;
}
__device__ __forceinline__ unsigned pack_h2(float x, float y){
    __half2 h = __floats2half2_rn(x, y);
    return *(unsigned*)&h;
}
__device__ __forceinline__ void cp16(unsigned dst, const void* src){
    asm volatile("cp.async.cg.shared.global [%0], [%1], 16;" :: "r"(dst), "l"(src));
}
__device__ __forceinline__ void cpcommit(){ asm volatile("cp.async.commit_group;" ::: "memory"); }
template<int N> __device__ __forceinline__ void cpwait(){
    asm volatile("cp.async.wait_group %0;" :: "n"(N) : "memory");
}

// ---------------- probe (keeps gemm_qkv in the profiled 4th slot) --------------
__global__ void probe_kernel(){
    if (threadIdx.x < BH_) g_bhmax[threadIdx.x] = 0.f;
}

// ---------------- prep: X -> fp16 ----------------------------------------------
__global__ void convX_kernel(const float* __restrict__ X){
    size_t i4 = (size_t)blockIdx.x * blockDim.x + threadIdx.x;
    float4 v = ((const float4*)X)[i4];
    __half h[4] = {__float2half_rn(v.x), __float2half_rn(v.y),
                   __float2half_rn(v.z), __float2half_rn(v.w)};
    *(uint2*)&g_Xh[i4*4] = *(uint2*)h;
}

// ---------------- prep: transpose weights -> [n][k] fp16 -----------------------
__global__ void convW_kernel(const float* __restrict__ Wq, const float* __restrict__ Wk,
                             const float* __restrict__ Wv, const float* __restrict__ Wo){
    __shared__ float t[32][33];
    int z = blockIdx.z;
    const float* W = (z==0) ? Wq : (z==1) ? Wk : (z==2) ? Wv : Wo;
    int n0 = blockIdx.x * 32, k0 = blockIdx.y * 32;
    int tx = threadIdx.x & 31, ty = threadIdx.x >> 5;
    #pragma unroll
    for (int r = 0; r < 4; r++){
        int ky = ty + r*8;
        t[ky][tx] = W[(size_t)(k0 + ky)*1024 + n0 + tx];
    }
    __syncthreads();
    #pragma unroll
    for (int r = 0; r < 4; r++){
        int ny = ty + r*8;
        size_t o = (size_t)z*1048576 + (size_t)(n0 + ny)*1024 + k0 + tx;
        g_Wth[o] = __float2half_rn(t[tx][ny]);
    }
}

// ================= fp16 HMMA GEMM mainloop (unchanged from R16) ================
#define ROWBY 80
#define TILEB (128*ROWBY)
#define STAGEB (2*TILEB)      // 20480
#define GSMEM (3*STAGEB)      // 61440

__device__ __forceinline__ void gemm_main(
    const __half* __restrict__ Ah, const __half* __restrict__ Bh,
    unsigned smb, float acc[2][8][4])
{
    const int tid = threadIdx.x, lane = tid & 31, w = tid >> 5;
    const int wr = w & 3, wc = w >> 2;

    unsigned aoff[2], boff[4];
    {
        int i = lane & 7, t8 = lane >> 3;
        #pragma unroll
        for (int t = 0; t < 2; t++)
            aoff[t] = (unsigned)((wr*32 + t*16 + (t8 & 1)*8 + i) * ROWBY + (t8 >> 1) * 16);
        #pragma unroll
        for (int q = 0; q < 4; q++)
            boff[q] = (unsigned)((wc*64 + q*16 + (t8 >> 1)*8 + i) * ROWBY + (t8 & 1) * 16);
    }

    auto issue = [&](int buf, int k0){
        #pragma unroll
        for (int r = 0; r < 4; r++){
            int idx = r*256 + tid;
            int c = idx & 3, row = (idx >> 2) & 127, tile = idx >> 9;
            const __half* src =
                (tile == 0) ? Ah + (size_t)row*1024 + k0 + c*8 :
                              Bh + (size_t)row*1024 + k0 + c*8;
            cp16(smb + buf*STAGEB + tile*TILEB + row*ROWBY + c*16, src);
        }
        cpcommit();
    };

    issue(0, 0);
    issue(1, 32);
    for (int s = 0; s < 32; s++){
        cpwait<1>();
        __syncthreads();
        if (s < 30) issue((s+2) % 3, (s+2)*32);

        unsigned base = smb + (s % 3)*STAGEB;
        #pragma unroll
        for (int kb = 0; kb < 2; kb++){
            unsigned ko = kb * 32;
            unsigned aH[2][4], bX[4][4];
            #pragma unroll
            for (int t = 0; t < 2; t++)
                ldsm4(aH[t][0], aH[t][1], aH[t][2], aH[t][3], base + aoff[t] + ko);
            #pragma unroll
            for (int q = 0; q < 4; q++)
                ldsm4(bX[q][0], bX[q][1], bX[q][2], bX[q][3], base + TILEB + boff[q] + ko);
            #pragma unroll
            for (int t = 0; t < 2; t++)
                #pragma unroll
                for (int q = 0; q < 4; q++){
                    mma16816h(acc[t][2*q],   aH[t], &bX[q][0]);
                    mma16816h(acc[t][2*q+1], aH[t], &bX[q][2]);
                }
        }
        __syncthreads();
    }
}

__global__ __launch_bounds__(256, 2)
void gemm_qkv(const float* __restrict__ bq, const float* __restrict__ bk,
              const float* __restrict__ bv, const float* __restrict__ mask,
              float* __restrict__ oq, float* __restrict__ okk, float* __restrict__ ov)
{
    extern __shared__ __align__(16) char smem[];
    unsigned smb = smem_u32(smem);
    int wsel = blockIdx.x >> 3, colt = blockIdx.x & 7;
    const __half* Ah = g_Xh + (size_t)blockIdx.y*128*1024;
    const __half* Bh = g_Wth + ((size_t)wsel*1024 + colt*128)*1024;

    float acc[2][8][4];
    #pragma unroll
    for (int t=0;t<2;t++)
        #pragma unroll
        for (int j=0;j<8;j++)
            #pragma unroll
            for (int e=0;e<4;e++) acc[t][j][e] = 0.f;

    gemm_main(Ah, Bh, smb, acc);

    const float* bias = (wsel==0) ? bq : (wsel==1) ? bk : bv;
    float* out = (wsel==0) ? oq : (wsel==1) ? okk : ov;
    const bool scaled = (wsel < 2);

    int lane = threadIdx.x & 31, w = threadIdx.x >> 5;
    int wr = w & 3, wc = w >> 2;
    int g = lane >> 2, tg = lane & 3;
    #pragma unroll
    for (int t = 0; t < 2; t++){
        #pragma unroll
        for (int half = 0; half < 2; half++){
            int row = blockIdx.y*128 + wr*32 + t*16 + g + half*8;
            float rs = scaled ? SCALE_ * mask[row] : 1.0f;
            int bb = row >> 12, sI = row & 4095;
            #pragma unroll
            for (int j = 0; j < 8; j++){
                int col = colt*128 + wc*64 + j*8 + tg*2;
                float c0 = (acc[t][j][half*2]   + bias[col])   * rs;
                float c1 = (acc[t][j][half*2+1] + bias[col+1]) * rs;
                int h = col >> 6, d = col & 63;
                *(float2*)(out + ((size_t)(bb*NH_ + h)*S_ + sI)*HD_ + d) = make_float2(c0, c1);
            }
        }
    }
}

__global__ __launch_bounds__(256, 2)
void gemm_out(const float* __restrict__ bias, float* __restrict__ out)
{
    extern __shared__ __align__(16) char smem[];
    unsigned smb = smem_u32(smem);
    const __half* Ah = g_ctxh + (size_t)blockIdx.y*128*1024;
    const __half* Bh = g_Wth + (size_t)3*1048576 + (size_t)blockIdx.x*128*1024;

    float acc[2][8][4];
    #pragma unroll
    for (int t=0;t<2;t++)
        #pragma unroll
        for (int j=0;j<8;j++)
            #pragma unroll
            for (int e=0;e<4;e++) acc[t][j][e] = 0.f;

    gemm_main(Ah, Bh, smb, acc);

    int lane = threadIdx.x & 31, w = threadIdx.x >> 5;
    int wr = w & 3, wc = w >> 2;
    int g = lane >> 2, tg = lane & 3;
    #pragma unroll
    for (int t = 0; t < 2; t++){
        #pragma unroll
        for (int half = 0; half < 2; half++){
            int row = blockIdx.y*128 + wr*32 + t*16 + g + half*8;
            #pragma unroll
            for (int j = 0; j < 8; j++){
                int col = blockIdx.x*128 + wc*64 + j*8 + tg*2;
                float c0 = acc[t][j][half*2]   + bias[col];
                float c1 = acc[t][j][half*2+1] + bias[col+1];
                *(float2*)(out + (size_t)row*1024 + col) = make_float2(c0, c1);
            }
        }
    }
}

// ---------------- landmarks ----------------------------------------------------
__global__ void landmark_kernel(){
    int idx = blockIdx.x*blockDim.x + threadIdx.x;
    int d  = idx & 63;
    int l  = (idx >> 6) & 127;
    int bh = idx >> 13;
    const float* q = g_Q + ((size_t)bh*S_ + l*SEG_)*HD_ + d;
    const float* k = g_K + ((size_t)bh*S_ + l*SEG_)*HD_ + d;
    float sq = 0.f, sk = 0.f;
    #pragma unroll
    for (int j=0; j<SEG_; j++){ sq += q[j*HD_]; sk += k[j*HD_]; }
    g_Ql[idx] = sq * (1.f/SEG_);
    g_Kl[idx] = sk * (1.f/SEG_);
}

// ---------------- k2 = softmax(Ql @ Kl^T) --------------------------------------
__global__ void k2_kernel(){
    int l = blockIdx.x, bh = blockIdx.y, m = threadIdx.x;
    const float4* ql = (const float4*)(g_Ql + ((size_t)bh*NL_ + l)*HD_);
    const float4* kl = (const float4*)(g_Kl + ((size_t)bh*NL_ + m)*HD_);
    float acc = 0.f;
    #pragma unroll
    for (int d4=0; d4<16; d4++){
        float4 a = ql[d4], b = kl[d4];
        acc += a.x*b.x + a.y*b.y + a.z*b.z + a.w*b.w;
    }
    __shared__ float red[128];
    red[m] = acc; __syncthreads();
    for (int off=64; off>0; off>>=1){
        if (m < off) red[m] = fmaxf(red[m], red[m+off]);
        __syncthreads();
    }
    float mx = red[0]; __syncthreads();
    float p = __expf(acc - mx);
    red[m] = p; __syncthreads();
    for (int off=64; off>0; off>>=1){
        if (m < off) red[m] += red[m+off];
        __syncthreads();
    }
    g_k2[((size_t)bh*NL_ + l)*NL_ + m] = p / red[0];
}

// ---------------- column sums of k2 -> per-bh max ------------------------------
__global__ void colmax_kernel(){
    int bh = blockIdx.x, m = threadIdx.x;
    float s = 0.f;
    for (int l=0; l<NL_; l++) s += g_k2[((size_t)bh*NL_ + l)*NL_ + m];
    __shared__ float red[128];
    red[m] = s; __syncthreads();
    for (int off=64; off>0; off>>=1){
        if (m < off) red[m] = fmaxf(red[m], red[m+off]);
        __syncthreads();
    }
    if (m == 0) g_bhmax[bh] = red[0];
}

// ---------------- k3 on HMMA: flash split-K, fp16 2-product --------------------
// smem slots: 0 QlH, 1 QlL (fp16 hi/lo), 2 K (fp16), 3 V (fp16) + mask
#define K3RS  144
#define K3MAT 18432
#define K3_SMEM (4*K3MAT + 512)   // 74240 -> 2 CTAs/SM

__global__ __launch_bounds__(256, 2)
void k3_mma(const float* __restrict__ mask){
    extern __shared__ __align__(16) char ksm[];
    const unsigned smb = smem_u32(ksm);
    const int chunk = blockIdx.x, bh = blockIdx.y;
    const int tid = threadIdx.x, lane = tid & 31, w = tid >> 5;
    const int g = lane >> 2, tg = lane & 3;
    const int i8 = lane & 7, t8 = lane >> 3;
    const int m0 = w * 16;
    float* msk = (float*)(ksm + 4*K3MAT);

    const float* Qlg = g_Ql + (size_t)bh*8192;
    for (int idx = tid; idx < 8192; idx += 256){
        int r = idx >> 6, c = idx & 63;
        float v = Qlg[idx];
        __half hi = __float2half_rn(v);
        __half lo = __float2half_rn(v - __half2float(hi));
        *(__half*)(ksm + 0*K3MAT + r*K3RS + c*2) = hi;
        *(__half*)(ksm + 1*K3MAT + r*K3RS + c*2) = lo;
    }

    const float* Kbh = g_K + (size_t)bh*S_*HD_;
    const float* Vbh = g_V + (size_t)bh*S_*HD_;
    const float* mrow = mask + (size_t)(bh >> 4)*S_;

    const unsigned aoff = (unsigned)((m0 + (t8&1)*8 + i8)*K3RS + (t8>>1)*16);

    float mr0 = -1e30f, mr1 = -1e30f, z0 = 0.f, z1 = 0.f;
    float o[8][4];
    #pragma unroll
    for (int j=0;j<8;j++)
        #pragma unroll
        for (int e=0;e<4;e++) o[j][e] = 0.f;

    for (int it = 0; it < 4; it++){
        int sbase = chunk*512 + it*128;
        __syncthreads();
        for (int idx = tid; idx < 8192; idx += 256){
            int r = idx >> 6, c = idx & 63;
            *(__half*)(ksm + 2*K3MAT + r*K3RS + c*2) =
                __float2half_rn(Kbh[(size_t)(sbase + r)*HD_ + c]);
            *(__half*)(ksm + 3*K3MAT + r*K3RS + c*2) =
                __float2half_rn(Vbh[(size_t)(sbase + r)*HD_ + c]);
        }
        if (tid < 128) msk[tid] = mrow[sbase + tid];
        __syncthreads();

        float st[16][4];
        #pragma unroll
        for (int nt=0;nt<16;nt++)
            #pragma unroll
            for (int e=0;e<4;e++) st[nt][e] = 0.f;

        #pragma unroll
        for (int kc = 0; kc < 4; kc++){
            unsigned aH[4], aL[4];
            ldsm4(aH[0],aH[1],aH[2],aH[3], smb + 0*K3MAT + aoff + kc*32);
            ldsm4(aL[0],aL[1],aL[2],aL[3], smb + 1*K3MAT + aoff + kc*32);
            #pragma unroll
            for (int q = 0; q < 8; q++){
                unsigned kOff = (unsigned)((q*16 + (t8>>1)*8 + i8)*K3RS + (t8&1)*16 + kc*32);
                unsigned bH[4];
                ldsm4(bH[0],bH[1],bH[2],bH[3], smb + 2*K3MAT + kOff);
                mma16816h(st[2*q],   aH, bH);
                mma16816h(st[2*q+1], aH, bH+2);
                mma16816h(st[2*q],   aL, bH);
                mma16816h(st[2*q+1], aL, bH+2);
            }
        }

        #pragma unroll
        for (int nt = 0; nt < 16; nt++){
            int c0 = nt*8 + tg*2;
            float p0 = -1e9f*(1.f - msk[c0]);
            float p1 = -1e9f*(1.f - msk[c0+1]);
            st[nt][0] += p0; st[nt][1] += p1;
            st[nt][2] += p0; st[nt][3] += p1;
        }

        float cm0 = -1e30f, cm1 = -1e30f;
        #pragma unroll
        for (int nt = 0; nt < 16; nt++){
            cm0 = fmaxf(cm0, fmaxf(st[nt][0], st[nt][1]));
            cm1 = fmaxf(cm1, fmaxf(st[nt][2], st[nt][3]));
        }
        cm0 = fmaxf(cm0, __shfl_xor_sync(0xffffffffu, cm0, 1));
        cm0 = fmaxf(cm0, __shfl_xor_sync(0xffffffffu, cm0, 2));
        cm1 = fmaxf(cm1, __shfl_xor_sync(0xffffffffu, cm1, 1));
        cm1 = fmaxf(cm1, __shfl_xor_sync(0xffffffffu, cm1, 2));
        float mn0 = fmaxf(mr0, cm0), mn1 = fmaxf(mr1, cm1);
        float cr0 = __expf(mr0 - mn0), cr1 = __expf(mr1 - mn1);
        mr0 = mn0; mr1 = mn1;
        z0 *= cr0; z1 *= cr1;
        #pragma unroll
        for (int j = 0; j < 8; j++){
            o[j][0] *= cr0; o[j][1] *= cr0;
            o[j][2] *= cr1; o[j][3] *= cr1;
        }
        float ps0 = 0.f, ps1 = 0.f;
        #pragma unroll
        for (int nt = 0; nt < 16; nt++){
            st[nt][0] = __expf(st[nt][0] - mn0);
            st[nt][1] = __expf(st[nt][1] - mn0);
            st[nt][2] = __expf(st[nt][2] - mn1);
            st[nt][3] = __expf(st[nt][3] - mn1);
            ps0 += st[nt][0] + st[nt][1];
            ps1 += st[nt][2] + st[nt][3];
        }
        ps0 += __shfl_xor_sync(0xffffffffu, ps0, 1);
        ps0 += __shfl_xor_sync(0xffffffffu, ps0, 2);
        ps1 += __shfl_xor_sync(0xffffffffu, ps1, 1);
        ps1 += __shfl_xor_sync(0xffffffffu, ps1, 2);
        z0 += ps0; z1 += ps1;

        // o += P @ V : P split fp16 (exact), V single fp16
        #pragma unroll
        for (int kc = 0; kc < 8; kc++){
            unsigned aH[4], aL[4]; float lx, ly;
            aH[0] = pack_hi_h(st[2*kc][0],   st[2*kc][1],   lx, ly); aL[0] = pack_h2(lx, ly);
            aH[1] = pack_hi_h(st[2*kc][2],   st[2*kc][3],   lx, ly); aL[1] = pack_h2(lx, ly);
            aH[2] = pack_hi_h(st[2*kc+1][0], st[2*kc+1][1], lx, ly); aL[2] = pack_h2(lx, ly);
            aH[3] = pack_hi_h(st[2*kc+1][2], st[2*kc+1][3], lx, ly); aL[3] = pack_h2(lx, ly);
            #pragma unroll
            for (int q = 0; q < 4; q++){
                unsigned wOff = (unsigned)(((t8&1)*8 + i8 + kc*16)*K3RS + (q*16 + (t8>>1)*8)*2);
                unsigned bH[4];
                ldsm4t(bH[0],bH[1],bH[2],bH[3], smb + 3*K3MAT + wOff);
                mma16816h(o[2*q],   aH, bH);
                mma16816h(o[2*q+1], aH, bH+2);
                mma16816h(o[2*q],   aL, bH);
                mma16816h(o[2*q+1], aL, bH+2);
            }
        }
    }

    size_t pbase = ((size_t)(bh*8 + chunk))*128;
    #pragma unroll
    for (int j = 0; j < 8; j++){
        int c = j*8 + tg*2;
        *(float2*)&g_k3o[(pbase + m0 + g)*64 + c]     = make_float2(o[j][0], o[j][1]);
        *(float2*)&g_k3o[(pbase + m0 + g + 8)*64 + c] = make_float2(o[j][2], o[j][3]);
    }
    if (tg == 0){
        g_k3mz[(pbase + m0 + g)*2]       = mr0;
        g_k3mz[(pbase + m0 + g)*2 + 1]   = z0;
        g_k3mz[(pbase + m0 + g + 8)*2]     = mr1;
        g_k3mz[(pbase + m0 + g + 8)*2 + 1] = z1;
    }
}

__global__ void k3_combine(){
    int bh = blockIdx.x, l = threadIdx.x;   // 128 threads
    float m[8], z[8], M = -1e30f;
    #pragma unroll
    for (int c = 0; c < 8; c++){
        m[c] = g_k3mz[((size_t)(bh*8 + c)*128 + l)*2];
        z[c] = g_k3mz[((size_t)(bh*8 + c)*128 + l)*2 + 1];
        M = fmaxf(M, m[c]);
    }
    float coef[8], Z = 0.f;
    #pragma unroll
    for (int c = 0; c < 8; c++){
        coef[c] = __expf(m[c] - M);
        Z += z[c]*coef[c];
    }
    float Zi = 1.f / Z;
    #pragma unroll
    for (int d4 = 0; d4 < 16; d4++){
        float4 acc = make_float4(0.f, 0.f, 0.f, 0.f);
        #pragma unroll
        for (int c = 0; c < 8; c++){
            float4 ov = *(const float4*)&g_k3o[((size_t)(bh*8 + c)*128 + l)*64 + d4*4];
            acc.x += coef[c]*ov.x; acc.y += coef[c]*ov.y;
            acc.z += coef[c]*ov.z; acc.w += coef[c]*ov.w;
        }
        acc.x *= Zi; acc.y *= Zi; acc.z *= Zi; acc.w *= Zi;
        *(float4*)&g_k3V[(size_t)bh*8192 + l*64 + d4*4] = acc;
    }
}

// ---------------- Newton inverse on HMMA: fp16 2-product (unchanged) -----------
#define IRS  272
#define IMAT 34816
#define INV_SMEM (6*IMAT)

__global__ __launch_bounds__(512, 1)
void inv_kernel(){
    extern __shared__ __align__(16) char ismem[];
    const unsigned smb = smem_u32(ismem);
    const int bh = blockIdx.x, tid = threadIdx.x;
    const int lane = tid & 31, w = tid >> 5;
    const int mw = w & 7, nw = w >> 3;
    const int m0 = mw*16, nb = nw*64;
    const int g = lane >> 2, tg = lane & 3;
    const int i8 = lane & 7, t8 = lane >> 3;

    float cmax = g_bhmax[0];
    #pragma unroll
    for (int q=1; q<BH_; q++) cmax = fmaxf(cmax, g_bhmax[q]);
    const float rinv = 1.f / cmax;
    const float* Kg = g_k2 + (size_t)bh*NL_*NL_;

    {
        int i = tid >> 2, h0 = (tid & 3) * 32;
        for (int j = 0; j < 32; j++){
            float v = Kg[(h0 + j)*128 + i] * rinv;
            __half hi = __float2half_rn(v);
            __half lo = __float2half_rn(v - __half2float(hi));
            *(__half*)(ismem + 0*IMAT + i*IRS + (h0+j)*2) = hi;
            *(__half*)(ismem + 1*IMAT + i*IRS + (h0+j)*2) = lo;
        }
    }
    __syncthreads();

    unsigned aoff = (unsigned)((m0 + (t8&1)*8 + i8)*IRS + (t8>>1)*16);
    unsigned boff[4];
    #pragma unroll
    for (int q = 0; q < 4; q++)
        boff[q] = (unsigned)(((t8&1)*8 + i8)*IRS + (nb + q*16 + (t8>>1)*8)*2);

    float P[8][4], Aa[8][4];

    auto mm_ss = [&](int Lh, int Rh){
        #pragma unroll
        for (int j=0;j<8;j++)
            #pragma unroll
            for (int e=0;e<4;e++) P[j][e] = 0.f;
        unsigned Lb = smb + (unsigned)Lh*IMAT;
        unsigned Rb = smb + (unsigned)Rh*IMAT;
        #pragma unroll
        for (int k = 0; k < 8; k++){
            unsigned aH[4], aL[4];
            ldsm4(aH[0],aH[1],aH[2],aH[3], Lb + aoff + k*32);
            ldsm4(aL[0],aL[1],aL[2],aL[3], Lb + IMAT + aoff + k*32);
            #pragma unroll
            for (int q = 0; q < 4; q++){
                unsigned bH[4];
                ldsm4t(bH[0],bH[1],bH[2],bH[3], Rb + boff[q] + k*16*IRS);
                mma16816h(P[2*q],   aH, bH);
                mma16816h(P[2*q+1], aH, bH+2);
                mma16816h(P[2*q],   aL, bH);
                mma16816h(P[2*q+1], aL, bH+2);
            }
        }
    };

    auto mm_KV = [&](){
        #pragma unroll
        for (int j=0;j<8;j++)
            #pragma unroll
            for (int e=0;e<4;e++) P[j][e] = 0.f;
        unsigned Rb = smb;
        #pragma unroll
        for (int k = 0; k < 8; k++){
            int k0 = k*16;
            int r = m0 + g, c = k0 + tg*2;
            float2 v0 = *(const float2*)&Kg[(size_t)r*128 + c];
            float2 v1 = *(const float2*)&Kg[(size_t)(r+8)*128 + c];
            float2 v2 = *(const float2*)&Kg[(size_t)r*128 + c + 8];
            float2 v3 = *(const float2*)&Kg[(size_t)(r+8)*128 + c + 8];
            unsigned aH[4], aL[4]; float lx, ly;
            aH[0] = pack_hi_h(v0.x, v0.y, lx, ly); aL[0] = pack_h2(lx, ly);
            aH[1] = pack_hi_h(v1.x, v1.y, lx, ly); aL[1] = pack_h2(lx, ly);
            aH[2] = pack_hi_h(v2.x, v2.y, lx, ly); aL[2] = pack_h2(lx, ly);
            aH[3] = pack_hi_h(v3.x, v3.y, lx, ly); aL[3] = pack_h2(lx, ly);
            #pragma unroll
            for (int q = 0; q < 4; q++){
                unsigned bH[4];
                ldsm4t(bH[0],bH[1],bH[2],bH[3], Rb + boff[q] + k*16*IRS);
                mma16816h(P[2*q],   aH, bH);
                mma16816h(P[2*q+1], aH, bH+2);
                mma16816h(P[2*q],   aL, bH);
                mma16816h(P[2*q+1], aL, bH+2);
            }
        }
    };

    auto store_mat = [&](int slot, float (*F)[4]){
        #pragma unroll
        for (int half = 0; half < 2; half++){
            int r = m0 + g + half*8;
            #pragma unroll
            for (int j = 0; j < 8; j++){
                int c = nb + j*8 + tg*2;
                float x = F[j][half*2], y = F[j][half*2+1];
                float lx, ly;
                unsigned hp = pack_hi_h(x, y, lx, ly);
                unsigned lp = pack_h2(lx, ly);
                *(unsigned*)(ismem + slot*IMAT + r*IRS + c*2) = hp;
                *(unsigned*)(ismem + (slot+1)*IMAT + r*IRS + c*2) = lp;
            }
        }
    };

    for (int it = 0; it < 6; it++){
        mm_KV();
        #pragma unroll
        for (int j=0;j<8;j++)
            #pragma unroll
            for (int e=0;e<4;e++) Aa[j][e] = P[j][e];
        __syncthreads();
        store_mat(2, Aa);
        __syncthreads();

        mm_ss(2, 2);
        #pragma unroll
        for (int j=0;j<8;j++)
            #pragma unroll
            for (int e=0;e<4;e++) P[j][e] = 7.f*Aa[j][e] - P[j][e];
        __syncthreads();
        store_mat(4, P);
        __syncthreads();

        mm_ss(2, 4);
        #pragma unroll
        for (int j=0;j<8;j++)
            #pragma unroll
            for (int e=0;e<4;e++) P[j][e] = 15.f*Aa[j][e] - P[j][e];
        __syncthreads();
        store_mat(4, P);
        __syncthreads();

        mm_ss(0, 4);
        __syncthreads();
        #pragma unroll
        for (int half = 0; half < 2; half++){
            int r = m0 + g + half*8;
            #pragma unroll
            for (int j = 0; j < 8; j++){
                int c = nb + j*8 + tg*2;
                unsigned hp = *(unsigned*)(ismem + 0*IMAT + r*IRS + c*2);
                unsigned lp = *(unsigned*)(ismem + 1*IMAT + r*IRS + c*2);
                __half2 hb = *(__half2*)&hp;
                __half2 lb = *(__half2*)&lp;
                float vx = __half2float(__low2half(hb))  + __half2float(__low2half(lb));
                float vy = __half2float(__high2half(hb)) + __half2float(__high2half(lb));
                P[j][half*2]   = 3.25f*vx - 0.25f*P[j][half*2];
                P[j][half*2+1] = 3.25f*vy - 0.25f*P[j][half*2+1];
            }
        }
        store_mat(0, P);
        __syncthreads();
    }

    {
        int i = tid >> 2, h0 = (tid & 3) * 16;
        const float* Ng = g_k3V + (size_t)bh*8192;
        for (int j = 0; j < 16; j++){
            float v = Ng[i*64 + h0 + j];
            *(__half*)(ismem + 2*IMAT + i*IRS + (h0+j)*2) = __float2half_rn(v);
        }
    }
    __syncthreads();
    {
        int nbW = nw * 32;
        unsigned boffW[2];
        #pragma unroll
        for (int q = 0; q < 2; q++)
            boffW[q] = (unsigned)(((t8&1)*8 + i8)*IRS + (nbW + q*16 + (t8>>1)*8)*2);

        float Pw[4][4];
        #pragma unroll
        for (int j=0;j<4;j++)
            #pragma unroll
            for (int e=0;e<4;e++) Pw[j][e] = 0.f;

        #pragma unroll
        for (int k = 0; k < 8; k++){
            unsigned aH[4], aL[4];
            ldsm4(aH[0],aH[1],aH[2],aH[3], smb + aoff + k*32);
            ldsm4(aL[0],aL[1],aL[2],aL[3], smb + IMAT + aoff + k*32);
            #pragma unroll
            for (int q = 0; q < 2; q++){
                unsigned bH[4];
                ldsm4t(bH[0],bH[1],bH[2],bH[3], smb + 2*IMAT + boffW[q] + k*16*IRS);
                mma16816h(Pw[2*q],   aH, bH);
                mma16816h(Pw[2*q+1], aH, bH+2);
                mma16816h(Pw[2*q],   aL, bH);
                mma16816h(Pw[2*q+1], aL, bH+2);
            }
        }
        float* Wg = g_W2 + (size_t)bh*8192;
        #pragma unroll
        for (int half = 0; half < 2; half++){
            int r = m0 + g + half*8;
            #pragma unroll
            for (int j = 0; j < 4; j++){
                int c = nbW + j*8 + tg*2;
                *(float2*)&Wg[r*64 + c] = make_float2(Pw[j][half*2], Pw[j][half*2+1]);
            }
        }
    }
}

// ---------------- k1 on HMMA: fp16 2-product -----------------------------------
// smem: slot0 = Kl fp16, slot1 = W2 fp16
#define KLRS 144
#define K1MAT 18432
#define K1_SMEM (2*K1MAT)   // 36864

__global__ __launch_bounds__(256, 4)
void k1_kernel(){
    extern __shared__ __align__(16) char ksm[];
    const unsigned smb = smem_u32(ksm);
    const int sblk = blockIdx.x, bh = blockIdx.y;
    const int tid = threadIdx.x, lane = tid & 31, w = tid >> 5;
    const int g = lane >> 2, tg = lane & 3;
    const int i8 = lane & 7, t8 = lane >> 3;
    const int m0 = w * 16;

    const float* Klg = g_Kl + (size_t)bh*8192;
    const float* W2g = g_W2 + (size_t)bh*8192;
    for (int idx = tid; idx < 8192; idx += 256){
        int r = idx >> 6, c = idx & 63;
        *(__half*)(ksm + 0*K1MAT + r*KLRS + c*2) = __float2half_rn(Klg[idx]);
        *(__half*)(ksm + 1*K1MAT + r*KLRS + c*2) = __float2half_rn(W2g[idx]);
    }
    __syncthreads();

    const float* Qg = g_Q + ((size_t)bh*S_ + sblk*128)*HD_;
    float st[16][4];
    #pragma unroll
    for (int nt=0;nt<16;nt++)
        #pragma unroll
        for (int e=0;e<4;e++) st[nt][e] = 0.f;

    #pragma unroll
    for (int kc = 0; kc < 4; kc++){
        int r = m0 + g, c = kc*16 + tg*2;
        float2 v0 = *(const float2*)&Qg[(size_t)r*64 + c];
        float2 v1 = *(const float2*)&Qg[(size_t)(r+8)*64 + c];
        float2 v2 = *(const float2*)&Qg[(size_t)r*64 + c + 8];
        float2 v3 = *(const float2*)&Qg[(size_t)(r+8)*64 + c + 8];
        unsigned aH[4], aL[4]; float lx, ly;
        aH[0] = pack_hi_h(v0.x, v0.y, lx, ly); aL[0] = pack_h2(lx, ly);
        aH[1] = pack_hi_h(v1.x, v1.y, lx, ly); aL[1] = pack_h2(lx, ly);
        aH[2] = pack_hi_h(v2.x, v2.y, lx, ly); aL[2] = pack_h2(lx, ly);
        aH[3] = pack_hi_h(v3.x, v3.y, lx, ly); aL[3] = pack_h2(lx, ly);
        #pragma unroll
        for (int q = 0; q < 8; q++){
            unsigned kOff = (unsigned)((q*16 + (t8>>1)*8 + i8)*KLRS + (t8&1)*16 + kc*32);
            unsigned bH[4];
            ldsm4(bH[0],bH[1],bH[2],bH[3], smb + 0*K1MAT + kOff);
            mma16816h(st[2*q],   aH, bH);
            mma16816h(st[2*q+1], aH, bH+2);
            mma16816h(st[2*q],   aL, bH);
            mma16816h(st[2*q+1], aL, bH+2);
        }
    }

    float mx0 = -1e30f, mx1 = -1e30f;
    #pragma unroll
    for (int nt = 0; nt < 16; nt++){
        mx0 = fmaxf(mx0, fmaxf(st[nt][0], st[nt][1]));
        mx1 = fmaxf(mx1, fmaxf(st[nt][2], st[nt][3]));
    }
    mx0 = fmaxf(mx0, __shfl_xor_sync(0xffffffffu, mx0, 1));
    mx0 = fmaxf(mx0, __shfl_xor_sync(0xffffffffu, mx0, 2));
    mx1 = fmaxf(mx1, __shfl_xor_sync(0xffffffffu, mx1, 1));
    mx1 = fmaxf(mx1, __shfl_xor_sync(0xffffffffu, mx1, 2));
    float z0 = 0.f, z1 = 0.f;
    #pragma unroll
    for (int nt = 0; nt < 16; nt++){
        st[nt][0] = __expf(st[nt][0] - mx0);
        st[nt][1] = __expf(st[nt][1] - mx0);
        st[nt][2] = __expf(st[nt][2] - mx1);
        st[nt][3] = __expf(st[nt][3] - mx1);
        z0 += st[nt][0] + st[nt][1];
        z1 += st[nt][2] + st[nt][3];
    }
    z0 += __shfl_xor_sync(0xffffffffu, z0, 1);
    z0 += __shfl_xor_sync(0xffffffffu, z0, 2);
    z1 += __shfl_xor_sync(0xffffffffu, z1, 1);
    z1 += __shfl_xor_sync(0xffffffffu, z1, 2);
    float zi0 = 1.f/z0, zi1 = 1.f/z1;
    #pragma unroll
    for (int nt = 0; nt < 16; nt++){
        st[nt][0] *= zi0; st[nt][1] *= zi0;
        st[nt][2] *= zi1; st[nt][3] *= zi1;
    }

    float o[8][4];
    #pragma unroll
    for (int j=0;j<8;j++)
        #pragma unroll
        for (int e=0;e<4;e++) o[j][e] = 0.f;

    #pragma unroll
    for (int kc = 0; kc < 8; kc++){
        unsigned aH[4], aL[4]; float lx, ly;
        aH[0] = pack_hi_h(st[2*kc][0],   st[2*kc][1],   lx, ly); aL[0] = pack_h2(lx, ly);
        aH[1] = pack_hi_h(st[2*kc][2],   st[2*kc][3],   lx, ly); aL[1] = pack_h2(lx, ly);
        aH[2] = pack_hi_h(st[2*kc+1][0], st[2*kc+1][1], lx, ly); aL[2] = pack_h2(lx, ly);
        aH[3] = pack_hi_h(st[2*kc+1][2], st[2*kc+1][3], lx, ly); aL[3] = pack_h2(lx, ly);
        #pragma unroll
        for (int q = 0; q < 4; q++){
            unsigned wOff = (unsigned)(((t8&1)*8 + i8 + kc*16)*KLRS + (q*16 + (t8>>1)*8)*2);
            unsigned bH[4];
            ldsm4t(bH[0],bH[1],bH[2],bH[3], smb + 1*K1MAT + wOff);
            mma16816h(o[2*q],   aH, bH);
            mma16816h(o[2*q+1], aH, bH+2);
            mma16816h(o[2*q],   aL, bH);
            mma16816h(o[2*q+1], aL, bH+2);
        }
    }

    int b = bh >> 4, h = bh & 15;
    #pragma unroll
    for (int half = 0; half < 2; half++){
        int sI = sblk*128 + m0 + g + half*8;
        size_t obase = ((size_t)(b*S_ + sI))*D_ + h*64;
        #pragma unroll
        for (int nt = 0; nt < 8; nt++){
            int d = nt*8 + tg*2;
            __half hv[2] = {__float2half_rn(o[nt][half*2]), __float2half_rn(o[nt][half*2+1])};
            *(unsigned*)&g_ctxh[obase + d] = *(unsigned*)hv;
        }
    }
}

// ---------------- launch -------------------------------------------------------
extern "C" void kernel_launch(void* const* d_in, const int* in_sizes, int n_in,
                              void* d_out, int out_size)
{
    const float* X    = (const float*)d_in[0];
    const float* mask = (const float*)d_in[1];
    const float* Wq   = (const float*)d_in[2];
    const float* bq   = (const float*)d_in[3];
    const float* Wk   = (const float*)d_in[4];
    const float* bk   = (const float*)d_in[5];
    const float* Wv   = (const float*)d_in[6];
    const float* bv   = (const float*)d_in[7];
    const float* Wo   = (const float*)d_in[8];
    const float* bo   = (const float*)d_in[9];
    float* out = (float*)d_out;

    void *pQ, *pK, *pV;
    cudaGetSymbolAddress(&pQ, g_Q);
    cudaGetSymbolAddress(&pK, g_K);
    cudaGetSymbolAddress(&pV, g_V);

    cudaFuncSetAttribute(gemm_qkv, cudaFuncAttributeMaxDynamicSharedMemorySize, GSMEM);
    cudaFuncSetAttribute(gemm_out, cudaFuncAttributeMaxDynamicSharedMemorySize, GSMEM);
    cudaFuncSetAttribute(inv_kernel, cudaFuncAttributeMaxDynamicSharedMemorySize, INV_SMEM);
    cudaFuncSetAttribute(k1_kernel,  cudaFuncAttributeMaxDynamicSharedMemorySize, K1_SMEM);
    cudaFuncSetAttribute(k3_mma,     cudaFuncAttributeMaxDynamicSharedMemorySize, K3_SMEM);

    convX_kernel<<<8192, 256>>>(X);                       // 1
    convW_kernel<<<dim3(32,32,4), 256>>>(Wq, Wk, Wv, Wo); // 2
    probe_kernel<<<1, 32>>>();                            // 3
    gemm_qkv<<<dim3(24,64), 256, GSMEM>>>(bq, bk, bv, mask,
                                          (float*)pQ, (float*)pK, (float*)pV); // 4 <- ncu

    landmark_kernel<<<(BH_*NL_*HD_)/256, 256>>>();
    k2_kernel<<<dim3(NL_, BH_), 128>>>();
    colmax_kernel<<<BH_, 128>>>();
    k3_mma<<<dim3(8, BH_), 256, K3_SMEM>>>(mask);
    k3_combine<<<BH_, 128>>>();
    inv_kernel<<<BH_, 512, INV_SMEM>>>();
    k1_kernel<<<dim3(32, BH_), 256, K1_SMEM>>>();

    gemm_out<<<dim3(8,64), 256, GSMEM>>>(bo, out);
}